// round 1
// baseline (speedup 1.0000x reference)
#include <cuda_runtime.h>
#include <math.h>

// Problem constants
#define TOK   8192        // B*N
#define DIMC  1024
#define EXPC  7168        // 3*DIM + 4*DIM
#define CINC  5120        // DIM + 4*DIM
#define NHC   16
#define HDC   64
#define SEQC  1024
#define NB    8

// Scratch (device globals; allocation-free)
__device__ float g_xn[(size_t)TOK * DIMC];                    //  32 MB
__device__ float g_y [(size_t)TOK * EXPC];                    // 235 MB
__device__ float g_s [(size_t)NB * NHC * SEQC * SEQC];        // 537 MB
__device__ float g_h [(size_t)TOK * CINC];                    // 168 MB
__device__ float g_z [(size_t)TOK * 2 * DIMC];                //  67 MB

// ---------------------------------------------------------------------------
// LayerNorm 1: xn = LN(x)*g + b, masked to d_in columns. One block per token.
// ---------------------------------------------------------------------------
__global__ void ln1_kernel(const float* __restrict__ x, const int* __restrict__ em,
                           const float* __restrict__ g, const float* __restrict__ b) {
    int t = blockIdx.x;
    const float* xr = x + (size_t)t * DIMC;
    int tid = threadIdx.x;
    float v[4]; float s = 0.f, s2 = 0.f;
#pragma unroll
    for (int i = 0; i < 4; i++) { float a = xr[tid + 256 * i]; v[i] = a; s += a; s2 += a * a; }
#pragma unroll
    for (int o = 16; o; o >>= 1) { s += __shfl_xor_sync(0xffffffffu, s, o); s2 += __shfl_xor_sync(0xffffffffu, s2, o); }
    __shared__ float red[18];
    int w = tid >> 5, l = tid & 31;
    if (l == 0) { red[w] = s; red[8 + w] = s2; }
    __syncthreads();
    if (tid == 0) {
        float ts = 0.f, ts2 = 0.f;
        for (int i = 0; i < 8; i++) { ts += red[i]; ts2 += red[8 + i]; }
        float m = ts * (1.f / DIMC);
        float var = ts2 * (1.f / DIMC) - m * m;
        red[16] = m; red[17] = rsqrtf(var + 1e-5f);
    }
    __syncthreads();
    float m = red[16], rs = red[17];
    int din = DIMC >> (3 - em[t]);
    float* o = g_xn + (size_t)t * DIMC;
#pragma unroll
    for (int i = 0; i < 4; i++) {
        int c = tid + 256 * i;
        float val = (v[i] - m) * rs * g[c] + b[c];
        o[c] = (c < din) ? val : 0.f;
    }
}

// ---------------------------------------------------------------------------
// LayerNorm 2: in-place LN of y[:, DIM:2*DIM] (k) and y[:, 2*DIM:3*DIM] (v).
// grid (TOK, 2); block 256.
// ---------------------------------------------------------------------------
__global__ void ln2_kernel(const float* __restrict__ g, const float* __restrict__ b) {
    int t = blockIdx.x;
    float* row = g_y + (size_t)t * EXPC + (size_t)DIMC * (1 + blockIdx.y);
    int tid = threadIdx.x;
    float v[4]; float s = 0.f, s2 = 0.f;
#pragma unroll
    for (int i = 0; i < 4; i++) { float a = row[tid + 256 * i]; v[i] = a; s += a; s2 += a * a; }
#pragma unroll
    for (int o = 16; o; o >>= 1) { s += __shfl_xor_sync(0xffffffffu, s, o); s2 += __shfl_xor_sync(0xffffffffu, s2, o); }
    __shared__ float red[18];
    int w = tid >> 5, l = tid & 31;
    if (l == 0) { red[w] = s; red[8 + w] = s2; }
    __syncthreads();
    if (tid == 0) {
        float ts = 0.f, ts2 = 0.f;
        for (int i = 0; i < 8; i++) { ts += red[i]; ts2 += red[8 + i]; }
        float m = ts * (1.f / DIMC);
        float var = ts2 * (1.f / DIMC) - m * m;
        red[16] = m; red[17] = rsqrtf(var + 1e-5f);
    }
    __syncthreads();
    float m = red[16], rs = red[17];
#pragma unroll
    for (int i = 0; i < 4; i++) {
        int c = tid + 256 * i;
        row[c] = (v[i] - m) * rs * g[c] + b[c];
    }
}

// ---------------------------------------------------------------------------
// Generic tiled SGEMM: C[m][n] = scale * sum_k A[m][k] * Bop[n][k]
//   BTN=true : B stored [N][K] (row-major, K contiguous)   -> TN
//   BTN=false: B stored [K][N] (row-major, N contiguous)   -> NN
// Two-level batch: z = zb*inner + zi, pointer offsets via (saO,saI) etc.
// All of M,N multiples of BM,BN; K multiple of 8. BK=8, 8x8 micro-tile.
// ---------------------------------------------------------------------------
template<int BM, int BN, bool BTN>
__global__ void __launch_bounds__((BM / 8) * (BN / 8))
gemm_kernel(const float* __restrict__ A, int lda, size_t saO, size_t saI,
            const float* __restrict__ B, int ldb, size_t sbO, size_t sbI,
            float* __restrict__ C, int ldc, size_t scO, size_t scI,
            int inner, int K, float scale) {
    constexpr int NT = (BM / 8) * (BN / 8);
    int zb = blockIdx.z / inner, zi = blockIdx.z % inner;
    const float* Ap = A + (size_t)zb * saO + (size_t)zi * saI + (size_t)(blockIdx.y * BM) * lda;
    const float* Bp = B + (size_t)zb * sbO + (size_t)zi * sbI;
    float* Cp = C + (size_t)zb * scO + (size_t)zi * scI
                  + (size_t)(blockIdx.y * BM) * ldc + (size_t)blockIdx.x * BN;
    int n0 = blockIdx.x * BN;

    __shared__ float As[8][BM + 4];
    __shared__ float Bs[8][BN + 4];
    float acc[8][8] = {};
    int tid = threadIdx.x;
    int tx = tid % (BN / 8), ty = tid / (BN / 8);

    for (int k0 = 0; k0 < K; k0 += 8) {
        // A tile -> As[k][m] (transpose on the fly)
        for (int i = tid; i < BM * 2; i += NT) {
            int row = i >> 1, cg = (i & 1) * 4;
            float4 va = *(const float4*)(Ap + (size_t)row * lda + k0 + cg);
            As[cg + 0][row] = va.x; As[cg + 1][row] = va.y;
            As[cg + 2][row] = va.z; As[cg + 3][row] = va.w;
        }
        if constexpr (BTN) {
            for (int i = tid; i < BN * 2; i += NT) {
                int row = i >> 1, cg = (i & 1) * 4;
                float4 vb = *(const float4*)(Bp + (size_t)(n0 + row) * ldb + k0 + cg);
                Bs[cg + 0][row] = vb.x; Bs[cg + 1][row] = vb.y;
                Bs[cg + 2][row] = vb.z; Bs[cg + 3][row] = vb.w;
            }
        } else {
            for (int i = tid; i < BN * 2; i += NT) {
                int kr = i / (BN / 4), cg = (i % (BN / 4)) * 4;
                *(float4*)(&Bs[kr][cg]) = *(const float4*)(Bp + (size_t)(k0 + kr) * ldb + n0 + cg);
            }
        }
        __syncthreads();
#pragma unroll
        for (int kk = 0; kk < 8; kk++) {
            float a[8], bv[8];
            *(float4*)(a)     = *(const float4*)(&As[kk][ty * 8]);
            *(float4*)(a + 4) = *(const float4*)(&As[kk][ty * 8 + 4]);
            *(float4*)(bv)     = *(const float4*)(&Bs[kk][tx * 8]);
            *(float4*)(bv + 4) = *(const float4*)(&Bs[kk][tx * 8 + 4]);
#pragma unroll
            for (int i = 0; i < 8; i++)
#pragma unroll
                for (int j = 0; j < 8; j++)
                    acc[i][j] = fmaf(a[i], bv[j], acc[i][j]);
        }
        __syncthreads();
    }
#pragma unroll
    for (int i = 0; i < 8; i++) {
        float4 o0, o1;
        o0.x = acc[i][0] * scale; o0.y = acc[i][1] * scale;
        o0.z = acc[i][2] * scale; o0.w = acc[i][3] * scale;
        o1.x = acc[i][4] * scale; o1.y = acc[i][5] * scale;
        o1.z = acc[i][6] * scale; o1.w = acc[i][7] * scale;
        float* cr = Cp + (size_t)(ty * 8 + i) * ldc + tx * 8;
        *(float4*)cr = o0; *(float4*)(cr + 4) = o1;
    }
}

// ---------------------------------------------------------------------------
// Row softmax over g_s (131072 rows of 1024). One block per row.
// ---------------------------------------------------------------------------
__global__ void softmax_kernel() {
    float* row = g_s + (size_t)blockIdx.x * SEQC;
    int tid = threadIdx.x;
    float v[4];
    float mx = -1e30f;
#pragma unroll
    for (int i = 0; i < 4; i++) { v[i] = row[tid + 256 * i]; mx = fmaxf(mx, v[i]); }
#pragma unroll
    for (int o = 16; o; o >>= 1) mx = fmaxf(mx, __shfl_xor_sync(0xffffffffu, mx, o));
    __shared__ float red[10];
    int w = tid >> 5, l = tid & 31;
    if (l == 0) red[w] = mx;
    __syncthreads();
    if (tid == 0) {
        float m = red[0];
        for (int i = 1; i < 8; i++) m = fmaxf(m, red[i]);
        red[8] = m;
    }
    __syncthreads();
    mx = red[8];
    float s = 0.f;
#pragma unroll
    for (int i = 0; i < 4; i++) { v[i] = __expf(v[i] - mx); s += v[i]; }
#pragma unroll
    for (int o = 16; o; o >>= 1) s += __shfl_xor_sync(0xffffffffu, s, o);
    if (l == 0) red[w] = s;
    __syncthreads();
    if (tid == 0) {
        float ts = 0.f;
        for (int i = 0; i < 8; i++) ts += red[i];
        red[9] = 1.f / ts;
    }
    __syncthreads();
    float inv = red[9];
#pragma unroll
    for (int i = 0; i < 4; i++) row[tid + 256 * i] = v[i] * inv;
}

// ---------------------------------------------------------------------------
// GELU(exact) of mlp_hidden + bias -> g_h[:, DIM:CIN]
// ---------------------------------------------------------------------------
__global__ void gelu_kernel(const float* __restrict__ mlpb) {
    size_t idx = (size_t)blockIdx.x * 256 + threadIdx.x;
    int t = (int)(idx >> 12);
    int j = (int)(idx & 4095);
    float xv = g_y[(size_t)t * EXPC + 3 * DIMC + j] + mlpb[j];
    g_h[(size_t)t * CINC + DIMC + j] = 0.5f * xv * (1.f + erff(xv * 0.70710678118654752f));
}

// ---------------------------------------------------------------------------
// Final epilogue: mask z by d_out, residual, router scaling.
// ---------------------------------------------------------------------------
__global__ void final_kernel(const float* __restrict__ x, const int* __restrict__ em,
                             const float* __restrict__ rp, const float* __restrict__ cb,
                             const float* __restrict__ alpha, float* __restrict__ out) {
    size_t idx = (size_t)blockIdx.x * 256 + threadIdx.x;
    int t = (int)(idx >> 10);
    int d = (int)(idx & 1023);
    int m = em[t];
    int dout = (2 * DIMC) >> (3 - m);
    const float* zr = g_z + (size_t)t * 2 * DIMC;
    float za = (d < dout) ? (zr[d] + cb[d]) : 0.f;
    float zm = (DIMC + d < dout) ? (zr[DIMC + d] + cb[DIMC + d]) : 0.f;
    float pr = rp[t * 4 + m];
    out[idx] = x[idx] + za + (alpha[0] * pr + 1.f) * zm;
}

// Pass-through outputs 2 and 3 (expert_mask as float, router_probs).
__global__ void tail_kernel(const int* __restrict__ em, const float* __restrict__ rp,
                            float* __restrict__ out) {
    int i = blockIdx.x * 256 + threadIdx.x;
    if (i < TOK)     out[(size_t)TOK * DIMC + i] = (float)em[i];
    if (i < TOK * 4) out[(size_t)TOK * DIMC + TOK + i] = rp[i];
}

// ---------------------------------------------------------------------------
extern "C" void kernel_launch(void* const* d_in, const int* in_sizes, int n_in,
                              void* d_out, int out_size) {
    const float* x     = (const float*)d_in[0];
    const int*   em    = (const int*)d_in[1];
    const float* rp    = (const float*)d_in[2];
    const float* wexp  = (const float*)d_in[3];
    const float* mlpb  = (const float*)d_in[4];
    const float* wc    = (const float*)d_in[5];
    const float* cb    = (const float*)d_in[6];
    const float* n1g   = (const float*)d_in[7];
    const float* n1b   = (const float*)d_in[8];
    const float* n2g   = (const float*)d_in[9];
    const float* n2b   = (const float*)d_in[10];
    const float* alpha = (const float*)d_in[11];
    float* out = (float*)d_out;

    float *p_xn, *p_y, *p_s, *p_h, *p_z;
    cudaGetSymbolAddress((void**)&p_xn, g_xn);
    cudaGetSymbolAddress((void**)&p_y,  g_y);
    cudaGetSymbolAddress((void**)&p_s,  g_s);
    cudaGetSymbolAddress((void**)&p_h,  g_h);
    cudaGetSymbolAddress((void**)&p_z,  g_z);

    // 1) LN1 + input mask
    ln1_kernel<<<TOK, 256>>>(x, em, n1g, n1b);

    // 2) y = xn @ Wexp^T  (M=8192, N=7168, K=1024, TN)
    gemm_kernel<128, 128, true><<<dim3(EXPC / 128, TOK / 128, 1), 256>>>(
        p_xn, DIMC, 0, 0,
        wexp, DIMC, 0, 0,
        p_y, EXPC, 0, 0,
        1, DIMC, 1.f);

    // 3) LN2 on k and v columns (in place)
    ln2_kernel<<<dim3(TOK, 2), 256>>>(n2g, n2b);

    // 4) attention scores: S = scale * Q K^T per (b,h). batch=128, M=N=1024, K=64.
    gemm_kernel<128, 128, true><<<dim3(SEQC / 128, SEQC / 128, NB * NHC), 256>>>(
        p_y,        EXPC, (size_t)SEQC * EXPC, (size_t)HDC,
        p_y + DIMC, EXPC, (size_t)SEQC * EXPC, (size_t)HDC,
        p_s,        SEQC, (size_t)NHC * SEQC * SEQC, (size_t)SEQC * SEQC,
        NHC, HDC, 0.125f);

    // 5) row softmax
    softmax_kernel<<<NB * NHC * SEQC, 256>>>();

    // 6) GELU(mlp_hidden + bias) -> h[:, 1024:5120]
    gelu_kernel<<<(TOK * 4096) / 256, 256>>>(mlpb);

    // 7) attn_out = P @ V per (b,h) -> h[:, 0:1024]. batch=128, M=1024, N=64, K=1024, NN.
    gemm_kernel<128, 64, false><<<dim3(1, SEQC / 128, NB * NHC), 128>>>(
        p_s,            SEQC, (size_t)NHC * SEQC * SEQC, (size_t)SEQC * SEQC,
        p_y + 2 * DIMC, EXPC, (size_t)SEQC * EXPC, (size_t)HDC,
        p_h,            CINC, (size_t)SEQC * CINC, (size_t)HDC,
        NHC, SEQC, 1.f);

    // 8) z = h @ Wc^T  (M=8192, N=2048, K=5120, TN)
    gemm_kernel<128, 128, true><<<dim3(2 * DIMC / 128, TOK / 128, 1), 256>>>(
        p_h, CINC, 0, 0,
        wc, CINC, 0, 0,
        p_z, 2 * DIMC, 0, 0,
        1, CINC, 1.f);

    // 9) epilogue + pass-through outputs
    final_kernel<<<(TOK * DIMC) / 256, 256>>>(x, em, rp, cb, alpha, out);
    tail_kernel<<<(TOK * 4 + 255) / 256, 256>>>(em, rp, out);
}

// round 3
// speedup vs baseline: 2.5209x; 2.5209x over previous
#include <cuda_runtime.h>
#include <cuda_bf16.h>
#include <math.h>
#include <stdint.h>

// Problem constants
#define TOK   8192        // B*N
#define DIMC  1024
#define EXPC  7168        // 3*DIM + 4*DIM
#define CINC  5120        // DIM + 4*DIM
#define NHC   16
#define HDC   64
#define SEQC  1024
#define NB    8

// ---------------------------------------------------------------------------
// Scratch (device globals; allocation-free)
// ---------------------------------------------------------------------------
__device__ float g_y [(size_t)TOK * EXPC];                    // 235 MB
__device__ float g_s [(size_t)NB * NHC * SEQC * SEQC];        // 537 MB
__device__ float g_z [(size_t)TOK * 2 * DIMC];                //  67 MB
__device__ float g_hattn[(size_t)TOK * DIMC];                 //  32 MB

__device__ __nv_bfloat16 g_xn_hi[(size_t)TOK * DIMC];
__device__ __nv_bfloat16 g_xn_lo[(size_t)TOK * DIMC];
__device__ __nv_bfloat16 g_we_hi[(size_t)EXPC * DIMC];
__device__ __nv_bfloat16 g_we_lo[(size_t)EXPC * DIMC];
__device__ __nv_bfloat16 g_wc_hi[(size_t)2 * DIMC * CINC];
__device__ __nv_bfloat16 g_wc_lo[(size_t)2 * DIMC * CINC];
__device__ __nv_bfloat16 g_h_hi[(size_t)TOK * CINC];
__device__ __nv_bfloat16 g_h_lo[(size_t)TOK * CINC];

// ---------------------------------------------------------------------------
// PTX helpers (sm_80-level features only: ldmatrix / mma / cp.async)
// ---------------------------------------------------------------------------
__device__ __forceinline__ uint32_t smem_u32(const void* p) {
    uint32_t a;
    asm("{ .reg .u64 t; cvta.to.shared.u64 t, %1; cvt.u32.u64 %0, t; }" : "=r"(a) : "l"(p));
    return a;
}
__device__ __forceinline__ void ldsm4(uint32_t* r, uint32_t a) {
    asm volatile("ldmatrix.sync.aligned.m8n8.x4.shared.b16 {%0,%1,%2,%3}, [%4];"
                 : "=r"(r[0]), "=r"(r[1]), "=r"(r[2]), "=r"(r[3]) : "r"(a));
}
__device__ __forceinline__ void mma16816(float* c, const uint32_t* a, const uint32_t* b) {
    asm volatile("mma.sync.aligned.m16n8k16.row.col.f32.bf16.bf16.f32 "
                 "{%0,%1,%2,%3}, {%4,%5,%6,%7}, {%8,%9}, {%0,%1,%2,%3};"
                 : "+f"(c[0]), "+f"(c[1]), "+f"(c[2]), "+f"(c[3])
                 : "r"(a[0]), "r"(a[1]), "r"(a[2]), "r"(a[3]), "r"(b[0]), "r"(b[1]));
}
__device__ __forceinline__ void cpa16(uint32_t s, const void* g) {
    asm volatile("cp.async.cg.shared.global [%0], [%1], 16;" :: "r"(s), "l"(g));
}
#define CP_COMMIT() asm volatile("cp.async.commit_group;")
#define CP_WAIT1()  asm volatile("cp.async.wait_group 1;")
#define CP_WAIT0()  asm volatile("cp.async.wait_group 0;")

// SW128 swizzle (byte offsets within a tile of 128-byte rows)
#define SWZ(o) ((o) ^ (((o) >> 3) & 0x70))

// ---------------------------------------------------------------------------
// bf16-split HMMA GEMM: C[M][N] = sum_k A[m][k]*B[n][k]  (TN; A,B as hi+lo)
// CTA tile 128x128, warp tile 32x64, K-chunk 64, double-buffered cp.async.
// grid = (N/128, M/128), 256 threads.
// ---------------------------------------------------------------------------
#define OFF_AH 0
#define OFF_AL 16384
#define OFF_BH 32768
#define OFF_BL 49152
#define BUFSZ  65536
#define GSMEM  (2 * BUFSZ + 1024)

__global__ void __launch_bounds__(256)
gemm_mma_kernel(const __nv_bfloat16* __restrict__ Ah, const __nv_bfloat16* __restrict__ Al,
                const __nv_bfloat16* __restrict__ Bh, const __nv_bfloat16* __restrict__ Bl,
                float* __restrict__ C, int N, int K) {
    extern __shared__ char smem_raw[];
    uint32_t sb = smem_u32(smem_raw);
    sb = (sb + 1023u) & ~1023u;

    const int tid  = threadIdx.x;
    const int wid  = tid >> 5;
    const int lane = tid & 31;
    const int wm = wid & 3;        // warp m index (0..3) -> m offset 32*wm
    const int wn = wid >> 2;       // warp n index (0..1) -> n offset 64*wn

    const int m0 = blockIdx.y * 128;
    const int n0 = blockIdx.x * 128;
    const __nv_bfloat16* ABh = Ah + (size_t)m0 * K;
    const __nv_bfloat16* ABl = Al + (size_t)m0 * K;
    const __nv_bfloat16* BBh = Bh + (size_t)n0 * K;
    const __nv_bfloat16* BBl = Bl + (size_t)n0 * K;

    // per-thread load mapping (8 A-vectors + 8 B-vectors of 16B per chunk)
    const int l_r  = tid >> 1;              // row 0..127 for it-strided scheme below
    // We use: i = tid + it*256, i in [0,2048): r=i>>4, rem=i&15, hl=rem>>3, kg=rem&7
    // (computed inline in the loop)

    const int NC = K / 64;

    // prologue: load chunk 0 into buffer 0
    {
        uint32_t bufb = sb;
#pragma unroll
        for (int it = 0; it < 8; it++) {
            int i = tid + it * 256;
            int r = i >> 4, rem = i & 15, hl = rem >> 3, kg = rem & 7;
            const __nv_bfloat16* src = (hl ? ABl : ABh) + (size_t)r * K + kg * 8;
            cpa16(bufb + (hl ? OFF_AL : OFF_AH) + SWZ(r * 128 + kg * 16), src);
        }
#pragma unroll
        for (int it = 0; it < 8; it++) {
            int i = tid + it * 256;
            int r = i >> 4, rem = i & 15, hl = rem >> 3, kg = rem & 7;
            const __nv_bfloat16* src = (hl ? BBl : BBh) + (size_t)r * K + kg * 8;
            cpa16(bufb + (hl ? OFF_BL : OFF_BH) + SWZ(r * 128 + kg * 16), src);
        }
        CP_COMMIT();
    }

    float acc[2][8][4];
#pragma unroll
    for (int i = 0; i < 2; i++)
#pragma unroll
        for (int j = 0; j < 8; j++)
#pragma unroll
            for (int k = 0; k < 4; k++) acc[i][j][k] = 0.f;

    // ldmatrix lane addressing (precomputed pieces)
    const int a_r16 = lane & 15;               // row within 16-row tile
    const int a_kb  = (lane >> 4) * 16;        // 0 or 16 bytes (k half)
    const int b_r8  = ((lane >> 4) << 3) + (lane & 7);   // row within 16 (two n8 tiles)
    const int b_kb  = ((lane >> 3) & 1) * 16;  // 0/16 bytes alternating per 8 lanes

    (void)l_r;

    for (int c = 0; c < NC; c++) {
        if (c + 1 < NC) {
            uint32_t bufb = sb + ((c + 1) & 1) * BUFSZ;
            int k0 = (c + 1) * 64;
#pragma unroll
            for (int it = 0; it < 8; it++) {
                int i = tid + it * 256;
                int r = i >> 4, rem = i & 15, hl = rem >> 3, kg = rem & 7;
                const __nv_bfloat16* src = (hl ? ABl : ABh) + (size_t)r * K + k0 + kg * 8;
                cpa16(bufb + (hl ? OFF_AL : OFF_AH) + SWZ(r * 128 + kg * 16), src);
            }
#pragma unroll
            for (int it = 0; it < 8; it++) {
                int i = tid + it * 256;
                int r = i >> 4, rem = i & 15, hl = rem >> 3, kg = rem & 7;
                const __nv_bfloat16* src = (hl ? BBl : BBh) + (size_t)r * K + k0 + kg * 8;
                cpa16(bufb + (hl ? OFF_BL : OFF_BH) + SWZ(r * 128 + kg * 16), src);
            }
            CP_COMMIT();
            CP_WAIT1();
        } else {
            CP_WAIT0();
        }
        __syncthreads();

        uint32_t bufb = sb + (c & 1) * BUFSZ;
#pragma unroll
        for (int kk = 0; kk < 4; kk++) {
            int kb = kk * 32;  // byte offset of this k16 within the 128B row
            uint32_t ah[2][4], al[2][4];
#pragma unroll
            for (int mt = 0; mt < 2; mt++) {
                int r = wm * 32 + mt * 16 + a_r16;
                uint32_t off = (uint32_t)(r * 128) + (uint32_t)((kb + a_kb) ^ ((r & 7) << 4));
                ldsm4(ah[mt], bufb + OFF_AH + off);
                ldsm4(al[mt], bufb + OFF_AL + off);
            }
#pragma unroll
            for (int ntp = 0; ntp < 4; ntp++) {
                int r = wn * 64 + ntp * 16 + b_r8;
                uint32_t off = (uint32_t)(r * 128) + (uint32_t)((kb + b_kb) ^ ((r & 7) << 4));
                uint32_t bh[4], bl[4];
                ldsm4(bh, bufb + OFF_BH + off);
                ldsm4(bl, bufb + OFF_BL + off);
#pragma unroll
                for (int mt = 0; mt < 2; mt++) {
                    mma16816(acc[mt][2 * ntp],     ah[mt], bh);
                    mma16816(acc[mt][2 * ntp],     ah[mt], bl);
                    mma16816(acc[mt][2 * ntp],     al[mt], bh);
                    mma16816(acc[mt][2 * ntp + 1], ah[mt], bh + 2);
                    mma16816(acc[mt][2 * ntp + 1], ah[mt], bl + 2);
                    mma16816(acc[mt][2 * ntp + 1], al[mt], bh + 2);
                }
            }
        }
        __syncthreads();
    }

    // Epilogue: write fp32 C
    const int g = lane >> 2, t4 = lane & 3;
#pragma unroll
    for (int mt = 0; mt < 2; mt++) {
        int mrow = m0 + wm * 32 + mt * 16;
#pragma unroll
        for (int nt = 0; nt < 8; nt++) {
            int ncol = n0 + wn * 64 + nt * 8 + t4 * 2;
            float2 v0 = make_float2(acc[mt][nt][0], acc[mt][nt][1]);
            float2 v1 = make_float2(acc[mt][nt][2], acc[mt][nt][3]);
            *(float2*)(C + (size_t)(mrow + g) * N + ncol)     = v0;
            *(float2*)(C + (size_t)(mrow + g + 8) * N + ncol) = v1;
        }
    }
}

// ---------------------------------------------------------------------------
// fp32 -> bf16 hi/lo split helpers
// ---------------------------------------------------------------------------
__device__ __forceinline__ void split1(float x, __nv_bfloat16& h, __nv_bfloat16& l) {
    h = __float2bfloat16(x);
    l = __float2bfloat16(x - __bfloat162float(h));
}

__global__ void split4_kernel(const float* __restrict__ s,
                              __nv_bfloat16* __restrict__ hi, __nv_bfloat16* __restrict__ lo) {
    size_t i = (size_t)blockIdx.x * 256 + threadIdx.x;
    float4 v = ((const float4*)s)[i];
    __nv_bfloat16 h0, h1, h2, h3, l0, l1, l2, l3;
    split1(v.x, h0, l0); split1(v.y, h1, l1); split1(v.z, h2, l2); split1(v.w, h3, l3);
    __nv_bfloat162* H = (__nv_bfloat162*)hi;
    __nv_bfloat162* L = (__nv_bfloat162*)lo;
    H[2 * i] = __nv_bfloat162(h0, h1); H[2 * i + 1] = __nv_bfloat162(h2, h3);
    L[2 * i] = __nv_bfloat162(l0, l1); L[2 * i + 1] = __nv_bfloat162(l2, l3);
}

__global__ void split_hattn_kernel() {
    size_t i = (size_t)blockIdx.x * 256 + threadIdx.x;  // uint4 index
    int t = (int)(i >> 8);
    int j = (int)(i & 255) * 4;
    float4 v = ((const float4*)g_hattn)[i];
    size_t o = (size_t)t * CINC + j;
    __nv_bfloat16 h0, h1, h2, h3, l0, l1, l2, l3;
    split1(v.x, h0, l0); split1(v.y, h1, l1); split1(v.z, h2, l2); split1(v.w, h3, l3);
    *(__nv_bfloat162*)(g_h_hi + o)     = __nv_bfloat162(h0, h1);
    *(__nv_bfloat162*)(g_h_hi + o + 2) = __nv_bfloat162(h2, h3);
    *(__nv_bfloat162*)(g_h_lo + o)     = __nv_bfloat162(l0, l1);
    *(__nv_bfloat162*)(g_h_lo + o + 2) = __nv_bfloat162(l2, l3);
}

// ---------------------------------------------------------------------------
// LayerNorm 1 -> masked xn as bf16 hi/lo
// ---------------------------------------------------------------------------
__global__ void ln1_kernel(const float* __restrict__ x, const int* __restrict__ em,
                           const float* __restrict__ g, const float* __restrict__ b) {
    int t = blockIdx.x;
    const float* xr = x + (size_t)t * DIMC;
    int tid = threadIdx.x;
    float v[4]; float s = 0.f, s2 = 0.f;
#pragma unroll
    for (int i = 0; i < 4; i++) { float a = xr[tid + 256 * i]; v[i] = a; s += a; s2 += a * a; }
#pragma unroll
    for (int o = 16; o; o >>= 1) { s += __shfl_xor_sync(0xffffffffu, s, o); s2 += __shfl_xor_sync(0xffffffffu, s2, o); }
    __shared__ float red[18];
    int w = tid >> 5, l = tid & 31;
    if (l == 0) { red[w] = s; red[8 + w] = s2; }
    __syncthreads();
    if (tid == 0) {
        float ts = 0.f, ts2 = 0.f;
        for (int i = 0; i < 8; i++) { ts += red[i]; ts2 += red[8 + i]; }
        float m = ts * (1.f / DIMC);
        float var = ts2 * (1.f / DIMC) - m * m;
        red[16] = m; red[17] = rsqrtf(var + 1e-5f);
    }
    __syncthreads();
    float m = red[16], rs = red[17];
    int din = DIMC >> (3 - em[t]);
#pragma unroll
    for (int i = 0; i < 4; i++) {
        int c = tid + 256 * i;
        float val = (v[i] - m) * rs * g[c] + b[c];
        val = (c < din) ? val : 0.f;
        __nv_bfloat16 h, lo; split1(val, h, lo);
        g_xn_hi[(size_t)t * DIMC + c] = h;
        g_xn_lo[(size_t)t * DIMC + c] = lo;
    }
}

// ---------------------------------------------------------------------------
// LayerNorm 2: in-place LN of y[:, DIM:2*DIM] (k) and y[:, 2*DIM:3*DIM] (v).
// ---------------------------------------------------------------------------
__global__ void ln2_kernel(const float* __restrict__ g, const float* __restrict__ b) {
    int t = blockIdx.x;
    float* row = g_y + (size_t)t * EXPC + (size_t)DIMC * (1 + blockIdx.y);
    int tid = threadIdx.x;
    float v[4]; float s = 0.f, s2 = 0.f;
#pragma unroll
    for (int i = 0; i < 4; i++) { float a = row[tid + 256 * i]; v[i] = a; s += a; s2 += a * a; }
#pragma unroll
    for (int o = 16; o; o >>= 1) { s += __shfl_xor_sync(0xffffffffu, s, o); s2 += __shfl_xor_sync(0xffffffffu, s2, o); }
    __shared__ float red[18];
    int w = tid >> 5, l = tid & 31;
    if (l == 0) { red[w] = s; red[8 + w] = s2; }
    __syncthreads();
    if (tid == 0) {
        float ts = 0.f, ts2 = 0.f;
        for (int i = 0; i < 8; i++) { ts += red[i]; ts2 += red[8 + i]; }
        float m = ts * (1.f / DIMC);
        float var = ts2 * (1.f / DIMC) - m * m;
        red[16] = m; red[17] = rsqrtf(var + 1e-5f);
    }
    __syncthreads();
    float m = red[16], rs = red[17];
#pragma unroll
    for (int i = 0; i < 4; i++) {
        int c = tid + 256 * i;
        row[c] = (v[i] - m) * rs * g[c] + b[c];
    }
}

// ---------------------------------------------------------------------------
// SIMT SGEMM (attention QK / PV)
// ---------------------------------------------------------------------------
template<int BM, int BN, bool BTN>
__global__ void __launch_bounds__((BM / 8) * (BN / 8))
gemm_kernel(const float* __restrict__ A, int lda, size_t saO, size_t saI,
            const float* __restrict__ B, int ldb, size_t sbO, size_t sbI,
            float* __restrict__ C, int ldc, size_t scO, size_t scI,
            int inner, int K, float scale) {
    constexpr int NT = (BM / 8) * (BN / 8);
    int zb = blockIdx.z / inner, zi = blockIdx.z % inner;
    const float* Ap = A + (size_t)zb * saO + (size_t)zi * saI + (size_t)(blockIdx.y * BM) * lda;
    const float* Bp = B + (size_t)zb * sbO + (size_t)zi * sbI;
    float* Cp = C + (size_t)zb * scO + (size_t)zi * scI
                  + (size_t)(blockIdx.y * BM) * ldc + (size_t)blockIdx.x * BN;
    int n0 = blockIdx.x * BN;

    __shared__ float As[8][BM + 4];
    __shared__ float Bs[8][BN + 4];
    float acc[8][8] = {};
    int tid = threadIdx.x;
    int tx = tid % (BN / 8), ty = tid / (BN / 8);

    for (int k0 = 0; k0 < K; k0 += 8) {
        for (int i = tid; i < BM * 2; i += NT) {
            int row = i >> 1, cg = (i & 1) * 4;
            float4 va = *(const float4*)(Ap + (size_t)row * lda + k0 + cg);
            As[cg + 0][row] = va.x; As[cg + 1][row] = va.y;
            As[cg + 2][row] = va.z; As[cg + 3][row] = va.w;
        }
        if constexpr (BTN) {
            for (int i = tid; i < BN * 2; i += NT) {
                int row = i >> 1, cg = (i & 1) * 4;
                float4 vb = *(const float4*)(Bp + (size_t)(n0 + row) * ldb + k0 + cg);
                Bs[cg + 0][row] = vb.x; Bs[cg + 1][row] = vb.y;
                Bs[cg + 2][row] = vb.z; Bs[cg + 3][row] = vb.w;
            }
        } else {
            for (int i = tid; i < BN * 2; i += NT) {
                int kr = i / (BN / 4), cg = (i % (BN / 4)) * 4;
                *(float4*)(&Bs[kr][cg]) = *(const float4*)(Bp + (size_t)(k0 + kr) * ldb + n0 + cg);
            }
        }
        __syncthreads();
#pragma unroll
        for (int kk = 0; kk < 8; kk++) {
            float a[8], bv[8];
            *(float4*)(a)      = *(const float4*)(&As[kk][ty * 8]);
            *(float4*)(a + 4)  = *(const float4*)(&As[kk][ty * 8 + 4]);
            *(float4*)(bv)     = *(const float4*)(&Bs[kk][tx * 8]);
            *(float4*)(bv + 4) = *(const float4*)(&Bs[kk][tx * 8 + 4]);
#pragma unroll
            for (int i = 0; i < 8; i++)
#pragma unroll
                for (int j = 0; j < 8; j++)
                    acc[i][j] = fmaf(a[i], bv[j], acc[i][j]);
        }
        __syncthreads();
    }
#pragma unroll
    for (int i = 0; i < 8; i++) {
        float4 o0, o1;
        o0.x = acc[i][0] * scale; o0.y = acc[i][1] * scale;
        o0.z = acc[i][2] * scale; o0.w = acc[i][3] * scale;
        o1.x = acc[i][4] * scale; o1.y = acc[i][5] * scale;
        o1.z = acc[i][6] * scale; o1.w = acc[i][7] * scale;
        float* cr = Cp + (size_t)(ty * 8 + i) * ldc + tx * 8;
        *(float4*)cr = o0; *(float4*)(cr + 4) = o1;
    }
}

// ---------------------------------------------------------------------------
// Row softmax over g_s (131072 rows of 1024)
// ---------------------------------------------------------------------------
__global__ void softmax_kernel() {
    float* row = g_s + (size_t)blockIdx.x * SEQC;
    int tid = threadIdx.x;
    float v[4];
    float mx = -1e30f;
#pragma unroll
    for (int i = 0; i < 4; i++) { v[i] = row[tid + 256 * i]; mx = fmaxf(mx, v[i]); }
#pragma unroll
    for (int o = 16; o; o >>= 1) mx = fmaxf(mx, __shfl_xor_sync(0xffffffffu, mx, o));
    __shared__ float red[10];
    int w = tid >> 5, l = tid & 31;
    if (l == 0) red[w] = mx;
    __syncthreads();
    if (tid == 0) {
        float m = red[0];
        for (int i = 1; i < 8; i++) m = fmaxf(m, red[i]);
        red[8] = m;
    }
    __syncthreads();
    mx = red[8];
    float s = 0.f;
#pragma unroll
    for (int i = 0; i < 4; i++) { v[i] = __expf(v[i] - mx); s += v[i]; }
#pragma unroll
    for (int o = 16; o; o >>= 1) s += __shfl_xor_sync(0xffffffffu, s, o);
    if (l == 0) red[w] = s;
    __syncthreads();
    if (tid == 0) {
        float ts = 0.f;
        for (int i = 0; i < 8; i++) ts += red[i];
        red[9] = 1.f / ts;
    }
    __syncthreads();
    float inv = red[9];
#pragma unroll
    for (int i = 0; i < 4; i++) row[tid + 256 * i] = v[i] * inv;
}

// ---------------------------------------------------------------------------
// GELU(exact) of mlp_hidden + bias -> g_h_hi/lo[:, DIM:CIN]
// ---------------------------------------------------------------------------
__global__ void gelu_kernel(const float* __restrict__ mlpb) {
    size_t idx = (size_t)blockIdx.x * 256 + threadIdx.x;
    int t = (int)(idx >> 12);
    int j = (int)(idx & 4095);
    float xv = g_y[(size_t)t * EXPC + 3 * DIMC + j] + mlpb[j];
    float gl = 0.5f * xv * (1.f + erff(xv * 0.70710678118654752f));
    __nv_bfloat16 h, lo; split1(gl, h, lo);
    g_h_hi[(size_t)t * CINC + DIMC + j] = h;
    g_h_lo[(size_t)t * CINC + DIMC + j] = lo;
}

// ---------------------------------------------------------------------------
// Final epilogue: mask z by d_out, residual, router scaling.
// ---------------------------------------------------------------------------
__global__ void final_kernel(const float* __restrict__ x, const int* __restrict__ em,
                             const float* __restrict__ rp, const float* __restrict__ cb,
                             const float* __restrict__ alpha, float* __restrict__ out) {
    size_t idx = (size_t)blockIdx.x * 256 + threadIdx.x;
    int t = (int)(idx >> 10);
    int d = (int)(idx & 1023);
    int m = em[t];
    int dout = (2 * DIMC) >> (3 - m);
    const float* zr = g_z + (size_t)t * 2 * DIMC;
    float za = (d < dout) ? (zr[d] + cb[d]) : 0.f;
    float zm = (DIMC + d < dout) ? (zr[DIMC + d] + cb[DIMC + d]) : 0.f;
    float pr = rp[t * 4 + m];
    out[idx] = x[idx] + za + (alpha[0] * pr + 1.f) * zm;
}

__global__ void tail_kernel(const int* __restrict__ em, const float* __restrict__ rp,
                            float* __restrict__ out) {
    int i = blockIdx.x * 256 + threadIdx.x;
    if (i < TOK)     out[(size_t)TOK * DIMC + i] = (float)em[i];
    if (i < TOK * 4) out[(size_t)TOK * DIMC + TOK + i] = rp[i];
}

// ---------------------------------------------------------------------------
extern "C" void kernel_launch(void* const* d_in, const int* in_sizes, int n_in,
                              void* d_out, int out_size) {
    const float* x     = (const float*)d_in[0];
    const int*   em    = (const int*)d_in[1];
    const float* rp    = (const float*)d_in[2];
    const float* wexp  = (const float*)d_in[3];
    const float* mlpb  = (const float*)d_in[4];
    const float* wc    = (const float*)d_in[5];
    const float* cb    = (const float*)d_in[6];
    const float* n1g   = (const float*)d_in[7];
    const float* n1b   = (const float*)d_in[8];
    const float* n2g   = (const float*)d_in[9];
    const float* n2b   = (const float*)d_in[10];
    const float* alpha = (const float*)d_in[11];
    float* out = (float*)d_out;

    float *p_y, *p_s, *p_z, *p_ha;
    __nv_bfloat16 *p_xnh, *p_xnl, *p_weh, *p_wel, *p_wch, *p_wcl, *p_hh, *p_hl;
    cudaGetSymbolAddress((void**)&p_y,   g_y);
    cudaGetSymbolAddress((void**)&p_s,   g_s);
    cudaGetSymbolAddress((void**)&p_z,   g_z);
    cudaGetSymbolAddress((void**)&p_ha,  g_hattn);
    cudaGetSymbolAddress((void**)&p_xnh, g_xn_hi);
    cudaGetSymbolAddress((void**)&p_xnl, g_xn_lo);
    cudaGetSymbolAddress((void**)&p_weh, g_we_hi);
    cudaGetSymbolAddress((void**)&p_wel, g_we_lo);
    cudaGetSymbolAddress((void**)&p_wch, g_wc_hi);
    cudaGetSymbolAddress((void**)&p_wcl, g_wc_lo);
    cudaGetSymbolAddress((void**)&p_hh,  g_h_hi);
    cudaGetSymbolAddress((void**)&p_hl,  g_h_lo);

    cudaFuncSetAttribute(gemm_mma_kernel, cudaFuncAttributeMaxDynamicSharedMemorySize, GSMEM);

    // 0) weight splits (fp32 -> bf16 hi/lo)
    split4_kernel<<<(EXPC * DIMC) / 4 / 256, 256>>>(wexp, p_weh, p_wel);
    split4_kernel<<<(2 * DIMC * CINC) / 4 / 256, 256>>>(wc, p_wch, p_wcl);

    // 1) LN1 + input mask -> xn hi/lo
    ln1_kernel<<<TOK, 256>>>(x, em, n1g, n1b);

    // 2) y = xn @ Wexp^T  (M=8192, N=7168, K=1024)  [HMMA bf16x3]
    gemm_mma_kernel<<<dim3(EXPC / 128, TOK / 128), 256, GSMEM>>>(
        p_xnh, p_xnl, p_weh, p_wel, p_y, EXPC, DIMC);

    // 3) LN2 on k and v columns (in place)
    ln2_kernel<<<dim3(TOK, 2), 256>>>(n2g, n2b);

    // 4) attention scores: S = scale * Q K^T per (b,h)
    gemm_kernel<128, 128, true><<<dim3(SEQC / 128, SEQC / 128, NB * NHC), 256>>>(
        p_y,        EXPC, (size_t)SEQC * EXPC, (size_t)HDC,
        p_y + DIMC, EXPC, (size_t)SEQC * EXPC, (size_t)HDC,
        p_s,        SEQC, (size_t)NHC * SEQC * SEQC, (size_t)SEQC * SEQC,
        NHC, HDC, 0.125f);

    // 5) row softmax
    softmax_kernel<<<NB * NHC * SEQC, 256>>>();

    // 6) GELU(mlp_hidden + bias) -> h_hi/lo[:, 1024:5120]
    gelu_kernel<<<(TOK * 4096) / 256, 256>>>(mlpb);

    // 7) attn_out = P @ V per (b,h) -> g_hattn (fp32)
    gemm_kernel<128, 64, false><<<dim3(1, SEQC / 128, NB * NHC), 128>>>(
        p_s,            SEQC, (size_t)NHC * SEQC * SEQC, (size_t)SEQC * SEQC,
        p_y + 2 * DIMC, EXPC, (size_t)SEQC * EXPC, (size_t)HDC,
        p_ha,           DIMC, (size_t)SEQC * DIMC, (size_t)HDC,
        NHC, SEQC, 1.f);

    // 7b) split attn_out -> h_hi/lo[:, 0:1024]
    split_hattn_kernel<<<(TOK * DIMC) / 4 / 256, 256>>>();

    // 8) z = h @ Wc^T  (M=8192, N=2048, K=5120)  [HMMA bf16x3]
    gemm_mma_kernel<<<dim3(2 * DIMC / 128, TOK / 128), 256, GSMEM>>>(
        p_hh, p_hl, p_wch, p_wcl, p_z, 2 * DIMC, CINC);

    // 9) epilogue + pass-through outputs
    final_kernel<<<(TOK * DIMC) / 256, 256>>>(x, em, rp, cb, alpha, out);
    tail_kernel<<<(TOK * 4 + 255) / 256, 256>>>(em, rp, out);
}

// round 4
// speedup vs baseline: 3.0457x; 1.2081x over previous
#include <cuda_runtime.h>
#include <cuda_bf16.h>
#include <math.h>
#include <stdint.h>

// Problem constants
#define TOK   8192        // B*N
#define DIMC  1024
#define EXPC  7168
#define CINC  5120
#define NHC   16
#define HDC   64
#define SEQC  1024
#define NB    8
#define BH    (NB * NHC)  // 128 batch-heads

// ---------------------------------------------------------------------------
// Scratch (device globals; allocation-free)
// ---------------------------------------------------------------------------
__device__ float g_y [(size_t)TOK * EXPC];                    // 235 MB
__device__ float g_s [(size_t)BH * SEQC * SEQC];              // 537 MB
__device__ float g_z [(size_t)TOK * 2 * DIMC];                //  67 MB
__device__ float g_hattn[(size_t)TOK * DIMC];                 //  32 MB

__device__ __nv_bfloat16 g_xn_hi[(size_t)TOK * DIMC];
__device__ __nv_bfloat16 g_xn_lo[(size_t)TOK * DIMC];
__device__ __nv_bfloat16 g_we_hi[(size_t)EXPC * DIMC];
__device__ __nv_bfloat16 g_we_lo[(size_t)EXPC * DIMC];
__device__ __nv_bfloat16 g_wc_hi[(size_t)2 * DIMC * CINC];
__device__ __nv_bfloat16 g_wc_lo[(size_t)2 * DIMC * CINC];
__device__ __nv_bfloat16 g_h_hi[(size_t)TOK * CINC];
__device__ __nv_bfloat16 g_h_lo[(size_t)TOK * CINC];

// attention operands (per-head layouts)
__device__ __nv_bfloat16 g_q_hi[(size_t)BH * SEQC * HDC];     // 16 MB each
__device__ __nv_bfloat16 g_q_lo[(size_t)BH * SEQC * HDC];
__device__ __nv_bfloat16 g_k_hi[(size_t)BH * SEQC * HDC];
__device__ __nv_bfloat16 g_k_lo[(size_t)BH * SEQC * HDC];
__device__ __nv_bfloat16 g_vt_hi[(size_t)BH * HDC * SEQC];    // transposed V
__device__ __nv_bfloat16 g_vt_lo[(size_t)BH * HDC * SEQC];
__device__ __nv_bfloat16 g_p_hi[(size_t)BH * SEQC * SEQC];    // 268 MB each
__device__ __nv_bfloat16 g_p_lo[(size_t)BH * SEQC * SEQC];

// ---------------------------------------------------------------------------
// PTX helpers (sm_80-level: ldmatrix / mma / cp.async)
// ---------------------------------------------------------------------------
__device__ __forceinline__ uint32_t smem_u32(const void* p) {
    uint32_t a;
    asm("{ .reg .u64 t; cvta.to.shared.u64 t, %1; cvt.u32.u64 %0, t; }" : "=r"(a) : "l"(p));
    return a;
}
__device__ __forceinline__ void ldsm4(uint32_t* r, uint32_t a) {
    asm volatile("ldmatrix.sync.aligned.m8n8.x4.shared.b16 {%0,%1,%2,%3}, [%4];"
                 : "=r"(r[0]), "=r"(r[1]), "=r"(r[2]), "=r"(r[3]) : "r"(a));
}
__device__ __forceinline__ void mma16816(float* c, const uint32_t* a, const uint32_t* b) {
    asm volatile("mma.sync.aligned.m16n8k16.row.col.f32.bf16.bf16.f32 "
                 "{%0,%1,%2,%3}, {%4,%5,%6,%7}, {%8,%9}, {%0,%1,%2,%3};"
                 : "+f"(c[0]), "+f"(c[1]), "+f"(c[2]), "+f"(c[3])
                 : "r"(a[0]), "r"(a[1]), "r"(a[2]), "r"(a[3]), "r"(b[0]), "r"(b[1]));
}
__device__ __forceinline__ void cpa16(uint32_t s, const void* g) {
    asm volatile("cp.async.cg.shared.global [%0], [%1], 16;" :: "r"(s), "l"(g));
}
#define CP_COMMIT() asm volatile("cp.async.commit_group;")
#define CP_WAIT2()  asm volatile("cp.async.wait_group 2;")
#define CP_WAIT1()  asm volatile("cp.async.wait_group 1;")
#define CP_WAIT0()  asm volatile("cp.async.wait_group 0;")

// SW128 swizzle (byte offsets within a tile of 128-byte rows)
#define SWZ(o) ((o) ^ (((o) >> 3) & 0x70))

// ---------------------------------------------------------------------------
// bf16-split HMMA GEMM: C = sum_k A[m][k]*B[n][k]  (TN; A,B hi+lo, 3 products)
// CTA tile 128 x BN, K-chunk 64, 3-stage cp.async pipeline, 256 threads.
// Batched: z = zb*inner + zi with independent A/B/C strides.
// ---------------------------------------------------------------------------
template<int BN>
__global__ void __launch_bounds__(256)
gemm_mma_kernel(const __nv_bfloat16* __restrict__ Ah, const __nv_bfloat16* __restrict__ Al,
                size_t saO, size_t saI,
                const __nv_bfloat16* __restrict__ Bh, const __nv_bfloat16* __restrict__ Bl,
                size_t sbO, size_t sbI,
                float* __restrict__ C, int ldc, size_t scO, size_t scI,
                int inner, int K) {
    constexpr int WN   = BN / 2;      // warp n-width
    constexpr int NTP  = BN / 32;     // n16 groups per warp
    constexpr int BIT  = BN / 16;     // B load iterations
    constexpr int OAH  = 0;
    constexpr int OAL  = 16384;
    constexpr int OBH  = 32768;
    constexpr int OBL  = 32768 + BN * 128;
    constexpr int BUF  = 32768 + 2 * BN * 128;

    extern __shared__ char smem_raw[];
    uint32_t sb = smem_u32(smem_raw);
    sb = (sb + 1023u) & ~1023u;

    const int tid  = threadIdx.x;
    const int wid  = tid >> 5;
    const int lane = tid & 31;
    const int wm = wid & 3;
    const int wn = wid >> 2;

    const int zb = blockIdx.z / inner, zi = blockIdx.z % inner;
    const int m0 = blockIdx.y * 128;
    const int n0 = blockIdx.x * BN;
    const __nv_bfloat16* ABh = Ah + (size_t)zb * saO + (size_t)zi * saI + (size_t)m0 * K;
    const __nv_bfloat16* ABl = Al + (size_t)zb * saO + (size_t)zi * saI + (size_t)m0 * K;
    const __nv_bfloat16* BBh = Bh + (size_t)zb * sbO + (size_t)zi * sbI + (size_t)n0 * K;
    const __nv_bfloat16* BBl = Bl + (size_t)zb * sbO + (size_t)zi * sbI + (size_t)n0 * K;
    float* Cp = C + (size_t)zb * scO + (size_t)zi * scI + (size_t)m0 * ldc + n0;

    const int NC = K / 64;

    // chunk loader
    auto load_chunk = [&](int c) {
        uint32_t bufb = sb + (uint32_t)(c % 3) * BUF;
        int k0 = c * 64;
#pragma unroll
        for (int it = 0; it < 8; it++) {
            int i = tid + it * 256;
            int r = i >> 4, rem = i & 15, hl = rem >> 3, kg = rem & 7;
            const __nv_bfloat16* src = (hl ? ABl : ABh) + (size_t)r * K + k0 + kg * 8;
            cpa16(bufb + OAH + (hl ? (OAL - OAH) : 0) + SWZ(r * 128 + kg * 16), src);
        }
#pragma unroll
        for (int it = 0; it < BIT; it++) {
            int i = tid + it * 256;
            int r = i >> 4, rem = i & 15, hl = rem >> 3, kg = rem & 7;
            const __nv_bfloat16* src = (hl ? BBl : BBh) + (size_t)r * K + k0 + kg * 8;
            cpa16(bufb + (hl ? OBL : OBH) + SWZ(r * 128 + kg * 16), src);
        }
        CP_COMMIT();
    };

    load_chunk(0);
    if (NC > 1) load_chunk(1);

    float acc[2][2 * NTP][4];
#pragma unroll
    for (int i = 0; i < 2; i++)
#pragma unroll
        for (int j = 0; j < 2 * NTP; j++)
#pragma unroll
            for (int k = 0; k < 4; k++) acc[i][j][k] = 0.f;

    const int a_r16 = lane & 15;
    const int a_kb  = (lane >> 4) * 16;
    const int b_r8  = ((lane >> 4) << 3) + (lane & 7);
    const int b_kb  = ((lane >> 3) & 1) * 16;

    for (int c = 0; c < NC; c++) {
        if (c + 2 < NC) load_chunk(c + 2);
        int pend = NC - 1 - c; if (pend > 2) pend = 2;
        if (pend == 2) CP_WAIT2(); else if (pend == 1) CP_WAIT1(); else CP_WAIT0();
        __syncthreads();

        uint32_t bufb = sb + (uint32_t)(c % 3) * BUF;
#pragma unroll
        for (int kk = 0; kk < 4; kk++) {
            int kb = kk * 32;
            uint32_t ah[2][4], al[2][4];
#pragma unroll
            for (int mt = 0; mt < 2; mt++) {
                int r = wm * 32 + mt * 16 + a_r16;
                uint32_t off = (uint32_t)(r * 128) + (uint32_t)((kb + a_kb) ^ ((r & 7) << 4));
                ldsm4(ah[mt], bufb + OAH + off);
                ldsm4(al[mt], bufb + OAL + off);
            }
#pragma unroll
            for (int ntp = 0; ntp < NTP; ntp++) {
                int r = wn * WN + ntp * 16 + b_r8;
                uint32_t off = (uint32_t)(r * 128) + (uint32_t)((kb + b_kb) ^ ((r & 7) << 4));
                uint32_t bh[4], bl[4];
                ldsm4(bh, bufb + OBH + off);
                ldsm4(bl, bufb + OBL + off);
#pragma unroll
                for (int mt = 0; mt < 2; mt++) {
                    mma16816(acc[mt][2 * ntp],     ah[mt], bh);
                    mma16816(acc[mt][2 * ntp],     ah[mt], bl);
                    mma16816(acc[mt][2 * ntp],     al[mt], bh);
                    mma16816(acc[mt][2 * ntp + 1], ah[mt], bh + 2);
                    mma16816(acc[mt][2 * ntp + 1], ah[mt], bl + 2);
                    mma16816(acc[mt][2 * ntp + 1], al[mt], bh + 2);
                }
            }
        }
        __syncthreads();
    }

    // Epilogue
    const int g = lane >> 2, t4 = lane & 3;
#pragma unroll
    for (int mt = 0; mt < 2; mt++) {
        int mrow = wm * 32 + mt * 16;
#pragma unroll
        for (int nt = 0; nt < 2 * NTP; nt++) {
            int ncol = wn * WN + nt * 8 + t4 * 2;
            *(float2*)(Cp + (size_t)(mrow + g) * ldc + ncol)     = make_float2(acc[mt][nt][0], acc[mt][nt][1]);
            *(float2*)(Cp + (size_t)(mrow + g + 8) * ldc + ncol) = make_float2(acc[mt][nt][2], acc[mt][nt][3]);
        }
    }
}

// ---------------------------------------------------------------------------
// fp32 -> bf16 hi/lo split helpers
// ---------------------------------------------------------------------------
__device__ __forceinline__ void split1(float x, __nv_bfloat16& h, __nv_bfloat16& l) {
    h = __float2bfloat16(x);
    l = __float2bfloat16(x - __bfloat162float(h));
}

__global__ void split4_kernel(const float* __restrict__ s,
                              __nv_bfloat16* __restrict__ hi, __nv_bfloat16* __restrict__ lo) {
    size_t i = (size_t)blockIdx.x * 256 + threadIdx.x;
    float4 v = ((const float4*)s)[i];
    __nv_bfloat16 h0, h1, h2, h3, l0, l1, l2, l3;
    split1(v.x, h0, l0); split1(v.y, h1, l1); split1(v.z, h2, l2); split1(v.w, h3, l3);
    __nv_bfloat162* H = (__nv_bfloat162*)hi;
    __nv_bfloat162* L = (__nv_bfloat162*)lo;
    H[2 * i] = __nv_bfloat162(h0, h1); H[2 * i + 1] = __nv_bfloat162(h2, h3);
    L[2 * i] = __nv_bfloat162(l0, l1); L[2 * i + 1] = __nv_bfloat162(l2, l3);
}

__global__ void split_hattn_kernel() {
    size_t i = (size_t)blockIdx.x * 256 + threadIdx.x;
    int t = (int)(i >> 8);
    int j = (int)(i & 255) * 4;
    float4 v = ((const float4*)g_hattn)[i];
    size_t o = (size_t)t * CINC + j;
    __nv_bfloat16 h0, h1, h2, h3, l0, l1, l2, l3;
    split1(v.x, h0, l0); split1(v.y, h1, l1); split1(v.z, h2, l2); split1(v.w, h3, l3);
    *(__nv_bfloat162*)(g_h_hi + o)     = __nv_bfloat162(h0, h1);
    *(__nv_bfloat162*)(g_h_hi + o + 2) = __nv_bfloat162(h2, h3);
    *(__nv_bfloat162*)(g_h_lo + o)     = __nv_bfloat162(l0, l1);
    *(__nv_bfloat162*)(g_h_lo + o + 2) = __nv_bfloat162(l2, l3);
}

// ---------------------------------------------------------------------------
// LayerNorm 1 -> masked xn as bf16 hi/lo
// ---------------------------------------------------------------------------
__global__ void ln1_kernel(const float* __restrict__ x, const int* __restrict__ em,
                           const float* __restrict__ g, const float* __restrict__ b) {
    int t = blockIdx.x;
    const float* xr = x + (size_t)t * DIMC;
    int tid = threadIdx.x;
    float v[4]; float s = 0.f, s2 = 0.f;
#pragma unroll
    for (int i = 0; i < 4; i++) { float a = xr[tid + 256 * i]; v[i] = a; s += a; s2 += a * a; }
#pragma unroll
    for (int o = 16; o; o >>= 1) { s += __shfl_xor_sync(0xffffffffu, s, o); s2 += __shfl_xor_sync(0xffffffffu, s2, o); }
    __shared__ float red[18];
    int w = tid >> 5, l = tid & 31;
    if (l == 0) { red[w] = s; red[8 + w] = s2; }
    __syncthreads();
    if (tid == 0) {
        float ts = 0.f, ts2 = 0.f;
        for (int i = 0; i < 8; i++) { ts += red[i]; ts2 += red[8 + i]; }
        float m = ts * (1.f / DIMC);
        float var = ts2 * (1.f / DIMC) - m * m;
        red[16] = m; red[17] = rsqrtf(var + 1e-5f);
    }
    __syncthreads();
    float m = red[16], rs = red[17];
    int din = DIMC >> (3 - em[t]);
#pragma unroll
    for (int i = 0; i < 4; i++) {
        int c = tid + 256 * i;
        float val = (v[i] - m) * rs * g[c] + b[c];
        val = (c < din) ? val : 0.f;
        __nv_bfloat16 h, lo; split1(val, h, lo);
        g_xn_hi[(size_t)t * DIMC + c] = h;
        g_xn_lo[(size_t)t * DIMC + c] = lo;
    }
}

// ---------------------------------------------------------------------------
// LayerNorm 2 (in place on g_y k/v columns)
// ---------------------------------------------------------------------------
__global__ void ln2_kernel(const float* __restrict__ g, const float* __restrict__ b) {
    int t = blockIdx.x;
    float* row = g_y + (size_t)t * EXPC + (size_t)DIMC * (1 + blockIdx.y);
    int tid = threadIdx.x;
    float v[4]; float s = 0.f, s2 = 0.f;
#pragma unroll
    for (int i = 0; i < 4; i++) { float a = row[tid + 256 * i]; v[i] = a; s += a; s2 += a * a; }
#pragma unroll
    for (int o = 16; o; o >>= 1) { s += __shfl_xor_sync(0xffffffffu, s, o); s2 += __shfl_xor_sync(0xffffffffu, s2, o); }
    __shared__ float red[18];
    int w = tid >> 5, l = tid & 31;
    if (l == 0) { red[w] = s; red[8 + w] = s2; }
    __syncthreads();
    if (tid == 0) {
        float ts = 0.f, ts2 = 0.f;
        for (int i = 0; i < 8; i++) { ts += red[i]; ts2 += red[8 + i]; }
        float m = ts * (1.f / DIMC);
        float var = ts2 * (1.f / DIMC) - m * m;
        red[16] = m; red[17] = rsqrtf(var + 1e-5f);
    }
    __syncthreads();
    float m = red[16], rs = red[17];
#pragma unroll
    for (int i = 0; i < 4; i++) {
        int c = tid + 256 * i;
        row[c] = (v[i] - m) * rs * g[c] + b[c];
    }
}

// ---------------------------------------------------------------------------
// Pack Q (scaled by 1/8) and K into per-head bf16 hi/lo: [bh][seq][64]
// ---------------------------------------------------------------------------
__global__ void qk_pack_kernel() {
    int t = blockIdx.x;
    int b = t >> 10, s = t & 1023;
    int tid = threadIdx.x;
#pragma unroll
    for (int i = 0; i < 4; i++) {
        int d = tid + 256 * i;
        int h = d >> 6, hd = d & 63;
        size_t o = ((size_t)(b * NHC + h) * SEQC + s) * HDC + hd;
        float q = g_y[(size_t)t * EXPC + d] * 0.125f;
        float k = g_y[(size_t)t * EXPC + DIMC + d];
        __nv_bfloat16 hh, ll;
        split1(q, hh, ll); g_q_hi[o] = hh; g_q_lo[o] = ll;
        split1(k, hh, ll); g_k_hi[o] = hh; g_k_lo[o] = ll;
    }
}

// ---------------------------------------------------------------------------
// Pack V transposed per head: g_vt[bh][hd][seq] from g_y[:, 2048+...]
// grid (BH, SEQC/64), block 256. 64x64 fp32 tile via smem.
// ---------------------------------------------------------------------------
__global__ void vt_pack_kernel() {
    __shared__ float tile[64][65];
    int bh = blockIdx.x;
    int b = bh >> 4, h = bh & 15;
    int s0 = blockIdx.y * 64;
    int tid = threadIdx.x;
#pragma unroll
    for (int i = 0; i < 16; i++) {
        int idx = tid + i * 256;
        int r = idx >> 6, c = idx & 63;   // r: seq row, c: hd col
        tile[r][c] = g_y[(size_t)(b * 1024 + s0 + r) * EXPC + 2 * DIMC + h * 64 + c];
    }
    __syncthreads();
#pragma unroll
    for (int i = 0; i < 16; i++) {
        int idx = tid + i * 256;
        int r = idx >> 6, c = idx & 63;   // r: hd row, c: seq col
        float v = tile[c][r];
        __nv_bfloat16 hh, ll; split1(v, hh, ll);
        size_t o = (size_t)bh * HDC * SEQC + (size_t)r * SEQC + s0 + c;
        g_vt_hi[o] = hh; g_vt_lo[o] = ll;
    }
}

// ---------------------------------------------------------------------------
// Row softmax over g_s -> P written as bf16 hi/lo
// ---------------------------------------------------------------------------
__global__ void softmax_kernel() {
    const float* row = g_s + (size_t)blockIdx.x * SEQC;
    __nv_bfloat16* ph = g_p_hi + (size_t)blockIdx.x * SEQC;
    __nv_bfloat16* pl = g_p_lo + (size_t)blockIdx.x * SEQC;
    int tid = threadIdx.x;
    float v[4];
    float mx = -1e30f;
#pragma unroll
    for (int i = 0; i < 4; i++) { v[i] = row[tid + 256 * i]; mx = fmaxf(mx, v[i]); }
#pragma unroll
    for (int o = 16; o; o >>= 1) mx = fmaxf(mx, __shfl_xor_sync(0xffffffffu, mx, o));
    __shared__ float red[10];
    int w = tid >> 5, l = tid & 31;
    if (l == 0) red[w] = mx;
    __syncthreads();
    if (tid == 0) {
        float m = red[0];
        for (int i = 1; i < 8; i++) m = fmaxf(m, red[i]);
        red[8] = m;
    }
    __syncthreads();
    mx = red[8];
    float s = 0.f;
#pragma unroll
    for (int i = 0; i < 4; i++) { v[i] = __expf(v[i] - mx); s += v[i]; }
#pragma unroll
    for (int o = 16; o; o >>= 1) s += __shfl_xor_sync(0xffffffffu, s, o);
    if (l == 0) red[w] = s;
    __syncthreads();
    if (tid == 0) {
        float ts = 0.f;
        for (int i = 0; i < 8; i++) ts += red[i];
        red[9] = 1.f / ts;
    }
    __syncthreads();
    float inv = red[9];
#pragma unroll
    for (int i = 0; i < 4; i++) {
        int c = tid + 256 * i;
        __nv_bfloat16 hh, ll; split1(v[i] * inv, hh, ll);
        ph[c] = hh; pl[c] = ll;
    }
}

// ---------------------------------------------------------------------------
// GELU(exact) -> g_h hi/lo mlp region
// ---------------------------------------------------------------------------
__global__ void gelu_kernel(const float* __restrict__ mlpb) {
    size_t idx = (size_t)blockIdx.x * 256 + threadIdx.x;
    int t = (int)(idx >> 12);
    int j = (int)(idx & 4095);
    float xv = g_y[(size_t)t * EXPC + 3 * DIMC + j] + mlpb[j];
    float gl = 0.5f * xv * (1.f + erff(xv * 0.70710678118654752f));
    __nv_bfloat16 h, lo; split1(gl, h, lo);
    g_h_hi[(size_t)t * CINC + DIMC + j] = h;
    g_h_lo[(size_t)t * CINC + DIMC + j] = lo;
}

// ---------------------------------------------------------------------------
// Final epilogue + pass-through tails
// ---------------------------------------------------------------------------
__global__ void final_kernel(const float* __restrict__ x, const int* __restrict__ em,
                             const float* __restrict__ rp, const float* __restrict__ cb,
                             const float* __restrict__ alpha, float* __restrict__ out) {
    size_t idx = (size_t)blockIdx.x * 256 + threadIdx.x;
    int t = (int)(idx >> 10);
    int d = (int)(idx & 1023);
    int m = em[t];
    int dout = (2 * DIMC) >> (3 - m);
    const float* zr = g_z + (size_t)t * 2 * DIMC;
    float za = (d < dout) ? (zr[d] + cb[d]) : 0.f;
    float zm = (DIMC + d < dout) ? (zr[DIMC + d] + cb[DIMC + d]) : 0.f;
    float pr = rp[t * 4 + m];
    out[idx] = x[idx] + za + (alpha[0] * pr + 1.f) * zm;
}

__global__ void tail_kernel(const int* __restrict__ em, const float* __restrict__ rp,
                            float* __restrict__ out) {
    int i = blockIdx.x * 256 + threadIdx.x;
    if (i < TOK)     out[(size_t)TOK * DIMC + i] = (float)em[i];
    if (i < TOK * 4) out[(size_t)TOK * DIMC + TOK + i] = rp[i];
}

// ---------------------------------------------------------------------------
extern "C" void kernel_launch(void* const* d_in, const int* in_sizes, int n_in,
                              void* d_out, int out_size) {
    const float* x     = (const float*)d_in[0];
    const int*   em    = (const int*)d_in[1];
    const float* rp    = (const float*)d_in[2];
    const float* wexp  = (const float*)d_in[3];
    const float* mlpb  = (const float*)d_in[4];
    const float* wc    = (const float*)d_in[5];
    const float* cb    = (const float*)d_in[6];
    const float* n1g   = (const float*)d_in[7];
    const float* n1b   = (const float*)d_in[8];
    const float* n2g   = (const float*)d_in[9];
    const float* n2b   = (const float*)d_in[10];
    const float* alpha = (const float*)d_in[11];
    float* out = (float*)d_out;

    float *p_y, *p_s, *p_z, *p_ha;
    __nv_bfloat16 *p_xnh, *p_xnl, *p_weh, *p_wel, *p_wch, *p_wcl, *p_hh, *p_hl;
    __nv_bfloat16 *p_qh, *p_ql, *p_kh, *p_kl, *p_vth, *p_vtl, *p_ph, *p_pl;
    cudaGetSymbolAddress((void**)&p_y,   g_y);
    cudaGetSymbolAddress((void**)&p_s,   g_s);
    cudaGetSymbolAddress((void**)&p_z,   g_z);
    cudaGetSymbolAddress((void**)&p_ha,  g_hattn);
    cudaGetSymbolAddress((void**)&p_xnh, g_xn_hi);
    cudaGetSymbolAddress((void**)&p_xnl, g_xn_lo);
    cudaGetSymbolAddress((void**)&p_weh, g_we_hi);
    cudaGetSymbolAddress((void**)&p_wel, g_we_lo);
    cudaGetSymbolAddress((void**)&p_wch, g_wc_hi);
    cudaGetSymbolAddress((void**)&p_wcl, g_wc_lo);
    cudaGetSymbolAddress((void**)&p_hh,  g_h_hi);
    cudaGetSymbolAddress((void**)&p_hl,  g_h_lo);
    cudaGetSymbolAddress((void**)&p_qh,  g_q_hi);
    cudaGetSymbolAddress((void**)&p_ql,  g_q_lo);
    cudaGetSymbolAddress((void**)&p_kh,  g_k_hi);
    cudaGetSymbolAddress((void**)&p_kl,  g_k_lo);
    cudaGetSymbolAddress((void**)&p_vth, g_vt_hi);
    cudaGetSymbolAddress((void**)&p_vtl, g_vt_lo);
    cudaGetSymbolAddress((void**)&p_ph,  g_p_hi);
    cudaGetSymbolAddress((void**)&p_pl,  g_p_lo);

    const int SM128 = 3 * (32768 + 2 * 128 * 128) + 1024;   // 197632
    const int SM64  = 3 * (32768 + 2 * 64 * 128) + 1024;    // 148480
    cudaFuncSetAttribute(gemm_mma_kernel<128>, cudaFuncAttributeMaxDynamicSharedMemorySize, SM128);
    cudaFuncSetAttribute(gemm_mma_kernel<64>,  cudaFuncAttributeMaxDynamicSharedMemorySize, SM64);

    // 0) weight splits
    split4_kernel<<<(EXPC * DIMC) / 4 / 256, 256>>>(wexp, p_weh, p_wel);
    split4_kernel<<<(2 * DIMC * CINC) / 4 / 256, 256>>>(wc, p_wch, p_wcl);

    // 1) LN1 + input mask
    ln1_kernel<<<TOK, 256>>>(x, em, n1g, n1b);

    // 2) expand: y = xn @ Wexp^T  (M=8192, N=7168, K=1024)
    gemm_mma_kernel<128><<<dim3(EXPC / 128, TOK / 128, 1), 256, SM128>>>(
        p_xnh, p_xnl, 0, 0, p_weh, p_wel, 0, 0, p_y, EXPC, 0, 0, 1, DIMC);

    // 3) LN2 on k/v
    ln2_kernel<<<dim3(TOK, 2), 256>>>(n2g, n2b);

    // 4) pack Q/K (scaled) and transposed V
    qk_pack_kernel<<<TOK, 256>>>();
    vt_pack_kernel<<<dim3(BH, SEQC / 64), 256>>>();

    // 5) S = (Q/8) K^T per head  (M=N=1024, K=64, batch 128)
    gemm_mma_kernel<128><<<dim3(SEQC / 128, SEQC / 128, BH), 256, SM128>>>(
        p_qh, p_ql, (size_t)SEQC * HDC, 0,
        p_kh, p_kl, (size_t)SEQC * HDC, 0,
        p_s, SEQC, (size_t)SEQC * SEQC, 0, 1, HDC);

    // 6) softmax -> P bf16 hi/lo
    softmax_kernel<<<BH * SEQC, 256>>>();

    // 7) GELU -> h mlp region
    gelu_kernel<<<(TOK * 4096) / 256, 256>>>(mlpb);

    // 8) attn_out = P @ V per head (M=1024, N=64, K=1024, batch 128)
    gemm_mma_kernel<64><<<dim3(1, SEQC / 128, BH), 256, SM64>>>(
        p_ph, p_pl, (size_t)NHC * SEQC * SEQC, (size_t)SEQC * SEQC,
        p_vth, p_vtl, (size_t)NHC * HDC * SEQC, (size_t)HDC * SEQC,
        p_ha, DIMC, (size_t)SEQC * DIMC, (size_t)HDC, NHC, SEQC);

    // 8b) split attn_out into h[:, 0:1024]
    split_hattn_kernel<<<(TOK * DIMC) / 4 / 256, 256>>>();

    // 9) contract: z = h @ Wc^T  (M=8192, N=2048, K=5120)
    gemm_mma_kernel<128><<<dim3(2 * DIMC / 128, TOK / 128, 1), 256, SM128>>>(
        p_hh, p_hl, 0, 0, p_wch, p_wcl, 0, 0, p_z, 2 * DIMC, 0, 0, 1, CINC);

    // 10) epilogue + tails
    final_kernel<<<(TOK * DIMC) / 256, 256>>>(x, em, rp, cb, alpha, out);
    tail_kernel<<<(TOK * 4 + 255) / 256, 256>>>(em, rp, out);
}

// round 5
// speedup vs baseline: 4.2565x; 1.3975x over previous
#include <cuda_runtime.h>
#include <cuda_bf16.h>
#include <math.h>
#include <stdint.h>

// Problem constants
#define TOK   8192        // B*N
#define DIMC  1024
#define EXPC  7168
#define CINC  5120
#define NHC   16
#define HDC   64
#define SEQC  1024
#define NB    8
#define BH    (NB * NHC)  // 128 batch-heads

// ---------------------------------------------------------------------------
// Scratch (device globals; allocation-free)
// ---------------------------------------------------------------------------
__device__ float g_y [(size_t)TOK * EXPC];                    // 235 MB
__device__ float g_s [(size_t)BH * SEQC * SEQC];              // 537 MB
__device__ float g_z [(size_t)TOK * 2 * DIMC];                //  67 MB
__device__ float g_hattn[(size_t)TOK * DIMC];                 //  32 MB

__device__ __nv_bfloat16 g_xn_hi[(size_t)TOK * DIMC];
__device__ __nv_bfloat16 g_xn_lo[(size_t)TOK * DIMC];
__device__ __nv_bfloat16 g_we_hi[(size_t)EXPC * DIMC];
__device__ __nv_bfloat16 g_we_lo[(size_t)EXPC * DIMC];
__device__ __nv_bfloat16 g_wc_hi[(size_t)2 * DIMC * CINC];
__device__ __nv_bfloat16 g_wc_lo[(size_t)2 * DIMC * CINC];
__device__ __nv_bfloat16 g_h_hi[(size_t)TOK * CINC];
__device__ __nv_bfloat16 g_h_lo[(size_t)TOK * CINC];

// attention operands (per-head layouts)
__device__ __nv_bfloat16 g_q_hi[(size_t)BH * SEQC * HDC];
__device__ __nv_bfloat16 g_q_lo[(size_t)BH * SEQC * HDC];
__device__ __nv_bfloat16 g_k_hi[(size_t)BH * SEQC * HDC];
__device__ __nv_bfloat16 g_k_lo[(size_t)BH * SEQC * HDC];
__device__ __nv_bfloat16 g_vt_hi[(size_t)BH * HDC * SEQC];
__device__ __nv_bfloat16 g_vt_lo[(size_t)BH * HDC * SEQC];
__device__ __nv_bfloat16 g_p_hi[(size_t)BH * SEQC * SEQC];
__device__ __nv_bfloat16 g_p_lo[(size_t)BH * SEQC * SEQC];

// expert grouping
__device__ int g_cnt[4];
__device__ int g_cur[4];
__device__ int g_goff[4];
__device__ int g_perm[TOK];

// ---------------------------------------------------------------------------
// PTX helpers (sm_80-level: ldmatrix / mma / cp.async)
// ---------------------------------------------------------------------------
__device__ __forceinline__ uint32_t smem_u32(const void* p) {
    uint32_t a;
    asm("{ .reg .u64 t; cvta.to.shared.u64 t, %1; cvt.u32.u64 %0, t; }" : "=r"(a) : "l"(p));
    return a;
}
__device__ __forceinline__ void ldsm4(uint32_t* r, uint32_t a) {
    asm volatile("ldmatrix.sync.aligned.m8n8.x4.shared.b16 {%0,%1,%2,%3}, [%4];"
                 : "=r"(r[0]), "=r"(r[1]), "=r"(r[2]), "=r"(r[3]) : "r"(a));
}
__device__ __forceinline__ void mma16816(float* c, const uint32_t* a, const uint32_t* b) {
    asm volatile("mma.sync.aligned.m16n8k16.row.col.f32.bf16.bf16.f32 "
                 "{%0,%1,%2,%3}, {%4,%5,%6,%7}, {%8,%9}, {%0,%1,%2,%3};"
                 : "+f"(c[0]), "+f"(c[1]), "+f"(c[2]), "+f"(c[3])
                 : "r"(a[0]), "r"(a[1]), "r"(a[2]), "r"(a[3]), "r"(b[0]), "r"(b[1]));
}
__device__ __forceinline__ void cpa16(uint32_t s, const void* g) {
    asm volatile("cp.async.cg.shared.global [%0], [%1], 16;" :: "r"(s), "l"(g));
}
#define CP_COMMIT() asm volatile("cp.async.commit_group;")
#define CP_WAIT2()  asm volatile("cp.async.wait_group 2;")
#define CP_WAIT1()  asm volatile("cp.async.wait_group 1;")
#define CP_WAIT0()  asm volatile("cp.async.wait_group 0;")

// SW128 swizzle
#define SWZ(o) ((o) ^ (((o) >> 3) & 0x70))

// ---------------------------------------------------------------------------
// bf16-split HMMA GEMM (dense, batched) — used for QK / PV
// ---------------------------------------------------------------------------
template<int BN>
__global__ void __launch_bounds__(256)
gemm_mma_kernel(const __nv_bfloat16* __restrict__ Ah, const __nv_bfloat16* __restrict__ Al,
                size_t saO, size_t saI,
                const __nv_bfloat16* __restrict__ Bh, const __nv_bfloat16* __restrict__ Bl,
                size_t sbO, size_t sbI,
                float* __restrict__ C, int ldc, size_t scO, size_t scI,
                int inner, int K) {
    constexpr int WN   = BN / 2;
    constexpr int NTP  = BN / 32;
    constexpr int BIT  = BN / 16;
    constexpr int OAH  = 0;
    constexpr int OAL  = 16384;
    constexpr int OBH  = 32768;
    constexpr int OBL  = 32768 + BN * 128;
    constexpr int BUF  = 32768 + 2 * BN * 128;

    extern __shared__ char smem_raw[];
    uint32_t sb = smem_u32(smem_raw);
    sb = (sb + 1023u) & ~1023u;

    const int tid  = threadIdx.x;
    const int wid  = tid >> 5;
    const int lane = tid & 31;
    const int wm = wid & 3;
    const int wn = wid >> 2;

    const int zb = blockIdx.z / inner, zi = blockIdx.z % inner;
    const int m0 = blockIdx.y * 128;
    const int n0 = blockIdx.x * BN;
    const __nv_bfloat16* ABh = Ah + (size_t)zb * saO + (size_t)zi * saI + (size_t)m0 * K;
    const __nv_bfloat16* ABl = Al + (size_t)zb * saO + (size_t)zi * saI + (size_t)m0 * K;
    const __nv_bfloat16* BBh = Bh + (size_t)zb * sbO + (size_t)zi * sbI + (size_t)n0 * K;
    const __nv_bfloat16* BBl = Bl + (size_t)zb * sbO + (size_t)zi * sbI + (size_t)n0 * K;
    float* Cp = C + (size_t)zb * scO + (size_t)zi * scI + (size_t)m0 * ldc + n0;

    const int NC = K / 64;

    auto load_chunk = [&](int c) {
        uint32_t bufb = sb + (uint32_t)(c % 3) * BUF;
        int k0 = c * 64;
#pragma unroll
        for (int it = 0; it < 8; it++) {
            int i = tid + it * 256;
            int r = i >> 4, rem = i & 15, hl = rem >> 3, kg = rem & 7;
            const __nv_bfloat16* src = (hl ? ABl : ABh) + (size_t)r * K + k0 + kg * 8;
            cpa16(bufb + (hl ? OAL : OAH) + SWZ(r * 128 + kg * 16), src);
        }
#pragma unroll
        for (int it = 0; it < BIT; it++) {
            int i = tid + it * 256;
            int r = i >> 4, rem = i & 15, hl = rem >> 3, kg = rem & 7;
            const __nv_bfloat16* src = (hl ? BBl : BBh) + (size_t)r * K + k0 + kg * 8;
            cpa16(bufb + (hl ? OBL : OBH) + SWZ(r * 128 + kg * 16), src);
        }
        CP_COMMIT();
    };

    load_chunk(0);
    if (NC > 1) load_chunk(1);

    float acc[2][2 * NTP][4];
#pragma unroll
    for (int i = 0; i < 2; i++)
#pragma unroll
        for (int j = 0; j < 2 * NTP; j++)
#pragma unroll
            for (int k = 0; k < 4; k++) acc[i][j][k] = 0.f;

    const int a_r16 = lane & 15;
    const int a_kb  = (lane >> 4) * 16;
    const int b_r8  = ((lane >> 4) << 3) + (lane & 7);
    const int b_kb  = ((lane >> 3) & 1) * 16;

    for (int c = 0; c < NC; c++) {
        if (c + 2 < NC) load_chunk(c + 2);
        int pend = NC - 1 - c; if (pend > 2) pend = 2;
        if (pend == 2) CP_WAIT2(); else if (pend == 1) CP_WAIT1(); else CP_WAIT0();
        __syncthreads();

        uint32_t bufb = sb + (uint32_t)(c % 3) * BUF;
#pragma unroll
        for (int kk = 0; kk < 4; kk++) {
            int kb = kk * 32;
            uint32_t ah[2][4], al[2][4];
#pragma unroll
            for (int mt = 0; mt < 2; mt++) {
                int r = wm * 32 + mt * 16 + a_r16;
                uint32_t off = (uint32_t)(r * 128) + (uint32_t)((kb + a_kb) ^ ((r & 7) << 4));
                ldsm4(ah[mt], bufb + OAH + off);
                ldsm4(al[mt], bufb + OAL + off);
            }
#pragma unroll
            for (int ntp = 0; ntp < NTP; ntp++) {
                int r = wn * WN + ntp * 16 + b_r8;
                uint32_t off = (uint32_t)(r * 128) + (uint32_t)((kb + b_kb) ^ ((r & 7) << 4));
                uint32_t bh[4], bl[4];
                ldsm4(bh, bufb + OBH + off);
                ldsm4(bl, bufb + OBL + off);
#pragma unroll
                for (int mt = 0; mt < 2; mt++) {
                    mma16816(acc[mt][2 * ntp],     ah[mt], bh);
                    mma16816(acc[mt][2 * ntp],     ah[mt], bl);
                    mma16816(acc[mt][2 * ntp],     al[mt], bh);
                    mma16816(acc[mt][2 * ntp + 1], ah[mt], bh + 2);
                    mma16816(acc[mt][2 * ntp + 1], ah[mt], bl + 2);
                    mma16816(acc[mt][2 * ntp + 1], al[mt], bh + 2);
                }
            }
        }
        __syncthreads();
    }

    const int g = lane >> 2, t4 = lane & 3;
#pragma unroll
    for (int mt = 0; mt < 2; mt++) {
        int mrow = wm * 32 + mt * 16;
#pragma unroll
        for (int nt = 0; nt < 2 * NTP; nt++) {
            int ncol = wn * WN + nt * 8 + t4 * 2;
            *(float2*)(Cp + (size_t)(mrow + g) * ldc + ncol)     = make_float2(acc[mt][nt][0], acc[mt][nt][1]);
            *(float2*)(Cp + (size_t)(mrow + g + 8) * ldc + ncol) = make_float2(acc[mt][nt][2], acc[mt][nt][3]);
        }
    }
}

// ---------------------------------------------------------------------------
// Expert-grouped bf16-split HMMA GEMM with row gather/scatter.
// blockIdx.z = expert e. K = Kscale ? Kbase<<e : Kbase. Nlim likewise.
// A[token][lda], B[n][ldb], C[token][ldc]. CTA tile 128x128.
// ---------------------------------------------------------------------------
#define GOAH 0
#define GOAL 16384
#define GOBH 32768
#define GOBL 49152
#define GBUF 65536
#define GSM  (1024 + 3 * GBUF)   // 197632 (tok array lives in first 512 B)

__global__ void __launch_bounds__(256)
gemm_grouped_kernel(const __nv_bfloat16* __restrict__ Ah, const __nv_bfloat16* __restrict__ Al, int lda,
                    const __nv_bfloat16* __restrict__ Bh, const __nv_bfloat16* __restrict__ Bl, int ldb,
                    float* __restrict__ C, int ldc,
                    int Kbase, int Kscale, int Nbase, int Nscale) {
    const int e = blockIdx.z;
    const int cnt  = g_cnt[e];
    const int goff = g_goff[e];
    const int m0 = blockIdx.y * 128;
    if (m0 >= cnt) return;
    const int K    = Kscale ? (Kbase << e) : Kbase;
    const int Nlim = Nscale ? (Nbase << e) : Nbase;
    const int n0 = blockIdx.x * 128;
    if (n0 >= Nlim) return;

    extern __shared__ char smem_raw[];
    uint32_t sb0 = smem_u32(smem_raw);
    sb0 = (sb0 + 1023u) & ~1023u;
    int* tok = (int*)(smem_raw + (sb0 - smem_u32(smem_raw)));   // first 512 B of aligned region? keep separate:
    // place tok at aligned base, buffers at +1024
    uint32_t sb = sb0 + 1024u;

    const int tid  = threadIdx.x;
    const int wid  = tid >> 5;
    const int lane = tid & 31;
    const int wm = wid & 3;
    const int wn = wid >> 2;

    if (tid < 128) {
        int gr = m0 + tid;
        tok[tid] = g_perm[goff + ((gr < cnt) ? gr : 0)];
    }
    __syncthreads();

    const __nv_bfloat16* BBh = Bh + (size_t)n0 * ldb;
    const __nv_bfloat16* BBl = Bl + (size_t)n0 * ldb;

    const int NC = K / 64;

    auto load_chunk = [&](int c) {
        uint32_t bufb = sb + (uint32_t)(c % 3) * GBUF;
        int k0 = c * 64;
#pragma unroll
        for (int it = 0; it < 8; it++) {
            int i = tid + it * 256;
            int r = i >> 4, rem = i & 15, hl = rem >> 3, kg = rem & 7;
            const __nv_bfloat16* src = (hl ? Al : Ah) + (size_t)tok[r] * lda + k0 + kg * 8;
            cpa16(bufb + (hl ? GOAL : GOAH) + SWZ(r * 128 + kg * 16), src);
        }
#pragma unroll
        for (int it = 0; it < 8; it++) {
            int i = tid + it * 256;
            int r = i >> 4, rem = i & 15, hl = rem >> 3, kg = rem & 7;
            const __nv_bfloat16* src = (hl ? BBl : BBh) + (size_t)r * ldb + k0 + kg * 8;
            cpa16(bufb + (hl ? GOBL : GOBH) + SWZ(r * 128 + kg * 16), src);
        }
        CP_COMMIT();
    };

    load_chunk(0);
    if (NC > 1) load_chunk(1);

    float acc[2][8][4];
#pragma unroll
    for (int i = 0; i < 2; i++)
#pragma unroll
        for (int j = 0; j < 8; j++)
#pragma unroll
            for (int k = 0; k < 4; k++) acc[i][j][k] = 0.f;

    const int a_r16 = lane & 15;
    const int a_kb  = (lane >> 4) * 16;
    const int b_r8  = ((lane >> 4) << 3) + (lane & 7);
    const int b_kb  = ((lane >> 3) & 1) * 16;

    for (int c = 0; c < NC; c++) {
        if (c + 2 < NC) load_chunk(c + 2);
        int pend = NC - 1 - c; if (pend > 2) pend = 2;
        if (pend == 2) CP_WAIT2(); else if (pend == 1) CP_WAIT1(); else CP_WAIT0();
        __syncthreads();

        uint32_t bufb = sb + (uint32_t)(c % 3) * GBUF;
#pragma unroll
        for (int kk = 0; kk < 4; kk++) {
            int kb = kk * 32;
            uint32_t ah[2][4], al[2][4];
#pragma unroll
            for (int mt = 0; mt < 2; mt++) {
                int r = wm * 32 + mt * 16 + a_r16;
                uint32_t off = (uint32_t)(r * 128) + (uint32_t)((kb + a_kb) ^ ((r & 7) << 4));
                ldsm4(ah[mt], bufb + GOAH + off);
                ldsm4(al[mt], bufb + GOAL + off);
            }
#pragma unroll
            for (int ntp = 0; ntp < 4; ntp++) {
                int r = wn * 64 + ntp * 16 + b_r8;
                uint32_t off = (uint32_t)(r * 128) + (uint32_t)((kb + b_kb) ^ ((r & 7) << 4));
                uint32_t bh[4], bl[4];
                ldsm4(bh, bufb + GOBH + off);
                ldsm4(bl, bufb + GOBL + off);
#pragma unroll
                for (int mt = 0; mt < 2; mt++) {
                    mma16816(acc[mt][2 * ntp],     ah[mt], bh);
                    mma16816(acc[mt][2 * ntp],     ah[mt], bl);
                    mma16816(acc[mt][2 * ntp],     al[mt], bh);
                    mma16816(acc[mt][2 * ntp + 1], ah[mt], bh + 2);
                    mma16816(acc[mt][2 * ntp + 1], ah[mt], bl + 2);
                    mma16816(acc[mt][2 * ntp + 1], al[mt], bh + 2);
                }
            }
        }
        __syncthreads();
    }

    // Scatter epilogue (guard dummy rows)
    const int g = lane >> 2, t4 = lane & 3;
#pragma unroll
    for (int mt = 0; mt < 2; mt++) {
        int r0 = wm * 32 + mt * 16 + g;
        int r1 = r0 + 8;
        int tk0 = tok[r0], tk1 = tok[r1];
        bool ok0 = (m0 + r0) < cnt, ok1 = (m0 + r1) < cnt;
#pragma unroll
        for (int nt = 0; nt < 8; nt++) {
            int ncol = n0 + wn * 64 + nt * 8 + t4 * 2;
            if (ok0) *(float2*)(C + (size_t)tk0 * ldc + ncol) = make_float2(acc[mt][nt][0], acc[mt][nt][1]);
            if (ok1) *(float2*)(C + (size_t)tk1 * ldc + ncol) = make_float2(acc[mt][nt][2], acc[mt][nt][3]);
        }
    }
}

// ---------------------------------------------------------------------------
// Expert permutation kernels
// ---------------------------------------------------------------------------
__global__ void perm_init_kernel() {
    if (threadIdx.x < 4) { g_cnt[threadIdx.x] = 0; g_cur[threadIdx.x] = 0; }
}
__global__ void perm_count_kernel(const int* __restrict__ em) {
    int i = blockIdx.x * 256 + threadIdx.x;
    if (i < TOK) atomicAdd(&g_cnt[em[i]], 1);
}
__global__ void perm_scan_kernel() {
    if (threadIdx.x == 0) {
        int o = 0;
        for (int e = 0; e < 4; e++) { g_goff[e] = o; o += g_cnt[e]; }
    }
}
__global__ void perm_fill_kernel(const int* __restrict__ em) {
    int i = blockIdx.x * 256 + threadIdx.x;
    if (i < TOK) {
        int e = em[i];
        int p = atomicAdd(&g_cur[e], 1);
        g_perm[g_goff[e] + p] = i;
    }
}

// ---------------------------------------------------------------------------
// fp32 -> bf16 hi/lo split helpers
// ---------------------------------------------------------------------------
__device__ __forceinline__ void split1(float x, __nv_bfloat16& h, __nv_bfloat16& l) {
    h = __float2bfloat16(x);
    l = __float2bfloat16(x - __bfloat162float(h));
}

__global__ void split4_kernel(const float* __restrict__ s,
                              __nv_bfloat16* __restrict__ hi, __nv_bfloat16* __restrict__ lo) {
    size_t i = (size_t)blockIdx.x * 256 + threadIdx.x;
    float4 v = ((const float4*)s)[i];
    __nv_bfloat16 h0, h1, h2, h3, l0, l1, l2, l3;
    split1(v.x, h0, l0); split1(v.y, h1, l1); split1(v.z, h2, l2); split1(v.w, h3, l3);
    __nv_bfloat162* H = (__nv_bfloat162*)hi;
    __nv_bfloat162* L = (__nv_bfloat162*)lo;
    H[2 * i] = __nv_bfloat162(h0, h1); H[2 * i + 1] = __nv_bfloat162(h2, h3);
    L[2 * i] = __nv_bfloat162(l0, l1); L[2 * i + 1] = __nv_bfloat162(l2, l3);
}

__global__ void split_hattn_kernel() {
    size_t i = (size_t)blockIdx.x * 256 + threadIdx.x;
    int t = (int)(i >> 8);
    int j = (int)(i & 255) * 4;
    float4 v = ((const float4*)g_hattn)[i];
    size_t o = (size_t)t * CINC + j;
    __nv_bfloat16 h0, h1, h2, h3, l0, l1, l2, l3;
    split1(v.x, h0, l0); split1(v.y, h1, l1); split1(v.z, h2, l2); split1(v.w, h3, l3);
    *(__nv_bfloat162*)(g_h_hi + o)     = __nv_bfloat162(h0, h1);
    *(__nv_bfloat162*)(g_h_hi + o + 2) = __nv_bfloat162(h2, h3);
    *(__nv_bfloat162*)(g_h_lo + o)     = __nv_bfloat162(l0, l1);
    *(__nv_bfloat162*)(g_h_lo + o + 2) = __nv_bfloat162(l2, l3);
}

// ---------------------------------------------------------------------------
// LayerNorm 1 -> masked xn as bf16 hi/lo
// ---------------------------------------------------------------------------
__global__ void ln1_kernel(const float* __restrict__ x, const int* __restrict__ em,
                           const float* __restrict__ g, const float* __restrict__ b) {
    int t = blockIdx.x;
    const float* xr = x + (size_t)t * DIMC;
    int tid = threadIdx.x;
    float v[4]; float s = 0.f, s2 = 0.f;
#pragma unroll
    for (int i = 0; i < 4; i++) { float a = xr[tid + 256 * i]; v[i] = a; s += a; s2 += a * a; }
#pragma unroll
    for (int o = 16; o; o >>= 1) { s += __shfl_xor_sync(0xffffffffu, s, o); s2 += __shfl_xor_sync(0xffffffffu, s2, o); }
    __shared__ float red[18];
    int w = tid >> 5, l = tid & 31;
    if (l == 0) { red[w] = s; red[8 + w] = s2; }
    __syncthreads();
    if (tid == 0) {
        float ts = 0.f, ts2 = 0.f;
        for (int i = 0; i < 8; i++) { ts += red[i]; ts2 += red[8 + i]; }
        float m = ts * (1.f / DIMC);
        float var = ts2 * (1.f / DIMC) - m * m;
        red[16] = m; red[17] = rsqrtf(var + 1e-5f);
    }
    __syncthreads();
    float m = red[16], rs = red[17];
    int din = DIMC >> (3 - em[t]);
#pragma unroll
    for (int i = 0; i < 4; i++) {
        int c = tid + 256 * i;
        float val = (v[i] - m) * rs * g[c] + b[c];
        val = (c < din) ? val : 0.f;
        __nv_bfloat16 h, lo; split1(val, h, lo);
        g_xn_hi[(size_t)t * DIMC + c] = h;
        g_xn_lo[(size_t)t * DIMC + c] = lo;
    }
}

// ---------------------------------------------------------------------------
// LayerNorm 2 (in place on g_y k/v columns)
// ---------------------------------------------------------------------------
__global__ void ln2_kernel(const float* __restrict__ g, const float* __restrict__ b) {
    int t = blockIdx.x;
    float* row = g_y + (size_t)t * EXPC + (size_t)DIMC * (1 + blockIdx.y);
    int tid = threadIdx.x;
    float v[4]; float s = 0.f, s2 = 0.f;
#pragma unroll
    for (int i = 0; i < 4; i++) { float a = row[tid + 256 * i]; v[i] = a; s += a; s2 += a * a; }
#pragma unroll
    for (int o = 16; o; o >>= 1) { s += __shfl_xor_sync(0xffffffffu, s, o); s2 += __shfl_xor_sync(0xffffffffu, s2, o); }
    __shared__ float red[18];
    int w = tid >> 5, l = tid & 31;
    if (l == 0) { red[w] = s; red[8 + w] = s2; }
    __syncthreads();
    if (tid == 0) {
        float ts = 0.f, ts2 = 0.f;
        for (int i = 0; i < 8; i++) { ts += red[i]; ts2 += red[8 + i]; }
        float m = ts * (1.f / DIMC);
        float var = ts2 * (1.f / DIMC) - m * m;
        red[16] = m; red[17] = rsqrtf(var + 1e-5f);
    }
    __syncthreads();
    float m = red[16], rs = red[17];
#pragma unroll
    for (int i = 0; i < 4; i++) {
        int c = tid + 256 * i;
        row[c] = (v[i] - m) * rs * g[c] + b[c];
    }
}

// ---------------------------------------------------------------------------
// Pack Q (scaled by 1/8) and K into per-head bf16 hi/lo: [bh][seq][64]
// ---------------------------------------------------------------------------
__global__ void qk_pack_kernel() {
    int t = blockIdx.x;
    int b = t >> 10, s = t & 1023;
    int tid = threadIdx.x;
#pragma unroll
    for (int i = 0; i < 4; i++) {
        int d = tid + 256 * i;
        int h = d >> 6, hd = d & 63;
        size_t o = ((size_t)(b * NHC + h) * SEQC + s) * HDC + hd;
        float q = g_y[(size_t)t * EXPC + d] * 0.125f;
        float k = g_y[(size_t)t * EXPC + DIMC + d];
        __nv_bfloat16 hh, ll;
        split1(q, hh, ll); g_q_hi[o] = hh; g_q_lo[o] = ll;
        split1(k, hh, ll); g_k_hi[o] = hh; g_k_lo[o] = ll;
    }
}

// ---------------------------------------------------------------------------
// Pack V transposed per head
// ---------------------------------------------------------------------------
__global__ void vt_pack_kernel() {
    __shared__ float tile[64][65];
    int bh = blockIdx.x;
    int b = bh >> 4, h = bh & 15;
    int s0 = blockIdx.y * 64;
    int tid = threadIdx.x;
#pragma unroll
    for (int i = 0; i < 16; i++) {
        int idx = tid + i * 256;
        int r = idx >> 6, c = idx & 63;
        tile[r][c] = g_y[(size_t)(b * 1024 + s0 + r) * EXPC + 2 * DIMC + h * 64 + c];
    }
    __syncthreads();
#pragma unroll
    for (int i = 0; i < 16; i++) {
        int idx = tid + i * 256;
        int r = idx >> 6, c = idx & 63;
        float v = tile[c][r];
        __nv_bfloat16 hh, ll; split1(v, hh, ll);
        size_t o = (size_t)bh * HDC * SEQC + (size_t)r * SEQC + s0 + c;
        g_vt_hi[o] = hh; g_vt_lo[o] = ll;
    }
}

// ---------------------------------------------------------------------------
// Row softmax over g_s -> P written as bf16 hi/lo
// ---------------------------------------------------------------------------
__global__ void softmax_kernel() {
    const float* row = g_s + (size_t)blockIdx.x * SEQC;
    __nv_bfloat16* ph = g_p_hi + (size_t)blockIdx.x * SEQC;
    __nv_bfloat16* pl = g_p_lo + (size_t)blockIdx.x * SEQC;
    int tid = threadIdx.x;
    float v[4];
    float mx = -1e30f;
#pragma unroll
    for (int i = 0; i < 4; i++) { v[i] = row[tid + 256 * i]; mx = fmaxf(mx, v[i]); }
#pragma unroll
    for (int o = 16; o; o >>= 1) mx = fmaxf(mx, __shfl_xor_sync(0xffffffffu, mx, o));
    __shared__ float red[10];
    int w = tid >> 5, l = tid & 31;
    if (l == 0) red[w] = mx;
    __syncthreads();
    if (tid == 0) {
        float m = red[0];
        for (int i = 1; i < 8; i++) m = fmaxf(m, red[i]);
        red[8] = m;
    }
    __syncthreads();
    mx = red[8];
    float s = 0.f;
#pragma unroll
    for (int i = 0; i < 4; i++) { v[i] = __expf(v[i] - mx); s += v[i]; }
#pragma unroll
    for (int o = 16; o; o >>= 1) s += __shfl_xor_sync(0xffffffffu, s, o);
    if (l == 0) red[w] = s;
    __syncthreads();
    if (tid == 0) {
        float ts = 0.f;
        for (int i = 0; i < 8; i++) ts += red[i];
        red[9] = 1.f / ts;
    }
    __syncthreads();
    float inv = red[9];
#pragma unroll
    for (int i = 0; i < 4; i++) {
        int c = tid + 256 * i;
        __nv_bfloat16 hh, ll; split1(v[i] * inv, hh, ll);
        ph[c] = hh; pl[c] = ll;
    }
}

// ---------------------------------------------------------------------------
// GELU(exact) -> g_h hi/lo mlp region
// ---------------------------------------------------------------------------
__global__ void gelu_kernel(const float* __restrict__ mlpb) {
    size_t idx = (size_t)blockIdx.x * 256 + threadIdx.x;
    int t = (int)(idx >> 12);
    int j = (int)(idx & 4095);
    float xv = g_y[(size_t)t * EXPC + 3 * DIMC + j] + mlpb[j];
    float gl = 0.5f * xv * (1.f + erff(xv * 0.70710678118654752f));
    __nv_bfloat16 h, lo; split1(gl, h, lo);
    g_h_hi[(size_t)t * CINC + DIMC + j] = h;
    g_h_lo[(size_t)t * CINC + DIMC + j] = lo;
}

// ---------------------------------------------------------------------------
// Final epilogue + pass-through tails
// ---------------------------------------------------------------------------
__global__ void final_kernel(const float* __restrict__ x, const int* __restrict__ em,
                             const float* __restrict__ rp, const float* __restrict__ cb,
                             const float* __restrict__ alpha, float* __restrict__ out) {
    size_t idx = (size_t)blockIdx.x * 256 + threadIdx.x;
    int t = (int)(idx >> 10);
    int d = (int)(idx & 1023);
    int m = em[t];
    int dout = (2 * DIMC) >> (3 - m);
    const float* zr = g_z + (size_t)t * 2 * DIMC;
    float za = (d < dout) ? (zr[d] + cb[d]) : 0.f;
    float zm = (DIMC + d < dout) ? (zr[DIMC + d] + cb[DIMC + d]) : 0.f;
    float pr = rp[t * 4 + m];
    out[idx] = x[idx] + za + (alpha[0] * pr + 1.f) * zm;
}

__global__ void tail_kernel(const int* __restrict__ em, const float* __restrict__ rp,
                            float* __restrict__ out) {
    int i = blockIdx.x * 256 + threadIdx.x;
    if (i < TOK)     out[(size_t)TOK * DIMC + i] = (float)em[i];
    if (i < TOK * 4) out[(size_t)TOK * DIMC + TOK + i] = rp[i];
}

// ---------------------------------------------------------------------------
extern "C" void kernel_launch(void* const* d_in, const int* in_sizes, int n_in,
                              void* d_out, int out_size) {
    const float* x     = (const float*)d_in[0];
    const int*   em    = (const int*)d_in[1];
    const float* rp    = (const float*)d_in[2];
    const float* wexp  = (const float*)d_in[3];
    const float* mlpb  = (const float*)d_in[4];
    const float* wc    = (const float*)d_in[5];
    const float* cb    = (const float*)d_in[6];
    const float* n1g   = (const float*)d_in[7];
    const float* n1b   = (const float*)d_in[8];
    const float* n2g   = (const float*)d_in[9];
    const float* n2b   = (const float*)d_in[10];
    const float* alpha = (const float*)d_in[11];
    float* out = (float*)d_out;

    float *p_y, *p_s, *p_z, *p_ha;
    __nv_bfloat16 *p_xnh, *p_xnl, *p_weh, *p_wel, *p_wch, *p_wcl, *p_hh, *p_hl;
    __nv_bfloat16 *p_qh, *p_ql, *p_kh, *p_kl, *p_vth, *p_vtl, *p_ph, *p_pl;
    cudaGetSymbolAddress((void**)&p_y,   g_y);
    cudaGetSymbolAddress((void**)&p_s,   g_s);
    cudaGetSymbolAddress((void**)&p_z,   g_z);
    cudaGetSymbolAddress((void**)&p_ha,  g_hattn);
    cudaGetSymbolAddress((void**)&p_xnh, g_xn_hi);
    cudaGetSymbolAddress((void**)&p_xnl, g_xn_lo);
    cudaGetSymbolAddress((void**)&p_weh, g_we_hi);
    cudaGetSymbolAddress((void**)&p_wel, g_we_lo);
    cudaGetSymbolAddress((void**)&p_wch, g_wc_hi);
    cudaGetSymbolAddress((void**)&p_wcl, g_wc_lo);
    cudaGetSymbolAddress((void**)&p_hh,  g_h_hi);
    cudaGetSymbolAddress((void**)&p_hl,  g_h_lo);
    cudaGetSymbolAddress((void**)&p_qh,  g_q_hi);
    cudaGetSymbolAddress((void**)&p_ql,  g_q_lo);
    cudaGetSymbolAddress((void**)&p_kh,  g_k_hi);
    cudaGetSymbolAddress((void**)&p_kl,  g_k_lo);
    cudaGetSymbolAddress((void**)&p_vth, g_vt_hi);
    cudaGetSymbolAddress((void**)&p_vtl, g_vt_lo);
    cudaGetSymbolAddress((void**)&p_ph,  g_p_hi);
    cudaGetSymbolAddress((void**)&p_pl,  g_p_lo);

    const int SM128 = 3 * (32768 + 2 * 128 * 128) + 1024;
    const int SM64  = 3 * (32768 + 2 * 64 * 128) + 1024;
    cudaFuncSetAttribute(gemm_mma_kernel<128>, cudaFuncAttributeMaxDynamicSharedMemorySize, SM128);
    cudaFuncSetAttribute(gemm_mma_kernel<64>,  cudaFuncAttributeMaxDynamicSharedMemorySize, SM64);
    cudaFuncSetAttribute(gemm_grouped_kernel,  cudaFuncAttributeMaxDynamicSharedMemorySize, GSM);

    // 0) expert permutation (deterministic output regardless of atomic order)
    perm_init_kernel<<<1, 32>>>();
    perm_count_kernel<<<TOK / 256, 256>>>(em);
    perm_scan_kernel<<<1, 32>>>();
    perm_fill_kernel<<<TOK / 256, 256>>>(em);

    // 0b) weight splits
    split4_kernel<<<(EXPC * DIMC) / 4 / 256, 256>>>(wexp, p_weh, p_wel);
    split4_kernel<<<(2 * DIMC * CINC) / 4 / 256, 256>>>(wc, p_wch, p_wcl);

    // 1) LN1 + input mask
    ln1_kernel<<<TOK, 256>>>(x, em, n1g, n1b);

    // 2) expand (grouped by expert): y = xn @ Wexp^T, K_e = 128<<e
    gemm_grouped_kernel<<<dim3(EXPC / 128, TOK / 128, 4), 256, GSM>>>(
        p_xnh, p_xnl, DIMC, p_weh, p_wel, DIMC, p_y, EXPC,
        128, 1, EXPC, 0);

    // 3) LN2 on k/v
    ln2_kernel<<<dim3(TOK, 2), 256>>>(n2g, n2b);

    // 4) pack Q/K and transposed V
    qk_pack_kernel<<<TOK, 256>>>();
    vt_pack_kernel<<<dim3(BH, SEQC / 64), 256>>>();

    // 5) S = (Q/8) K^T per head
    gemm_mma_kernel<128><<<dim3(SEQC / 128, SEQC / 128, BH), 256, SM128>>>(
        p_qh, p_ql, (size_t)SEQC * HDC, 0,
        p_kh, p_kl, (size_t)SEQC * HDC, 0,
        p_s, SEQC, (size_t)SEQC * SEQC, 0, 1, HDC);

    // 6) softmax -> P bf16 hi/lo
    softmax_kernel<<<BH * SEQC, 256>>>();

    // 7) GELU -> h mlp region
    gelu_kernel<<<(TOK * 4096) / 256, 256>>>(mlpb);

    // 8) attn_out = P @ V per head
    gemm_mma_kernel<64><<<dim3(1, SEQC / 128, BH), 256, SM64>>>(
        p_ph, p_pl, (size_t)NHC * SEQC * SEQC, (size_t)SEQC * SEQC,
        p_vth, p_vtl, (size_t)NHC * HDC * SEQC, (size_t)HDC * SEQC,
        p_ha, DIMC, (size_t)SEQC * DIMC, (size_t)HDC, NHC, SEQC);

    // 8b) split attn_out into h[:, 0:1024]
    split_hattn_kernel<<<(TOK * DIMC) / 4 / 256, 256>>>();

    // 9) contract (grouped by expert): z = h @ Wc^T, N_e = 256<<e
    gemm_grouped_kernel<<<dim3(16, TOK / 128, 4), 256, GSM>>>(
        p_hh, p_hl, CINC, p_wch, p_wcl, CINC, p_z, 2 * DIMC,
        CINC, 0, 256, 1);

    // 10) epilogue + tails
    final_kernel<<<(TOK * DIMC) / 256, 256>>>(x, em, rp, cb, alpha, out);
    tail_kernel<<<(TOK * 4 + 255) / 256, 256>>>(em, rp, out);
}

// round 6
// speedup vs baseline: 5.0148x; 1.1782x over previous
#include <cuda_runtime.h>
#include <cuda_bf16.h>
#include <math.h>
#include <stdint.h>

// Problem constants
#define TOK   8192        // B*N
#define DIMC  1024
#define EXPC  7168
#define CINC  5120
#define NHC   16
#define HDC   64
#define SEQC  1024
#define NB    8
#define BH    (NB * NHC)  // 128 batch-heads

// ---------------------------------------------------------------------------
// Scratch (device globals; allocation-free)
// ---------------------------------------------------------------------------
__device__ float g_y [(size_t)TOK * EXPC];                    // 235 MB
__device__ float g_z [(size_t)TOK * 2 * DIMC];                //  67 MB

__device__ __nv_bfloat16 g_xn_hi[(size_t)TOK * DIMC];
__device__ __nv_bfloat16 g_xn_lo[(size_t)TOK * DIMC];
__device__ __nv_bfloat16 g_we_hi[(size_t)EXPC * DIMC];
__device__ __nv_bfloat16 g_we_lo[(size_t)EXPC * DIMC];
__device__ __nv_bfloat16 g_wc_hi[(size_t)2 * DIMC * CINC];
__device__ __nv_bfloat16 g_wc_lo[(size_t)2 * DIMC * CINC];
__device__ __nv_bfloat16 g_h_hi[(size_t)TOK * CINC];
__device__ __nv_bfloat16 g_h_lo[(size_t)TOK * CINC];

// attention operands (per-head layouts)
__device__ __nv_bfloat16 g_q_hi[(size_t)BH * SEQC * HDC];
__device__ __nv_bfloat16 g_q_lo[(size_t)BH * SEQC * HDC];
__device__ __nv_bfloat16 g_k_hi[(size_t)BH * SEQC * HDC];
__device__ __nv_bfloat16 g_k_lo[(size_t)BH * SEQC * HDC];
__device__ __nv_bfloat16 g_vt_hi[(size_t)BH * HDC * SEQC];
__device__ __nv_bfloat16 g_vt_lo[(size_t)BH * HDC * SEQC];

// expert grouping
__device__ int g_cnt[4];
__device__ int g_cur[4];
__device__ int g_goff[4];
__device__ int g_perm[TOK];

// ---------------------------------------------------------------------------
// PTX helpers (sm_80-level: ldmatrix / mma / cp.async)
// ---------------------------------------------------------------------------
__device__ __forceinline__ uint32_t smem_u32(const void* p) {
    uint32_t a;
    asm("{ .reg .u64 t; cvta.to.shared.u64 t, %1; cvt.u32.u64 %0, t; }" : "=r"(a) : "l"(p));
    return a;
}
__device__ __forceinline__ void ldsm4(uint32_t* r, uint32_t a) {
    asm volatile("ldmatrix.sync.aligned.m8n8.x4.shared.b16 {%0,%1,%2,%3}, [%4];"
                 : "=r"(r[0]), "=r"(r[1]), "=r"(r[2]), "=r"(r[3]) : "r"(a));
}
__device__ __forceinline__ void mma16816(float* c, const uint32_t* a, const uint32_t* b) {
    asm volatile("mma.sync.aligned.m16n8k16.row.col.f32.bf16.bf16.f32 "
                 "{%0,%1,%2,%3}, {%4,%5,%6,%7}, {%8,%9}, {%0,%1,%2,%3};"
                 : "+f"(c[0]), "+f"(c[1]), "+f"(c[2]), "+f"(c[3])
                 : "r"(a[0]), "r"(a[1]), "r"(a[2]), "r"(a[3]), "r"(b[0]), "r"(b[1]));
}
__device__ __forceinline__ void cpa16(uint32_t s, const void* g) {
    asm volatile("cp.async.cg.shared.global [%0], [%1], 16;" :: "r"(s), "l"(g));
}
#define CP_COMMIT() asm volatile("cp.async.commit_group;")
#define CP_WAIT2()  asm volatile("cp.async.wait_group 2;")
#define CP_WAIT1()  asm volatile("cp.async.wait_group 1;")
#define CP_WAIT0()  asm volatile("cp.async.wait_group 0;")

// SW128 swizzle
#define SWZ(o) ((o) ^ (((o) >> 3) & 0x70))

__device__ __forceinline__ void split1(float x, __nv_bfloat16& h, __nv_bfloat16& l) {
    h = __float2bfloat16(x);
    l = __float2bfloat16(x - __bfloat162float(h));
}
__device__ __forceinline__ uint32_t pack_bf2(__nv_bfloat16 a, __nv_bfloat16 b) {
    __nv_bfloat162 v(a, b);
    return *(uint32_t*)&v;
}

// ---------------------------------------------------------------------------
// Expert-grouped bf16-split HMMA GEMM with row gather/scatter.
// ---------------------------------------------------------------------------
#define GOAH 0
#define GOAL 16384
#define GOBH 32768
#define GOBL 49152
#define GBUF 65536
#define GSM  (1024 + 3 * GBUF)

__global__ void __launch_bounds__(256)
gemm_grouped_kernel(const __nv_bfloat16* __restrict__ Ah, const __nv_bfloat16* __restrict__ Al, int lda,
                    const __nv_bfloat16* __restrict__ Bh, const __nv_bfloat16* __restrict__ Bl, int ldb,
                    float* __restrict__ C, int ldc,
                    int Kbase, int Kscale, int Nbase, int Nscale) {
    const int e = blockIdx.z;
    const int cnt  = g_cnt[e];
    const int goff = g_goff[e];
    const int m0 = blockIdx.y * 128;
    if (m0 >= cnt) return;
    const int K    = Kscale ? (Kbase << e) : Kbase;
    const int Nlim = Nscale ? (Nbase << e) : Nbase;
    const int n0 = blockIdx.x * 128;
    if (n0 >= Nlim) return;

    extern __shared__ char smem_raw[];
    uint32_t sb0 = smem_u32(smem_raw);
    sb0 = (sb0 + 1023u) & ~1023u;
    int* tok = (int*)(smem_raw + (sb0 - smem_u32(smem_raw)));
    uint32_t sb = sb0 + 1024u;

    const int tid  = threadIdx.x;
    const int wid  = tid >> 5;
    const int lane = tid & 31;
    const int wm = wid & 3;
    const int wn = wid >> 2;

    if (tid < 128) {
        int gr = m0 + tid;
        tok[tid] = g_perm[goff + ((gr < cnt) ? gr : 0)];
    }
    __syncthreads();

    const __nv_bfloat16* BBh = Bh + (size_t)n0 * ldb;
    const __nv_bfloat16* BBl = Bl + (size_t)n0 * ldb;

    const int NC = K / 64;

    auto load_chunk = [&](int c) {
        uint32_t bufb = sb + (uint32_t)(c % 3) * GBUF;
        int k0 = c * 64;
#pragma unroll
        for (int it = 0; it < 8; it++) {
            int i = tid + it * 256;
            int r = i >> 4, rem = i & 15, hl = rem >> 3, kg = rem & 7;
            const __nv_bfloat16* src = (hl ? Al : Ah) + (size_t)tok[r] * lda + k0 + kg * 8;
            cpa16(bufb + (hl ? GOAL : GOAH) + SWZ(r * 128 + kg * 16), src);
        }
#pragma unroll
        for (int it = 0; it < 8; it++) {
            int i = tid + it * 256;
            int r = i >> 4, rem = i & 15, hl = rem >> 3, kg = rem & 7;
            const __nv_bfloat16* src = (hl ? BBl : BBh) + (size_t)r * ldb + k0 + kg * 8;
            cpa16(bufb + (hl ? GOBL : GOBH) + SWZ(r * 128 + kg * 16), src);
        }
        CP_COMMIT();
    };

    load_chunk(0);
    if (NC > 1) load_chunk(1);

    float acc[2][8][4];
#pragma unroll
    for (int i = 0; i < 2; i++)
#pragma unroll
        for (int j = 0; j < 8; j++)
#pragma unroll
            for (int k = 0; k < 4; k++) acc[i][j][k] = 0.f;

    const int a_r16 = lane & 15;
    const int a_kb  = (lane >> 4) * 16;
    const int b_r8  = ((lane >> 4) << 3) + (lane & 7);
    const int b_kb  = ((lane >> 3) & 1) * 16;

    for (int c = 0; c < NC; c++) {
        if (c + 2 < NC) load_chunk(c + 2);
        int pend = NC - 1 - c; if (pend > 2) pend = 2;
        if (pend == 2) CP_WAIT2(); else if (pend == 1) CP_WAIT1(); else CP_WAIT0();
        __syncthreads();

        uint32_t bufb = sb + (uint32_t)(c % 3) * GBUF;
#pragma unroll
        for (int kk = 0; kk < 4; kk++) {
            int kb = kk * 32;
            uint32_t ah[2][4], al[2][4];
#pragma unroll
            for (int mt = 0; mt < 2; mt++) {
                int r = wm * 32 + mt * 16 + a_r16;
                uint32_t off = (uint32_t)(r * 128) + (uint32_t)((kb + a_kb) ^ ((r & 7) << 4));
                ldsm4(ah[mt], bufb + GOAH + off);
                ldsm4(al[mt], bufb + GOAL + off);
            }
#pragma unroll
            for (int ntp = 0; ntp < 4; ntp++) {
                int r = wn * 64 + ntp * 16 + b_r8;
                uint32_t off = (uint32_t)(r * 128) + (uint32_t)((kb + b_kb) ^ ((r & 7) << 4));
                uint32_t bh[4], bl[4];
                ldsm4(bh, bufb + GOBH + off);
                ldsm4(bl, bufb + GOBL + off);
#pragma unroll
                for (int mt = 0; mt < 2; mt++) {
                    mma16816(acc[mt][2 * ntp],     ah[mt], bh);
                    mma16816(acc[mt][2 * ntp],     ah[mt], bl);
                    mma16816(acc[mt][2 * ntp],     al[mt], bh);
                    mma16816(acc[mt][2 * ntp + 1], ah[mt], bh + 2);
                    mma16816(acc[mt][2 * ntp + 1], ah[mt], bl + 2);
                    mma16816(acc[mt][2 * ntp + 1], al[mt], bh + 2);
                }
            }
        }
        __syncthreads();
    }

    const int g = lane >> 2, t4 = lane & 3;
#pragma unroll
    for (int mt = 0; mt < 2; mt++) {
        int r0 = wm * 32 + mt * 16 + g;
        int r1 = r0 + 8;
        int tk0 = tok[r0], tk1 = tok[r1];
        bool ok0 = (m0 + r0) < cnt, ok1 = (m0 + r1) < cnt;
#pragma unroll
        for (int nt = 0; nt < 8; nt++) {
            int ncol = n0 + wn * 64 + nt * 8 + t4 * 2;
            if (ok0) *(float2*)(C + (size_t)tk0 * ldc + ncol) = make_float2(acc[mt][nt][0], acc[mt][nt][1]);
            if (ok1) *(float2*)(C + (size_t)tk1 * ldc + ncol) = make_float2(acc[mt][nt][2], acc[mt][nt][3]);
        }
    }
}

// ---------------------------------------------------------------------------
// Flash attention: one CTA = 128 queries x one (b,h); streams 16 key-tiles.
// S and P in registers (hi/lo splits), O fp32, written as bf16 hi/lo to g_h.
// grid (8, BH), 256 threads (8 warps x 16 query rows).
// ---------------------------------------------------------------------------
#define FQH 0
#define FQL 16384
#define FST 32768     // stage base; per stage: KH +0, KL +8192, VH +16384, VL +24576
#define FSS 32768
#define FSM (32768 + 2 * 32768 + 1024)

__global__ void __launch_bounds__(256)
flash_kernel() {
    extern __shared__ char smem_raw[];
    uint32_t sb = smem_u32(smem_raw);
    sb = (sb + 1023u) & ~1023u;

    const int tid  = threadIdx.x;
    const int wid  = tid >> 5;
    const int lane = tid & 31;
    const int bh = blockIdx.y;
    const int q0 = blockIdx.x * 128;
    const int b = bh >> 4, h = bh & 15;

    const size_t qkbase = (size_t)bh * SEQC * HDC;
    const size_t vbase  = (size_t)bh * HDC * SEQC;

    auto load_q = [&]() {
#pragma unroll
        for (int it = 0; it < 8; it++) {
            int i = tid + it * 256;
            int r = i >> 4, rem = i & 15, hl = rem >> 3, kg = rem & 7;
            const __nv_bfloat16* src = (hl ? g_q_lo : g_q_hi) + qkbase + (size_t)(q0 + r) * HDC + kg * 8;
            cpa16(sb + (hl ? FQL : FQH) + SWZ(r * 128 + kg * 16), src);
        }
    };
    auto load_kv = [&](int t) {
        uint32_t bufb = sb + FST + (uint32_t)(t & 1) * FSS;
#pragma unroll
        for (int it = 0; it < 4; it++) {
            int i = tid + it * 256;
            int r = i >> 4, rem = i & 15, hl = rem >> 3, kg = rem & 7;
            const __nv_bfloat16* src = (hl ? g_k_lo : g_k_hi) + qkbase + (size_t)(t * 64 + r) * HDC + kg * 8;
            cpa16(bufb + (hl ? 8192 : 0) + SWZ(r * 128 + kg * 16), src);
        }
#pragma unroll
        for (int it = 0; it < 4; it++) {
            int i = tid + it * 256;
            int r = i >> 4, rem = i & 15, hl = rem >> 3, kg = rem & 7;
            const __nv_bfloat16* src = (hl ? g_vt_lo : g_vt_hi) + vbase + (size_t)r * SEQC + t * 64 + kg * 8;
            cpa16(bufb + 16384 + (hl ? 8192 : 0) + SWZ(r * 128 + kg * 16), src);
        }
        CP_COMMIT();
    };

    load_q(); load_kv(0); CP_COMMIT();   // group 0: Q + stage0
    load_kv(1);                          // group 1: stage1 (commit inside load_kv)

    const int a_r16 = lane & 15;
    const int a_kb  = (lane >> 4) * 16;
    const int b_r8  = ((lane >> 4) << 3) + (lane & 7);
    const int b_kb  = ((lane >> 3) & 1) * 16;

    uint32_t qhf[4][4], qlf[4][4];
    float o[8][4];
#pragma unroll
    for (int j = 0; j < 8; j++)
#pragma unroll
        for (int k = 0; k < 4; k++) o[j][k] = 0.f;
    float ml0 = -1e30f, ml1 = -1e30f, ls0 = 0.f, ls1 = 0.f;

    for (int t = 0; t < 16; t++) {
        if (t < 15) CP_WAIT1(); else CP_WAIT0();
        __syncthreads();
        if (t == 0) {
            // Q fragments (once)
#pragma unroll
            for (int kk = 0; kk < 4; kk++) {
                int r = wid * 16 + a_r16;
                uint32_t off = (uint32_t)(r * 128) + (uint32_t)((kk * 32 + a_kb) ^ ((r & 7) << 4));
                ldsm4(qhf[kk], sb + FQH + off);
                ldsm4(qlf[kk], sb + FQL + off);
            }
        }
        uint32_t bufb = sb + FST + (uint32_t)(t & 1) * FSS;

        // --- S = Q K^T (128x64 per CTA; 16x64 per warp) ---
        float s[8][4];
#pragma unroll
        for (int j = 0; j < 8; j++)
#pragma unroll
            for (int k = 0; k < 4; k++) s[j][k] = 0.f;
#pragma unroll
        for (int kk = 0; kk < 4; kk++) {
#pragma unroll
            for (int ntp = 0; ntp < 4; ntp++) {
                int r = ntp * 16 + b_r8;
                uint32_t off = (uint32_t)(r * 128) + (uint32_t)((kk * 32 + b_kb) ^ ((r & 7) << 4));
                uint32_t khf[4], klf[4];
                ldsm4(khf, bufb + off);
                ldsm4(klf, bufb + 8192 + off);
                mma16816(s[2 * ntp],     qhf[kk], khf);
                mma16816(s[2 * ntp],     qhf[kk], klf);
                mma16816(s[2 * ntp],     qlf[kk], khf);
                mma16816(s[2 * ntp + 1], qhf[kk], khf + 2);
                mma16816(s[2 * ntp + 1], qhf[kk], klf + 2);
                mma16816(s[2 * ntp + 1], qlf[kk], khf + 2);
            }
        }

        // --- online softmax (rows g and g+8 within warp's 16) ---
        float m0t = -1e30f, m1t = -1e30f;
#pragma unroll
        for (int j = 0; j < 8; j++) {
            m0t = fmaxf(m0t, fmaxf(s[j][0], s[j][1]));
            m1t = fmaxf(m1t, fmaxf(s[j][2], s[j][3]));
        }
        m0t = fmaxf(m0t, __shfl_xor_sync(0xffffffffu, m0t, 1));
        m0t = fmaxf(m0t, __shfl_xor_sync(0xffffffffu, m0t, 2));
        m1t = fmaxf(m1t, __shfl_xor_sync(0xffffffffu, m1t, 1));
        m1t = fmaxf(m1t, __shfl_xor_sync(0xffffffffu, m1t, 2));
        float mn0 = fmaxf(ml0, m0t), mn1 = fmaxf(ml1, m1t);
        float sc0 = __expf(ml0 - mn0), sc1 = __expf(ml1 - mn1);
        ml0 = mn0; ml1 = mn1;
        float r0 = 0.f, r1 = 0.f;
#pragma unroll
        for (int j = 0; j < 8; j++) {
            s[j][0] = __expf(s[j][0] - mn0);
            s[j][1] = __expf(s[j][1] - mn0);
            s[j][2] = __expf(s[j][2] - mn1);
            s[j][3] = __expf(s[j][3] - mn1);
            r0 += s[j][0] + s[j][1];
            r1 += s[j][2] + s[j][3];
        }
        r0 += __shfl_xor_sync(0xffffffffu, r0, 1);
        r0 += __shfl_xor_sync(0xffffffffu, r0, 2);
        r1 += __shfl_xor_sync(0xffffffffu, r1, 1);
        r1 += __shfl_xor_sync(0xffffffffu, r1, 2);
        ls0 = ls0 * sc0 + r0;
        ls1 = ls1 * sc1 + r1;
#pragma unroll
        for (int j = 0; j < 8; j++) {
            o[j][0] *= sc0; o[j][1] *= sc0;
            o[j][2] *= sc1; o[j][3] *= sc1;
        }

        // --- pack P into A fragments (hi/lo) ---
        uint32_t pah[4][4], pal[4][4];
#pragma unroll
        for (int kt = 0; kt < 4; kt++) {
            __nv_bfloat16 h0, l0, h1, l1;
            split1(s[2 * kt][0], h0, l0); split1(s[2 * kt][1], h1, l1);
            pah[kt][0] = pack_bf2(h0, h1); pal[kt][0] = pack_bf2(l0, l1);
            split1(s[2 * kt][2], h0, l0); split1(s[2 * kt][3], h1, l1);
            pah[kt][1] = pack_bf2(h0, h1); pal[kt][1] = pack_bf2(l0, l1);
            split1(s[2 * kt + 1][0], h0, l0); split1(s[2 * kt + 1][1], h1, l1);
            pah[kt][2] = pack_bf2(h0, h1); pal[kt][2] = pack_bf2(l0, l1);
            split1(s[2 * kt + 1][2], h0, l0); split1(s[2 * kt + 1][3], h1, l1);
            pah[kt][3] = pack_bf2(h0, h1); pal[kt][3] = pack_bf2(l0, l1);
        }

        // --- O += P V  (B = V^T tile [hd][keys]) ---
#pragma unroll
        for (int kt = 0; kt < 4; kt++) {
#pragma unroll
            for (int nv = 0; nv < 4; nv++) {
                int r = nv * 16 + b_r8;
                uint32_t off = (uint32_t)(r * 128) + (uint32_t)((kt * 32 + b_kb) ^ ((r & 7) << 4));
                uint32_t vhf[4], vlf[4];
                ldsm4(vhf, bufb + 16384 + off);
                ldsm4(vlf, bufb + 24576 + off);
                mma16816(o[2 * nv],     pah[kt], vhf);
                mma16816(o[2 * nv],     pah[kt], vlf);
                mma16816(o[2 * nv],     pal[kt], vhf);
                mma16816(o[2 * nv + 1], pah[kt], vhf + 2);
                mma16816(o[2 * nv + 1], pah[kt], vlf + 2);
                mma16816(o[2 * nv + 1], pal[kt], vhf + 2);
            }
        }
        __syncthreads();
        if (t + 2 < 16) load_kv(t + 2);
    }

    // --- epilogue: O / l -> g_h hi/lo rows ---
    const int g = lane >> 2, t4 = lane & 3;
    float i0 = 1.f / ls0, i1 = 1.f / ls1;
    int tok0 = b * 1024 + q0 + wid * 16 + g;
    int tok1 = tok0 + 8;
#pragma unroll
    for (int j = 0; j < 8; j++) {
        int col = h * 64 + j * 8 + t4 * 2;
        __nv_bfloat16 h0, l0, h1, l1;
        split1(o[j][0] * i0, h0, l0); split1(o[j][1] * i0, h1, l1);
        *(uint32_t*)(g_h_hi + (size_t)tok0 * CINC + col) = pack_bf2(h0, h1);
        *(uint32_t*)(g_h_lo + (size_t)tok0 * CINC + col) = pack_bf2(l0, l1);
        split1(o[j][2] * i1, h0, l0); split1(o[j][3] * i1, h1, l1);
        *(uint32_t*)(g_h_hi + (size_t)tok1 * CINC + col) = pack_bf2(h0, h1);
        *(uint32_t*)(g_h_lo + (size_t)tok1 * CINC + col) = pack_bf2(l0, l1);
    }
}

// ---------------------------------------------------------------------------
// Expert permutation kernels
// ---------------------------------------------------------------------------
__global__ void perm_init_kernel() {
    if (threadIdx.x < 4) { g_cnt[threadIdx.x] = 0; g_cur[threadIdx.x] = 0; }
}
__global__ void perm_count_kernel(const int* __restrict__ em) {
    int i = blockIdx.x * 256 + threadIdx.x;
    if (i < TOK) atomicAdd(&g_cnt[em[i]], 1);
}
__global__ void perm_scan_kernel() {
    if (threadIdx.x == 0) {
        int o = 0;
        for (int e = 0; e < 4; e++) { g_goff[e] = o; o += g_cnt[e]; }
    }
}
__global__ void perm_fill_kernel(const int* __restrict__ em) {
    int i = blockIdx.x * 256 + threadIdx.x;
    if (i < TOK) {
        int e = em[i];
        int p = atomicAdd(&g_cur[e], 1);
        g_perm[g_goff[e] + p] = i;
    }
}

// ---------------------------------------------------------------------------
// splits / LN / packs / GELU / epilogue (as before)
// ---------------------------------------------------------------------------
__global__ void split4_kernel(const float* __restrict__ s,
                              __nv_bfloat16* __restrict__ hi, __nv_bfloat16* __restrict__ lo) {
    size_t i = (size_t)blockIdx.x * 256 + threadIdx.x;
    float4 v = ((const float4*)s)[i];
    __nv_bfloat16 h0, h1, h2, h3, l0, l1, l2, l3;
    split1(v.x, h0, l0); split1(v.y, h1, l1); split1(v.z, h2, l2); split1(v.w, h3, l3);
    __nv_bfloat162* H = (__nv_bfloat162*)hi;
    __nv_bfloat162* L = (__nv_bfloat162*)lo;
    H[2 * i] = __nv_bfloat162(h0, h1); H[2 * i + 1] = __nv_bfloat162(h2, h3);
    L[2 * i] = __nv_bfloat162(l0, l1); L[2 * i + 1] = __nv_bfloat162(l2, l3);
}

__global__ void ln1_kernel(const float* __restrict__ x, const int* __restrict__ em,
                           const float* __restrict__ g, const float* __restrict__ b) {
    int t = blockIdx.x;
    const float* xr = x + (size_t)t * DIMC;
    int tid = threadIdx.x;
    float v[4]; float s = 0.f, s2 = 0.f;
#pragma unroll
    for (int i = 0; i < 4; i++) { float a = xr[tid + 256 * i]; v[i] = a; s += a; s2 += a * a; }
#pragma unroll
    for (int o = 16; o; o >>= 1) { s += __shfl_xor_sync(0xffffffffu, s, o); s2 += __shfl_xor_sync(0xffffffffu, s2, o); }
    __shared__ float red[18];
    int w = tid >> 5, l = tid & 31;
    if (l == 0) { red[w] = s; red[8 + w] = s2; }
    __syncthreads();
    if (tid == 0) {
        float ts = 0.f, ts2 = 0.f;
        for (int i = 0; i < 8; i++) { ts += red[i]; ts2 += red[8 + i]; }
        float m = ts * (1.f / DIMC);
        float var = ts2 * (1.f / DIMC) - m * m;
        red[16] = m; red[17] = rsqrtf(var + 1e-5f);
    }
    __syncthreads();
    float m = red[16], rs = red[17];
    int din = DIMC >> (3 - em[t]);
#pragma unroll
    for (int i = 0; i < 4; i++) {
        int c = tid + 256 * i;
        float val = (v[i] - m) * rs * g[c] + b[c];
        val = (c < din) ? val : 0.f;
        __nv_bfloat16 h, lo; split1(val, h, lo);
        g_xn_hi[(size_t)t * DIMC + c] = h;
        g_xn_lo[(size_t)t * DIMC + c] = lo;
    }
}

__global__ void ln2_kernel(const float* __restrict__ g, const float* __restrict__ b) {
    int t = blockIdx.x;
    float* row = g_y + (size_t)t * EXPC + (size_t)DIMC * (1 + blockIdx.y);
    int tid = threadIdx.x;
    float v[4]; float s = 0.f, s2 = 0.f;
#pragma unroll
    for (int i = 0; i < 4; i++) { float a = row[tid + 256 * i]; v[i] = a; s += a; s2 += a * a; }
#pragma unroll
    for (int o = 16; o; o >>= 1) { s += __shfl_xor_sync(0xffffffffu, s, o); s2 += __shfl_xor_sync(0xffffffffu, s2, o); }
    __shared__ float red[18];
    int w = tid >> 5, l = tid & 31;
    if (l == 0) { red[w] = s; red[8 + w] = s2; }
    __syncthreads();
    if (tid == 0) {
        float ts = 0.f, ts2 = 0.f;
        for (int i = 0; i < 8; i++) { ts += red[i]; ts2 += red[8 + i]; }
        float m = ts * (1.f / DIMC);
        float var = ts2 * (1.f / DIMC) - m * m;
        red[16] = m; red[17] = rsqrtf(var + 1e-5f);
    }
    __syncthreads();
    float m = red[16], rs = red[17];
#pragma unroll
    for (int i = 0; i < 4; i++) {
        int c = tid + 256 * i;
        row[c] = (v[i] - m) * rs * g[c] + b[c];
    }
}

__global__ void qk_pack_kernel() {
    int t = blockIdx.x;
    int b = t >> 10, s = t & 1023;
    int tid = threadIdx.x;
#pragma unroll
    for (int i = 0; i < 4; i++) {
        int d = tid + 256 * i;
        int h = d >> 6, hd = d & 63;
        size_t o = ((size_t)(b * NHC + h) * SEQC + s) * HDC + hd;
        float q = g_y[(size_t)t * EXPC + d] * 0.125f;
        float k = g_y[(size_t)t * EXPC + DIMC + d];
        __nv_bfloat16 hh, ll;
        split1(q, hh, ll); g_q_hi[o] = hh; g_q_lo[o] = ll;
        split1(k, hh, ll); g_k_hi[o] = hh; g_k_lo[o] = ll;
    }
}

__global__ void vt_pack_kernel() {
    __shared__ float tile[64][65];
    int bh = blockIdx.x;
    int b = bh >> 4, h = bh & 15;
    int s0 = blockIdx.y * 64;
    int tid = threadIdx.x;
#pragma unroll
    for (int i = 0; i < 16; i++) {
        int idx = tid + i * 256;
        int r = idx >> 6, c = idx & 63;
        tile[r][c] = g_y[(size_t)(b * 1024 + s0 + r) * EXPC + 2 * DIMC + h * 64 + c];
    }
    __syncthreads();
#pragma unroll
    for (int i = 0; i < 16; i++) {
        int idx = tid + i * 256;
        int r = idx >> 6, c = idx & 63;
        float v = tile[c][r];
        __nv_bfloat16 hh, ll; split1(v, hh, ll);
        size_t o = (size_t)bh * HDC * SEQC + (size_t)r * SEQC + s0 + c;
        g_vt_hi[o] = hh; g_vt_lo[o] = ll;
    }
}

__global__ void gelu_kernel(const float* __restrict__ mlpb) {
    size_t idx = (size_t)blockIdx.x * 256 + threadIdx.x;
    int t = (int)(idx >> 12);
    int j = (int)(idx & 4095);
    float xv = g_y[(size_t)t * EXPC + 3 * DIMC + j] + mlpb[j];
    float gl = 0.5f * xv * (1.f + erff(xv * 0.70710678118654752f));
    __nv_bfloat16 h, lo; split1(gl, h, lo);
    g_h_hi[(size_t)t * CINC + DIMC + j] = h;
    g_h_lo[(size_t)t * CINC + DIMC + j] = lo;
}

__global__ void final_kernel(const float* __restrict__ x, const int* __restrict__ em,
                             const float* __restrict__ rp, const float* __restrict__ cb,
                             const float* __restrict__ alpha, float* __restrict__ out) {
    size_t idx = (size_t)blockIdx.x * 256 + threadIdx.x;
    int t = (int)(idx >> 10);
    int d = (int)(idx & 1023);
    int m = em[t];
    int dout = (2 * DIMC) >> (3 - m);
    const float* zr = g_z + (size_t)t * 2 * DIMC;
    float za = (d < dout) ? (zr[d] + cb[d]) : 0.f;
    float zm = (DIMC + d < dout) ? (zr[DIMC + d] + cb[DIMC + d]) : 0.f;
    float pr = rp[t * 4 + m];
    out[idx] = x[idx] + za + (alpha[0] * pr + 1.f) * zm;
}

__global__ void tail_kernel(const int* __restrict__ em, const float* __restrict__ rp,
                            float* __restrict__ out) {
    int i = blockIdx.x * 256 + threadIdx.x;
    if (i < TOK)     out[(size_t)TOK * DIMC + i] = (float)em[i];
    if (i < TOK * 4) out[(size_t)TOK * DIMC + TOK + i] = rp[i];
}

// ---------------------------------------------------------------------------
extern "C" void kernel_launch(void* const* d_in, const int* in_sizes, int n_in,
                              void* d_out, int out_size) {
    const float* x     = (const float*)d_in[0];
    const int*   em    = (const int*)d_in[1];
    const float* rp    = (const float*)d_in[2];
    const float* wexp  = (const float*)d_in[3];
    const float* mlpb  = (const float*)d_in[4];
    const float* wc    = (const float*)d_in[5];
    const float* cb    = (const float*)d_in[6];
    const float* n1g   = (const float*)d_in[7];
    const float* n1b   = (const float*)d_in[8];
    const float* n2g   = (const float*)d_in[9];
    const float* n2b   = (const float*)d_in[10];
    const float* alpha = (const float*)d_in[11];
    float* out = (float*)d_out;

    float *p_y, *p_z;
    __nv_bfloat16 *p_xnh, *p_xnl, *p_weh, *p_wel, *p_wch, *p_wcl, *p_hh, *p_hl;
    cudaGetSymbolAddress((void**)&p_y,   g_y);
    cudaGetSymbolAddress((void**)&p_z,   g_z);
    cudaGetSymbolAddress((void**)&p_xnh, g_xn_hi);
    cudaGetSymbolAddress((void**)&p_xnl, g_xn_lo);
    cudaGetSymbolAddress((void**)&p_weh, g_we_hi);
    cudaGetSymbolAddress((void**)&p_wel, g_we_lo);
    cudaGetSymbolAddress((void**)&p_wch, g_wc_hi);
    cudaGetSymbolAddress((void**)&p_wcl, g_wc_lo);
    cudaGetSymbolAddress((void**)&p_hh,  g_h_hi);
    cudaGetSymbolAddress((void**)&p_hl,  g_h_lo);

    cudaFuncSetAttribute(gemm_grouped_kernel, cudaFuncAttributeMaxDynamicSharedMemorySize, GSM);
    cudaFuncSetAttribute(flash_kernel,        cudaFuncAttributeMaxDynamicSharedMemorySize, FSM);

    // 0) expert permutation (deterministic output regardless of atomic order)
    perm_init_kernel<<<1, 32>>>();
    perm_count_kernel<<<TOK / 256, 256>>>(em);
    perm_scan_kernel<<<1, 32>>>();
    perm_fill_kernel<<<TOK / 256, 256>>>(em);

    // 0b) weight splits
    split4_kernel<<<(EXPC * DIMC) / 4 / 256, 256>>>(wexp, p_weh, p_wel);
    split4_kernel<<<(2 * DIMC * CINC) / 4 / 256, 256>>>(wc, p_wch, p_wcl);

    // 1) LN1 + input mask
    ln1_kernel<<<TOK, 256>>>(x, em, n1g, n1b);

    // 2) expand (grouped): y = xn @ Wexp^T, K_e = 128<<e
    gemm_grouped_kernel<<<dim3(EXPC / 128, TOK / 128, 4), 256, GSM>>>(
        p_xnh, p_xnl, DIMC, p_weh, p_wel, DIMC, p_y, EXPC,
        128, 1, EXPC, 0);

    // 3) LN2 on k/v
    ln2_kernel<<<dim3(TOK, 2), 256>>>(n2g, n2b);

    // 4) pack Q/K (scaled) and transposed V
    qk_pack_kernel<<<TOK, 256>>>();
    vt_pack_kernel<<<dim3(BH, SEQC / 64), 256>>>();

    // 5) GELU -> h mlp region
    gelu_kernel<<<(TOK * 4096) / 256, 256>>>(mlpb);

    // 6) flash attention -> h[:, 0:1024] (hi/lo)
    flash_kernel<<<dim3(SEQC / 128, BH), 256, FSM>>>();

    // 7) contract (grouped): z = h @ Wc^T, N_e = 256<<e
    gemm_grouped_kernel<<<dim3(16, TOK / 128, 4), 256, GSM>>>(
        p_hh, p_hl, CINC, p_wch, p_wcl, CINC, p_z, 2 * DIMC,
        CINC, 0, 256, 1);

    // 8) epilogue + tails
    final_kernel<<<(TOK * DIMC) / 256, 256>>>(x, em, rp, cb, alpha, out);
    tail_kernel<<<(TOK * 4 + 255) / 256, 256>>>(em, rp, out);
}

// round 7
// speedup vs baseline: 5.3136x; 1.0596x over previous
#include <cuda_runtime.h>
#include <cuda_bf16.h>
#include <math.h>
#include <stdint.h>

// Problem constants
#define TOK   8192        // B*N
#define DIMC  1024
#define EXPC  7168
#define CINC  5120
#define NHC   16
#define HDC   64
#define SEQC  1024
#define NB    8
#define BH    (NB * NHC)  // 128 batch-heads

// ---------------------------------------------------------------------------
// Scratch (device globals; allocation-free)
// ---------------------------------------------------------------------------
__device__ float g_y [(size_t)TOK * 2 * DIMC];                //  67 MB (k,v fp32 only)
__device__ float g_z [(size_t)TOK * 2 * DIMC];                //  67 MB

__device__ __nv_bfloat16 g_xn_hi[(size_t)TOK * DIMC];
__device__ __nv_bfloat16 g_xn_lo[(size_t)TOK * DIMC];
__device__ __nv_bfloat16 g_we_hi[(size_t)EXPC * DIMC];
__device__ __nv_bfloat16 g_we_lo[(size_t)EXPC * DIMC];
__device__ __nv_bfloat16 g_wc_hi[(size_t)2 * DIMC * CINC];
__device__ __nv_bfloat16 g_wc_lo[(size_t)2 * DIMC * CINC];
__device__ __nv_bfloat16 g_h_hi[(size_t)TOK * CINC];
__device__ __nv_bfloat16 g_h_lo[(size_t)TOK * CINC];

// attention operands (per-head layouts)
__device__ __nv_bfloat16 g_q_hi[(size_t)BH * SEQC * HDC];
__device__ __nv_bfloat16 g_q_lo[(size_t)BH * SEQC * HDC];
__device__ __nv_bfloat16 g_k_hi[(size_t)BH * SEQC * HDC];
__device__ __nv_bfloat16 g_k_lo[(size_t)BH * SEQC * HDC];
__device__ __nv_bfloat16 g_vt_hi[(size_t)BH * HDC * SEQC];
__device__ __nv_bfloat16 g_vt_lo[(size_t)BH * HDC * SEQC];

// expert grouping
__device__ int g_cnt[4];
__device__ int g_cur[4];
__device__ int g_goff[4];
__device__ int g_perm[TOK];

// ---------------------------------------------------------------------------
// PTX helpers
// ---------------------------------------------------------------------------
__device__ __forceinline__ uint32_t smem_u32(const void* p) {
    uint32_t a;
    asm("{ .reg .u64 t; cvta.to.shared.u64 t, %1; cvt.u32.u64 %0, t; }" : "=r"(a) : "l"(p));
    return a;
}
__device__ __forceinline__ void ldsm4(uint32_t* r, uint32_t a) {
    asm volatile("ldmatrix.sync.aligned.m8n8.x4.shared.b16 {%0,%1,%2,%3}, [%4];"
                 : "=r"(r[0]), "=r"(r[1]), "=r"(r[2]), "=r"(r[3]) : "r"(a));
}
__device__ __forceinline__ void mma16816(float* c, const uint32_t* a, const uint32_t* b) {
    asm volatile("mma.sync.aligned.m16n8k16.row.col.f32.bf16.bf16.f32 "
                 "{%0,%1,%2,%3}, {%4,%5,%6,%7}, {%8,%9}, {%0,%1,%2,%3};"
                 : "+f"(c[0]), "+f"(c[1]), "+f"(c[2]), "+f"(c[3])
                 : "r"(a[0]), "r"(a[1]), "r"(a[2]), "r"(a[3]), "r"(b[0]), "r"(b[1]));
}
__device__ __forceinline__ void cpa16(uint32_t s, const void* g) {
    asm volatile("cp.async.cg.shared.global [%0], [%1], 16;" :: "r"(s), "l"(g));
}
#define CP_COMMIT() asm volatile("cp.async.commit_group;")
#define CP_WAIT2()  asm volatile("cp.async.wait_group 2;")
#define CP_WAIT1()  asm volatile("cp.async.wait_group 1;")
#define CP_WAIT0()  asm volatile("cp.async.wait_group 0;")

#define SWZ(o) ((o) ^ (((o) >> 3) & 0x70))

__device__ __forceinline__ void split1(float x, __nv_bfloat16& h, __nv_bfloat16& l) {
    h = __float2bfloat16(x);
    l = __float2bfloat16(x - __bfloat162float(h));
}
__device__ __forceinline__ uint32_t pack_bf2(__nv_bfloat16 a, __nv_bfloat16 b) {
    __nv_bfloat162 v(a, b);
    return *(uint32_t*)&v;
}
__device__ __forceinline__ float gelu1(float x) {
    return 0.5f * x * (1.f + erff(x * 0.70710678118654752f));
}

// ---------------------------------------------------------------------------
// Expert-grouped bf16-split HMMA GEMM with row gather.
// MODE 0: plain fp32 scatter to C (contract).
// MODE 1: expand fused epilogue (q-pack / y fp32 / gelu+h-pack by n-region).
// ---------------------------------------------------------------------------
#define GOAH 0
#define GOAL 16384
#define GOBH 32768
#define GOBL 49152
#define GBUF 65536
#define GSM  (1024 + 3 * GBUF)

template<int MODE>
__global__ void __launch_bounds__(256)
gemm_grouped_kernel(const __nv_bfloat16* __restrict__ Ah, const __nv_bfloat16* __restrict__ Al, int lda,
                    const __nv_bfloat16* __restrict__ Bh, const __nv_bfloat16* __restrict__ Bl, int ldb,
                    float* __restrict__ C, int ldc,
                    const float* __restrict__ mlpb,
                    int Kbase, int Kscale, int Nbase, int Nscale) {
    const int e = blockIdx.z;
    const int cnt  = g_cnt[e];
    const int goff = g_goff[e];
    const int m0 = blockIdx.y * 128;
    if (m0 >= cnt) return;
    const int K    = Kscale ? (Kbase << e) : Kbase;
    const int Nlim = Nscale ? (Nbase << e) : Nbase;
    const int n0 = blockIdx.x * 128;
    if (n0 >= Nlim) return;

    extern __shared__ char smem_raw[];
    uint32_t sb0 = smem_u32(smem_raw);
    sb0 = (sb0 + 1023u) & ~1023u;
    int* tok = (int*)(smem_raw + (sb0 - smem_u32(smem_raw)));
    uint32_t sb = sb0 + 1024u;

    const int tid  = threadIdx.x;
    const int wid  = tid >> 5;
    const int lane = tid & 31;
    const int wm = wid & 3;
    const int wn = wid >> 2;

    if (tid < 128) {
        int gr = m0 + tid;
        tok[tid] = g_perm[goff + ((gr < cnt) ? gr : 0)];
    }
    __syncthreads();

    const __nv_bfloat16* BBh = Bh + (size_t)n0 * ldb;
    const __nv_bfloat16* BBl = Bl + (size_t)n0 * ldb;

    const int NC = K / 64;

    auto load_chunk = [&](int c) {
        uint32_t bufb = sb + (uint32_t)(c % 3) * GBUF;
        int k0 = c * 64;
#pragma unroll
        for (int it = 0; it < 8; it++) {
            int i = tid + it * 256;
            int r = i >> 4, rem = i & 15, hl = rem >> 3, kg = rem & 7;
            const __nv_bfloat16* src = (hl ? Al : Ah) + (size_t)tok[r] * lda + k0 + kg * 8;
            cpa16(bufb + (hl ? GOAL : GOAH) + SWZ(r * 128 + kg * 16), src);
        }
#pragma unroll
        for (int it = 0; it < 8; it++) {
            int i = tid + it * 256;
            int r = i >> 4, rem = i & 15, hl = rem >> 3, kg = rem & 7;
            const __nv_bfloat16* src = (hl ? BBl : BBh) + (size_t)r * ldb + k0 + kg * 8;
            cpa16(bufb + (hl ? GOBL : GOBH) + SWZ(r * 128 + kg * 16), src);
        }
        CP_COMMIT();
    };

    load_chunk(0);
    if (NC > 1) load_chunk(1);

    float acc[2][8][4];
#pragma unroll
    for (int i = 0; i < 2; i++)
#pragma unroll
        for (int j = 0; j < 8; j++)
#pragma unroll
            for (int k = 0; k < 4; k++) acc[i][j][k] = 0.f;

    const int a_r16 = lane & 15;
    const int a_kb  = (lane >> 4) * 16;
    const int b_r8  = ((lane >> 4) << 3) + (lane & 7);
    const int b_kb  = ((lane >> 3) & 1) * 16;

    for (int c = 0; c < NC; c++) {
        if (c + 2 < NC) load_chunk(c + 2);
        int pend = NC - 1 - c; if (pend > 2) pend = 2;
        if (pend == 2) CP_WAIT2(); else if (pend == 1) CP_WAIT1(); else CP_WAIT0();
        __syncthreads();

        uint32_t bufb = sb + (uint32_t)(c % 3) * GBUF;
#pragma unroll
        for (int kk = 0; kk < 4; kk++) {
            int kb = kk * 32;
            uint32_t ah[2][4], al[2][4];
#pragma unroll
            for (int mt = 0; mt < 2; mt++) {
                int r = wm * 32 + mt * 16 + a_r16;
                uint32_t off = (uint32_t)(r * 128) + (uint32_t)((kb + a_kb) ^ ((r & 7) << 4));
                ldsm4(ah[mt], bufb + GOAH + off);
                ldsm4(al[mt], bufb + GOAL + off);
            }
#pragma unroll
            for (int ntp = 0; ntp < 4; ntp++) {
                int r = wn * 64 + ntp * 16 + b_r8;
                uint32_t off = (uint32_t)(r * 128) + (uint32_t)((kb + b_kb) ^ ((r & 7) << 4));
                uint32_t bh[4], bl[4];
                ldsm4(bh, bufb + GOBH + off);
                ldsm4(bl, bufb + GOBL + off);
#pragma unroll
                for (int mt = 0; mt < 2; mt++) {
                    mma16816(acc[mt][2 * ntp],     ah[mt], bh);
                    mma16816(acc[mt][2 * ntp],     ah[mt], bl);
                    mma16816(acc[mt][2 * ntp],     al[mt], bh);
                    mma16816(acc[mt][2 * ntp + 1], ah[mt], bh + 2);
                    mma16816(acc[mt][2 * ntp + 1], ah[mt], bl + 2);
                    mma16816(acc[mt][2 * ntp + 1], al[mt], bh + 2);
                }
            }
        }
        __syncthreads();
    }

    const int g = lane >> 2, t4 = lane & 3;

    if (MODE == 0) {
        // Plain fp32 scatter (contract)
#pragma unroll
        for (int mt = 0; mt < 2; mt++) {
            int r0 = wm * 32 + mt * 16 + g;
            int r1 = r0 + 8;
            int tk0 = tok[r0], tk1 = tok[r1];
            bool ok0 = (m0 + r0) < cnt, ok1 = (m0 + r1) < cnt;
#pragma unroll
            for (int nt = 0; nt < 8; nt++) {
                int ncol = n0 + wn * 64 + nt * 8 + t4 * 2;
                if (ok0) *(float2*)(C + (size_t)tk0 * ldc + ncol) = make_float2(acc[mt][nt][0], acc[mt][nt][1]);
                if (ok1) *(float2*)(C + (size_t)tk1 * ldc + ncol) = make_float2(acc[mt][nt][2], acc[mt][nt][3]);
            }
        }
    } else {
        // Expand fused epilogue; region per CTA (n0 is 128-aligned; regions 1024-aligned)
#pragma unroll
        for (int mt = 0; mt < 2; mt++) {
            int r0 = wm * 32 + mt * 16 + g;
            int r1 = r0 + 8;
            int tk0 = tok[r0], tk1 = tok[r1];
            bool ok0 = (m0 + r0) < cnt, ok1 = (m0 + r1) < cnt;
            if (n0 < 1024) {
                // Q region: scale 1/8, split, per-head layout
#pragma unroll
                for (int nt = 0; nt < 8; nt++) {
                    int d = n0 + wn * 64 + nt * 8 + t4 * 2;
                    int h = d >> 6, hd = d & 63;
                    __nv_bfloat16 h0, l0, h1, l1;
                    if (ok0) {
                        size_t o = ((size_t)((tk0 >> 10) * NHC + h) * SEQC + (tk0 & 1023)) * HDC + hd;
                        split1(acc[mt][nt][0] * 0.125f, h0, l0);
                        split1(acc[mt][nt][1] * 0.125f, h1, l1);
                        *(uint32_t*)(g_q_hi + o) = pack_bf2(h0, h1);
                        *(uint32_t*)(g_q_lo + o) = pack_bf2(l0, l1);
                    }
                    if (ok1) {
                        size_t o = ((size_t)((tk1 >> 10) * NHC + h) * SEQC + (tk1 & 1023)) * HDC + hd;
                        split1(acc[mt][nt][2] * 0.125f, h0, l0);
                        split1(acc[mt][nt][3] * 0.125f, h1, l1);
                        *(uint32_t*)(g_q_hi + o) = pack_bf2(h0, h1);
                        *(uint32_t*)(g_q_lo + o) = pack_bf2(l0, l1);
                    }
                }
            } else if (n0 < 3072) {
                // K/V region: fp32 to g_y [TOK][2048]
#pragma unroll
                for (int nt = 0; nt < 8; nt++) {
                    int col = n0 - 1024 + wn * 64 + nt * 8 + t4 * 2;
                    if (ok0) *(float2*)(g_y + (size_t)tk0 * 2048 + col) = make_float2(acc[mt][nt][0], acc[mt][nt][1]);
                    if (ok1) *(float2*)(g_y + (size_t)tk1 * 2048 + col) = make_float2(acc[mt][nt][2], acc[mt][nt][3]);
                }
            } else {
                // MLP region: +bias, GELU, split -> g_h[:, 1024+j]
#pragma unroll
                for (int nt = 0; nt < 8; nt++) {
                    int j = n0 - 3072 + wn * 64 + nt * 8 + t4 * 2;
                    float b0 = mlpb[j], b1 = mlpb[j + 1];
                    __nv_bfloat16 h0, l0, h1, l1;
                    if (ok0) {
                        split1(gelu1(acc[mt][nt][0] + b0), h0, l0);
                        split1(gelu1(acc[mt][nt][1] + b1), h1, l1);
                        size_t o = (size_t)tk0 * CINC + 1024 + j;
                        *(uint32_t*)(g_h_hi + o) = pack_bf2(h0, h1);
                        *(uint32_t*)(g_h_lo + o) = pack_bf2(l0, l1);
                    }
                    if (ok1) {
                        split1(gelu1(acc[mt][nt][2] + b0), h0, l0);
                        split1(gelu1(acc[mt][nt][3] + b1), h1, l1);
                        size_t o = (size_t)tk1 * CINC + 1024 + j;
                        *(uint32_t*)(g_h_hi + o) = pack_bf2(h0, h1);
                        *(uint32_t*)(g_h_lo + o) = pack_bf2(l0, l1);
                    }
                }
            }
        }
    }
}

// ---------------------------------------------------------------------------
// Flash attention (as round 6)
// ---------------------------------------------------------------------------
#define FQH 0
#define FQL 16384
#define FST 32768
#define FSS 32768
#define FSM (32768 + 2 * 32768 + 1024)

__global__ void __launch_bounds__(256)
flash_kernel() {
    extern __shared__ char smem_raw[];
    uint32_t sb = smem_u32(smem_raw);
    sb = (sb + 1023u) & ~1023u;

    const int tid  = threadIdx.x;
    const int wid  = tid >> 5;
    const int lane = tid & 31;
    const int bh = blockIdx.y;
    const int q0 = blockIdx.x * 128;
    const int b = bh >> 4, h = bh & 15;

    const size_t qkbase = (size_t)bh * SEQC * HDC;
    const size_t vbase  = (size_t)bh * HDC * SEQC;

    auto load_q = [&]() {
#pragma unroll
        for (int it = 0; it < 8; it++) {
            int i = tid + it * 256;
            int r = i >> 4, rem = i & 15, hl = rem >> 3, kg = rem & 7;
            const __nv_bfloat16* src = (hl ? g_q_lo : g_q_hi) + qkbase + (size_t)(q0 + r) * HDC + kg * 8;
            cpa16(sb + (hl ? FQL : FQH) + SWZ(r * 128 + kg * 16), src);
        }
    };
    auto load_kv = [&](int t) {
        uint32_t bufb = sb + FST + (uint32_t)(t & 1) * FSS;
#pragma unroll
        for (int it = 0; it < 4; it++) {
            int i = tid + it * 256;
            int r = i >> 4, rem = i & 15, hl = rem >> 3, kg = rem & 7;
            const __nv_bfloat16* src = (hl ? g_k_lo : g_k_hi) + qkbase + (size_t)(t * 64 + r) * HDC + kg * 8;
            cpa16(bufb + (hl ? 8192 : 0) + SWZ(r * 128 + kg * 16), src);
        }
#pragma unroll
        for (int it = 0; it < 4; it++) {
            int i = tid + it * 256;
            int r = i >> 4, rem = i & 15, hl = rem >> 3, kg = rem & 7;
            const __nv_bfloat16* src = (hl ? g_vt_lo : g_vt_hi) + vbase + (size_t)r * SEQC + t * 64 + kg * 8;
            cpa16(bufb + 16384 + (hl ? 8192 : 0) + SWZ(r * 128 + kg * 16), src);
        }
        CP_COMMIT();
    };

    load_q(); load_kv(0); CP_COMMIT();
    load_kv(1);

    const int a_r16 = lane & 15;
    const int a_kb  = (lane >> 4) * 16;
    const int b_r8  = ((lane >> 4) << 3) + (lane & 7);
    const int b_kb  = ((lane >> 3) & 1) * 16;

    uint32_t qhf[4][4], qlf[4][4];
    float o[8][4];
#pragma unroll
    for (int j = 0; j < 8; j++)
#pragma unroll
        for (int k = 0; k < 4; k++) o[j][k] = 0.f;
    float ml0 = -1e30f, ml1 = -1e30f, ls0 = 0.f, ls1 = 0.f;

    for (int t = 0; t < 16; t++) {
        if (t < 15) CP_WAIT1(); else CP_WAIT0();
        __syncthreads();
        if (t == 0) {
#pragma unroll
            for (int kk = 0; kk < 4; kk++) {
                int r = wid * 16 + a_r16;
                uint32_t off = (uint32_t)(r * 128) + (uint32_t)((kk * 32 + a_kb) ^ ((r & 7) << 4));
                ldsm4(qhf[kk], sb + FQH + off);
                ldsm4(qlf[kk], sb + FQL + off);
            }
        }
        uint32_t bufb = sb + FST + (uint32_t)(t & 1) * FSS;

        float s[8][4];
#pragma unroll
        for (int j = 0; j < 8; j++)
#pragma unroll
            for (int k = 0; k < 4; k++) s[j][k] = 0.f;
#pragma unroll
        for (int kk = 0; kk < 4; kk++) {
#pragma unroll
            for (int ntp = 0; ntp < 4; ntp++) {
                int r = ntp * 16 + b_r8;
                uint32_t off = (uint32_t)(r * 128) + (uint32_t)((kk * 32 + b_kb) ^ ((r & 7) << 4));
                uint32_t khf[4], klf[4];
                ldsm4(khf, bufb + off);
                ldsm4(klf, bufb + 8192 + off);
                mma16816(s[2 * ntp],     qhf[kk], khf);
                mma16816(s[2 * ntp],     qhf[kk], klf);
                mma16816(s[2 * ntp],     qlf[kk], khf);
                mma16816(s[2 * ntp + 1], qhf[kk], khf + 2);
                mma16816(s[2 * ntp + 1], qhf[kk], klf + 2);
                mma16816(s[2 * ntp + 1], qlf[kk], khf + 2);
            }
        }

        float m0t = -1e30f, m1t = -1e30f;
#pragma unroll
        for (int j = 0; j < 8; j++) {
            m0t = fmaxf(m0t, fmaxf(s[j][0], s[j][1]));
            m1t = fmaxf(m1t, fmaxf(s[j][2], s[j][3]));
        }
        m0t = fmaxf(m0t, __shfl_xor_sync(0xffffffffu, m0t, 1));
        m0t = fmaxf(m0t, __shfl_xor_sync(0xffffffffu, m0t, 2));
        m1t = fmaxf(m1t, __shfl_xor_sync(0xffffffffu, m1t, 1));
        m1t = fmaxf(m1t, __shfl_xor_sync(0xffffffffu, m1t, 2));
        float mn0 = fmaxf(ml0, m0t), mn1 = fmaxf(ml1, m1t);
        float sc0 = __expf(ml0 - mn0), sc1 = __expf(ml1 - mn1);
        ml0 = mn0; ml1 = mn1;
        float r0 = 0.f, r1 = 0.f;
#pragma unroll
        for (int j = 0; j < 8; j++) {
            s[j][0] = __expf(s[j][0] - mn0);
            s[j][1] = __expf(s[j][1] - mn0);
            s[j][2] = __expf(s[j][2] - mn1);
            s[j][3] = __expf(s[j][3] - mn1);
            r0 += s[j][0] + s[j][1];
            r1 += s[j][2] + s[j][3];
        }
        r0 += __shfl_xor_sync(0xffffffffu, r0, 1);
        r0 += __shfl_xor_sync(0xffffffffu, r0, 2);
        r1 += __shfl_xor_sync(0xffffffffu, r1, 1);
        r1 += __shfl_xor_sync(0xffffffffu, r1, 2);
        ls0 = ls0 * sc0 + r0;
        ls1 = ls1 * sc1 + r1;
#pragma unroll
        for (int j = 0; j < 8; j++) {
            o[j][0] *= sc0; o[j][1] *= sc0;
            o[j][2] *= sc1; o[j][3] *= sc1;
        }

        uint32_t pah[4][4], pal[4][4];
#pragma unroll
        for (int kt = 0; kt < 4; kt++) {
            __nv_bfloat16 h0, l0, h1, l1;
            split1(s[2 * kt][0], h0, l0); split1(s[2 * kt][1], h1, l1);
            pah[kt][0] = pack_bf2(h0, h1); pal[kt][0] = pack_bf2(l0, l1);
            split1(s[2 * kt][2], h0, l0); split1(s[2 * kt][3], h1, l1);
            pah[kt][1] = pack_bf2(h0, h1); pal[kt][1] = pack_bf2(l0, l1);
            split1(s[2 * kt + 1][0], h0, l0); split1(s[2 * kt + 1][1], h1, l1);
            pah[kt][2] = pack_bf2(h0, h1); pal[kt][2] = pack_bf2(l0, l1);
            split1(s[2 * kt + 1][2], h0, l0); split1(s[2 * kt + 1][3], h1, l1);
            pah[kt][3] = pack_bf2(h0, h1); pal[kt][3] = pack_bf2(l0, l1);
        }

#pragma unroll
        for (int kt = 0; kt < 4; kt++) {
#pragma unroll
            for (int nv = 0; nv < 4; nv++) {
                int r = nv * 16 + b_r8;
                uint32_t off = (uint32_t)(r * 128) + (uint32_t)((kt * 32 + b_kb) ^ ((r & 7) << 4));
                uint32_t vhf[4], vlf[4];
                ldsm4(vhf, bufb + 16384 + off);
                ldsm4(vlf, bufb + 24576 + off);
                mma16816(o[2 * nv],     pah[kt], vhf);
                mma16816(o[2 * nv],     pah[kt], vlf);
                mma16816(o[2 * nv],     pal[kt], vhf);
                mma16816(o[2 * nv + 1], pah[kt], vhf + 2);
                mma16816(o[2 * nv + 1], pah[kt], vlf + 2);
                mma16816(o[2 * nv + 1], pal[kt], vhf + 2);
            }
        }
        __syncthreads();
        if (t + 2 < 16) load_kv(t + 2);
    }

    const int g = lane >> 2, t4 = lane & 3;
    float i0 = 1.f / ls0, i1 = 1.f / ls1;
    int tok0 = b * 1024 + q0 + wid * 16 + g;
    int tok1 = tok0 + 8;
#pragma unroll
    for (int j = 0; j < 8; j++) {
        int col = h * 64 + j * 8 + t4 * 2;
        __nv_bfloat16 h0, l0, h1, l1;
        split1(o[j][0] * i0, h0, l0); split1(o[j][1] * i0, h1, l1);
        *(uint32_t*)(g_h_hi + (size_t)tok0 * CINC + col) = pack_bf2(h0, h1);
        *(uint32_t*)(g_h_lo + (size_t)tok0 * CINC + col) = pack_bf2(l0, l1);
        split1(o[j][2] * i1, h0, l0); split1(o[j][3] * i1, h1, l1);
        *(uint32_t*)(g_h_hi + (size_t)tok1 * CINC + col) = pack_bf2(h0, h1);
        *(uint32_t*)(g_h_lo + (size_t)tok1 * CINC + col) = pack_bf2(l0, l1);
    }
}

// ---------------------------------------------------------------------------
// Expert permutation kernels
// ---------------------------------------------------------------------------
__global__ void perm_init_kernel() {
    if (threadIdx.x < 4) { g_cnt[threadIdx.x] = 0; g_cur[threadIdx.x] = 0; }
}
__global__ void perm_count_kernel(const int* __restrict__ em) {
    int i = blockIdx.x * 256 + threadIdx.x;
    if (i < TOK) atomicAdd(&g_cnt[em[i]], 1);
}
__global__ void perm_scan_kernel() {
    if (threadIdx.x == 0) {
        int o = 0;
        for (int e = 0; e < 4; e++) { g_goff[e] = o; o += g_cnt[e]; }
    }
}
__global__ void perm_fill_kernel(const int* __restrict__ em) {
    int i = blockIdx.x * 256 + threadIdx.x;
    if (i < TOK) {
        int e = em[i];
        int p = atomicAdd(&g_cur[e], 1);
        g_perm[g_goff[e] + p] = i;
    }
}

// ---------------------------------------------------------------------------
// splits / LN / packs / epilogue
// ---------------------------------------------------------------------------
__global__ void split4_kernel(const float* __restrict__ s,
                              __nv_bfloat16* __restrict__ hi, __nv_bfloat16* __restrict__ lo) {
    size_t i = (size_t)blockIdx.x * 256 + threadIdx.x;
    float4 v = ((const float4*)s)[i];
    __nv_bfloat16 h0, h1, h2, h3, l0, l1, l2, l3;
    split1(v.x, h0, l0); split1(v.y, h1, l1); split1(v.z, h2, l2); split1(v.w, h3, l3);
    __nv_bfloat162* H = (__nv_bfloat162*)hi;
    __nv_bfloat162* L = (__nv_bfloat162*)lo;
    H[2 * i] = __nv_bfloat162(h0, h1); H[2 * i + 1] = __nv_bfloat162(h2, h3);
    L[2 * i] = __nv_bfloat162(l0, l1); L[2 * i + 1] = __nv_bfloat162(l2, l3);
}

__global__ void ln1_kernel(const float* __restrict__ x, const int* __restrict__ em,
                           const float* __restrict__ g, const float* __restrict__ b) {
    int t = blockIdx.x;
    const float* xr = x + (size_t)t * DIMC;
    int tid = threadIdx.x;
    float v[4]; float s = 0.f, s2 = 0.f;
#pragma unroll
    for (int i = 0; i < 4; i++) { float a = xr[tid + 256 * i]; v[i] = a; s += a; s2 += a * a; }
#pragma unroll
    for (int o = 16; o; o >>= 1) { s += __shfl_xor_sync(0xffffffffu, s, o); s2 += __shfl_xor_sync(0xffffffffu, s2, o); }
    __shared__ float red[18];
    int w = tid >> 5, l = tid & 31;
    if (l == 0) { red[w] = s; red[8 + w] = s2; }
    __syncthreads();
    if (tid == 0) {
        float ts = 0.f, ts2 = 0.f;
        for (int i = 0; i < 8; i++) { ts += red[i]; ts2 += red[8 + i]; }
        float m = ts * (1.f / DIMC);
        float var = ts2 * (1.f / DIMC) - m * m;
        red[16] = m; red[17] = rsqrtf(var + 1e-5f);
    }
    __syncthreads();
    float m = red[16], rs = red[17];
    int din = DIMC >> (3 - em[t]);
#pragma unroll
    for (int i = 0; i < 4; i++) {
        int c = tid + 256 * i;
        float val = (v[i] - m) * rs * g[c] + b[c];
        val = (c < din) ? val : 0.f;
        __nv_bfloat16 h, lo; split1(val, h, lo);
        g_xn_hi[(size_t)t * DIMC + c] = h;
        g_xn_lo[(size_t)t * DIMC + c] = lo;
    }
}

// LN2 fused: blockIdx.y==0 -> k path (LN, write g_k hi/lo per-head layout);
//            blockIdx.y==1 -> v path (LN in place on g_y fp32 for vt_pack).
__global__ void ln2kv_kernel(const float* __restrict__ g, const float* __restrict__ b) {
    int t = blockIdx.x;
    int which = blockIdx.y;
    float* row = g_y + (size_t)t * 2048 + (size_t)DIMC * which;
    int tid = threadIdx.x;
    float v[4]; float s = 0.f, s2 = 0.f;
#pragma unroll
    for (int i = 0; i < 4; i++) { float a = row[tid + 256 * i]; v[i] = a; s += a; s2 += a * a; }
#pragma unroll
    for (int o = 16; o; o >>= 1) { s += __shfl_xor_sync(0xffffffffu, s, o); s2 += __shfl_xor_sync(0xffffffffu, s2, o); }
    __shared__ float red[18];
    int w = tid >> 5, l = tid & 31;
    if (l == 0) { red[w] = s; red[8 + w] = s2; }
    __syncthreads();
    if (tid == 0) {
        float ts = 0.f, ts2 = 0.f;
        for (int i = 0; i < 8; i++) { ts += red[i]; ts2 += red[8 + i]; }
        float m = ts * (1.f / DIMC);
        float var = ts2 * (1.f / DIMC) - m * m;
        red[16] = m; red[17] = rsqrtf(var + 1e-5f);
    }
    __syncthreads();
    float m = red[16], rs = red[17];
    int bb = t >> 10, ss = t & 1023;
#pragma unroll
    for (int i = 0; i < 4; i++) {
        int c = tid + 256 * i;
        float val = (v[i] - m) * rs * g[c] + b[c];
        if (which == 0) {
            int h = c >> 6, hd = c & 63;
            size_t o = ((size_t)(bb * NHC + h) * SEQC + ss) * HDC + hd;
            __nv_bfloat16 hh, ll; split1(val, hh, ll);
            g_k_hi[o] = hh; g_k_lo[o] = ll;
        } else {
            row[c] = val;
        }
    }
}

// Pack V transposed per head (reads normalized v from g_y cols [1024,2048))
__global__ void vt_pack_kernel() {
    __shared__ float tile[64][65];
    int bh = blockIdx.x;
    int b = bh >> 4, h = bh & 15;
    int s0 = blockIdx.y * 64;
    int tid = threadIdx.x;
#pragma unroll
    for (int i = 0; i < 16; i++) {
        int idx = tid + i * 256;
        int r = idx >> 6, c = idx & 63;
        tile[r][c] = g_y[(size_t)(b * 1024 + s0 + r) * 2048 + 1024 + h * 64 + c];
    }
    __syncthreads();
#pragma unroll
    for (int i = 0; i < 16; i++) {
        int idx = tid + i * 256;
        int r = idx >> 6, c = idx & 63;
        float v = tile[c][r];
        __nv_bfloat16 hh, ll; split1(v, hh, ll);
        size_t o = (size_t)bh * HDC * SEQC + (size_t)r * SEQC + s0 + c;
        g_vt_hi[o] = hh; g_vt_lo[o] = ll;
    }
}

__global__ void final_kernel(const float* __restrict__ x, const int* __restrict__ em,
                             const float* __restrict__ rp, const float* __restrict__ cb,
                             const float* __restrict__ alpha, float* __restrict__ out) {
    size_t idx = (size_t)blockIdx.x * 256 + threadIdx.x;
    int t = (int)(idx >> 10);
    int d = (int)(idx & 1023);
    int m = em[t];
    int dout = (2 * DIMC) >> (3 - m);
    const float* zr = g_z + (size_t)t * 2 * DIMC;
    float za = (d < dout) ? (zr[d] + cb[d]) : 0.f;
    float zm = (DIMC + d < dout) ? (zr[DIMC + d] + cb[DIMC + d]) : 0.f;
    float pr = rp[t * 4 + m];
    out[idx] = x[idx] + za + (alpha[0] * pr + 1.f) * zm;
}

__global__ void tail_kernel(const int* __restrict__ em, const float* __restrict__ rp,
                            float* __restrict__ out) {
    int i = blockIdx.x * 256 + threadIdx.x;
    if (i < TOK)     out[(size_t)TOK * DIMC + i] = (float)em[i];
    if (i < TOK * 4) out[(size_t)TOK * DIMC + TOK + i] = rp[i];
}

// ---------------------------------------------------------------------------
extern "C" void kernel_launch(void* const* d_in, const int* in_sizes, int n_in,
                              void* d_out, int out_size) {
    const float* x     = (const float*)d_in[0];
    const int*   em    = (const int*)d_in[1];
    const float* rp    = (const float*)d_in[2];
    const float* wexp  = (const float*)d_in[3];
    const float* mlpb  = (const float*)d_in[4];
    const float* wc    = (const float*)d_in[5];
    const float* cb    = (const float*)d_in[6];
    const float* n1g   = (const float*)d_in[7];
    const float* n1b   = (const float*)d_in[8];
    const float* n2g   = (const float*)d_in[9];
    const float* n2b   = (const float*)d_in[10];
    const float* alpha = (const float*)d_in[11];
    float* out = (float*)d_out;

    float *p_z;
    __nv_bfloat16 *p_xnh, *p_xnl, *p_weh, *p_wel, *p_wch, *p_wcl, *p_hh, *p_hl;
    cudaGetSymbolAddress((void**)&p_z,   g_z);
    cudaGetSymbolAddress((void**)&p_xnh, g_xn_hi);
    cudaGetSymbolAddress((void**)&p_xnl, g_xn_lo);
    cudaGetSymbolAddress((void**)&p_weh, g_we_hi);
    cudaGetSymbolAddress((void**)&p_wel, g_we_lo);
    cudaGetSymbolAddress((void**)&p_wch, g_wc_hi);
    cudaGetSymbolAddress((void**)&p_wcl, g_wc_lo);
    cudaGetSymbolAddress((void**)&p_hh,  g_h_hi);
    cudaGetSymbolAddress((void**)&p_hl,  g_h_lo);

    cudaFuncSetAttribute(gemm_grouped_kernel<0>, cudaFuncAttributeMaxDynamicSharedMemorySize, GSM);
    cudaFuncSetAttribute(gemm_grouped_kernel<1>, cudaFuncAttributeMaxDynamicSharedMemorySize, GSM);
    cudaFuncSetAttribute(flash_kernel,           cudaFuncAttributeMaxDynamicSharedMemorySize, FSM);

    // 0) expert permutation
    perm_init_kernel<<<1, 32>>>();
    perm_count_kernel<<<TOK / 256, 256>>>(em);
    perm_scan_kernel<<<1, 32>>>();
    perm_fill_kernel<<<TOK / 256, 256>>>(em);

    // 0b) weight splits
    split4_kernel<<<(EXPC * DIMC) / 4 / 256, 256>>>(wexp, p_weh, p_wel);
    split4_kernel<<<(2 * DIMC * CINC) / 4 / 256, 256>>>(wc, p_wch, p_wcl);

    // 1) LN1 + input mask
    ln1_kernel<<<TOK, 256>>>(x, em, n1g, n1b);

    // 2) expand (grouped, fused epilogue): q-pack / y fp32 (k,v) / gelu+h-pack
    gemm_grouped_kernel<1><<<dim3(EXPC / 128, TOK / 128, 4), 256, GSM>>>(
        p_xnh, p_xnl, DIMC, p_weh, p_wel, DIMC, nullptr, 0, mlpb,
        128, 1, EXPC, 0);

    // 3) LN2 fused with k-pack; v normalized in place
    ln2kv_kernel<<<dim3(TOK, 2), 256>>>(n2g, n2b);

    // 4) transposed V pack
    vt_pack_kernel<<<dim3(BH, SEQC / 64), 256>>>();

    // 5) flash attention -> h[:, 0:1024]
    flash_kernel<<<dim3(SEQC / 128, BH), 256, FSM>>>();

    // 6) contract (grouped): z = h @ Wc^T, N_e = 256<<e
    gemm_grouped_kernel<0><<<dim3(16, TOK / 128, 4), 256, GSM>>>(
        p_hh, p_hl, CINC, p_wch, p_wcl, CINC, p_z, 2 * DIMC, nullptr,
        CINC, 0, 256, 1);

    // 7) epilogue + tails
    final_kernel<<<(TOK * DIMC) / 256, 256>>>(x, em, rp, cb, alpha, out);
    tail_kernel<<<(TOK * 4 + 255) / 256, 256>>>(em, rp, out);
}

// round 8
// speedup vs baseline: 5.3209x; 1.0014x over previous
#include <cuda_runtime.h>
#include <cuda_bf16.h>
#include <math.h>
#include <stdint.h>

// Problem constants
#define TOK   8192        // B*N
#define DIMC  1024
#define EXPC  7168
#define CINC  5120
#define NHC   16
#define HDC   64
#define SEQC  1024
#define NB    8
#define BH    (NB * NHC)  // 128 batch-heads

#define LOG2E 1.44269504088896340736f

// ---------------------------------------------------------------------------
// Scratch (device globals; allocation-free)
// ---------------------------------------------------------------------------
__device__ float g_y [(size_t)TOK * 2 * DIMC];                //  67 MB (k,v fp32 only)
__device__ float g_z [(size_t)TOK * 2 * DIMC];                //  67 MB

__device__ __nv_bfloat16 g_xn_hi[(size_t)TOK * DIMC];
__device__ __nv_bfloat16 g_xn_lo[(size_t)TOK * DIMC];
__device__ __nv_bfloat16 g_we_hi[(size_t)EXPC * DIMC];
__device__ __nv_bfloat16 g_we_lo[(size_t)EXPC * DIMC];
__device__ __nv_bfloat16 g_wc_hi[(size_t)2 * DIMC * CINC];
__device__ __nv_bfloat16 g_wc_lo[(size_t)2 * DIMC * CINC];
__device__ __nv_bfloat16 g_h_hi[(size_t)TOK * CINC];
__device__ __nv_bfloat16 g_h_lo[(size_t)TOK * CINC];

// attention operands (per-head layouts)
__device__ __nv_bfloat16 g_q_hi[(size_t)BH * SEQC * HDC];
__device__ __nv_bfloat16 g_q_lo[(size_t)BH * SEQC * HDC];
__device__ __nv_bfloat16 g_k_hi[(size_t)BH * SEQC * HDC];
__device__ __nv_bfloat16 g_k_lo[(size_t)BH * SEQC * HDC];
__device__ __nv_bfloat16 g_vt_hi[(size_t)BH * HDC * SEQC];
__device__ __nv_bfloat16 g_vt_lo[(size_t)BH * HDC * SEQC];

// expert grouping
__device__ int g_cnt[4];
__device__ int g_cur[4];
__device__ int g_goff[4];
__device__ int g_perm[TOK];

// ---------------------------------------------------------------------------
// PTX helpers
// ---------------------------------------------------------------------------
__device__ __forceinline__ uint32_t smem_u32(const void* p) {
    uint32_t a;
    asm("{ .reg .u64 t; cvta.to.shared.u64 t, %1; cvt.u32.u64 %0, t; }" : "=r"(a) : "l"(p));
    return a;
}
__device__ __forceinline__ void ldsm4(uint32_t* r, uint32_t a) {
    asm volatile("ldmatrix.sync.aligned.m8n8.x4.shared.b16 {%0,%1,%2,%3}, [%4];"
                 : "=r"(r[0]), "=r"(r[1]), "=r"(r[2]), "=r"(r[3]) : "r"(a));
}
__device__ __forceinline__ void mma16816(float* c, const uint32_t* a, const uint32_t* b) {
    asm volatile("mma.sync.aligned.m16n8k16.row.col.f32.bf16.bf16.f32 "
                 "{%0,%1,%2,%3}, {%4,%5,%6,%7}, {%8,%9}, {%0,%1,%2,%3};"
                 : "+f"(c[0]), "+f"(c[1]), "+f"(c[2]), "+f"(c[3])
                 : "r"(a[0]), "r"(a[1]), "r"(a[2]), "r"(a[3]), "r"(b[0]), "r"(b[1]));
}
__device__ __forceinline__ void cpa16(uint32_t s, const void* g) {
    asm volatile("cp.async.cg.shared.global [%0], [%1], 16;" :: "r"(s), "l"(g));
}
#define CP_COMMIT() asm volatile("cp.async.commit_group;")
#define CP_WAIT2()  asm volatile("cp.async.wait_group 2;")
#define CP_WAIT1()  asm volatile("cp.async.wait_group 1;")
#define CP_WAIT0()  asm volatile("cp.async.wait_group 0;")

#define SWZ(o) ((o) ^ (((o) >> 3) & 0x70))

__device__ __forceinline__ void split1(float x, __nv_bfloat16& h, __nv_bfloat16& l) {
    h = __float2bfloat16(x);
    l = __float2bfloat16(x - __bfloat162float(h));
}
__device__ __forceinline__ uint32_t pack_bf2(__nv_bfloat16 a, __nv_bfloat16 b) {
    __nv_bfloat162 v(a, b);
    return *(uint32_t*)&v;
}
__device__ __forceinline__ float gelu1(float x) {
    return 0.5f * x * (1.f + erff(x * 0.70710678118654752f));
}

// ---------------------------------------------------------------------------
// Expert-grouped bf16-split HMMA GEMM with row gather.
// 512 threads, 16 warps (4x4), warp tile 32x32, CTA tile 128x128, K-chunk 64,
// 3-stage cp.async pipeline.
// MODE 0: plain fp32 scatter to C (contract).
// MODE 1: expand fused epilogue (q-pack / y fp32 / gelu+h-pack by n-region).
// ---------------------------------------------------------------------------
#define GOAH 0
#define GOAL 16384
#define GOBH 32768
#define GOBL 49152
#define GBUF 65536
#define GSM  (1024 + 3 * GBUF)

template<int MODE>
__global__ void __launch_bounds__(512)
gemm_grouped_kernel(const __nv_bfloat16* __restrict__ Ah, const __nv_bfloat16* __restrict__ Al, int lda,
                    const __nv_bfloat16* __restrict__ Bh, const __nv_bfloat16* __restrict__ Bl, int ldb,
                    float* __restrict__ C, int ldc,
                    const float* __restrict__ mlpb,
                    int Kbase, int Kscale, int Nbase, int Nscale) {
    const int e = blockIdx.z;
    const int cnt  = g_cnt[e];
    const int goff = g_goff[e];
    const int m0 = blockIdx.y * 128;
    if (m0 >= cnt) return;
    const int K    = Kscale ? (Kbase << e) : Kbase;
    const int Nlim = Nscale ? (Nbase << e) : Nbase;
    const int n0 = blockIdx.x * 128;
    if (n0 >= Nlim) return;

    extern __shared__ char smem_raw[];
    uint32_t sb0 = smem_u32(smem_raw);
    sb0 = (sb0 + 1023u) & ~1023u;
    int* tok = (int*)(smem_raw + (sb0 - smem_u32(smem_raw)));
    uint32_t sb = sb0 + 1024u;

    const int tid  = threadIdx.x;
    const int wid  = tid >> 5;
    const int lane = tid & 31;
    const int wm = wid & 3;     // m: 32*wm
    const int wn = wid >> 2;    // n: 32*wn

    if (tid < 128) {
        int gr = m0 + tid;
        tok[tid] = g_perm[goff + ((gr < cnt) ? gr : 0)];
    }
    __syncthreads();

    const __nv_bfloat16* BBh = Bh + (size_t)n0 * ldb;
    const __nv_bfloat16* BBl = Bl + (size_t)n0 * ldb;

    const int NC = K / 64;

    auto load_chunk = [&](int c) {
        uint32_t bufb = sb + (uint32_t)(c % 3) * GBUF;
        int k0 = c * 64;
#pragma unroll
        for (int it = 0; it < 4; it++) {
            int i = tid + it * 512;
            int r = i >> 4, rem = i & 15, hl = rem >> 3, kg = rem & 7;
            const __nv_bfloat16* src = (hl ? Al : Ah) + (size_t)tok[r] * lda + k0 + kg * 8;
            cpa16(bufb + (hl ? GOAL : GOAH) + SWZ(r * 128 + kg * 16), src);
        }
#pragma unroll
        for (int it = 0; it < 4; it++) {
            int i = tid + it * 512;
            int r = i >> 4, rem = i & 15, hl = rem >> 3, kg = rem & 7;
            const __nv_bfloat16* src = (hl ? BBl : BBh) + (size_t)r * ldb + k0 + kg * 8;
            cpa16(bufb + (hl ? GOBL : GOBH) + SWZ(r * 128 + kg * 16), src);
        }
        CP_COMMIT();
    };

    load_chunk(0);
    if (NC > 1) load_chunk(1);

    float acc[2][4][4];
#pragma unroll
    for (int i = 0; i < 2; i++)
#pragma unroll
        for (int j = 0; j < 4; j++)
#pragma unroll
            for (int k = 0; k < 4; k++) acc[i][j][k] = 0.f;

    const int a_r16 = lane & 15;
    const int a_kb  = (lane >> 4) * 16;
    const int b_r8  = ((lane >> 4) << 3) + (lane & 7);
    const int b_kb  = ((lane >> 3) & 1) * 16;

    for (int c = 0; c < NC; c++) {
        if (c + 2 < NC) load_chunk(c + 2);
        int pend = NC - 1 - c; if (pend > 2) pend = 2;
        if (pend == 2) CP_WAIT2(); else if (pend == 1) CP_WAIT1(); else CP_WAIT0();
        __syncthreads();

        uint32_t bufb = sb + (uint32_t)(c % 3) * GBUF;
#pragma unroll
        for (int kk = 0; kk < 4; kk++) {
            int kb = kk * 32;
            uint32_t ah[2][4], al[2][4];
#pragma unroll
            for (int mt = 0; mt < 2; mt++) {
                int r = wm * 32 + mt * 16 + a_r16;
                uint32_t off = (uint32_t)(r * 128) + (uint32_t)((kb + a_kb) ^ ((r & 7) << 4));
                ldsm4(ah[mt], bufb + GOAH + off);
                ldsm4(al[mt], bufb + GOAL + off);
            }
#pragma unroll
            for (int ntp = 0; ntp < 2; ntp++) {
                int r = wn * 32 + ntp * 16 + b_r8;
                uint32_t off = (uint32_t)(r * 128) + (uint32_t)((kb + b_kb) ^ ((r & 7) << 4));
                uint32_t bh[4], bl[4];
                ldsm4(bh, bufb + GOBH + off);
                ldsm4(bl, bufb + GOBL + off);
#pragma unroll
                for (int mt = 0; mt < 2; mt++) {
                    mma16816(acc[mt][2 * ntp],     ah[mt], bh);
                    mma16816(acc[mt][2 * ntp],     ah[mt], bl);
                    mma16816(acc[mt][2 * ntp],     al[mt], bh);
                    mma16816(acc[mt][2 * ntp + 1], ah[mt], bh + 2);
                    mma16816(acc[mt][2 * ntp + 1], ah[mt], bl + 2);
                    mma16816(acc[mt][2 * ntp + 1], al[mt], bh + 2);
                }
            }
        }
        __syncthreads();
    }

    const int g = lane >> 2, t4 = lane & 3;

    if (MODE == 0) {
        // Plain fp32 scatter (contract)
#pragma unroll
        for (int mt = 0; mt < 2; mt++) {
            int r0 = wm * 32 + mt * 16 + g;
            int r1 = r0 + 8;
            int tk0 = tok[r0], tk1 = tok[r1];
            bool ok0 = (m0 + r0) < cnt, ok1 = (m0 + r1) < cnt;
#pragma unroll
            for (int nt = 0; nt < 4; nt++) {
                int ncol = n0 + wn * 32 + nt * 8 + t4 * 2;
                if (ok0) *(float2*)(C + (size_t)tk0 * ldc + ncol) = make_float2(acc[mt][nt][0], acc[mt][nt][1]);
                if (ok1) *(float2*)(C + (size_t)tk1 * ldc + ncol) = make_float2(acc[mt][nt][2], acc[mt][nt][3]);
            }
        }
    } else {
        // Expand fused epilogue; region per CTA (n0 is 128-aligned)
#pragma unroll
        for (int mt = 0; mt < 2; mt++) {
            int r0 = wm * 32 + mt * 16 + g;
            int r1 = r0 + 8;
            int tk0 = tok[r0], tk1 = tok[r1];
            bool ok0 = (m0 + r0) < cnt, ok1 = (m0 + r1) < cnt;
            if (n0 < 1024) {
                // Q region: scale (1/8)*log2e, split, per-head layout
#pragma unroll
                for (int nt = 0; nt < 4; nt++) {
                    int d = n0 + wn * 32 + nt * 8 + t4 * 2;
                    int h = d >> 6, hd = d & 63;
                    const float QS = 0.125f * LOG2E;
                    __nv_bfloat16 h0, l0, h1, l1;
                    if (ok0) {
                        size_t o = ((size_t)((tk0 >> 10) * NHC + h) * SEQC + (tk0 & 1023)) * HDC + hd;
                        split1(acc[mt][nt][0] * QS, h0, l0);
                        split1(acc[mt][nt][1] * QS, h1, l1);
                        *(uint32_t*)(g_q_hi + o) = pack_bf2(h0, h1);
                        *(uint32_t*)(g_q_lo + o) = pack_bf2(l0, l1);
                    }
                    if (ok1) {
                        size_t o = ((size_t)((tk1 >> 10) * NHC + h) * SEQC + (tk1 & 1023)) * HDC + hd;
                        split1(acc[mt][nt][2] * QS, h0, l0);
                        split1(acc[mt][nt][3] * QS, h1, l1);
                        *(uint32_t*)(g_q_hi + o) = pack_bf2(h0, h1);
                        *(uint32_t*)(g_q_lo + o) = pack_bf2(l0, l1);
                    }
                }
            } else if (n0 < 3072) {
                // K/V region: fp32 to g_y [TOK][2048]
#pragma unroll
                for (int nt = 0; nt < 4; nt++) {
                    int col = n0 - 1024 + wn * 32 + nt * 8 + t4 * 2;
                    if (ok0) *(float2*)(g_y + (size_t)tk0 * 2048 + col) = make_float2(acc[mt][nt][0], acc[mt][nt][1]);
                    if (ok1) *(float2*)(g_y + (size_t)tk1 * 2048 + col) = make_float2(acc[mt][nt][2], acc[mt][nt][3]);
                }
            } else {
                // MLP region: +bias, GELU, split -> g_h[:, 1024+j]
#pragma unroll
                for (int nt = 0; nt < 4; nt++) {
                    int j = n0 - 3072 + wn * 32 + nt * 8 + t4 * 2;
                    float b0 = mlpb[j], b1 = mlpb[j + 1];
                    __nv_bfloat16 h0, l0, h1, l1;
                    if (ok0) {
                        split1(gelu1(acc[mt][nt][0] + b0), h0, l0);
                        split1(gelu1(acc[mt][nt][1] + b1), h1, l1);
                        size_t o = (size_t)tk0 * CINC + 1024 + j;
                        *(uint32_t*)(g_h_hi + o) = pack_bf2(h0, h1);
                        *(uint32_t*)(g_h_lo + o) = pack_bf2(l0, l1);
                    }
                    if (ok1) {
                        split1(gelu1(acc[mt][nt][2] + b0), h0, l0);
                        split1(gelu1(acc[mt][nt][3] + b1), h1, l1);
                        size_t o = (size_t)tk1 * CINC + 1024 + j;
                        *(uint32_t*)(g_h_hi + o) = pack_bf2(h0, h1);
                        *(uint32_t*)(g_h_lo + o) = pack_bf2(l0, l1);
                    }
                }
            }
        }
    }
}

// ---------------------------------------------------------------------------
// Flash attention (scores arrive pre-scaled by log2e -> exp2f softmax)
// ---------------------------------------------------------------------------
#define FQH 0
#define FQL 16384
#define FST 32768
#define FSS 32768
#define FSM (32768 + 2 * 32768 + 1024)

__global__ void __launch_bounds__(256)
flash_kernel() {
    extern __shared__ char smem_raw[];
    uint32_t sb = smem_u32(smem_raw);
    sb = (sb + 1023u) & ~1023u;

    const int tid  = threadIdx.x;
    const int wid  = tid >> 5;
    const int lane = tid & 31;
    const int bh = blockIdx.y;
    const int q0 = blockIdx.x * 128;
    const int b = bh >> 4, h = bh & 15;

    const size_t qkbase = (size_t)bh * SEQC * HDC;
    const size_t vbase  = (size_t)bh * HDC * SEQC;

    auto load_q = [&]() {
#pragma unroll
        for (int it = 0; it < 8; it++) {
            int i = tid + it * 256;
            int r = i >> 4, rem = i & 15, hl = rem >> 3, kg = rem & 7;
            const __nv_bfloat16* src = (hl ? g_q_lo : g_q_hi) + qkbase + (size_t)(q0 + r) * HDC + kg * 8;
            cpa16(sb + (hl ? FQL : FQH) + SWZ(r * 128 + kg * 16), src);
        }
    };
    auto load_kv = [&](int t) {
        uint32_t bufb = sb + FST + (uint32_t)(t & 1) * FSS;
#pragma unroll
        for (int it = 0; it < 4; it++) {
            int i = tid + it * 256;
            int r = i >> 4, rem = i & 15, hl = rem >> 3, kg = rem & 7;
            const __nv_bfloat16* src = (hl ? g_k_lo : g_k_hi) + qkbase + (size_t)(t * 64 + r) * HDC + kg * 8;
            cpa16(bufb + (hl ? 8192 : 0) + SWZ(r * 128 + kg * 16), src);
        }
#pragma unroll
        for (int it = 0; it < 4; it++) {
            int i = tid + it * 256;
            int r = i >> 4, rem = i & 15, hl = rem >> 3, kg = rem & 7;
            const __nv_bfloat16* src = (hl ? g_vt_lo : g_vt_hi) + vbase + (size_t)r * SEQC + t * 64 + kg * 8;
            cpa16(bufb + 16384 + (hl ? 8192 : 0) + SWZ(r * 128 + kg * 16), src);
        }
        CP_COMMIT();
    };

    load_q(); load_kv(0); CP_COMMIT();
    load_kv(1);

    const int a_r16 = lane & 15;
    const int a_kb  = (lane >> 4) * 16;
    const int b_r8  = ((lane >> 4) << 3) + (lane & 7);
    const int b_kb  = ((lane >> 3) & 1) * 16;

    uint32_t qhf[4][4], qlf[4][4];
    float o[8][4];
#pragma unroll
    for (int j = 0; j < 8; j++)
#pragma unroll
        for (int k = 0; k < 4; k++) o[j][k] = 0.f;
    float ml0 = -1e30f, ml1 = -1e30f, ls0 = 0.f, ls1 = 0.f;

    for (int t = 0; t < 16; t++) {
        if (t < 15) CP_WAIT1(); else CP_WAIT0();
        __syncthreads();
        if (t == 0) {
#pragma unroll
            for (int kk = 0; kk < 4; kk++) {
                int r = wid * 16 + a_r16;
                uint32_t off = (uint32_t)(r * 128) + (uint32_t)((kk * 32 + a_kb) ^ ((r & 7) << 4));
                ldsm4(qhf[kk], sb + FQH + off);
                ldsm4(qlf[kk], sb + FQL + off);
            }
        }
        uint32_t bufb = sb + FST + (uint32_t)(t & 1) * FSS;

        float s[8][4];
#pragma unroll
        for (int j = 0; j < 8; j++)
#pragma unroll
            for (int k = 0; k < 4; k++) s[j][k] = 0.f;
#pragma unroll
        for (int kk = 0; kk < 4; kk++) {
#pragma unroll
            for (int ntp = 0; ntp < 4; ntp++) {
                int r = ntp * 16 + b_r8;
                uint32_t off = (uint32_t)(r * 128) + (uint32_t)((kk * 32 + b_kb) ^ ((r & 7) << 4));
                uint32_t khf[4], klf[4];
                ldsm4(khf, bufb + off);
                ldsm4(klf, bufb + 8192 + off);
                mma16816(s[2 * ntp],     qhf[kk], khf);
                mma16816(s[2 * ntp],     qhf[kk], klf);
                mma16816(s[2 * ntp],     qlf[kk], khf);
                mma16816(s[2 * ntp + 1], qhf[kk], khf + 2);
                mma16816(s[2 * ntp + 1], qhf[kk], klf + 2);
                mma16816(s[2 * ntp + 1], qlf[kk], khf + 2);
            }
        }

        float m0t = -1e30f, m1t = -1e30f;
#pragma unroll
        for (int j = 0; j < 8; j++) {
            m0t = fmaxf(m0t, fmaxf(s[j][0], s[j][1]));
            m1t = fmaxf(m1t, fmaxf(s[j][2], s[j][3]));
        }
        m0t = fmaxf(m0t, __shfl_xor_sync(0xffffffffu, m0t, 1));
        m0t = fmaxf(m0t, __shfl_xor_sync(0xffffffffu, m0t, 2));
        m1t = fmaxf(m1t, __shfl_xor_sync(0xffffffffu, m1t, 1));
        m1t = fmaxf(m1t, __shfl_xor_sync(0xffffffffu, m1t, 2));
        float mn0 = fmaxf(ml0, m0t), mn1 = fmaxf(ml1, m1t);
        float sc0 = exp2f(ml0 - mn0), sc1 = exp2f(ml1 - mn1);
        ml0 = mn0; ml1 = mn1;
        float r0 = 0.f, r1 = 0.f;
#pragma unroll
        for (int j = 0; j < 8; j++) {
            s[j][0] = exp2f(s[j][0] - mn0);
            s[j][1] = exp2f(s[j][1] - mn0);
            s[j][2] = exp2f(s[j][2] - mn1);
            s[j][3] = exp2f(s[j][3] - mn1);
            r0 += s[j][0] + s[j][1];
            r1 += s[j][2] + s[j][3];
        }
        r0 += __shfl_xor_sync(0xffffffffu, r0, 1);
        r0 += __shfl_xor_sync(0xffffffffu, r0, 2);
        r1 += __shfl_xor_sync(0xffffffffu, r1, 1);
        r1 += __shfl_xor_sync(0xffffffffu, r1, 2);
        ls0 = ls0 * sc0 + r0;
        ls1 = ls1 * sc1 + r1;
#pragma unroll
        for (int j = 0; j < 8; j++) {
            o[j][0] *= sc0; o[j][1] *= sc0;
            o[j][2] *= sc1; o[j][3] *= sc1;
        }

        uint32_t pah[4][4], pal[4][4];
#pragma unroll
        for (int kt = 0; kt < 4; kt++) {
            __nv_bfloat16 h0, l0, h1, l1;
            split1(s[2 * kt][0], h0, l0); split1(s[2 * kt][1], h1, l1);
            pah[kt][0] = pack_bf2(h0, h1); pal[kt][0] = pack_bf2(l0, l1);
            split1(s[2 * kt][2], h0, l0); split1(s[2 * kt][3], h1, l1);
            pah[kt][1] = pack_bf2(h0, h1); pal[kt][1] = pack_bf2(l0, l1);
            split1(s[2 * kt + 1][0], h0, l0); split1(s[2 * kt + 1][1], h1, l1);
            pah[kt][2] = pack_bf2(h0, h1); pal[kt][2] = pack_bf2(l0, l1);
            split1(s[2 * kt + 1][2], h0, l0); split1(s[2 * kt + 1][3], h1, l1);
            pah[kt][3] = pack_bf2(h0, h1); pal[kt][3] = pack_bf2(l0, l1);
        }

#pragma unroll
        for (int kt = 0; kt < 4; kt++) {
#pragma unroll
            for (int nv = 0; nv < 4; nv++) {
                int r = nv * 16 + b_r8;
                uint32_t off = (uint32_t)(r * 128) + (uint32_t)((kt * 32 + b_kb) ^ ((r & 7) << 4));
                uint32_t vhf[4], vlf[4];
                ldsm4(vhf, bufb + 16384 + off);
                ldsm4(vlf, bufb + 24576 + off);
                mma16816(o[2 * nv],     pah[kt], vhf);
                mma16816(o[2 * nv],     pah[kt], vlf);
                mma16816(o[2 * nv],     pal[kt], vhf);
                mma16816(o[2 * nv + 1], pah[kt], vhf + 2);
                mma16816(o[2 * nv + 1], pah[kt], vlf + 2);
                mma16816(o[2 * nv + 1], pal[kt], vhf + 2);
            }
        }
        __syncthreads();
        if (t + 2 < 16) load_kv(t + 2);
    }

    const int g = lane >> 2, t4 = lane & 3;
    float i0 = 1.f / ls0, i1 = 1.f / ls1;
    int tok0 = b * 1024 + q0 + wid * 16 + g;
    int tok1 = tok0 + 8;
#pragma unroll
    for (int j = 0; j < 8; j++) {
        int col = h * 64 + j * 8 + t4 * 2;
        __nv_bfloat16 h0, l0, h1, l1;
        split1(o[j][0] * i0, h0, l0); split1(o[j][1] * i0, h1, l1);
        *(uint32_t*)(g_h_hi + (size_t)tok0 * CINC + col) = pack_bf2(h0, h1);
        *(uint32_t*)(g_h_lo + (size_t)tok0 * CINC + col) = pack_bf2(l0, l1);
        split1(o[j][2] * i1, h0, l0); split1(o[j][3] * i1, h1, l1);
        *(uint32_t*)(g_h_hi + (size_t)tok1 * CINC + col) = pack_bf2(h0, h1);
        *(uint32_t*)(g_h_lo + (size_t)tok1 * CINC + col) = pack_bf2(l0, l1);
    }
}

// ---------------------------------------------------------------------------
// Expert permutation kernels
// ---------------------------------------------------------------------------
__global__ void perm_init_kernel() {
    if (threadIdx.x < 4) { g_cnt[threadIdx.x] = 0; g_cur[threadIdx.x] = 0; }
}
__global__ void perm_count_kernel(const int* __restrict__ em) {
    int i = blockIdx.x * 256 + threadIdx.x;
    if (i < TOK) atomicAdd(&g_cnt[em[i]], 1);
}
__global__ void perm_scan_kernel() {
    if (threadIdx.x == 0) {
        int o = 0;
        for (int e = 0; e < 4; e++) { g_goff[e] = o; o += g_cnt[e]; }
    }
}
__global__ void perm_fill_kernel(const int* __restrict__ em) {
    int i = blockIdx.x * 256 + threadIdx.x;
    if (i < TOK) {
        int e = em[i];
        int p = atomicAdd(&g_cur[e], 1);
        g_perm[g_goff[e] + p] = i;
    }
}

// ---------------------------------------------------------------------------
// splits / LN / packs / epilogue
// ---------------------------------------------------------------------------
__global__ void split4_kernel(const float* __restrict__ s,
                              __nv_bfloat16* __restrict__ hi, __nv_bfloat16* __restrict__ lo) {
    size_t i = (size_t)blockIdx.x * 256 + threadIdx.x;
    float4 v = ((const float4*)s)[i];
    __nv_bfloat16 h0, h1, h2, h3, l0, l1, l2, l3;
    split1(v.x, h0, l0); split1(v.y, h1, l1); split1(v.z, h2, l2); split1(v.w, h3, l3);
    __nv_bfloat162* H = (__nv_bfloat162*)hi;
    __nv_bfloat162* L = (__nv_bfloat162*)lo;
    H[2 * i] = __nv_bfloat162(h0, h1); H[2 * i + 1] = __nv_bfloat162(h2, h3);
    L[2 * i] = __nv_bfloat162(l0, l1); L[2 * i + 1] = __nv_bfloat162(l2, l3);
}

__global__ void ln1_kernel(const float* __restrict__ x, const int* __restrict__ em,
                           const float* __restrict__ g, const float* __restrict__ b) {
    int t = blockIdx.x;
    const float* xr = x + (size_t)t * DIMC;
    int tid = threadIdx.x;
    float v[4]; float s = 0.f, s2 = 0.f;
#pragma unroll
    for (int i = 0; i < 4; i++) { float a = xr[tid + 256 * i]; v[i] = a; s += a; s2 += a * a; }
#pragma unroll
    for (int o = 16; o; o >>= 1) { s += __shfl_xor_sync(0xffffffffu, s, o); s2 += __shfl_xor_sync(0xffffffffu, s2, o); }
    __shared__ float red[18];
    int w = tid >> 5, l = tid & 31;
    if (l == 0) { red[w] = s; red[8 + w] = s2; }
    __syncthreads();
    if (tid == 0) {
        float ts = 0.f, ts2 = 0.f;
        for (int i = 0; i < 8; i++) { ts += red[i]; ts2 += red[8 + i]; }
        float m = ts * (1.f / DIMC);
        float var = ts2 * (1.f / DIMC) - m * m;
        red[16] = m; red[17] = rsqrtf(var + 1e-5f);
    }
    __syncthreads();
    float m = red[16], rs = red[17];
    int din = DIMC >> (3 - em[t]);
#pragma unroll
    for (int i = 0; i < 4; i++) {
        int c = tid + 256 * i;
        float val = (v[i] - m) * rs * g[c] + b[c];
        val = (c < din) ? val : 0.f;
        __nv_bfloat16 h, lo; split1(val, h, lo);
        g_xn_hi[(size_t)t * DIMC + c] = h;
        g_xn_lo[(size_t)t * DIMC + c] = lo;
    }
}

// LN2 fused: blockIdx.y==0 -> k path (LN, write g_k hi/lo per-head layout);
//            blockIdx.y==1 -> v path (LN in place on g_y fp32 for vt_pack).
__global__ void ln2kv_kernel(const float* __restrict__ g, const float* __restrict__ b) {
    int t = blockIdx.x;
    int which = blockIdx.y;
    float* row = g_y + (size_t)t * 2048 + (size_t)DIMC * which;
    int tid = threadIdx.x;
    float v[4]; float s = 0.f, s2 = 0.f;
#pragma unroll
    for (int i = 0; i < 4; i++) { float a = row[tid + 256 * i]; v[i] = a; s += a; s2 += a * a; }
#pragma unroll
    for (int o = 16; o; o >>= 1) { s += __shfl_xor_sync(0xffffffffu, s, o); s2 += __shfl_xor_sync(0xffffffffu, s2, o); }
    __shared__ float red[18];
    int w = tid >> 5, l = tid & 31;
    if (l == 0) { red[w] = s; red[8 + w] = s2; }
    __syncthreads();
    if (tid == 0) {
        float ts = 0.f, ts2 = 0.f;
        for (int i = 0; i < 8; i++) { ts += red[i]; ts2 += red[8 + i]; }
        float m = ts * (1.f / DIMC);
        float var = ts2 * (1.f / DIMC) - m * m;
        red[16] = m; red[17] = rsqrtf(var + 1e-5f);
    }
    __syncthreads();
    float m = red[16], rs = red[17];
    int bb = t >> 10, ss = t & 1023;
#pragma unroll
    for (int i = 0; i < 4; i++) {
        int c = tid + 256 * i;
        float val = (v[i] - m) * rs * g[c] + b[c];
        if (which == 0) {
            int h = c >> 6, hd = c & 63;
            size_t o = ((size_t)(bb * NHC + h) * SEQC + ss) * HDC + hd;
            __nv_bfloat16 hh, ll; split1(val, hh, ll);
            g_k_hi[o] = hh; g_k_lo[o] = ll;
        } else {
            row[c] = val;
        }
    }
}

// Pack V transposed per head (reads normalized v from g_y cols [1024,2048))
__global__ void vt_pack_kernel() {
    __shared__ float tile[64][65];
    int bh = blockIdx.x;
    int b = bh >> 4, h = bh & 15;
    int s0 = blockIdx.y * 64;
    int tid = threadIdx.x;
#pragma unroll
    for (int i = 0; i < 16; i++) {
        int idx = tid + i * 256;
        int r = idx >> 6, c = idx & 63;
        tile[r][c] = g_y[(size_t)(b * 1024 + s0 + r) * 2048 + 1024 + h * 64 + c];
    }
    __syncthreads();
#pragma unroll
    for (int i = 0; i < 16; i++) {
        int idx = tid + i * 256;
        int r = idx >> 6, c = idx & 63;
        float v = tile[c][r];
        __nv_bfloat16 hh, ll; split1(v, hh, ll);
        size_t o = (size_t)bh * HDC * SEQC + (size_t)r * SEQC + s0 + c;
        g_vt_hi[o] = hh; g_vt_lo[o] = ll;
    }
}

__global__ void final_kernel(const float* __restrict__ x, const int* __restrict__ em,
                             const float* __restrict__ rp, const float* __restrict__ cb,
                             const float* __restrict__ alpha, float* __restrict__ out) {
    size_t idx = (size_t)blockIdx.x * 256 + threadIdx.x;
    int t = (int)(idx >> 10);
    int d = (int)(idx & 1023);
    int m = em[t];
    int dout = (2 * DIMC) >> (3 - m);
    const float* zr = g_z + (size_t)t * 2 * DIMC;
    float za = (d < dout) ? (zr[d] + cb[d]) : 0.f;
    float zm = (DIMC + d < dout) ? (zr[DIMC + d] + cb[DIMC + d]) : 0.f;
    float pr = rp[t * 4 + m];
    out[idx] = x[idx] + za + (alpha[0] * pr + 1.f) * zm;
}

__global__ void tail_kernel(const int* __restrict__ em, const float* __restrict__ rp,
                            float* __restrict__ out) {
    int i = blockIdx.x * 256 + threadIdx.x;
    if (i < TOK)     out[(size_t)TOK * DIMC + i] = (float)em[i];
    if (i < TOK * 4) out[(size_t)TOK * DIMC + TOK + i] = rp[i];
}

// ---------------------------------------------------------------------------
extern "C" void kernel_launch(void* const* d_in, const int* in_sizes, int n_in,
                              void* d_out, int out_size) {
    const float* x     = (const float*)d_in[0];
    const int*   em    = (const int*)d_in[1];
    const float* rp    = (const float*)d_in[2];
    const float* wexp  = (const float*)d_in[3];
    const float* mlpb  = (const float*)d_in[4];
    const float* wc    = (const float*)d_in[5];
    const float* cb    = (const float*)d_in[6];
    const float* n1g   = (const float*)d_in[7];
    const float* n1b   = (const float*)d_in[8];
    const float* n2g   = (const float*)d_in[9];
    const float* n2b   = (const float*)d_in[10];
    const float* alpha = (const float*)d_in[11];
    float* out = (float*)d_out;

    float *p_z;
    __nv_bfloat16 *p_xnh, *p_xnl, *p_weh, *p_wel, *p_wch, *p_wcl, *p_hh, *p_hl;
    cudaGetSymbolAddress((void**)&p_z,   g_z);
    cudaGetSymbolAddress((void**)&p_xnh, g_xn_hi);
    cudaGetSymbolAddress((void**)&p_xnl, g_xn_lo);
    cudaGetSymbolAddress((void**)&p_weh, g_we_hi);
    cudaGetSymbolAddress((void**)&p_wel, g_we_lo);
    cudaGetSymbolAddress((void**)&p_wch, g_wc_hi);
    cudaGetSymbolAddress((void**)&p_wcl, g_wc_lo);
    cudaGetSymbolAddress((void**)&p_hh,  g_h_hi);
    cudaGetSymbolAddress((void**)&p_hl,  g_h_lo);

    cudaFuncSetAttribute(gemm_grouped_kernel<0>, cudaFuncAttributeMaxDynamicSharedMemorySize, GSM);
    cudaFuncSetAttribute(gemm_grouped_kernel<1>, cudaFuncAttributeMaxDynamicSharedMemorySize, GSM);
    cudaFuncSetAttribute(flash_kernel,           cudaFuncAttributeMaxDynamicSharedMemorySize, FSM);

    // 0) expert permutation
    perm_init_kernel<<<1, 32>>>();
    perm_count_kernel<<<TOK / 256, 256>>>(em);
    perm_scan_kernel<<<1, 32>>>();
    perm_fill_kernel<<<TOK / 256, 256>>>(em);

    // 0b) weight splits
    split4_kernel<<<(EXPC * DIMC) / 4 / 256, 256>>>(wexp, p_weh, p_wel);
    split4_kernel<<<(2 * DIMC * CINC) / 4 / 256, 256>>>(wc, p_wch, p_wcl);

    // 1) LN1 + input mask
    ln1_kernel<<<TOK, 256>>>(x, em, n1g, n1b);

    // 2) expand (grouped, fused epilogue): q-pack / y fp32 (k,v) / gelu+h-pack
    gemm_grouped_kernel<1><<<dim3(EXPC / 128, TOK / 128, 4), 512, GSM>>>(
        p_xnh, p_xnl, DIMC, p_weh, p_wel, DIMC, nullptr, 0, mlpb,
        128, 1, EXPC, 0);

    // 3) LN2 fused with k-pack; v normalized in place
    ln2kv_kernel<<<dim3(TOK, 2), 256>>>(n2g, n2b);

    // 4) transposed V pack
    vt_pack_kernel<<<dim3(BH, SEQC / 64), 256>>>();

    // 5) flash attention -> h[:, 0:1024]
    flash_kernel<<<dim3(SEQC / 128, BH), 256, FSM>>>();

    // 6) contract (grouped): z = h @ Wc^T, N_e = 256<<e
    gemm_grouped_kernel<0><<<dim3(16, TOK / 128, 4), 512, GSM>>>(
        p_hh, p_hl, CINC, p_wch, p_wcl, CINC, p_z, 2 * DIMC, nullptr,
        CINC, 0, 256, 1);

    // 7) epilogue + tails
    final_kernel<<<(TOK * DIMC) / 256, 256>>>(x, em, rp, cb, alpha, out);
    tail_kernel<<<(TOK * 4 + 255) / 256, 256>>>(em, rp, out);
}

// round 9
// speedup vs baseline: 5.3781x; 1.0108x over previous
#include <cuda_runtime.h>
#include <cuda_bf16.h>
#include <math.h>
#include <stdint.h>

// Problem constants
#define TOK   8192        // B*N
#define DIMC  1024
#define EXPC  7168
#define CINC  5120
#define NHC   16
#define HDC   64
#define SEQC  1024
#define NB    8
#define BH    (NB * NHC)  // 128 batch-heads

#define LOG2E 1.44269504088896340736f

// ---------------------------------------------------------------------------
// Scratch (device globals; allocation-free)
// ---------------------------------------------------------------------------
__device__ float g_y [(size_t)TOK * 2 * DIMC];                //  67 MB (k,v fp32 pre-LN)
__device__ float g_z [(size_t)TOK * 2 * DIMC];                //  67 MB

__device__ __nv_bfloat16 g_xn_hi[(size_t)TOK * DIMC];
__device__ __nv_bfloat16 g_xn_lo[(size_t)TOK * DIMC];
__device__ __nv_bfloat16 g_we_hi[(size_t)EXPC * DIMC];
__device__ __nv_bfloat16 g_we_lo[(size_t)EXPC * DIMC];
__device__ __nv_bfloat16 g_wc_hi[(size_t)2 * DIMC * CINC];
__device__ __nv_bfloat16 g_wc_lo[(size_t)2 * DIMC * CINC];
__device__ __nv_bfloat16 g_h_hi[(size_t)TOK * CINC];
__device__ __nv_bfloat16 g_h_lo[(size_t)TOK * CINC];

// attention operands (per-head [bh][seq][hd] layouts)
__device__ __nv_bfloat16 g_q_hi[(size_t)BH * SEQC * HDC];
__device__ __nv_bfloat16 g_q_lo[(size_t)BH * SEQC * HDC];
__device__ __nv_bfloat16 g_k_hi[(size_t)BH * SEQC * HDC];
__device__ __nv_bfloat16 g_k_lo[(size_t)BH * SEQC * HDC];
__device__ __nv_bfloat16 g_v_hi[(size_t)BH * SEQC * HDC];
__device__ __nv_bfloat16 g_v_lo[(size_t)BH * SEQC * HDC];

// expert grouping
__device__ int g_cnt[4];
__device__ int g_cur[4];
__device__ int g_goff[4];
__device__ int g_perm[TOK];

// ---------------------------------------------------------------------------
// PTX helpers
// ---------------------------------------------------------------------------
__device__ __forceinline__ uint32_t smem_u32(const void* p) {
    uint32_t a;
    asm("{ .reg .u64 t; cvta.to.shared.u64 t, %1; cvt.u32.u64 %0, t; }" : "=r"(a) : "l"(p));
    return a;
}
__device__ __forceinline__ void ldsm4(uint32_t* r, uint32_t a) {
    asm volatile("ldmatrix.sync.aligned.m8n8.x4.shared.b16 {%0,%1,%2,%3}, [%4];"
                 : "=r"(r[0]), "=r"(r[1]), "=r"(r[2]), "=r"(r[3]) : "r"(a));
}
__device__ __forceinline__ void ldsm4t(uint32_t* r, uint32_t a) {
    asm volatile("ldmatrix.sync.aligned.m8n8.x4.trans.shared.b16 {%0,%1,%2,%3}, [%4];"
                 : "=r"(r[0]), "=r"(r[1]), "=r"(r[2]), "=r"(r[3]) : "r"(a));
}
__device__ __forceinline__ void mma16816(float* c, const uint32_t* a, const uint32_t* b) {
    asm volatile("mma.sync.aligned.m16n8k16.row.col.f32.bf16.bf16.f32 "
                 "{%0,%1,%2,%3}, {%4,%5,%6,%7}, {%8,%9}, {%0,%1,%2,%3};"
                 : "+f"(c[0]), "+f"(c[1]), "+f"(c[2]), "+f"(c[3])
                 : "r"(a[0]), "r"(a[1]), "r"(a[2]), "r"(a[3]), "r"(b[0]), "r"(b[1]));
}
__device__ __forceinline__ void cpa16(uint32_t s, const void* g) {
    asm volatile("cp.async.cg.shared.global [%0], [%1], 16;" :: "r"(s), "l"(g));
}
#define CP_COMMIT() asm volatile("cp.async.commit_group;")
#define CP_WAIT2()  asm volatile("cp.async.wait_group 2;")
#define CP_WAIT1()  asm volatile("cp.async.wait_group 1;")
#define CP_WAIT0()  asm volatile("cp.async.wait_group 0;")

#define SWZ(o) ((o) ^ (((o) >> 3) & 0x70))

__device__ __forceinline__ void split1(float x, __nv_bfloat16& h, __nv_bfloat16& l) {
    h = __float2bfloat16(x);
    l = __float2bfloat16(x - __bfloat162float(h));
}
__device__ __forceinline__ uint32_t pack_bf2(__nv_bfloat16 a, __nv_bfloat16 b) {
    __nv_bfloat162 v(a, b);
    return *(uint32_t*)&v;
}
__device__ __forceinline__ float gelu1(float x) {
    return 0.5f * x * (1.f + erff(x * 0.70710678118654752f));
}

// ---------------------------------------------------------------------------
// Expert-grouped bf16-split HMMA GEMM with row gather. (512 thr, 4x4 warps,
// warp tile 32x32, CTA 128x128, K-chunk 64, 3-stage cp.async)
// MODE 0: plain fp32 scatter to C (contract).
// MODE 1: expand fused epilogue (q-pack / y fp32 / gelu+h-pack by n-region).
// ---------------------------------------------------------------------------
#define GOAH 0
#define GOAL 16384
#define GOBH 32768
#define GOBL 49152
#define GBUF 65536
#define GSM  (1024 + 3 * GBUF)

template<int MODE>
__global__ void __launch_bounds__(512)
gemm_grouped_kernel(const __nv_bfloat16* __restrict__ Ah, const __nv_bfloat16* __restrict__ Al, int lda,
                    const __nv_bfloat16* __restrict__ Bh, const __nv_bfloat16* __restrict__ Bl, int ldb,
                    float* __restrict__ C, int ldc,
                    const float* __restrict__ mlpb,
                    int Kbase, int Kscale, int Nbase, int Nscale) {
    const int e = blockIdx.z;
    const int cnt  = g_cnt[e];
    const int goff = g_goff[e];
    const int m0 = blockIdx.y * 128;
    if (m0 >= cnt) return;
    const int K    = Kscale ? (Kbase << e) : Kbase;
    const int Nlim = Nscale ? (Nbase << e) : Nbase;
    const int n0 = blockIdx.x * 128;
    if (n0 >= Nlim) return;

    extern __shared__ char smem_raw[];
    uint32_t sb0 = smem_u32(smem_raw);
    sb0 = (sb0 + 1023u) & ~1023u;
    int* tok = (int*)(smem_raw + (sb0 - smem_u32(smem_raw)));
    uint32_t sb = sb0 + 1024u;

    const int tid  = threadIdx.x;
    const int wid  = tid >> 5;
    const int lane = tid & 31;
    const int wm = wid & 3;
    const int wn = wid >> 2;

    if (tid < 128) {
        int gr = m0 + tid;
        tok[tid] = g_perm[goff + ((gr < cnt) ? gr : 0)];
    }
    __syncthreads();

    const __nv_bfloat16* BBh = Bh + (size_t)n0 * ldb;
    const __nv_bfloat16* BBl = Bl + (size_t)n0 * ldb;

    const int NC = K / 64;

    auto load_chunk = [&](int c) {
        uint32_t bufb = sb + (uint32_t)(c % 3) * GBUF;
        int k0 = c * 64;
#pragma unroll
        for (int it = 0; it < 4; it++) {
            int i = tid + it * 512;
            int r = i >> 4, rem = i & 15, hl = rem >> 3, kg = rem & 7;
            const __nv_bfloat16* src = (hl ? Al : Ah) + (size_t)tok[r] * lda + k0 + kg * 8;
            cpa16(bufb + (hl ? GOAL : GOAH) + SWZ(r * 128 + kg * 16), src);
        }
#pragma unroll
        for (int it = 0; it < 4; it++) {
            int i = tid + it * 512;
            int r = i >> 4, rem = i & 15, hl = rem >> 3, kg = rem & 7;
            const __nv_bfloat16* src = (hl ? BBl : BBh) + (size_t)r * ldb + k0 + kg * 8;
            cpa16(bufb + (hl ? GOBL : GOBH) + SWZ(r * 128 + kg * 16), src);
        }
        CP_COMMIT();
    };

    load_chunk(0);
    if (NC > 1) load_chunk(1);

    float acc[2][4][4];
#pragma unroll
    for (int i = 0; i < 2; i++)
#pragma unroll
        for (int j = 0; j < 4; j++)
#pragma unroll
            for (int k = 0; k < 4; k++) acc[i][j][k] = 0.f;

    const int a_r16 = lane & 15;
    const int a_kb  = (lane >> 4) * 16;
    const int b_r8  = ((lane >> 4) << 3) + (lane & 7);
    const int b_kb  = ((lane >> 3) & 1) * 16;

    for (int c = 0; c < NC; c++) {
        if (c + 2 < NC) load_chunk(c + 2);
        int pend = NC - 1 - c; if (pend > 2) pend = 2;
        if (pend == 2) CP_WAIT2(); else if (pend == 1) CP_WAIT1(); else CP_WAIT0();
        __syncthreads();

        uint32_t bufb = sb + (uint32_t)(c % 3) * GBUF;
#pragma unroll
        for (int kk = 0; kk < 4; kk++) {
            int kb = kk * 32;
            uint32_t ah[2][4], al[2][4];
#pragma unroll
            for (int mt = 0; mt < 2; mt++) {
                int r = wm * 32 + mt * 16 + a_r16;
                uint32_t off = (uint32_t)(r * 128) + (uint32_t)((kb + a_kb) ^ ((r & 7) << 4));
                ldsm4(ah[mt], bufb + GOAH + off);
                ldsm4(al[mt], bufb + GOAL + off);
            }
#pragma unroll
            for (int ntp = 0; ntp < 2; ntp++) {
                int r = wn * 32 + ntp * 16 + b_r8;
                uint32_t off = (uint32_t)(r * 128) + (uint32_t)((kb + b_kb) ^ ((r & 7) << 4));
                uint32_t bh[4], bl[4];
                ldsm4(bh, bufb + GOBH + off);
                ldsm4(bl, bufb + GOBL + off);
#pragma unroll
                for (int mt = 0; mt < 2; mt++) {
                    mma16816(acc[mt][2 * ntp],     ah[mt], bh);
                    mma16816(acc[mt][2 * ntp],     ah[mt], bl);
                    mma16816(acc[mt][2 * ntp],     al[mt], bh);
                    mma16816(acc[mt][2 * ntp + 1], ah[mt], bh + 2);
                    mma16816(acc[mt][2 * ntp + 1], ah[mt], bl + 2);
                    mma16816(acc[mt][2 * ntp + 1], al[mt], bh + 2);
                }
            }
        }
        __syncthreads();
    }

    const int g = lane >> 2, t4 = lane & 3;

    if (MODE == 0) {
#pragma unroll
        for (int mt = 0; mt < 2; mt++) {
            int r0 = wm * 32 + mt * 16 + g;
            int r1 = r0 + 8;
            int tk0 = tok[r0], tk1 = tok[r1];
            bool ok0 = (m0 + r0) < cnt, ok1 = (m0 + r1) < cnt;
#pragma unroll
            for (int nt = 0; nt < 4; nt++) {
                int ncol = n0 + wn * 32 + nt * 8 + t4 * 2;
                if (ok0) *(float2*)(C + (size_t)tk0 * ldc + ncol) = make_float2(acc[mt][nt][0], acc[mt][nt][1]);
                if (ok1) *(float2*)(C + (size_t)tk1 * ldc + ncol) = make_float2(acc[mt][nt][2], acc[mt][nt][3]);
            }
        }
    } else {
#pragma unroll
        for (int mt = 0; mt < 2; mt++) {
            int r0 = wm * 32 + mt * 16 + g;
            int r1 = r0 + 8;
            int tk0 = tok[r0], tk1 = tok[r1];
            bool ok0 = (m0 + r0) < cnt, ok1 = (m0 + r1) < cnt;
            if (n0 < 1024) {
                // Q region: scale (1/8)*log2e, split, per-head layout
#pragma unroll
                for (int nt = 0; nt < 4; nt++) {
                    int d = n0 + wn * 32 + nt * 8 + t4 * 2;
                    int h = d >> 6, hd = d & 63;
                    const float QS = 0.125f * LOG2E;
                    __nv_bfloat16 h0, l0, h1, l1;
                    if (ok0) {
                        size_t o = ((size_t)((tk0 >> 10) * NHC + h) * SEQC + (tk0 & 1023)) * HDC + hd;
                        split1(acc[mt][nt][0] * QS, h0, l0);
                        split1(acc[mt][nt][1] * QS, h1, l1);
                        *(uint32_t*)(g_q_hi + o) = pack_bf2(h0, h1);
                        *(uint32_t*)(g_q_lo + o) = pack_bf2(l0, l1);
                    }
                    if (ok1) {
                        size_t o = ((size_t)((tk1 >> 10) * NHC + h) * SEQC + (tk1 & 1023)) * HDC + hd;
                        split1(acc[mt][nt][2] * QS, h0, l0);
                        split1(acc[mt][nt][3] * QS, h1, l1);
                        *(uint32_t*)(g_q_hi + o) = pack_bf2(h0, h1);
                        *(uint32_t*)(g_q_lo + o) = pack_bf2(l0, l1);
                    }
                }
            } else if (n0 < 3072) {
                // K/V region: fp32 to g_y [TOK][2048]
#pragma unroll
                for (int nt = 0; nt < 4; nt++) {
                    int col = n0 - 1024 + wn * 32 + nt * 8 + t4 * 2;
                    if (ok0) *(float2*)(g_y + (size_t)tk0 * 2048 + col) = make_float2(acc[mt][nt][0], acc[mt][nt][1]);
                    if (ok1) *(float2*)(g_y + (size_t)tk1 * 2048 + col) = make_float2(acc[mt][nt][2], acc[mt][nt][3]);
                }
            } else {
                // MLP region: +bias, GELU, split -> g_h[:, 1024+j]
#pragma unroll
                for (int nt = 0; nt < 4; nt++) {
                    int j = n0 - 3072 + wn * 32 + nt * 8 + t4 * 2;
                    float b0 = mlpb[j], b1 = mlpb[j + 1];
                    __nv_bfloat16 h0, l0, h1, l1;
                    if (ok0) {
                        split1(gelu1(acc[mt][nt][0] + b0), h0, l0);
                        split1(gelu1(acc[mt][nt][1] + b1), h1, l1);
                        size_t o = (size_t)tk0 * CINC + 1024 + j;
                        *(uint32_t*)(g_h_hi + o) = pack_bf2(h0, h1);
                        *(uint32_t*)(g_h_lo + o) = pack_bf2(l0, l1);
                    }
                    if (ok1) {
                        split1(gelu1(acc[mt][nt][2] + b0), h0, l0);
                        split1(gelu1(acc[mt][nt][3] + b1), h1, l1);
                        size_t o = (size_t)tk1 * CINC + 1024 + j;
                        *(uint32_t*)(g_h_hi + o) = pack_bf2(h0, h1);
                        *(uint32_t*)(g_h_lo + o) = pack_bf2(l0, l1);
                    }
                }
            }
        }
    }
}

// ---------------------------------------------------------------------------
// Flash attention. V consumed row-major [seq][hd] via ldmatrix.trans.
// ---------------------------------------------------------------------------
#define FQH 0
#define FQL 16384
#define FST 32768
#define FSS 32768
#define FSM (32768 + 2 * 32768 + 1024)

__global__ void __launch_bounds__(256)
flash_kernel() {
    extern __shared__ char smem_raw[];
    uint32_t sb = smem_u32(smem_raw);
    sb = (sb + 1023u) & ~1023u;

    const int tid  = threadIdx.x;
    const int wid  = tid >> 5;
    const int lane = tid & 31;
    const int bh = blockIdx.y;
    const int q0 = blockIdx.x * 128;
    const int b = bh >> 4, h = bh & 15;

    const size_t base = (size_t)bh * SEQC * HDC;

    auto load_q = [&]() {
#pragma unroll
        for (int it = 0; it < 8; it++) {
            int i = tid + it * 256;
            int r = i >> 4, rem = i & 15, hl = rem >> 3, kg = rem & 7;
            const __nv_bfloat16* src = (hl ? g_q_lo : g_q_hi) + base + (size_t)(q0 + r) * HDC + kg * 8;
            cpa16(sb + (hl ? FQL : FQH) + SWZ(r * 128 + kg * 16), src);
        }
    };
    auto load_kv = [&](int t) {
        uint32_t bufb = sb + FST + (uint32_t)(t & 1) * FSS;
#pragma unroll
        for (int it = 0; it < 4; it++) {
            int i = tid + it * 256;
            int r = i >> 4, rem = i & 15, hl = rem >> 3, kg = rem & 7;
            const __nv_bfloat16* src = (hl ? g_k_lo : g_k_hi) + base + (size_t)(t * 64 + r) * HDC + kg * 8;
            cpa16(bufb + (hl ? 8192 : 0) + SWZ(r * 128 + kg * 16), src);
        }
#pragma unroll
        for (int it = 0; it < 4; it++) {
            int i = tid + it * 256;
            int r = i >> 4, rem = i & 15, hl = rem >> 3, kg = rem & 7;
            const __nv_bfloat16* src = (hl ? g_v_lo : g_v_hi) + base + (size_t)(t * 64 + r) * HDC + kg * 8;
            cpa16(bufb + 16384 + (hl ? 8192 : 0) + SWZ(r * 128 + kg * 16), src);
        }
        CP_COMMIT();
    };

    load_q(); load_kv(0); CP_COMMIT();
    load_kv(1);

    const int a_r16 = lane & 15;
    const int a_kb  = (lane >> 4) * 16;
    const int b_r8  = ((lane >> 4) << 3) + (lane & 7);
    const int b_kb  = ((lane >> 3) & 1) * 16;
    // trans addressing for V [keys][hd]: rows = k, bytes = n
    const int v_r  = ((lane >> 3) & 1) * 8 + (lane & 7);
    const int v_cb = (lane >> 4) * 16;

    uint32_t qhf[4][4], qlf[4][4];
    float o[8][4];
#pragma unroll
    for (int j = 0; j < 8; j++)
#pragma unroll
        for (int k = 0; k < 4; k++) o[j][k] = 0.f;
    float ml0 = -1e30f, ml1 = -1e30f, ls0 = 0.f, ls1 = 0.f;

    for (int t = 0; t < 16; t++) {
        if (t < 15) CP_WAIT1(); else CP_WAIT0();
        __syncthreads();
        if (t == 0) {
#pragma unroll
            for (int kk = 0; kk < 4; kk++) {
                int r = wid * 16 + a_r16;
                uint32_t off = (uint32_t)(r * 128) + (uint32_t)((kk * 32 + a_kb) ^ ((r & 7) << 4));
                ldsm4(qhf[kk], sb + FQH + off);
                ldsm4(qlf[kk], sb + FQL + off);
            }
        }
        uint32_t bufb = sb + FST + (uint32_t)(t & 1) * FSS;

        float s[8][4];
#pragma unroll
        for (int j = 0; j < 8; j++)
#pragma unroll
            for (int k = 0; k < 4; k++) s[j][k] = 0.f;
#pragma unroll
        for (int kk = 0; kk < 4; kk++) {
#pragma unroll
            for (int ntp = 0; ntp < 4; ntp++) {
                int r = ntp * 16 + b_r8;
                uint32_t off = (uint32_t)(r * 128) + (uint32_t)((kk * 32 + b_kb) ^ ((r & 7) << 4));
                uint32_t khf[4], klf[4];
                ldsm4(khf, bufb + off);
                ldsm4(klf, bufb + 8192 + off);
                mma16816(s[2 * ntp],     qhf[kk], khf);
                mma16816(s[2 * ntp],     qhf[kk], klf);
                mma16816(s[2 * ntp],     qlf[kk], khf);
                mma16816(s[2 * ntp + 1], qhf[kk], khf + 2);
                mma16816(s[2 * ntp + 1], qhf[kk], klf + 2);
                mma16816(s[2 * ntp + 1], qlf[kk], khf + 2);
            }
        }

        float m0t = -1e30f, m1t = -1e30f;
#pragma unroll
        for (int j = 0; j < 8; j++) {
            m0t = fmaxf(m0t, fmaxf(s[j][0], s[j][1]));
            m1t = fmaxf(m1t, fmaxf(s[j][2], s[j][3]));
        }
        m0t = fmaxf(m0t, __shfl_xor_sync(0xffffffffu, m0t, 1));
        m0t = fmaxf(m0t, __shfl_xor_sync(0xffffffffu, m0t, 2));
        m1t = fmaxf(m1t, __shfl_xor_sync(0xffffffffu, m1t, 1));
        m1t = fmaxf(m1t, __shfl_xor_sync(0xffffffffu, m1t, 2));
        float mn0 = fmaxf(ml0, m0t), mn1 = fmaxf(ml1, m1t);
        float sc0 = exp2f(ml0 - mn0), sc1 = exp2f(ml1 - mn1);
        ml0 = mn0; ml1 = mn1;
        float r0 = 0.f, r1 = 0.f;
#pragma unroll
        for (int j = 0; j < 8; j++) {
            s[j][0] = exp2f(s[j][0] - mn0);
            s[j][1] = exp2f(s[j][1] - mn0);
            s[j][2] = exp2f(s[j][2] - mn1);
            s[j][3] = exp2f(s[j][3] - mn1);
            r0 += s[j][0] + s[j][1];
            r1 += s[j][2] + s[j][3];
        }
        r0 += __shfl_xor_sync(0xffffffffu, r0, 1);
        r0 += __shfl_xor_sync(0xffffffffu, r0, 2);
        r1 += __shfl_xor_sync(0xffffffffu, r1, 1);
        r1 += __shfl_xor_sync(0xffffffffu, r1, 2);
        ls0 = ls0 * sc0 + r0;
        ls1 = ls1 * sc1 + r1;
#pragma unroll
        for (int j = 0; j < 8; j++) {
            o[j][0] *= sc0; o[j][1] *= sc0;
            o[j][2] *= sc1; o[j][3] *= sc1;
        }

        uint32_t pah[4][4], pal[4][4];
#pragma unroll
        for (int kt = 0; kt < 4; kt++) {
            __nv_bfloat16 h0, l0, h1, l1;
            split1(s[2 * kt][0], h0, l0); split1(s[2 * kt][1], h1, l1);
            pah[kt][0] = pack_bf2(h0, h1); pal[kt][0] = pack_bf2(l0, l1);
            split1(s[2 * kt][2], h0, l0); split1(s[2 * kt][3], h1, l1);
            pah[kt][1] = pack_bf2(h0, h1); pal[kt][1] = pack_bf2(l0, l1);
            split1(s[2 * kt + 1][0], h0, l0); split1(s[2 * kt + 1][1], h1, l1);
            pah[kt][2] = pack_bf2(h0, h1); pal[kt][2] = pack_bf2(l0, l1);
            split1(s[2 * kt + 1][2], h0, l0); split1(s[2 * kt + 1][3], h1, l1);
            pah[kt][3] = pack_bf2(h0, h1); pal[kt][3] = pack_bf2(l0, l1);
        }

        // O += P V, V fragments via ldmatrix.trans from [keys][hd] tile
#pragma unroll
        for (int kt = 0; kt < 4; kt++) {
#pragma unroll
            for (int nv = 0; nv < 4; nv++) {
                int r = kt * 16 + v_r;
                uint32_t off = (uint32_t)(r * 128) + (uint32_t)((nv * 32 + v_cb) ^ ((r & 7) << 4));
                uint32_t vhf[4], vlf[4];
                ldsm4t(vhf, bufb + 16384 + off);
                ldsm4t(vlf, bufb + 24576 + off);
                mma16816(o[2 * nv],     pah[kt], vhf);
                mma16816(o[2 * nv],     pah[kt], vlf);
                mma16816(o[2 * nv],     pal[kt], vhf);
                mma16816(o[2 * nv + 1], pah[kt], vhf + 2);
                mma16816(o[2 * nv + 1], pah[kt], vlf + 2);
                mma16816(o[2 * nv + 1], pal[kt], vhf + 2);
            }
        }
        __syncthreads();
        if (t + 2 < 16) load_kv(t + 2);
    }

    const int g = lane >> 2, t4 = lane & 3;
    float i0 = 1.f / ls0, i1 = 1.f / ls1;
    int tok0 = b * 1024 + q0 + wid * 16 + g;
    int tok1 = tok0 + 8;
#pragma unroll
    for (int j = 0; j < 8; j++) {
        int col = h * 64 + j * 8 + t4 * 2;
        __nv_bfloat16 h0, l0, h1, l1;
        split1(o[j][0] * i0, h0, l0); split1(o[j][1] * i0, h1, l1);
        *(uint32_t*)(g_h_hi + (size_t)tok0 * CINC + col) = pack_bf2(h0, h1);
        *(uint32_t*)(g_h_lo + (size_t)tok0 * CINC + col) = pack_bf2(l0, l1);
        split1(o[j][2] * i1, h0, l0); split1(o[j][3] * i1, h1, l1);
        *(uint32_t*)(g_h_hi + (size_t)tok1 * CINC + col) = pack_bf2(h0, h1);
        *(uint32_t*)(g_h_lo + (size_t)tok1 * CINC + col) = pack_bf2(l0, l1);
    }
}

// ---------------------------------------------------------------------------
// Expert permutation kernels
// ---------------------------------------------------------------------------
__global__ void perm_init_kernel() {
    if (threadIdx.x < 4) { g_cnt[threadIdx.x] = 0; g_cur[threadIdx.x] = 0; }
}
__global__ void perm_count_kernel(const int* __restrict__ em) {
    int i = blockIdx.x * 256 + threadIdx.x;
    if (i < TOK) atomicAdd(&g_cnt[em[i]], 1);
}
__global__ void perm_scan_kernel() {
    if (threadIdx.x == 0) {
        int o = 0;
        for (int e = 0; e < 4; e++) { g_goff[e] = o; o += g_cnt[e]; }
    }
}
__global__ void perm_fill_kernel(const int* __restrict__ em) {
    int i = blockIdx.x * 256 + threadIdx.x;
    if (i < TOK) {
        int e = em[i];
        int p = atomicAdd(&g_cur[e], 1);
        g_perm[g_goff[e] + p] = i;
    }
}

// ---------------------------------------------------------------------------
// splits / LN / epilogue
// ---------------------------------------------------------------------------
__global__ void split4_kernel(const float* __restrict__ s,
                              __nv_bfloat16* __restrict__ hi, __nv_bfloat16* __restrict__ lo) {
    size_t i = (size_t)blockIdx.x * 256 + threadIdx.x;
    float4 v = ((const float4*)s)[i];
    __nv_bfloat16 h0, h1, h2, h3, l0, l1, l2, l3;
    split1(v.x, h0, l0); split1(v.y, h1, l1); split1(v.z, h2, l2); split1(v.w, h3, l3);
    __nv_bfloat162* H = (__nv_bfloat162*)hi;
    __nv_bfloat162* L = (__nv_bfloat162*)lo;
    H[2 * i] = __nv_bfloat162(h0, h1); H[2 * i + 1] = __nv_bfloat162(h2, h3);
    L[2 * i] = __nv_bfloat162(l0, l1); L[2 * i + 1] = __nv_bfloat162(l2, l3);
}

// LN1 -> masked xn as bf16 hi/lo (float4 loads, paired stores)
__global__ void ln1_kernel(const float* __restrict__ x, const int* __restrict__ em,
                           const float* __restrict__ g, const float* __restrict__ b) {
    int t = blockIdx.x;
    const float4* xr = (const float4*)(x + (size_t)t * DIMC);
    int tid = threadIdx.x;
    float4 v = xr[tid];
    float s  = v.x + v.y + v.z + v.w;
    float s2 = v.x * v.x + v.y * v.y + v.z * v.z + v.w * v.w;
#pragma unroll
    for (int o = 16; o; o >>= 1) { s += __shfl_xor_sync(0xffffffffu, s, o); s2 += __shfl_xor_sync(0xffffffffu, s2, o); }
    __shared__ float red[18];
    int w = tid >> 5, l = tid & 31;
    if (l == 0) { red[w] = s; red[8 + w] = s2; }
    __syncthreads();
    if (tid == 0) {
        float ts = 0.f, ts2 = 0.f;
        for (int i = 0; i < 8; i++) { ts += red[i]; ts2 += red[8 + i]; }
        float m = ts * (1.f / DIMC);
        float var = ts2 * (1.f / DIMC) - m * m;
        red[16] = m; red[17] = rsqrtf(var + 1e-5f);
    }
    __syncthreads();
    float m = red[16], rs = red[17];
    int din = DIMC >> (3 - em[t]);
    int c = tid * 4;
    float4 gg = ((const float4*)g)[tid];
    float4 bb = ((const float4*)b)[tid];
    float o0 = (c + 0 < din) ? ((v.x - m) * rs * gg.x + bb.x) : 0.f;
    float o1 = (c + 1 < din) ? ((v.y - m) * rs * gg.y + bb.y) : 0.f;
    float o2 = (c + 2 < din) ? ((v.z - m) * rs * gg.z + bb.z) : 0.f;
    float o3 = (c + 3 < din) ? ((v.w - m) * rs * gg.w + bb.w) : 0.f;
    __nv_bfloat16 h0, l0, h1, l1, h2, l2, h3, l3;
    split1(o0, h0, l0); split1(o1, h1, l1); split1(o2, h2, l2); split1(o3, h3, l3);
    size_t o = (size_t)t * DIMC + c;
    *(uint32_t*)(g_xn_hi + o)     = pack_bf2(h0, h1);
    *(uint32_t*)(g_xn_hi + o + 2) = pack_bf2(h2, h3);
    *(uint32_t*)(g_xn_lo + o)     = pack_bf2(l0, l1);
    *(uint32_t*)(g_xn_lo + o + 2) = pack_bf2(l2, l3);
}

// LN2: which==0 -> k, which==1 -> v. Both write per-head hi/lo directly.
__global__ void ln2kv_kernel(const float* __restrict__ g, const float* __restrict__ b) {
    int t = blockIdx.x;
    int which = blockIdx.y;
    const float4* row = (const float4*)(g_y + (size_t)t * 2048 + (size_t)DIMC * which);
    int tid = threadIdx.x;
    float4 v = row[tid];
    float s  = v.x + v.y + v.z + v.w;
    float s2 = v.x * v.x + v.y * v.y + v.z * v.z + v.w * v.w;
#pragma unroll
    for (int o = 16; o; o >>= 1) { s += __shfl_xor_sync(0xffffffffu, s, o); s2 += __shfl_xor_sync(0xffffffffu, s2, o); }
    __shared__ float red[18];
    int w = tid >> 5, l = tid & 31;
    if (l == 0) { red[w] = s; red[8 + w] = s2; }
    __syncthreads();
    if (tid == 0) {
        float ts = 0.f, ts2 = 0.f;
        for (int i = 0; i < 8; i++) { ts += red[i]; ts2 += red[8 + i]; }
        float m = ts * (1.f / DIMC);
        float var = ts2 * (1.f / DIMC) - m * m;
        red[16] = m; red[17] = rsqrtf(var + 1e-5f);
    }
    __syncthreads();
    float m = red[16], rs = red[17];
    int bb2 = t >> 10, ss = t & 1023;
    int c = tid * 4;
    float4 gg = ((const float4*)g)[tid];
    float4 bv = ((const float4*)b)[tid];
    float o0 = (v.x - m) * rs * gg.x + bv.x;
    float o1 = (v.y - m) * rs * gg.y + bv.y;
    float o2 = (v.z - m) * rs * gg.z + bv.z;
    float o3 = (v.w - m) * rs * gg.w + bv.w;
    __nv_bfloat16 h0, l0, h1, l1, h2, l2, h3, l3;
    split1(o0, h0, l0); split1(o1, h1, l1); split1(o2, h2, l2); split1(o3, h3, l3);
    int hh = c >> 6, hd = c & 63;
    size_t o = ((size_t)(bb2 * NHC + hh) * SEQC + ss) * HDC + hd;
    __nv_bfloat16* dh = which ? g_v_hi : g_k_hi;
    __nv_bfloat16* dl = which ? g_v_lo : g_k_lo;
    *(uint32_t*)(dh + o)     = pack_bf2(h0, h1);
    *(uint32_t*)(dh + o + 2) = pack_bf2(h2, h3);
    *(uint32_t*)(dl + o)     = pack_bf2(l0, l1);
    *(uint32_t*)(dl + o + 2) = pack_bf2(l2, l3);
}

// Final epilogue + pass-through tails (merged)
__global__ void final_kernel(const float* __restrict__ x, const int* __restrict__ em,
                             const float* __restrict__ rp, const float* __restrict__ cb,
                             const float* __restrict__ alpha, float* __restrict__ out) {
    size_t idx = (size_t)blockIdx.x * 256 + threadIdx.x;
    int t = (int)(idx >> 10);
    int d = (int)(idx & 1023);
    int m = em[t];
    int dout = (2 * DIMC) >> (3 - m);
    const float* zr = g_z + (size_t)t * 2 * DIMC;
    float za = (d < dout) ? (zr[d] + cb[d]) : 0.f;
    float zm = (DIMC + d < dout) ? (zr[DIMC + d] + cb[DIMC + d]) : 0.f;
    float pr = rp[t * 4 + m];
    out[idx] = x[idx] + za + (alpha[0] * pr + 1.f) * zm;
    if (idx < TOK)     out[(size_t)TOK * DIMC + idx] = (float)em[idx];
    if (idx < TOK * 4) out[(size_t)TOK * DIMC + TOK + idx] = rp[idx];
}

// ---------------------------------------------------------------------------
extern "C" void kernel_launch(void* const* d_in, const int* in_sizes, int n_in,
                              void* d_out, int out_size) {
    const float* x     = (const float*)d_in[0];
    const int*   em    = (const int*)d_in[1];
    const float* rp    = (const float*)d_in[2];
    const float* wexp  = (const float*)d_in[3];
    const float* mlpb  = (const float*)d_in[4];
    const float* wc    = (const float*)d_in[5];
    const float* cb    = (const float*)d_in[6];
    const float* n1g   = (const float*)d_in[7];
    const float* n1b   = (const float*)d_in[8];
    const float* n2g   = (const float*)d_in[9];
    const float* n2b   = (const float*)d_in[10];
    const float* alpha = (const float*)d_in[11];
    float* out = (float*)d_out;

    float *p_z;
    __nv_bfloat16 *p_xnh, *p_xnl, *p_weh, *p_wel, *p_wch, *p_wcl, *p_hh, *p_hl;
    cudaGetSymbolAddress((void**)&p_z,   g_z);
    cudaGetSymbolAddress((void**)&p_xnh, g_xn_hi);
    cudaGetSymbolAddress((void**)&p_xnl, g_xn_lo);
    cudaGetSymbolAddress((void**)&p_weh, g_we_hi);
    cudaGetSymbolAddress((void**)&p_wel, g_we_lo);
    cudaGetSymbolAddress((void**)&p_wch, g_wc_hi);
    cudaGetSymbolAddress((void**)&p_wcl, g_wc_lo);
    cudaGetSymbolAddress((void**)&p_hh,  g_h_hi);
    cudaGetSymbolAddress((void**)&p_hl,  g_h_lo);

    cudaFuncSetAttribute(gemm_grouped_kernel<0>, cudaFuncAttributeMaxDynamicSharedMemorySize, GSM);
    cudaFuncSetAttribute(gemm_grouped_kernel<1>, cudaFuncAttributeMaxDynamicSharedMemorySize, GSM);
    cudaFuncSetAttribute(flash_kernel,           cudaFuncAttributeMaxDynamicSharedMemorySize, FSM);

    // 0) expert permutation
    perm_init_kernel<<<1, 32>>>();
    perm_count_kernel<<<TOK / 256, 256>>>(em);
    perm_scan_kernel<<<1, 32>>>();
    perm_fill_kernel<<<TOK / 256, 256>>>(em);

    // 0b) weight splits
    split4_kernel<<<(EXPC * DIMC) / 4 / 256, 256>>>(wexp, p_weh, p_wel);
    split4_kernel<<<(2 * DIMC * CINC) / 4 / 256, 256>>>(wc, p_wch, p_wcl);

    // 1) LN1 + input mask
    ln1_kernel<<<TOK, 256>>>(x, em, n1g, n1b);

    // 2) expand (grouped, fused epilogue): q-pack / y fp32 (k,v) / gelu+h-pack
    gemm_grouped_kernel<1><<<dim3(EXPC / 128, TOK / 128, 4), 512, GSM>>>(
        p_xnh, p_xnl, DIMC, p_weh, p_wel, DIMC, nullptr, 0, mlpb,
        128, 1, EXPC, 0);

    // 3) LN2 -> k and v per-head hi/lo (no transpose pass)
    ln2kv_kernel<<<dim3(TOK, 2), 256>>>(n2g, n2b);

    // 4) flash attention -> h[:, 0:1024]
    flash_kernel<<<dim3(SEQC / 128, BH), 256, FSM>>>();

    // 5) contract (grouped): z = h @ Wc^T, N_e = 256<<e
    gemm_grouped_kernel<0><<<dim3(16, TOK / 128, 4), 512, GSM>>>(
        p_hh, p_hl, CINC, p_wch, p_wcl, CINC, p_z, 2 * DIMC, nullptr,
        CINC, 0, 256, 1);

    // 6) epilogue + tails (merged)
    final_kernel<<<(TOK * DIMC) / 256, 256>>>(x, em, rp, cb, alpha, out);
}

// round 10
// speedup vs baseline: 6.7656x; 1.2580x over previous
#include <cuda_runtime.h>
#include <cuda_bf16.h>
#include <cuda_fp16.h>
#include <math.h>
#include <stdint.h>

// Problem constants
#define TOK   8192        // B*N
#define DIMC  1024
#define EXPC  7168
#define CINC  5120
#define NHC   16
#define HDC   64
#define SEQC  1024
#define NB    8
#define BH    (NB * NHC)  // 128 batch-heads

#define LOG2E 1.44269504088896340736f

// ---------------------------------------------------------------------------
// Scratch (device globals; allocation-free)
// ---------------------------------------------------------------------------
__device__ float g_y [(size_t)TOK * 2 * DIMC];                //  67 MB (k,v fp32 pre-LN)
__device__ float g_z [(size_t)TOK * 2 * DIMC];                //  67 MB

__device__ __half g_xn[(size_t)TOK * DIMC];                   // fp16 single
__device__ __half g_we_hi[(size_t)EXPC * DIMC];
__device__ __half g_we_lo[(size_t)EXPC * DIMC];
__device__ __half g_wc_hi[(size_t)2 * DIMC * CINC];
__device__ __half g_wc_lo[(size_t)2 * DIMC * CINC];
__device__ __half g_h [(size_t)TOK * CINC];                   // fp16 single

// attention operands (per-head [bh][seq][hd] layouts; bf16 hi/lo, 3-product)
__device__ __nv_bfloat16 g_q_hi[(size_t)BH * SEQC * HDC];
__device__ __nv_bfloat16 g_q_lo[(size_t)BH * SEQC * HDC];
__device__ __nv_bfloat16 g_k_hi[(size_t)BH * SEQC * HDC];
__device__ __nv_bfloat16 g_k_lo[(size_t)BH * SEQC * HDC];
__device__ __nv_bfloat16 g_v_hi[(size_t)BH * SEQC * HDC];
__device__ __nv_bfloat16 g_v_lo[(size_t)BH * SEQC * HDC];

// expert grouping
__device__ int g_cnt[4];
__device__ int g_goff[4];
__device__ int g_perm[TOK];

// ---------------------------------------------------------------------------
// PTX helpers
// ---------------------------------------------------------------------------
__device__ __forceinline__ uint32_t smem_u32(const void* p) {
    uint32_t a;
    asm("{ .reg .u64 t; cvta.to.shared.u64 t, %1; cvt.u32.u64 %0, t; }" : "=r"(a) : "l"(p));
    return a;
}
__device__ __forceinline__ void ldsm4(uint32_t* r, uint32_t a) {
    asm volatile("ldmatrix.sync.aligned.m8n8.x4.shared.b16 {%0,%1,%2,%3}, [%4];"
                 : "=r"(r[0]), "=r"(r[1]), "=r"(r[2]), "=r"(r[3]) : "r"(a));
}
__device__ __forceinline__ void ldsm4t(uint32_t* r, uint32_t a) {
    asm volatile("ldmatrix.sync.aligned.m8n8.x4.trans.shared.b16 {%0,%1,%2,%3}, [%4];"
                 : "=r"(r[0]), "=r"(r[1]), "=r"(r[2]), "=r"(r[3]) : "r"(a));
}
__device__ __forceinline__ void mma16816(float* c, const uint32_t* a, const uint32_t* b) {
    asm volatile("mma.sync.aligned.m16n8k16.row.col.f32.bf16.bf16.f32 "
                 "{%0,%1,%2,%3}, {%4,%5,%6,%7}, {%8,%9}, {%0,%1,%2,%3};"
                 : "+f"(c[0]), "+f"(c[1]), "+f"(c[2]), "+f"(c[3])
                 : "r"(a[0]), "r"(a[1]), "r"(a[2]), "r"(a[3]), "r"(b[0]), "r"(b[1]));
}
__device__ __forceinline__ void mma16816h(float* c, const uint32_t* a, const uint32_t* b) {
    asm volatile("mma.sync.aligned.m16n8k16.row.col.f32.f16.f16.f32 "
                 "{%0,%1,%2,%3}, {%4,%5,%6,%7}, {%8,%9}, {%0,%1,%2,%3};"
                 : "+f"(c[0]), "+f"(c[1]), "+f"(c[2]), "+f"(c[3])
                 : "r"(a[0]), "r"(a[1]), "r"(a[2]), "r"(a[3]), "r"(b[0]), "r"(b[1]));
}
__device__ __forceinline__ void cpa16(uint32_t s, const void* g) {
    asm volatile("cp.async.cg.shared.global [%0], [%1], 16;" :: "r"(s), "l"(g));
}
#define CP_COMMIT() asm volatile("cp.async.commit_group;")
#define CP_WAIT2()  asm volatile("cp.async.wait_group 2;")
#define CP_WAIT1()  asm volatile("cp.async.wait_group 1;")
#define CP_WAIT0()  asm volatile("cp.async.wait_group 0;")

#define SWZ(o) ((o) ^ (((o) >> 3) & 0x70))

__device__ __forceinline__ void split1(float x, __nv_bfloat16& h, __nv_bfloat16& l) {
    h = __float2bfloat16(x);
    l = __float2bfloat16(x - __bfloat162float(h));
}
__device__ __forceinline__ void split1h(float x, __half& h, __half& l) {
    h = __float2half_rn(x);
    l = __float2half_rn(x - __half2float(h));
}
__device__ __forceinline__ uint32_t pack_bf2(__nv_bfloat16 a, __nv_bfloat16 b) {
    __nv_bfloat162 v(a, b);
    return *(uint32_t*)&v;
}
__device__ __forceinline__ uint32_t pack_h2(__half a, __half b) {
    __half2 v(a, b);
    return *(uint32_t*)&v;
}
__device__ __forceinline__ float gelu1(float x) {
    return 0.5f * x * (1.f + erff(x * 0.70710678118654752f));
}

// ---------------------------------------------------------------------------
// Expert-grouped fp16 2-product HMMA GEMM with row gather.
// A plain fp16; B = Bh + Bl (fp16 split). 512 thr, 4x4 warps, warp 32x32,
// CTA 128x128, K-chunk 64, 3-stage cp.async.
// MODE 0: plain fp32 scatter (contract).
// MODE 1: expand fused epilogue (q-pack bf16 / y fp32 / gelu h fp16).
// ---------------------------------------------------------------------------
#define GOA  0
#define GOBH 16384
#define GOBL 32768
#define GBUF 49152
#define GSM  (1024 + 3 * GBUF)    // 148480

template<int MODE>
__global__ void __launch_bounds__(512)
gemm_grouped_kernel(const __half* __restrict__ A, int lda,
                    const __half* __restrict__ Bh, const __half* __restrict__ Bl, int ldb,
                    float* __restrict__ C, int ldc,
                    const float* __restrict__ mlpb,
                    int Kbase, int Kscale, int Nbase, int Nscale) {
    const int e = blockIdx.z;
    const int cnt  = g_cnt[e];
    const int goff = g_goff[e];
    const int m0 = blockIdx.y * 128;
    if (m0 >= cnt) return;
    const int K    = Kscale ? (Kbase << e) : Kbase;
    const int Nlim = Nscale ? (Nbase << e) : Nbase;
    const int n0 = blockIdx.x * 128;
    if (n0 >= Nlim) return;

    extern __shared__ char smem_raw[];
    uint32_t sb0 = smem_u32(smem_raw);
    sb0 = (sb0 + 1023u) & ~1023u;
    int* tok = (int*)(smem_raw + (sb0 - smem_u32(smem_raw)));
    uint32_t sb = sb0 + 1024u;

    const int tid  = threadIdx.x;
    const int wid  = tid >> 5;
    const int lane = tid & 31;
    const int wm = wid & 3;
    const int wn = wid >> 2;

    if (tid < 128) {
        int gr = m0 + tid;
        tok[tid] = g_perm[goff + ((gr < cnt) ? gr : 0)];
    }
    __syncthreads();

    const __half* BBh = Bh + (size_t)n0 * ldb;
    const __half* BBl = Bl + (size_t)n0 * ldb;

    const int NC = K / 64;

    auto load_chunk = [&](int c) {
        uint32_t bufb = sb + (uint32_t)(c % 3) * GBUF;
        int k0 = c * 64;
#pragma unroll
        for (int it = 0; it < 2; it++) {
            int i = tid + it * 512;              // 0..1023
            int r = i >> 3, kg = i & 7;
            const __half* src = A + (size_t)tok[r] * lda + k0 + kg * 8;
            cpa16(bufb + GOA + SWZ(r * 128 + kg * 16), src);
        }
#pragma unroll
        for (int it = 0; it < 4; it++) {
            int i = tid + it * 512;              // 0..2047
            int r = i >> 4, rem = i & 15, hl = rem >> 3, kg = rem & 7;
            const __half* src = (hl ? BBl : BBh) + (size_t)r * ldb + k0 + kg * 8;
            cpa16(bufb + (hl ? GOBL : GOBH) + SWZ(r * 128 + kg * 16), src);
        }
        CP_COMMIT();
    };

    load_chunk(0);
    if (NC > 1) load_chunk(1);

    float acc[2][4][4];
#pragma unroll
    for (int i = 0; i < 2; i++)
#pragma unroll
        for (int j = 0; j < 4; j++)
#pragma unroll
            for (int k = 0; k < 4; k++) acc[i][j][k] = 0.f;

    const int a_r16 = lane & 15;
    const int a_kb  = (lane >> 4) * 16;
    const int b_r8  = ((lane >> 4) << 3) + (lane & 7);
    const int b_kb  = ((lane >> 3) & 1) * 16;

    for (int c = 0; c < NC; c++) {
        if (c + 2 < NC) load_chunk(c + 2);
        int pend = NC - 1 - c; if (pend > 2) pend = 2;
        if (pend == 2) CP_WAIT2(); else if (pend == 1) CP_WAIT1(); else CP_WAIT0();
        __syncthreads();

        uint32_t bufb = sb + (uint32_t)(c % 3) * GBUF;
#pragma unroll
        for (int kk = 0; kk < 4; kk++) {
            int kb = kk * 32;
            uint32_t ah[2][4];
#pragma unroll
            for (int mt = 0; mt < 2; mt++) {
                int r = wm * 32 + mt * 16 + a_r16;
                uint32_t off = (uint32_t)(r * 128) + (uint32_t)((kb + a_kb) ^ ((r & 7) << 4));
                ldsm4(ah[mt], bufb + GOA + off);
            }
#pragma unroll
            for (int ntp = 0; ntp < 2; ntp++) {
                int r = wn * 32 + ntp * 16 + b_r8;
                uint32_t off = (uint32_t)(r * 128) + (uint32_t)((kb + b_kb) ^ ((r & 7) << 4));
                uint32_t bh[4], bl[4];
                ldsm4(bh, bufb + GOBH + off);
                ldsm4(bl, bufb + GOBL + off);
#pragma unroll
                for (int mt = 0; mt < 2; mt++) {
                    mma16816h(acc[mt][2 * ntp],     ah[mt], bh);
                    mma16816h(acc[mt][2 * ntp],     ah[mt], bl);
                    mma16816h(acc[mt][2 * ntp + 1], ah[mt], bh + 2);
                    mma16816h(acc[mt][2 * ntp + 1], ah[mt], bl + 2);
                }
            }
        }
        __syncthreads();
    }

    const int g = lane >> 2, t4 = lane & 3;

    if (MODE == 0) {
#pragma unroll
        for (int mt = 0; mt < 2; mt++) {
            int r0 = wm * 32 + mt * 16 + g;
            int r1 = r0 + 8;
            int tk0 = tok[r0], tk1 = tok[r1];
            bool ok0 = (m0 + r0) < cnt, ok1 = (m0 + r1) < cnt;
#pragma unroll
            for (int nt = 0; nt < 4; nt++) {
                int ncol = n0 + wn * 32 + nt * 8 + t4 * 2;
                if (ok0) *(float2*)(C + (size_t)tk0 * ldc + ncol) = make_float2(acc[mt][nt][0], acc[mt][nt][1]);
                if (ok1) *(float2*)(C + (size_t)tk1 * ldc + ncol) = make_float2(acc[mt][nt][2], acc[mt][nt][3]);
            }
        }
    } else {
#pragma unroll
        for (int mt = 0; mt < 2; mt++) {
            int r0 = wm * 32 + mt * 16 + g;
            int r1 = r0 + 8;
            int tk0 = tok[r0], tk1 = tok[r1];
            bool ok0 = (m0 + r0) < cnt, ok1 = (m0 + r1) < cnt;
            if (n0 < 1024) {
                // Q region: scale (1/8)*log2e, split bf16 hi/lo, per-head layout
#pragma unroll
                for (int nt = 0; nt < 4; nt++) {
                    int d = n0 + wn * 32 + nt * 8 + t4 * 2;
                    int h = d >> 6, hd = d & 63;
                    const float QS = 0.125f * LOG2E;
                    __nv_bfloat16 h0, l0, h1, l1;
                    if (ok0) {
                        size_t o = ((size_t)((tk0 >> 10) * NHC + h) * SEQC + (tk0 & 1023)) * HDC + hd;
                        split1(acc[mt][nt][0] * QS, h0, l0);
                        split1(acc[mt][nt][1] * QS, h1, l1);
                        *(uint32_t*)(g_q_hi + o) = pack_bf2(h0, h1);
                        *(uint32_t*)(g_q_lo + o) = pack_bf2(l0, l1);
                    }
                    if (ok1) {
                        size_t o = ((size_t)((tk1 >> 10) * NHC + h) * SEQC + (tk1 & 1023)) * HDC + hd;
                        split1(acc[mt][nt][2] * QS, h0, l0);
                        split1(acc[mt][nt][3] * QS, h1, l1);
                        *(uint32_t*)(g_q_hi + o) = pack_bf2(h0, h1);
                        *(uint32_t*)(g_q_lo + o) = pack_bf2(l0, l1);
                    }
                }
            } else if (n0 < 3072) {
                // K/V region: fp32 to g_y [TOK][2048]
#pragma unroll
                for (int nt = 0; nt < 4; nt++) {
                    int col = n0 - 1024 + wn * 32 + nt * 8 + t4 * 2;
                    if (ok0) *(float2*)(g_y + (size_t)tk0 * 2048 + col) = make_float2(acc[mt][nt][0], acc[mt][nt][1]);
                    if (ok1) *(float2*)(g_y + (size_t)tk1 * 2048 + col) = make_float2(acc[mt][nt][2], acc[mt][nt][3]);
                }
            } else {
                // MLP region: +bias, GELU -> g_h fp16 [:, 1024+j]
#pragma unroll
                for (int nt = 0; nt < 4; nt++) {
                    int j = n0 - 3072 + wn * 32 + nt * 8 + t4 * 2;
                    float b0 = mlpb[j], b1 = mlpb[j + 1];
                    if (ok0) {
                        __half u0 = __float2half_rn(gelu1(acc[mt][nt][0] + b0));
                        __half u1 = __float2half_rn(gelu1(acc[mt][nt][1] + b1));
                        *(uint32_t*)(g_h + (size_t)tk0 * CINC + 1024 + j) = pack_h2(u0, u1);
                    }
                    if (ok1) {
                        __half u0 = __float2half_rn(gelu1(acc[mt][nt][2] + b0));
                        __half u1 = __float2half_rn(gelu1(acc[mt][nt][3] + b1));
                        *(uint32_t*)(g_h + (size_t)tk1 * CINC + 1024 + j) = pack_h2(u0, u1);
                    }
                }
            }
        }
    }
}

// ---------------------------------------------------------------------------
// Flash attention (bf16 3-product; V row-major via ldmatrix.trans).
// Output written as fp16 single into g_h[:, 0:1024].
// ---------------------------------------------------------------------------
#define FQH 0
#define FQL 16384
#define FST 32768
#define FSS 32768
#define FSM (32768 + 2 * 32768 + 1024)

__global__ void __launch_bounds__(256)
flash_kernel() {
    extern __shared__ char smem_raw[];
    uint32_t sb = smem_u32(smem_raw);
    sb = (sb + 1023u) & ~1023u;

    const int tid  = threadIdx.x;
    const int wid  = tid >> 5;
    const int lane = tid & 31;
    const int bh = blockIdx.y;
    const int q0 = blockIdx.x * 128;
    const int b = bh >> 4, h = bh & 15;

    const size_t base = (size_t)bh * SEQC * HDC;

    auto load_q = [&]() {
#pragma unroll
        for (int it = 0; it < 8; it++) {
            int i = tid + it * 256;
            int r = i >> 4, rem = i & 15, hl = rem >> 3, kg = rem & 7;
            const __nv_bfloat16* src = (hl ? g_q_lo : g_q_hi) + base + (size_t)(q0 + r) * HDC + kg * 8;
            cpa16(sb + (hl ? FQL : FQH) + SWZ(r * 128 + kg * 16), src);
        }
    };
    auto load_kv = [&](int t) {
        uint32_t bufb = sb + FST + (uint32_t)(t & 1) * FSS;
#pragma unroll
        for (int it = 0; it < 4; it++) {
            int i = tid + it * 256;
            int r = i >> 4, rem = i & 15, hl = rem >> 3, kg = rem & 7;
            const __nv_bfloat16* src = (hl ? g_k_lo : g_k_hi) + base + (size_t)(t * 64 + r) * HDC + kg * 8;
            cpa16(bufb + (hl ? 8192 : 0) + SWZ(r * 128 + kg * 16), src);
        }
#pragma unroll
        for (int it = 0; it < 4; it++) {
            int i = tid + it * 256;
            int r = i >> 4, rem = i & 15, hl = rem >> 3, kg = rem & 7;
            const __nv_bfloat16* src = (hl ? g_v_lo : g_v_hi) + base + (size_t)(t * 64 + r) * HDC + kg * 8;
            cpa16(bufb + 16384 + (hl ? 8192 : 0) + SWZ(r * 128 + kg * 16), src);
        }
        CP_COMMIT();
    };

    load_q(); load_kv(0); CP_COMMIT();
    load_kv(1);

    const int a_r16 = lane & 15;
    const int a_kb  = (lane >> 4) * 16;
    const int b_r8  = ((lane >> 4) << 3) + (lane & 7);
    const int b_kb  = ((lane >> 3) & 1) * 16;
    const int v_r  = ((lane >> 3) & 1) * 8 + (lane & 7);
    const int v_cb = (lane >> 4) * 16;

    uint32_t qhf[4][4], qlf[4][4];
    float o[8][4];
#pragma unroll
    for (int j = 0; j < 8; j++)
#pragma unroll
        for (int k = 0; k < 4; k++) o[j][k] = 0.f;
    float ml0 = -1e30f, ml1 = -1e30f, ls0 = 0.f, ls1 = 0.f;

    for (int t = 0; t < 16; t++) {
        if (t < 15) CP_WAIT1(); else CP_WAIT0();
        __syncthreads();
        if (t == 0) {
#pragma unroll
            for (int kk = 0; kk < 4; kk++) {
                int r = wid * 16 + a_r16;
                uint32_t off = (uint32_t)(r * 128) + (uint32_t)((kk * 32 + a_kb) ^ ((r & 7) << 4));
                ldsm4(qhf[kk], sb + FQH + off);
                ldsm4(qlf[kk], sb + FQL + off);
            }
        }
        uint32_t bufb = sb + FST + (uint32_t)(t & 1) * FSS;

        float s[8][4];
#pragma unroll
        for (int j = 0; j < 8; j++)
#pragma unroll
            for (int k = 0; k < 4; k++) s[j][k] = 0.f;
#pragma unroll
        for (int kk = 0; kk < 4; kk++) {
#pragma unroll
            for (int ntp = 0; ntp < 4; ntp++) {
                int r = ntp * 16 + b_r8;
                uint32_t off = (uint32_t)(r * 128) + (uint32_t)((kk * 32 + b_kb) ^ ((r & 7) << 4));
                uint32_t khf[4], klf[4];
                ldsm4(khf, bufb + off);
                ldsm4(klf, bufb + 8192 + off);
                mma16816(s[2 * ntp],     qhf[kk], khf);
                mma16816(s[2 * ntp],     qhf[kk], klf);
                mma16816(s[2 * ntp],     qlf[kk], khf);
                mma16816(s[2 * ntp + 1], qhf[kk], khf + 2);
                mma16816(s[2 * ntp + 1], qhf[kk], klf + 2);
                mma16816(s[2 * ntp + 1], qlf[kk], khf + 2);
            }
        }

        float m0t = -1e30f, m1t = -1e30f;
#pragma unroll
        for (int j = 0; j < 8; j++) {
            m0t = fmaxf(m0t, fmaxf(s[j][0], s[j][1]));
            m1t = fmaxf(m1t, fmaxf(s[j][2], s[j][3]));
        }
        m0t = fmaxf(m0t, __shfl_xor_sync(0xffffffffu, m0t, 1));
        m0t = fmaxf(m0t, __shfl_xor_sync(0xffffffffu, m0t, 2));
        m1t = fmaxf(m1t, __shfl_xor_sync(0xffffffffu, m1t, 1));
        m1t = fmaxf(m1t, __shfl_xor_sync(0xffffffffu, m1t, 2));
        float mn0 = fmaxf(ml0, m0t), mn1 = fmaxf(ml1, m1t);
        float sc0 = exp2f(ml0 - mn0), sc1 = exp2f(ml1 - mn1);
        ml0 = mn0; ml1 = mn1;
        float r0 = 0.f, r1 = 0.f;
#pragma unroll
        for (int j = 0; j < 8; j++) {
            s[j][0] = exp2f(s[j][0] - mn0);
            s[j][1] = exp2f(s[j][1] - mn0);
            s[j][2] = exp2f(s[j][2] - mn1);
            s[j][3] = exp2f(s[j][3] - mn1);
            r0 += s[j][0] + s[j][1];
            r1 += s[j][2] + s[j][3];
        }
        r0 += __shfl_xor_sync(0xffffffffu, r0, 1);
        r0 += __shfl_xor_sync(0xffffffffu, r0, 2);
        r1 += __shfl_xor_sync(0xffffffffu, r1, 1);
        r1 += __shfl_xor_sync(0xffffffffu, r1, 2);
        ls0 = ls0 * sc0 + r0;
        ls1 = ls1 * sc1 + r1;
#pragma unroll
        for (int j = 0; j < 8; j++) {
            o[j][0] *= sc0; o[j][1] *= sc0;
            o[j][2] *= sc1; o[j][3] *= sc1;
        }

        uint32_t pah[4][4], pal[4][4];
#pragma unroll
        for (int kt = 0; kt < 4; kt++) {
            __nv_bfloat16 h0, l0, h1, l1;
            split1(s[2 * kt][0], h0, l0); split1(s[2 * kt][1], h1, l1);
            pah[kt][0] = pack_bf2(h0, h1); pal[kt][0] = pack_bf2(l0, l1);
            split1(s[2 * kt][2], h0, l0); split1(s[2 * kt][3], h1, l1);
            pah[kt][1] = pack_bf2(h0, h1); pal[kt][1] = pack_bf2(l0, l1);
            split1(s[2 * kt + 1][0], h0, l0); split1(s[2 * kt + 1][1], h1, l1);
            pah[kt][2] = pack_bf2(h0, h1); pal[kt][2] = pack_bf2(l0, l1);
            split1(s[2 * kt + 1][2], h0, l0); split1(s[2 * kt + 1][3], h1, l1);
            pah[kt][3] = pack_bf2(h0, h1); pal[kt][3] = pack_bf2(l0, l1);
        }

#pragma unroll
        for (int kt = 0; kt < 4; kt++) {
#pragma unroll
            for (int nv = 0; nv < 4; nv++) {
                int r = kt * 16 + v_r;
                uint32_t off = (uint32_t)(r * 128) + (uint32_t)((nv * 32 + v_cb) ^ ((r & 7) << 4));
                uint32_t vhf[4], vlf[4];
                ldsm4t(vhf, bufb + 16384 + off);
                ldsm4t(vlf, bufb + 24576 + off);
                mma16816(o[2 * nv],     pah[kt], vhf);
                mma16816(o[2 * nv],     pah[kt], vlf);
                mma16816(o[2 * nv],     pal[kt], vhf);
                mma16816(o[2 * nv + 1], pah[kt], vhf + 2);
                mma16816(o[2 * nv + 1], pah[kt], vlf + 2);
                mma16816(o[2 * nv + 1], pal[kt], vhf + 2);
            }
        }
        __syncthreads();
        if (t + 2 < 16) load_kv(t + 2);
    }

    const int g = lane >> 2, t4 = lane & 3;
    float i0 = 1.f / ls0, i1 = 1.f / ls1;
    int tok0 = b * 1024 + q0 + wid * 16 + g;
    int tok1 = tok0 + 8;
#pragma unroll
    for (int j = 0; j < 8; j++) {
        int col = h * 64 + j * 8 + t4 * 2;
        __half u0 = __float2half_rn(o[j][0] * i0);
        __half u1 = __float2half_rn(o[j][1] * i0);
        *(uint32_t*)(g_h + (size_t)tok0 * CINC + col) = pack_h2(u0, u1);
        u0 = __float2half_rn(o[j][2] * i1);
        u1 = __float2half_rn(o[j][3] * i1);
        *(uint32_t*)(g_h + (size_t)tok1 * CINC + col) = pack_h2(u0, u1);
    }
}

// ---------------------------------------------------------------------------
// Expert permutation: single CTA (count + scan + fill)
// ---------------------------------------------------------------------------
__global__ void __launch_bounds__(1024) perm_kernel(const int* __restrict__ em) {
    __shared__ int cnt[4], off[4], cur[4];
    int tid = threadIdx.x;
    if (tid < 4) { cnt[tid] = 0; cur[tid] = 0; }
    __syncthreads();
    int ev[8];
#pragma unroll
    for (int i = 0; i < 8; i++) {
        ev[i] = em[tid + i * 1024];
        atomicAdd(&cnt[ev[i]], 1);
    }
    __syncthreads();
    if (tid == 0) {
        int o = 0;
        for (int j = 0; j < 4; j++) { off[j] = o; g_goff[j] = o; g_cnt[j] = cnt[j]; o += cnt[j]; }
    }
    __syncthreads();
#pragma unroll
    for (int i = 0; i < 8; i++) {
        int p = atomicAdd(&cur[ev[i]], 1);
        g_perm[off[ev[i]] + p] = tid + i * 1024;
    }
}

// ---------------------------------------------------------------------------
// weight split (fp32 -> fp16 hi/lo)
// ---------------------------------------------------------------------------
__global__ void splitw_kernel(const float* __restrict__ s,
                              __half* __restrict__ hi, __half* __restrict__ lo) {
    size_t i = (size_t)blockIdx.x * 256 + threadIdx.x;
    float4 v = ((const float4*)s)[i];
    __half h0, h1, h2, h3, l0, l1, l2, l3;
    split1h(v.x, h0, l0); split1h(v.y, h1, l1); split1h(v.z, h2, l2); split1h(v.w, h3, l3);
    ((uint32_t*)hi)[2 * i]     = pack_h2(h0, h1);
    ((uint32_t*)hi)[2 * i + 1] = pack_h2(h2, h3);
    ((uint32_t*)lo)[2 * i]     = pack_h2(l0, l1);
    ((uint32_t*)lo)[2 * i + 1] = pack_h2(l2, l3);
}

// ---------------------------------------------------------------------------
// LN1 -> masked xn fp16 single
// ---------------------------------------------------------------------------
__global__ void ln1_kernel(const float* __restrict__ x, const int* __restrict__ em,
                           const float* __restrict__ g, const float* __restrict__ b) {
    int t = blockIdx.x;
    const float4* xr = (const float4*)(x + (size_t)t * DIMC);
    int tid = threadIdx.x;
    float4 v = xr[tid];
    float s  = v.x + v.y + v.z + v.w;
    float s2 = v.x * v.x + v.y * v.y + v.z * v.z + v.w * v.w;
#pragma unroll
    for (int o = 16; o; o >>= 1) { s += __shfl_xor_sync(0xffffffffu, s, o); s2 += __shfl_xor_sync(0xffffffffu, s2, o); }
    __shared__ float red[18];
    int w = tid >> 5, l = tid & 31;
    if (l == 0) { red[w] = s; red[8 + w] = s2; }
    __syncthreads();
    if (tid == 0) {
        float ts = 0.f, ts2 = 0.f;
        for (int i = 0; i < 8; i++) { ts += red[i]; ts2 += red[8 + i]; }
        float m = ts * (1.f / DIMC);
        float var = ts2 * (1.f / DIMC) - m * m;
        red[16] = m; red[17] = rsqrtf(var + 1e-5f);
    }
    __syncthreads();
    float m = red[16], rs = red[17];
    int din = DIMC >> (3 - em[t]);
    int c = tid * 4;
    float4 gg = ((const float4*)g)[tid];
    float4 bb = ((const float4*)b)[tid];
    float o0 = (c + 0 < din) ? ((v.x - m) * rs * gg.x + bb.x) : 0.f;
    float o1 = (c + 1 < din) ? ((v.y - m) * rs * gg.y + bb.y) : 0.f;
    float o2 = (c + 2 < din) ? ((v.z - m) * rs * gg.z + bb.z) : 0.f;
    float o3 = (c + 3 < din) ? ((v.w - m) * rs * gg.w + bb.w) : 0.f;
    size_t o = (size_t)t * DIMC + c;
    *(uint32_t*)(g_xn + o)     = pack_h2(__float2half_rn(o0), __float2half_rn(o1));
    *(uint32_t*)(g_xn + o + 2) = pack_h2(__float2half_rn(o2), __float2half_rn(o3));
}

// LN2: which==0 -> k, which==1 -> v. Both write per-head bf16 hi/lo.
__global__ void ln2kv_kernel(const float* __restrict__ g, const float* __restrict__ b) {
    int t = blockIdx.x;
    int which = blockIdx.y;
    const float4* row = (const float4*)(g_y + (size_t)t * 2048 + (size_t)DIMC * which);
    int tid = threadIdx.x;
    float4 v = row[tid];
    float s  = v.x + v.y + v.z + v.w;
    float s2 = v.x * v.x + v.y * v.y + v.z * v.z + v.w * v.w;
#pragma unroll
    for (int o = 16; o; o >>= 1) { s += __shfl_xor_sync(0xffffffffu, s, o); s2 += __shfl_xor_sync(0xffffffffu, s2, o); }
    __shared__ float red[18];
    int w = tid >> 5, l = tid & 31;
    if (l == 0) { red[w] = s; red[8 + w] = s2; }
    __syncthreads();
    if (tid == 0) {
        float ts = 0.f, ts2 = 0.f;
        for (int i = 0; i < 8; i++) { ts += red[i]; ts2 += red[8 + i]; }
        float m = ts * (1.f / DIMC);
        float var = ts2 * (1.f / DIMC) - m * m;
        red[16] = m; red[17] = rsqrtf(var + 1e-5f);
    }
    __syncthreads();
    float m = red[16], rs = red[17];
    int bb2 = t >> 10, ss = t & 1023;
    int c = tid * 4;
    float4 gg = ((const float4*)g)[tid];
    float4 bv = ((const float4*)b)[tid];
    float o0 = (v.x - m) * rs * gg.x + bv.x;
    float o1 = (v.y - m) * rs * gg.y + bv.y;
    float o2 = (v.z - m) * rs * gg.z + bv.z;
    float o3 = (v.w - m) * rs * gg.w + bv.w;
    __nv_bfloat16 h0, l0, h1, l1, h2, l2, h3, l3;
    split1(o0, h0, l0); split1(o1, h1, l1); split1(o2, h2, l2); split1(o3, h3, l3);
    int hh = c >> 6, hd = c & 63;
    size_t o = ((size_t)(bb2 * NHC + hh) * SEQC + ss) * HDC + hd;
    __nv_bfloat16* dh = which ? g_v_hi : g_k_hi;
    __nv_bfloat16* dl = which ? g_v_lo : g_k_lo;
    *(uint32_t*)(dh + o)     = pack_bf2(h0, h1);
    *(uint32_t*)(dh + o + 2) = pack_bf2(h2, h3);
    *(uint32_t*)(dl + o)     = pack_bf2(l0, l1);
    *(uint32_t*)(dl + o + 2) = pack_bf2(l2, l3);
}

// Final epilogue + pass-through tails (merged)
__global__ void final_kernel(const float* __restrict__ x, const int* __restrict__ em,
                             const float* __restrict__ rp, const float* __restrict__ cb,
                             const float* __restrict__ alpha, float* __restrict__ out) {
    size_t idx = (size_t)blockIdx.x * 256 + threadIdx.x;
    int t = (int)(idx >> 10);
    int d = (int)(idx & 1023);
    int m = em[t];
    int dout = (2 * DIMC) >> (3 - m);
    const float* zr = g_z + (size_t)t * 2 * DIMC;
    float za = (d < dout) ? (zr[d] + cb[d]) : 0.f;
    float zm = (DIMC + d < dout) ? (zr[DIMC + d] + cb[DIMC + d]) : 0.f;
    float pr = rp[t * 4 + m];
    out[idx] = x[idx] + za + (alpha[0] * pr + 1.f) * zm;
    if (idx < TOK)     out[(size_t)TOK * DIMC + idx] = (float)em[idx];
    if (idx < TOK * 4) out[(size_t)TOK * DIMC + TOK + idx] = rp[idx];
}

// ---------------------------------------------------------------------------
extern "C" void kernel_launch(void* const* d_in, const int* in_sizes, int n_in,
                              void* d_out, int out_size) {
    const float* x     = (const float*)d_in[0];
    const int*   em    = (const int*)d_in[1];
    const float* rp    = (const float*)d_in[2];
    const float* wexp  = (const float*)d_in[3];
    const float* mlpb  = (const float*)d_in[4];
    const float* wc    = (const float*)d_in[5];
    const float* cb    = (const float*)d_in[6];
    const float* n1g   = (const float*)d_in[7];
    const float* n1b   = (const float*)d_in[8];
    const float* n2g   = (const float*)d_in[9];
    const float* n2b   = (const float*)d_in[10];
    const float* alpha = (const float*)d_in[11];
    float* out = (float*)d_out;

    float *p_z;
    __half *p_xn, *p_weh, *p_wel, *p_wch, *p_wcl, *p_h;
    cudaGetSymbolAddress((void**)&p_z,   g_z);
    cudaGetSymbolAddress((void**)&p_xn,  g_xn);
    cudaGetSymbolAddress((void**)&p_weh, g_we_hi);
    cudaGetSymbolAddress((void**)&p_wel, g_we_lo);
    cudaGetSymbolAddress((void**)&p_wch, g_wc_hi);
    cudaGetSymbolAddress((void**)&p_wcl, g_wc_lo);
    cudaGetSymbolAddress((void**)&p_h,   g_h);

    cudaFuncSetAttribute(gemm_grouped_kernel<0>, cudaFuncAttributeMaxDynamicSharedMemorySize, GSM);
    cudaFuncSetAttribute(gemm_grouped_kernel<1>, cudaFuncAttributeMaxDynamicSharedMemorySize, GSM);
    cudaFuncSetAttribute(flash_kernel,           cudaFuncAttributeMaxDynamicSharedMemorySize, FSM);

    // 0) expert permutation (single CTA)
    perm_kernel<<<1, 1024>>>(em);

    // 0b) weight splits (fp32 -> fp16 hi/lo)
    splitw_kernel<<<(EXPC * DIMC) / 4 / 256, 256>>>(wexp, p_weh, p_wel);
    splitw_kernel<<<(2 * DIMC * CINC) / 4 / 256, 256>>>(wc, p_wch, p_wcl);

    // 1) LN1 + input mask -> xn fp16
    ln1_kernel<<<TOK, 256>>>(x, em, n1g, n1b);

    // 2) expand (grouped, fp16 2-product, fused epilogue)
    gemm_grouped_kernel<1><<<dim3(EXPC / 128, TOK / 128, 4), 512, GSM>>>(
        p_xn, DIMC, p_weh, p_wel, DIMC, nullptr, 0, mlpb,
        128, 1, EXPC, 0);

    // 3) LN2 -> k and v per-head bf16 hi/lo
    ln2kv_kernel<<<dim3(TOK, 2), 256>>>(n2g, n2b);

    // 4) flash attention -> g_h fp16 [:, 0:1024]
    flash_kernel<<<dim3(SEQC / 128, BH), 256, FSM>>>();

    // 5) contract (grouped, fp16 2-product): z = h @ Wc^T, N_e = 256<<e
    gemm_grouped_kernel<0><<<dim3(16, TOK / 128, 4), 512, GSM>>>(
        p_h, CINC, p_wch, p_wcl, CINC, p_z, 2 * DIMC, nullptr,
        CINC, 0, 256, 1);

    // 6) epilogue + tails (merged)
    final_kernel<<<(TOK * DIMC) / 256, 256>>>(x, em, rp, cb, alpha, out);
}

// round 11
// speedup vs baseline: 7.1114x; 1.0511x over previous
#include <cuda_runtime.h>
#include <cuda_bf16.h>
#include <cuda_fp16.h>
#include <math.h>
#include <stdint.h>

// Problem constants
#define TOK   8192        // B*N
#define DIMC  1024
#define EXPC  7168
#define CINC  5120
#define NHC   16
#define HDC   64
#define SEQC  1024
#define NB    8
#define BH    (NB * NHC)  // 128 batch-heads

#define LOG2E 1.44269504088896340736f

// ---------------------------------------------------------------------------
// Scratch (device globals; allocation-free)
// ---------------------------------------------------------------------------
__device__ float g_y [(size_t)TOK * 2 * DIMC];                //  67 MB (k,v fp32 pre-LN)
__device__ float g_z [(size_t)TOK * 2 * DIMC];                //  67 MB

__device__ __half g_xn[(size_t)TOK * DIMC];                   // fp16 single
__device__ __half g_we_hi[(size_t)EXPC * DIMC];
__device__ __half g_we_lo[(size_t)EXPC * DIMC];
__device__ __half g_wc_hi[(size_t)2 * DIMC * CINC];
__device__ __half g_wc_lo[(size_t)2 * DIMC * CINC];
__device__ __half g_h [(size_t)TOK * CINC];                   // fp16 single

// attention operands (per-head [bh][seq][hd]; Q hi/lo fp16, K/V single fp16)
__device__ __half g_q_hi[(size_t)BH * SEQC * HDC];
__device__ __half g_q_lo[(size_t)BH * SEQC * HDC];
__device__ __half g_k   [(size_t)BH * SEQC * HDC];
__device__ __half g_v   [(size_t)BH * SEQC * HDC];

// expert grouping
__device__ int g_cnt[4];
__device__ int g_goff[4];
__device__ int g_perm[TOK];

// ---------------------------------------------------------------------------
// PTX helpers
// ---------------------------------------------------------------------------
__device__ __forceinline__ uint32_t smem_u32(const void* p) {
    uint32_t a;
    asm("{ .reg .u64 t; cvta.to.shared.u64 t, %1; cvt.u32.u64 %0, t; }" : "=r"(a) : "l"(p));
    return a;
}
__device__ __forceinline__ void ldsm4(uint32_t* r, uint32_t a) {
    asm volatile("ldmatrix.sync.aligned.m8n8.x4.shared.b16 {%0,%1,%2,%3}, [%4];"
                 : "=r"(r[0]), "=r"(r[1]), "=r"(r[2]), "=r"(r[3]) : "r"(a));
}
__device__ __forceinline__ void ldsm4t(uint32_t* r, uint32_t a) {
    asm volatile("ldmatrix.sync.aligned.m8n8.x4.trans.shared.b16 {%0,%1,%2,%3}, [%4];"
                 : "=r"(r[0]), "=r"(r[1]), "=r"(r[2]), "=r"(r[3]) : "r"(a));
}
__device__ __forceinline__ void mma16816h(float* c, const uint32_t* a, const uint32_t* b) {
    asm volatile("mma.sync.aligned.m16n8k16.row.col.f32.f16.f16.f32 "
                 "{%0,%1,%2,%3}, {%4,%5,%6,%7}, {%8,%9}, {%0,%1,%2,%3};"
                 : "+f"(c[0]), "+f"(c[1]), "+f"(c[2]), "+f"(c[3])
                 : "r"(a[0]), "r"(a[1]), "r"(a[2]), "r"(a[3]), "r"(b[0]), "r"(b[1]));
}
__device__ __forceinline__ void cpa16(uint32_t s, const void* g) {
    asm volatile("cp.async.cg.shared.global [%0], [%1], 16;" :: "r"(s), "l"(g));
}
#define CP_COMMIT() asm volatile("cp.async.commit_group;")
#define CP_WAIT2()  asm volatile("cp.async.wait_group 2;")
#define CP_WAIT1()  asm volatile("cp.async.wait_group 1;")
#define CP_WAIT0()  asm volatile("cp.async.wait_group 0;")

#define SWZ(o) ((o) ^ (((o) >> 3) & 0x70))

__device__ __forceinline__ void split1h(float x, __half& h, __half& l) {
    h = __float2half_rn(x);
    l = __float2half_rn(x - __half2float(h));
}
__device__ __forceinline__ uint32_t pack_h2(__half a, __half b) {
    __half2 v(a, b);
    return *(uint32_t*)&v;
}
__device__ __forceinline__ float gelu1(float x) {
    return 0.5f * x * (1.f + erff(x * 0.70710678118654752f));
}

// ---------------------------------------------------------------------------
// Expert-grouped fp16 2-product HMMA GEMM with row gather.
// ---------------------------------------------------------------------------
#define GOA  0
#define GOBH 16384
#define GOBL 32768
#define GBUF 49152
#define GSM  (1024 + 3 * GBUF)    // 148480

template<int MODE>
__global__ void __launch_bounds__(512)
gemm_grouped_kernel(const __half* __restrict__ A, int lda,
                    const __half* __restrict__ Bh, const __half* __restrict__ Bl, int ldb,
                    float* __restrict__ C, int ldc,
                    const float* __restrict__ mlpb,
                    int Kbase, int Kscale, int Nbase, int Nscale) {
    const int e = blockIdx.z;
    const int cnt  = g_cnt[e];
    const int goff = g_goff[e];
    const int m0 = blockIdx.y * 128;
    if (m0 >= cnt) return;
    const int K    = Kscale ? (Kbase << e) : Kbase;
    const int Nlim = Nscale ? (Nbase << e) : Nbase;
    const int n0 = blockIdx.x * 128;
    if (n0 >= Nlim) return;

    extern __shared__ char smem_raw[];
    uint32_t sb0 = smem_u32(smem_raw);
    sb0 = (sb0 + 1023u) & ~1023u;
    int* tok = (int*)(smem_raw + (sb0 - smem_u32(smem_raw)));
    uint32_t sb = sb0 + 1024u;

    const int tid  = threadIdx.x;
    const int wid  = tid >> 5;
    const int lane = tid & 31;
    const int wm = wid & 3;
    const int wn = wid >> 2;

    if (tid < 128) {
        int gr = m0 + tid;
        tok[tid] = g_perm[goff + ((gr < cnt) ? gr : 0)];
    }
    __syncthreads();

    const __half* BBh = Bh + (size_t)n0 * ldb;
    const __half* BBl = Bl + (size_t)n0 * ldb;

    const int NC = K / 64;

    auto load_chunk = [&](int c) {
        uint32_t bufb = sb + (uint32_t)(c % 3) * GBUF;
        int k0 = c * 64;
#pragma unroll
        for (int it = 0; it < 2; it++) {
            int i = tid + it * 512;
            int r = i >> 3, kg = i & 7;
            const __half* src = A + (size_t)tok[r] * lda + k0 + kg * 8;
            cpa16(bufb + GOA + SWZ(r * 128 + kg * 16), src);
        }
#pragma unroll
        for (int it = 0; it < 4; it++) {
            int i = tid + it * 512;
            int r = i >> 4, rem = i & 15, hl = rem >> 3, kg = rem & 7;
            const __half* src = (hl ? BBl : BBh) + (size_t)r * ldb + k0 + kg * 8;
            cpa16(bufb + (hl ? GOBL : GOBH) + SWZ(r * 128 + kg * 16), src);
        }
        CP_COMMIT();
    };

    load_chunk(0);
    if (NC > 1) load_chunk(1);

    float acc[2][4][4];
#pragma unroll
    for (int i = 0; i < 2; i++)
#pragma unroll
        for (int j = 0; j < 4; j++)
#pragma unroll
            for (int k = 0; k < 4; k++) acc[i][j][k] = 0.f;

    const int a_r16 = lane & 15;
    const int a_kb  = (lane >> 4) * 16;
    const int b_r8  = ((lane >> 4) << 3) + (lane & 7);
    const int b_kb  = ((lane >> 3) & 1) * 16;

    for (int c = 0; c < NC; c++) {
        if (c + 2 < NC) load_chunk(c + 2);
        int pend = NC - 1 - c; if (pend > 2) pend = 2;
        if (pend == 2) CP_WAIT2(); else if (pend == 1) CP_WAIT1(); else CP_WAIT0();
        __syncthreads();

        uint32_t bufb = sb + (uint32_t)(c % 3) * GBUF;
#pragma unroll
        for (int kk = 0; kk < 4; kk++) {
            int kb = kk * 32;
            uint32_t ah[2][4];
#pragma unroll
            for (int mt = 0; mt < 2; mt++) {
                int r = wm * 32 + mt * 16 + a_r16;
                uint32_t off = (uint32_t)(r * 128) + (uint32_t)((kb + a_kb) ^ ((r & 7) << 4));
                ldsm4(ah[mt], bufb + GOA + off);
            }
#pragma unroll
            for (int ntp = 0; ntp < 2; ntp++) {
                int r = wn * 32 + ntp * 16 + b_r8;
                uint32_t off = (uint32_t)(r * 128) + (uint32_t)((kb + b_kb) ^ ((r & 7) << 4));
                uint32_t bh[4], bl[4];
                ldsm4(bh, bufb + GOBH + off);
                ldsm4(bl, bufb + GOBL + off);
#pragma unroll
                for (int mt = 0; mt < 2; mt++) {
                    mma16816h(acc[mt][2 * ntp],     ah[mt], bh);
                    mma16816h(acc[mt][2 * ntp],     ah[mt], bl);
                    mma16816h(acc[mt][2 * ntp + 1], ah[mt], bh + 2);
                    mma16816h(acc[mt][2 * ntp + 1], ah[mt], bl + 2);
                }
            }
        }
        __syncthreads();
    }

    const int g = lane >> 2, t4 = lane & 3;

    if (MODE == 0) {
#pragma unroll
        for (int mt = 0; mt < 2; mt++) {
            int r0 = wm * 32 + mt * 16 + g;
            int r1 = r0 + 8;
            int tk0 = tok[r0], tk1 = tok[r1];
            bool ok0 = (m0 + r0) < cnt, ok1 = (m0 + r1) < cnt;
#pragma unroll
            for (int nt = 0; nt < 4; nt++) {
                int ncol = n0 + wn * 32 + nt * 8 + t4 * 2;
                if (ok0) *(float2*)(C + (size_t)tk0 * ldc + ncol) = make_float2(acc[mt][nt][0], acc[mt][nt][1]);
                if (ok1) *(float2*)(C + (size_t)tk1 * ldc + ncol) = make_float2(acc[mt][nt][2], acc[mt][nt][3]);
            }
        }
    } else {
#pragma unroll
        for (int mt = 0; mt < 2; mt++) {
            int r0 = wm * 32 + mt * 16 + g;
            int r1 = r0 + 8;
            int tk0 = tok[r0], tk1 = tok[r1];
            bool ok0 = (m0 + r0) < cnt, ok1 = (m0 + r1) < cnt;
            if (n0 < 1024) {
                // Q region: scale (1/8)*log2e, split fp16 hi/lo, per-head layout
#pragma unroll
                for (int nt = 0; nt < 4; nt++) {
                    int d = n0 + wn * 32 + nt * 8 + t4 * 2;
                    int h = d >> 6, hd = d & 63;
                    const float QS = 0.125f * LOG2E;
                    __half h0, l0, h1, l1;
                    if (ok0) {
                        size_t o = ((size_t)((tk0 >> 10) * NHC + h) * SEQC + (tk0 & 1023)) * HDC + hd;
                        split1h(acc[mt][nt][0] * QS, h0, l0);
                        split1h(acc[mt][nt][1] * QS, h1, l1);
                        *(uint32_t*)(g_q_hi + o) = pack_h2(h0, h1);
                        *(uint32_t*)(g_q_lo + o) = pack_h2(l0, l1);
                    }
                    if (ok1) {
                        size_t o = ((size_t)((tk1 >> 10) * NHC + h) * SEQC + (tk1 & 1023)) * HDC + hd;
                        split1h(acc[mt][nt][2] * QS, h0, l0);
                        split1h(acc[mt][nt][3] * QS, h1, l1);
                        *(uint32_t*)(g_q_hi + o) = pack_h2(h0, h1);
                        *(uint32_t*)(g_q_lo + o) = pack_h2(l0, l1);
                    }
                }
            } else if (n0 < 3072) {
                // K/V region: fp32 to g_y [TOK][2048]
#pragma unroll
                for (int nt = 0; nt < 4; nt++) {
                    int col = n0 - 1024 + wn * 32 + nt * 8 + t4 * 2;
                    if (ok0) *(float2*)(g_y + (size_t)tk0 * 2048 + col) = make_float2(acc[mt][nt][0], acc[mt][nt][1]);
                    if (ok1) *(float2*)(g_y + (size_t)tk1 * 2048 + col) = make_float2(acc[mt][nt][2], acc[mt][nt][3]);
                }
            } else {
                // MLP region: +bias, GELU -> g_h fp16 [:, 1024+j]
#pragma unroll
                for (int nt = 0; nt < 4; nt++) {
                    int j = n0 - 3072 + wn * 32 + nt * 8 + t4 * 2;
                    float b0 = mlpb[j], b1 = mlpb[j + 1];
                    if (ok0) {
                        __half u0 = __float2half_rn(gelu1(acc[mt][nt][0] + b0));
                        __half u1 = __float2half_rn(gelu1(acc[mt][nt][1] + b1));
                        *(uint32_t*)(g_h + (size_t)tk0 * CINC + 1024 + j) = pack_h2(u0, u1);
                    }
                    if (ok1) {
                        __half u0 = __float2half_rn(gelu1(acc[mt][nt][2] + b0));
                        __half u1 = __float2half_rn(gelu1(acc[mt][nt][3] + b1));
                        *(uint32_t*)(g_h + (size_t)tk1 * CINC + 1024 + j) = pack_h2(u0, u1);
                    }
                }
            }
        }
    }
}

// ---------------------------------------------------------------------------
// Flash attention (fp16 2-product): S = (Qh+Ql)K, O = (Ph+Pl)V.
// Q hi/lo fp16 in smem (32 KB); stages: K 8KB + V 8KB each, double buffered.
// ---------------------------------------------------------------------------
#define FQH 0
#define FQL 16384
#define FST 32768
#define FSS 16384
#define FSM (32768 + 2 * 16384 + 1024)   // 66560

__global__ void __launch_bounds__(256)
flash_kernel() {
    extern __shared__ char smem_raw[];
    uint32_t sb = smem_u32(smem_raw);
    sb = (sb + 1023u) & ~1023u;

    const int tid  = threadIdx.x;
    const int wid  = tid >> 5;
    const int lane = tid & 31;
    const int bh = blockIdx.y;
    const int q0 = blockIdx.x * 128;
    const int b = bh >> 4, h = bh & 15;

    const size_t base = (size_t)bh * SEQC * HDC;

    auto load_q = [&]() {
#pragma unroll
        for (int it = 0; it < 8; it++) {
            int i = tid + it * 256;
            int r = i >> 4, rem = i & 15, hl = rem >> 3, kg = rem & 7;
            const __half* src = (hl ? g_q_lo : g_q_hi) + base + (size_t)(q0 + r) * HDC + kg * 8;
            cpa16(sb + (hl ? FQL : FQH) + SWZ(r * 128 + kg * 16), src);
        }
    };
    auto load_kv = [&](int t) {
        uint32_t bufb = sb + FST + (uint32_t)(t & 1) * FSS;
#pragma unroll
        for (int it = 0; it < 2; it++) {
            int i = tid + it * 256;
            int r = i >> 3, kg = i & 7;
            const __half* src = g_k + base + (size_t)(t * 64 + r) * HDC + kg * 8;
            cpa16(bufb + SWZ(r * 128 + kg * 16), src);
        }
#pragma unroll
        for (int it = 0; it < 2; it++) {
            int i = tid + it * 256;
            int r = i >> 3, kg = i & 7;
            const __half* src = g_v + base + (size_t)(t * 64 + r) * HDC + kg * 8;
            cpa16(bufb + 8192 + SWZ(r * 128 + kg * 16), src);
        }
        CP_COMMIT();
    };

    load_q(); load_kv(0); CP_COMMIT();
    load_kv(1);

    const int a_r16 = lane & 15;
    const int a_kb  = (lane >> 4) * 16;
    const int b_r8  = ((lane >> 4) << 3) + (lane & 7);
    const int b_kb  = ((lane >> 3) & 1) * 16;
    const int v_r  = ((lane >> 3) & 1) * 8 + (lane & 7);
    const int v_cb = (lane >> 4) * 16;

    uint32_t qhf[4][4], qlf[4][4];
    float o[8][4];
#pragma unroll
    for (int j = 0; j < 8; j++)
#pragma unroll
        for (int k = 0; k < 4; k++) o[j][k] = 0.f;
    float ml0 = -1e30f, ml1 = -1e30f, ls0 = 0.f, ls1 = 0.f;

    for (int t = 0; t < 16; t++) {
        if (t < 15) CP_WAIT1(); else CP_WAIT0();
        __syncthreads();
        if (t == 0) {
#pragma unroll
            for (int kk = 0; kk < 4; kk++) {
                int r = wid * 16 + a_r16;
                uint32_t off = (uint32_t)(r * 128) + (uint32_t)((kk * 32 + a_kb) ^ ((r & 7) << 4));
                ldsm4(qhf[kk], sb + FQH + off);
                ldsm4(qlf[kk], sb + FQL + off);
            }
        }
        uint32_t bufb = sb + FST + (uint32_t)(t & 1) * FSS;

        float s[8][4];
#pragma unroll
        for (int j = 0; j < 8; j++)
#pragma unroll
            for (int k = 0; k < 4; k++) s[j][k] = 0.f;
#pragma unroll
        for (int kk = 0; kk < 4; kk++) {
#pragma unroll
            for (int ntp = 0; ntp < 4; ntp++) {
                int r = ntp * 16 + b_r8;
                uint32_t off = (uint32_t)(r * 128) + (uint32_t)((kk * 32 + b_kb) ^ ((r & 7) << 4));
                uint32_t kf[4];
                ldsm4(kf, bufb + off);
                mma16816h(s[2 * ntp],     qhf[kk], kf);
                mma16816h(s[2 * ntp],     qlf[kk], kf);
                mma16816h(s[2 * ntp + 1], qhf[kk], kf + 2);
                mma16816h(s[2 * ntp + 1], qlf[kk], kf + 2);
            }
        }

        float m0t = -1e30f, m1t = -1e30f;
#pragma unroll
        for (int j = 0; j < 8; j++) {
            m0t = fmaxf(m0t, fmaxf(s[j][0], s[j][1]));
            m1t = fmaxf(m1t, fmaxf(s[j][2], s[j][3]));
        }
        m0t = fmaxf(m0t, __shfl_xor_sync(0xffffffffu, m0t, 1));
        m0t = fmaxf(m0t, __shfl_xor_sync(0xffffffffu, m0t, 2));
        m1t = fmaxf(m1t, __shfl_xor_sync(0xffffffffu, m1t, 1));
        m1t = fmaxf(m1t, __shfl_xor_sync(0xffffffffu, m1t, 2));
        float mn0 = fmaxf(ml0, m0t), mn1 = fmaxf(ml1, m1t);
        float sc0 = exp2f(ml0 - mn0), sc1 = exp2f(ml1 - mn1);
        ml0 = mn0; ml1 = mn1;
        float r0 = 0.f, r1 = 0.f;
#pragma unroll
        for (int j = 0; j < 8; j++) {
            s[j][0] = exp2f(s[j][0] - mn0);
            s[j][1] = exp2f(s[j][1] - mn0);
            s[j][2] = exp2f(s[j][2] - mn1);
            s[j][3] = exp2f(s[j][3] - mn1);
            r0 += s[j][0] + s[j][1];
            r1 += s[j][2] + s[j][3];
        }
        r0 += __shfl_xor_sync(0xffffffffu, r0, 1);
        r0 += __shfl_xor_sync(0xffffffffu, r0, 2);
        r1 += __shfl_xor_sync(0xffffffffu, r1, 1);
        r1 += __shfl_xor_sync(0xffffffffu, r1, 2);
        ls0 = ls0 * sc0 + r0;
        ls1 = ls1 * sc1 + r1;
#pragma unroll
        for (int j = 0; j < 8; j++) {
            o[j][0] *= sc0; o[j][1] *= sc0;
            o[j][2] *= sc1; o[j][3] *= sc1;
        }

        // pack P into A fragments (fp16 hi/lo)
        uint32_t pah[4][4], pal[4][4];
#pragma unroll
        for (int kt = 0; kt < 4; kt++) {
            __half h0, l0, h1, l1;
            split1h(s[2 * kt][0], h0, l0); split1h(s[2 * kt][1], h1, l1);
            pah[kt][0] = pack_h2(h0, h1); pal[kt][0] = pack_h2(l0, l1);
            split1h(s[2 * kt][2], h0, l0); split1h(s[2 * kt][3], h1, l1);
            pah[kt][1] = pack_h2(h0, h1); pal[kt][1] = pack_h2(l0, l1);
            split1h(s[2 * kt + 1][0], h0, l0); split1h(s[2 * kt + 1][1], h1, l1);
            pah[kt][2] = pack_h2(h0, h1); pal[kt][2] = pack_h2(l0, l1);
            split1h(s[2 * kt + 1][2], h0, l0); split1h(s[2 * kt + 1][3], h1, l1);
            pah[kt][3] = pack_h2(h0, h1); pal[kt][3] = pack_h2(l0, l1);
        }

        // O += P V (V via ldmatrix.trans from [keys][hd] tile)
#pragma unroll
        for (int kt = 0; kt < 4; kt++) {
#pragma unroll
            for (int nv = 0; nv < 4; nv++) {
                int r = kt * 16 + v_r;
                uint32_t off = (uint32_t)(r * 128) + (uint32_t)((nv * 32 + v_cb) ^ ((r & 7) << 4));
                uint32_t vf[4];
                ldsm4t(vf, bufb + 8192 + off);
                mma16816h(o[2 * nv],     pah[kt], vf);
                mma16816h(o[2 * nv],     pal[kt], vf);
                mma16816h(o[2 * nv + 1], pah[kt], vf + 2);
                mma16816h(o[2 * nv + 1], pal[kt], vf + 2);
            }
        }
        __syncthreads();
        if (t + 2 < 16) load_kv(t + 2);
    }

    const int g = lane >> 2, t4 = lane & 3;
    float i0 = 1.f / ls0, i1 = 1.f / ls1;
    int tok0 = b * 1024 + q0 + wid * 16 + g;
    int tok1 = tok0 + 8;
#pragma unroll
    for (int j = 0; j < 8; j++) {
        int col = h * 64 + j * 8 + t4 * 2;
        __half u0 = __float2half_rn(o[j][0] * i0);
        __half u1 = __float2half_rn(o[j][1] * i0);
        *(uint32_t*)(g_h + (size_t)tok0 * CINC + col) = pack_h2(u0, u1);
        u0 = __float2half_rn(o[j][2] * i1);
        u1 = __float2half_rn(o[j][3] * i1);
        *(uint32_t*)(g_h + (size_t)tok1 * CINC + col) = pack_h2(u0, u1);
    }
}

// ---------------------------------------------------------------------------
// Expert permutation: single CTA
// ---------------------------------------------------------------------------
__global__ void __launch_bounds__(1024) perm_kernel(const int* __restrict__ em) {
    __shared__ int cnt[4], off[4], cur[4];
    int tid = threadIdx.x;
    if (tid < 4) { cnt[tid] = 0; cur[tid] = 0; }
    __syncthreads();
    int ev[8];
#pragma unroll
    for (int i = 0; i < 8; i++) {
        ev[i] = em[tid + i * 1024];
        atomicAdd(&cnt[ev[i]], 1);
    }
    __syncthreads();
    if (tid == 0) {
        int o = 0;
        for (int j = 0; j < 4; j++) { off[j] = o; g_goff[j] = o; g_cnt[j] = cnt[j]; o += cnt[j]; }
    }
    __syncthreads();
#pragma unroll
    for (int i = 0; i < 8; i++) {
        int p = atomicAdd(&cur[ev[i]], 1);
        g_perm[off[ev[i]] + p] = tid + i * 1024;
    }
}

// weight split (fp32 -> fp16 hi/lo)
__global__ void splitw_kernel(const float* __restrict__ s,
                              __half* __restrict__ hi, __half* __restrict__ lo) {
    size_t i = (size_t)blockIdx.x * 256 + threadIdx.x;
    float4 v = ((const float4*)s)[i];
    __half h0, h1, h2, h3, l0, l1, l2, l3;
    split1h(v.x, h0, l0); split1h(v.y, h1, l1); split1h(v.z, h2, l2); split1h(v.w, h3, l3);
    ((uint32_t*)hi)[2 * i]     = pack_h2(h0, h1);
    ((uint32_t*)hi)[2 * i + 1] = pack_h2(h2, h3);
    ((uint32_t*)lo)[2 * i]     = pack_h2(l0, l1);
    ((uint32_t*)lo)[2 * i + 1] = pack_h2(l2, l3);
}

// LN1 -> masked xn fp16 single
__global__ void ln1_kernel(const float* __restrict__ x, const int* __restrict__ em,
                           const float* __restrict__ g, const float* __restrict__ b) {
    int t = blockIdx.x;
    const float4* xr = (const float4*)(x + (size_t)t * DIMC);
    int tid = threadIdx.x;
    float4 v = xr[tid];
    float s  = v.x + v.y + v.z + v.w;
    float s2 = v.x * v.x + v.y * v.y + v.z * v.z + v.w * v.w;
#pragma unroll
    for (int o = 16; o; o >>= 1) { s += __shfl_xor_sync(0xffffffffu, s, o); s2 += __shfl_xor_sync(0xffffffffu, s2, o); }
    __shared__ float red[18];
    int w = tid >> 5, l = tid & 31;
    if (l == 0) { red[w] = s; red[8 + w] = s2; }
    __syncthreads();
    if (tid == 0) {
        float ts = 0.f, ts2 = 0.f;
        for (int i = 0; i < 8; i++) { ts += red[i]; ts2 += red[8 + i]; }
        float m = ts * (1.f / DIMC);
        float var = ts2 * (1.f / DIMC) - m * m;
        red[16] = m; red[17] = rsqrtf(var + 1e-5f);
    }
    __syncthreads();
    float m = red[16], rs = red[17];
    int din = DIMC >> (3 - em[t]);
    int c = tid * 4;
    float4 gg = ((const float4*)g)[tid];
    float4 bb = ((const float4*)b)[tid];
    float o0 = (c + 0 < din) ? ((v.x - m) * rs * gg.x + bb.x) : 0.f;
    float o1 = (c + 1 < din) ? ((v.y - m) * rs * gg.y + bb.y) : 0.f;
    float o2 = (c + 2 < din) ? ((v.z - m) * rs * gg.z + bb.z) : 0.f;
    float o3 = (c + 3 < din) ? ((v.w - m) * rs * gg.w + bb.w) : 0.f;
    size_t o = (size_t)t * DIMC + c;
    *(uint32_t*)(g_xn + o)     = pack_h2(__float2half_rn(o0), __float2half_rn(o1));
    *(uint32_t*)(g_xn + o + 2) = pack_h2(__float2half_rn(o2), __float2half_rn(o3));
}

// LN2: which==0 -> k, which==1 -> v. Per-head single fp16.
__global__ void ln2kv_kernel(const float* __restrict__ g, const float* __restrict__ b) {
    int t = blockIdx.x;
    int which = blockIdx.y;
    const float4* row = (const float4*)(g_y + (size_t)t * 2048 + (size_t)DIMC * which);
    int tid = threadIdx.x;
    float4 v = row[tid];
    float s  = v.x + v.y + v.z + v.w;
    float s2 = v.x * v.x + v.y * v.y + v.z * v.z + v.w * v.w;
#pragma unroll
    for (int o = 16; o; o >>= 1) { s += __shfl_xor_sync(0xffffffffu, s, o); s2 += __shfl_xor_sync(0xffffffffu, s2, o); }
    __shared__ float red[18];
    int w = tid >> 5, l = tid & 31;
    if (l == 0) { red[w] = s; red[8 + w] = s2; }
    __syncthreads();
    if (tid == 0) {
        float ts = 0.f, ts2 = 0.f;
        for (int i = 0; i < 8; i++) { ts += red[i]; ts2 += red[8 + i]; }
        float m = ts * (1.f / DIMC);
        float var = ts2 * (1.f / DIMC) - m * m;
        red[16] = m; red[17] = rsqrtf(var + 1e-5f);
    }
    __syncthreads();
    float m = red[16], rs = red[17];
    int bb2 = t >> 10, ss = t & 1023;
    int c = tid * 4;
    float4 gg = ((const float4*)g)[tid];
    float4 bv = ((const float4*)b)[tid];
    float o0 = (v.x - m) * rs * gg.x + bv.x;
    float o1 = (v.y - m) * rs * gg.y + bv.y;
    float o2 = (v.z - m) * rs * gg.z + bv.z;
    float o3 = (v.w - m) * rs * gg.w + bv.w;
    int hh = c >> 6, hd = c & 63;
    size_t o = ((size_t)(bb2 * NHC + hh) * SEQC + ss) * HDC + hd;
    __half* d = which ? g_v : g_k;
    *(uint32_t*)(d + o)     = pack_h2(__float2half_rn(o0), __float2half_rn(o1));
    *(uint32_t*)(d + o + 2) = pack_h2(__float2half_rn(o2), __float2half_rn(o3));
}

// Final epilogue + pass-through tails (merged)
__global__ void final_kernel(const float* __restrict__ x, const int* __restrict__ em,
                             const float* __restrict__ rp, const float* __restrict__ cb,
                             const float* __restrict__ alpha, float* __restrict__ out) {
    size_t idx = (size_t)blockIdx.x * 256 + threadIdx.x;
    int t = (int)(idx >> 10);
    int d = (int)(idx & 1023);
    int m = em[t];
    int dout = (2 * DIMC) >> (3 - m);
    const float* zr = g_z + (size_t)t * 2 * DIMC;
    float za = (d < dout) ? (zr[d] + cb[d]) : 0.f;
    float zm = (DIMC + d < dout) ? (zr[DIMC + d] + cb[DIMC + d]) : 0.f;
    float pr = rp[t * 4 + m];
    out[idx] = x[idx] + za + (alpha[0] * pr + 1.f) * zm;
    if (idx < TOK)     out[(size_t)TOK * DIMC + idx] = (float)em[idx];
    if (idx < TOK * 4) out[(size_t)TOK * DIMC + TOK + idx] = rp[idx];
}

// ---------------------------------------------------------------------------
extern "C" void kernel_launch(void* const* d_in, const int* in_sizes, int n_in,
                              void* d_out, int out_size) {
    const float* x     = (const float*)d_in[0];
    const int*   em    = (const int*)d_in[1];
    const float* rp    = (const float*)d_in[2];
    const float* wexp  = (const float*)d_in[3];
    const float* mlpb  = (const float*)d_in[4];
    const float* wc    = (const float*)d_in[5];
    const float* cb    = (const float*)d_in[6];
    const float* n1g   = (const float*)d_in[7];
    const float* n1b   = (const float*)d_in[8];
    const float* n2g   = (const float*)d_in[9];
    const float* n2b   = (const float*)d_in[10];
    const float* alpha = (const float*)d_in[11];
    float* out = (float*)d_out;

    float *p_z;
    __half *p_xn, *p_weh, *p_wel, *p_wch, *p_wcl, *p_h;
    cudaGetSymbolAddress((void**)&p_z,   g_z);
    cudaGetSymbolAddress((void**)&p_xn,  g_xn);
    cudaGetSymbolAddress((void**)&p_weh, g_we_hi);
    cudaGetSymbolAddress((void**)&p_wel, g_we_lo);
    cudaGetSymbolAddress((void**)&p_wch, g_wc_hi);
    cudaGetSymbolAddress((void**)&p_wcl, g_wc_lo);
    cudaGetSymbolAddress((void**)&p_h,   g_h);

    cudaFuncSetAttribute(gemm_grouped_kernel<0>, cudaFuncAttributeMaxDynamicSharedMemorySize, GSM);
    cudaFuncSetAttribute(gemm_grouped_kernel<1>, cudaFuncAttributeMaxDynamicSharedMemorySize, GSM);
    cudaFuncSetAttribute(flash_kernel,           cudaFuncAttributeMaxDynamicSharedMemorySize, FSM);

    // 0) expert permutation (single CTA)
    perm_kernel<<<1, 1024>>>(em);

    // 0b) weight splits (fp32 -> fp16 hi/lo)
    splitw_kernel<<<(EXPC * DIMC) / 4 / 256, 256>>>(wexp, p_weh, p_wel);
    splitw_kernel<<<(2 * DIMC * CINC) / 4 / 256, 256>>>(wc, p_wch, p_wcl);

    // 1) LN1 + input mask -> xn fp16
    ln1_kernel<<<TOK, 256>>>(x, em, n1g, n1b);

    // 2) expand (grouped, fp16 2-product, fused epilogue)
    gemm_grouped_kernel<1><<<dim3(EXPC / 128, TOK / 128, 4), 512, GSM>>>(
        p_xn, DIMC, p_weh, p_wel, DIMC, nullptr, 0, mlpb,
        128, 1, EXPC, 0);

    // 3) LN2 -> k and v per-head single fp16
    ln2kv_kernel<<<dim3(TOK, 2), 256>>>(n2g, n2b);

    // 4) flash attention (fp16 2-product) -> g_h fp16 [:, 0:1024]
    flash_kernel<<<dim3(SEQC / 128, BH), 256, FSM>>>();

    // 5) contract (grouped, fp16 2-product): z = h @ Wc^T, N_e = 256<<e
    gemm_grouped_kernel<0><<<dim3(16, TOK / 128, 4), 512, GSM>>>(
        p_h, CINC, p_wch, p_wcl, CINC, p_z, 2 * DIMC, nullptr,
        CINC, 0, 256, 1);

    // 6) epilogue + tails (merged)
    final_kernel<<<(TOK * DIMC) / 256, 256>>>(x, em, rp, cb, alpha, out);
}

// round 12
// speedup vs baseline: 10.9530x; 1.5402x over previous
#include <cuda_runtime.h>
#include <cuda_fp16.h>
#include <math.h>
#include <stdint.h>

// Problem constants
#define TOK   8192        // B*N
#define DIMC  1024
#define EXPC  7168
#define CINC  5120
#define NHC   16
#define HDC   64
#define SEQC  1024
#define NB    8
#define BH    (NB * NHC)  // 128 batch-heads

#define LOG2E 1.44269504088896340736f

// ---------------------------------------------------------------------------
// Scratch (device globals; allocation-free)
// ---------------------------------------------------------------------------
__device__ float g_y [(size_t)TOK * 2 * DIMC];                //  67 MB (k,v fp32 pre-LN)
__device__ float g_z [(size_t)TOK * 2 * DIMC];                //  67 MB

__device__ __half g_xn[(size_t)TOK * DIMC];
__device__ __half g_we[(size_t)EXPC * DIMC];
__device__ __half g_wc[(size_t)2 * DIMC * CINC];
__device__ __half g_h [(size_t)TOK * CINC];

// attention operands (per-head [bh][seq][hd]; all single fp16)
__device__ __half g_q[(size_t)BH * SEQC * HDC];
__device__ __half g_k[(size_t)BH * SEQC * HDC];
__device__ __half g_v[(size_t)BH * SEQC * HDC];

// expert grouping
__device__ int g_cnt[4];
__device__ int g_goff[4];
__device__ int g_perm[TOK];

// ---------------------------------------------------------------------------
// PTX helpers
// ---------------------------------------------------------------------------
__device__ __forceinline__ uint32_t smem_u32(const void* p) {
    uint32_t a;
    asm("{ .reg .u64 t; cvta.to.shared.u64 t, %1; cvt.u32.u64 %0, t; }" : "=r"(a) : "l"(p));
    return a;
}
__device__ __forceinline__ void ldsm4(uint32_t* r, uint32_t a) {
    asm volatile("ldmatrix.sync.aligned.m8n8.x4.shared.b16 {%0,%1,%2,%3}, [%4];"
                 : "=r"(r[0]), "=r"(r[1]), "=r"(r[2]), "=r"(r[3]) : "r"(a));
}
__device__ __forceinline__ void ldsm4t(uint32_t* r, uint32_t a) {
    asm volatile("ldmatrix.sync.aligned.m8n8.x4.trans.shared.b16 {%0,%1,%2,%3}, [%4];"
                 : "=r"(r[0]), "=r"(r[1]), "=r"(r[2]), "=r"(r[3]) : "r"(a));
}
__device__ __forceinline__ void mma16816h(float* c, const uint32_t* a, const uint32_t* b) {
    asm volatile("mma.sync.aligned.m16n8k16.row.col.f32.f16.f16.f32 "
                 "{%0,%1,%2,%3}, {%4,%5,%6,%7}, {%8,%9}, {%0,%1,%2,%3};"
                 : "+f"(c[0]), "+f"(c[1]), "+f"(c[2]), "+f"(c[3])
                 : "r"(a[0]), "r"(a[1]), "r"(a[2]), "r"(a[3]), "r"(b[0]), "r"(b[1]));
}
__device__ __forceinline__ void cpa16(uint32_t s, const void* g) {
    asm volatile("cp.async.cg.shared.global [%0], [%1], 16;" :: "r"(s), "l"(g));
}
#define CP_COMMIT() asm volatile("cp.async.commit_group;")
#define CP_WAIT2()  asm volatile("cp.async.wait_group 2;")
#define CP_WAIT1()  asm volatile("cp.async.wait_group 1;")
#define CP_WAIT0()  asm volatile("cp.async.wait_group 0;")

#define SWZ(o) ((o) ^ (((o) >> 3) & 0x70))

__device__ __forceinline__ uint32_t pack_h2(__half a, __half b) {
    __half2 v(a, b);
    return *(uint32_t*)&v;
}
__device__ __forceinline__ float gelu1(float x) {
    return 0.5f * x * (1.f + erff(x * 0.70710678118654752f));
}

// ---------------------------------------------------------------------------
// Expert-grouped plain-fp16 HMMA GEMM with row gather. (512 thr, 4x4 warps,
// warp tile 32x32, CTA 128x128, K-chunk 64, 3-stage cp.async)
// MODE 0: plain fp32 scatter (contract).
// MODE 1: expand fused epilogue (q fp16 / y fp32 / gelu h fp16).
// ---------------------------------------------------------------------------
#define GOA  0
#define GOB  16384
#define GBUF 32768
#define GSM  (1024 + 3 * GBUF)    // 99328

template<int MODE>
__global__ void __launch_bounds__(512)
gemm_grouped_kernel(const __half* __restrict__ A, int lda,
                    const __half* __restrict__ B, int ldb,
                    float* __restrict__ C, int ldc,
                    const float* __restrict__ mlpb,
                    int Kbase, int Kscale, int Nbase, int Nscale) {
    const int e = blockIdx.z;
    const int cnt  = g_cnt[e];
    const int goff = g_goff[e];
    const int m0 = blockIdx.y * 128;
    if (m0 >= cnt) return;
    const int K    = Kscale ? (Kbase << e) : Kbase;
    const int Nlim = Nscale ? (Nbase << e) : Nbase;
    const int n0 = blockIdx.x * 128;
    if (n0 >= Nlim) return;

    extern __shared__ char smem_raw[];
    uint32_t sb0 = smem_u32(smem_raw);
    sb0 = (sb0 + 1023u) & ~1023u;
    int* tok = (int*)(smem_raw + (sb0 - smem_u32(smem_raw)));
    uint32_t sb = sb0 + 1024u;

    const int tid  = threadIdx.x;
    const int wid  = tid >> 5;
    const int lane = tid & 31;
    const int wm = wid & 3;
    const int wn = wid >> 2;

    if (tid < 128) {
        int gr = m0 + tid;
        tok[tid] = g_perm[goff + ((gr < cnt) ? gr : 0)];
    }
    __syncthreads();

    const __half* BB = B + (size_t)n0 * ldb;

    const int NC = K / 64;

    auto load_chunk = [&](int c) {
        uint32_t bufb = sb + (uint32_t)(c % 3) * GBUF;
        int k0 = c * 64;
#pragma unroll
        for (int it = 0; it < 2; it++) {
            int i = tid + it * 512;
            int r = i >> 3, kg = i & 7;
            const __half* src = A + (size_t)tok[r] * lda + k0 + kg * 8;
            cpa16(bufb + GOA + SWZ(r * 128 + kg * 16), src);
        }
#pragma unroll
        for (int it = 0; it < 2; it++) {
            int i = tid + it * 512;
            int r = i >> 3, kg = i & 7;
            const __half* src = BB + (size_t)r * ldb + k0 + kg * 8;
            cpa16(bufb + GOB + SWZ(r * 128 + kg * 16), src);
        }
        CP_COMMIT();
    };

    load_chunk(0);
    if (NC > 1) load_chunk(1);

    float acc[2][4][4];
#pragma unroll
    for (int i = 0; i < 2; i++)
#pragma unroll
        for (int j = 0; j < 4; j++)
#pragma unroll
            for (int k = 0; k < 4; k++) acc[i][j][k] = 0.f;

    const int a_r16 = lane & 15;
    const int a_kb  = (lane >> 4) * 16;
    const int b_r8  = ((lane >> 4) << 3) + (lane & 7);
    const int b_kb  = ((lane >> 3) & 1) * 16;

    for (int c = 0; c < NC; c++) {
        if (c + 2 < NC) load_chunk(c + 2);
        int pend = NC - 1 - c; if (pend > 2) pend = 2;
        if (pend == 2) CP_WAIT2(); else if (pend == 1) CP_WAIT1(); else CP_WAIT0();
        __syncthreads();

        uint32_t bufb = sb + (uint32_t)(c % 3) * GBUF;
#pragma unroll
        for (int kk = 0; kk < 4; kk++) {
            int kb = kk * 32;
            uint32_t ah[2][4];
#pragma unroll
            for (int mt = 0; mt < 2; mt++) {
                int r = wm * 32 + mt * 16 + a_r16;
                uint32_t off = (uint32_t)(r * 128) + (uint32_t)((kb + a_kb) ^ ((r & 7) << 4));
                ldsm4(ah[mt], bufb + GOA + off);
            }
#pragma unroll
            for (int ntp = 0; ntp < 2; ntp++) {
                int r = wn * 32 + ntp * 16 + b_r8;
                uint32_t off = (uint32_t)(r * 128) + (uint32_t)((kb + b_kb) ^ ((r & 7) << 4));
                uint32_t bf[4];
                ldsm4(bf, bufb + GOB + off);
#pragma unroll
                for (int mt = 0; mt < 2; mt++) {
                    mma16816h(acc[mt][2 * ntp],     ah[mt], bf);
                    mma16816h(acc[mt][2 * ntp + 1], ah[mt], bf + 2);
                }
            }
        }
        __syncthreads();
    }

    const int g = lane >> 2, t4 = lane & 3;

    if (MODE == 0) {
#pragma unroll
        for (int mt = 0; mt < 2; mt++) {
            int r0 = wm * 32 + mt * 16 + g;
            int r1 = r0 + 8;
            int tk0 = tok[r0], tk1 = tok[r1];
            bool ok0 = (m0 + r0) < cnt, ok1 = (m0 + r1) < cnt;
#pragma unroll
            for (int nt = 0; nt < 4; nt++) {
                int ncol = n0 + wn * 32 + nt * 8 + t4 * 2;
                if (ok0) *(float2*)(C + (size_t)tk0 * ldc + ncol) = make_float2(acc[mt][nt][0], acc[mt][nt][1]);
                if (ok1) *(float2*)(C + (size_t)tk1 * ldc + ncol) = make_float2(acc[mt][nt][2], acc[mt][nt][3]);
            }
        }
    } else {
#pragma unroll
        for (int mt = 0; mt < 2; mt++) {
            int r0 = wm * 32 + mt * 16 + g;
            int r1 = r0 + 8;
            int tk0 = tok[r0], tk1 = tok[r1];
            bool ok0 = (m0 + r0) < cnt, ok1 = (m0 + r1) < cnt;
            if (n0 < 1024) {
                // Q region: scale (1/8)*log2e -> g_q fp16 per-head layout
#pragma unroll
                for (int nt = 0; nt < 4; nt++) {
                    int d = n0 + wn * 32 + nt * 8 + t4 * 2;
                    int h = d >> 6, hd = d & 63;
                    const float QS = 0.125f * LOG2E;
                    if (ok0) {
                        size_t o = ((size_t)((tk0 >> 10) * NHC + h) * SEQC + (tk0 & 1023)) * HDC + hd;
                        *(uint32_t*)(g_q + o) = pack_h2(__float2half_rn(acc[mt][nt][0] * QS),
                                                       __float2half_rn(acc[mt][nt][1] * QS));
                    }
                    if (ok1) {
                        size_t o = ((size_t)((tk1 >> 10) * NHC + h) * SEQC + (tk1 & 1023)) * HDC + hd;
                        *(uint32_t*)(g_q + o) = pack_h2(__float2half_rn(acc[mt][nt][2] * QS),
                                                       __float2half_rn(acc[mt][nt][3] * QS));
                    }
                }
            } else if (n0 < 3072) {
                // K/V region: fp32 to g_y [TOK][2048]
#pragma unroll
                for (int nt = 0; nt < 4; nt++) {
                    int col = n0 - 1024 + wn * 32 + nt * 8 + t4 * 2;
                    if (ok0) *(float2*)(g_y + (size_t)tk0 * 2048 + col) = make_float2(acc[mt][nt][0], acc[mt][nt][1]);
                    if (ok1) *(float2*)(g_y + (size_t)tk1 * 2048 + col) = make_float2(acc[mt][nt][2], acc[mt][nt][3]);
                }
            } else {
                // MLP region: +bias, GELU -> g_h fp16 [:, 1024+j]
#pragma unroll
                for (int nt = 0; nt < 4; nt++) {
                    int j = n0 - 3072 + wn * 32 + nt * 8 + t4 * 2;
                    float b0 = mlpb[j], b1 = mlpb[j + 1];
                    if (ok0) {
                        __half u0 = __float2half_rn(gelu1(acc[mt][nt][0] + b0));
                        __half u1 = __float2half_rn(gelu1(acc[mt][nt][1] + b1));
                        *(uint32_t*)(g_h + (size_t)tk0 * CINC + 1024 + j) = pack_h2(u0, u1);
                    }
                    if (ok1) {
                        __half u0 = __float2half_rn(gelu1(acc[mt][nt][2] + b0));
                        __half u1 = __float2half_rn(gelu1(acc[mt][nt][3] + b1));
                        *(uint32_t*)(g_h + (size_t)tk1 * CINC + 1024 + j) = pack_h2(u0, u1);
                    }
                }
            }
        }
    }
}

// ---------------------------------------------------------------------------
// Flash attention (all single fp16): S = Q K, O = P V.
// Q 16KB smem; per-stage K 8KB + V 8KB, double buffered. 49 KB total.
// ---------------------------------------------------------------------------
#define FQ  0
#define FST 16384
#define FSS 16384
#define FSM (16384 + 2 * 16384 + 1024)   // 50176

__global__ void __launch_bounds__(256)
flash_kernel() {
    extern __shared__ char smem_raw[];
    uint32_t sb = smem_u32(smem_raw);
    sb = (sb + 1023u) & ~1023u;

    const int tid  = threadIdx.x;
    const int wid  = tid >> 5;
    const int lane = tid & 31;
    const int bh = blockIdx.y;
    const int q0 = blockIdx.x * 128;
    const int b = bh >> 4, h = bh & 15;

    const size_t base = (size_t)bh * SEQC * HDC;

    auto load_q = [&]() {
#pragma unroll
        for (int it = 0; it < 4; it++) {
            int i = tid + it * 256;
            int r = i >> 3, kg = i & 7;
            const __half* src = g_q + base + (size_t)(q0 + r) * HDC + kg * 8;
            cpa16(sb + FQ + SWZ(r * 128 + kg * 16), src);
        }
    };
    auto load_kv = [&](int t) {
        uint32_t bufb = sb + FST + (uint32_t)(t & 1) * FSS;
#pragma unroll
        for (int it = 0; it < 2; it++) {
            int i = tid + it * 256;
            int r = i >> 3, kg = i & 7;
            const __half* src = g_k + base + (size_t)(t * 64 + r) * HDC + kg * 8;
            cpa16(bufb + SWZ(r * 128 + kg * 16), src);
        }
#pragma unroll
        for (int it = 0; it < 2; it++) {
            int i = tid + it * 256;
            int r = i >> 3, kg = i & 7;
            const __half* src = g_v + base + (size_t)(t * 64 + r) * HDC + kg * 8;
            cpa16(bufb + 8192 + SWZ(r * 128 + kg * 16), src);
        }
        CP_COMMIT();
    };

    load_q(); load_kv(0); CP_COMMIT();
    load_kv(1);

    const int a_r16 = lane & 15;
    const int a_kb  = (lane >> 4) * 16;
    const int b_r8  = ((lane >> 4) << 3) + (lane & 7);
    const int b_kb  = ((lane >> 3) & 1) * 16;
    const int v_r  = ((lane >> 3) & 1) * 8 + (lane & 7);
    const int v_cb = (lane >> 4) * 16;

    uint32_t qf[4][4];
    float o[8][4];
#pragma unroll
    for (int j = 0; j < 8; j++)
#pragma unroll
        for (int k = 0; k < 4; k++) o[j][k] = 0.f;
    float ml0 = -1e30f, ml1 = -1e30f, ls0 = 0.f, ls1 = 0.f;

    for (int t = 0; t < 16; t++) {
        if (t < 15) CP_WAIT1(); else CP_WAIT0();
        __syncthreads();
        if (t == 0) {
#pragma unroll
            for (int kk = 0; kk < 4; kk++) {
                int r = wid * 16 + a_r16;
                uint32_t off = (uint32_t)(r * 128) + (uint32_t)((kk * 32 + a_kb) ^ ((r & 7) << 4));
                ldsm4(qf[kk], sb + FQ + off);
            }
        }
        uint32_t bufb = sb + FST + (uint32_t)(t & 1) * FSS;

        float s[8][4];
#pragma unroll
        for (int j = 0; j < 8; j++)
#pragma unroll
            for (int k = 0; k < 4; k++) s[j][k] = 0.f;
#pragma unroll
        for (int kk = 0; kk < 4; kk++) {
#pragma unroll
            for (int ntp = 0; ntp < 4; ntp++) {
                int r = ntp * 16 + b_r8;
                uint32_t off = (uint32_t)(r * 128) + (uint32_t)((kk * 32 + b_kb) ^ ((r & 7) << 4));
                uint32_t kf[4];
                ldsm4(kf, bufb + off);
                mma16816h(s[2 * ntp],     qf[kk], kf);
                mma16816h(s[2 * ntp + 1], qf[kk], kf + 2);
            }
        }

        float m0t = -1e30f, m1t = -1e30f;
#pragma unroll
        for (int j = 0; j < 8; j++) {
            m0t = fmaxf(m0t, fmaxf(s[j][0], s[j][1]));
            m1t = fmaxf(m1t, fmaxf(s[j][2], s[j][3]));
        }
        m0t = fmaxf(m0t, __shfl_xor_sync(0xffffffffu, m0t, 1));
        m0t = fmaxf(m0t, __shfl_xor_sync(0xffffffffu, m0t, 2));
        m1t = fmaxf(m1t, __shfl_xor_sync(0xffffffffu, m1t, 1));
        m1t = fmaxf(m1t, __shfl_xor_sync(0xffffffffu, m1t, 2));
        float mn0 = fmaxf(ml0, m0t), mn1 = fmaxf(ml1, m1t);
        float sc0 = exp2f(ml0 - mn0), sc1 = exp2f(ml1 - mn1);
        ml0 = mn0; ml1 = mn1;
        float r0 = 0.f, r1 = 0.f;
#pragma unroll
        for (int j = 0; j < 8; j++) {
            s[j][0] = exp2f(s[j][0] - mn0);
            s[j][1] = exp2f(s[j][1] - mn0);
            s[j][2] = exp2f(s[j][2] - mn1);
            s[j][3] = exp2f(s[j][3] - mn1);
            r0 += s[j][0] + s[j][1];
            r1 += s[j][2] + s[j][3];
        }
        r0 += __shfl_xor_sync(0xffffffffu, r0, 1);
        r0 += __shfl_xor_sync(0xffffffffu, r0, 2);
        r1 += __shfl_xor_sync(0xffffffffu, r1, 1);
        r1 += __shfl_xor_sync(0xffffffffu, r1, 2);
        ls0 = ls0 * sc0 + r0;
        ls1 = ls1 * sc1 + r1;
#pragma unroll
        for (int j = 0; j < 8; j++) {
            o[j][0] *= sc0; o[j][1] *= sc0;
            o[j][2] *= sc1; o[j][3] *= sc1;
        }

        // pack P (single fp16) into A fragments
        uint32_t pa[4][4];
#pragma unroll
        for (int kt = 0; kt < 4; kt++) {
            pa[kt][0] = pack_h2(__float2half_rn(s[2 * kt][0]),     __float2half_rn(s[2 * kt][1]));
            pa[kt][1] = pack_h2(__float2half_rn(s[2 * kt][2]),     __float2half_rn(s[2 * kt][3]));
            pa[kt][2] = pack_h2(__float2half_rn(s[2 * kt + 1][0]), __float2half_rn(s[2 * kt + 1][1]));
            pa[kt][3] = pack_h2(__float2half_rn(s[2 * kt + 1][2]), __float2half_rn(s[2 * kt + 1][3]));
        }

        // O += P V (V via ldmatrix.trans from [keys][hd] tile)
#pragma unroll
        for (int kt = 0; kt < 4; kt++) {
#pragma unroll
            for (int nv = 0; nv < 4; nv++) {
                int r = kt * 16 + v_r;
                uint32_t off = (uint32_t)(r * 128) + (uint32_t)((nv * 32 + v_cb) ^ ((r & 7) << 4));
                uint32_t vf[4];
                ldsm4t(vf, bufb + 8192 + off);
                mma16816h(o[2 * nv],     pa[kt], vf);
                mma16816h(o[2 * nv + 1], pa[kt], vf + 2);
            }
        }
        __syncthreads();
        if (t + 2 < 16) load_kv(t + 2);
    }

    const int g = lane >> 2, t4 = lane & 3;
    float i0 = 1.f / ls0, i1 = 1.f / ls1;
    int tok0 = b * 1024 + q0 + wid * 16 + g;
    int tok1 = tok0 + 8;
#pragma unroll
    for (int j = 0; j < 8; j++) {
        int col = h * 64 + j * 8 + t4 * 2;
        *(uint32_t*)(g_h + (size_t)tok0 * CINC + col) =
            pack_h2(__float2half_rn(o[j][0] * i0), __float2half_rn(o[j][1] * i0));
        *(uint32_t*)(g_h + (size_t)tok1 * CINC + col) =
            pack_h2(__float2half_rn(o[j][2] * i1), __float2half_rn(o[j][3] * i1));
    }
}

// ---------------------------------------------------------------------------
// Expert permutation: single CTA
// ---------------------------------------------------------------------------
__global__ void __launch_bounds__(1024) perm_kernel(const int* __restrict__ em) {
    __shared__ int cnt[4], off[4], cur[4];
    int tid = threadIdx.x;
    if (tid < 4) { cnt[tid] = 0; cur[tid] = 0; }
    __syncthreads();
    int ev[8];
#pragma unroll
    for (int i = 0; i < 8; i++) {
        ev[i] = em[tid + i * 1024];
        atomicAdd(&cnt[ev[i]], 1);
    }
    __syncthreads();
    if (tid == 0) {
        int o = 0;
        for (int j = 0; j < 4; j++) { off[j] = o; g_goff[j] = o; g_cnt[j] = cnt[j]; o += cnt[j]; }
    }
    __syncthreads();
#pragma unroll
    for (int i = 0; i < 8; i++) {
        int p = atomicAdd(&cur[ev[i]], 1);
        g_perm[off[ev[i]] + p] = tid + i * 1024;
    }
}

// weight convert (fp32 -> fp16)
__global__ void convw_kernel(const float* __restrict__ s, __half* __restrict__ d) {
    size_t i = (size_t)blockIdx.x * 256 + threadIdx.x;
    float4 v = ((const float4*)s)[i];
    ((uint32_t*)d)[2 * i]     = pack_h2(__float2half_rn(v.x), __float2half_rn(v.y));
    ((uint32_t*)d)[2 * i + 1] = pack_h2(__float2half_rn(v.z), __float2half_rn(v.w));
}

// LN1 -> masked xn fp16
__global__ void ln1_kernel(const float* __restrict__ x, const int* __restrict__ em,
                           const float* __restrict__ g, const float* __restrict__ b) {
    int t = blockIdx.x;
    const float4* xr = (const float4*)(x + (size_t)t * DIMC);
    int tid = threadIdx.x;
    float4 v = xr[tid];
    float s  = v.x + v.y + v.z + v.w;
    float s2 = v.x * v.x + v.y * v.y + v.z * v.z + v.w * v.w;
#pragma unroll
    for (int o = 16; o; o >>= 1) { s += __shfl_xor_sync(0xffffffffu, s, o); s2 += __shfl_xor_sync(0xffffffffu, s2, o); }
    __shared__ float red[18];
    int w = tid >> 5, l = tid & 31;
    if (l == 0) { red[w] = s; red[8 + w] = s2; }
    __syncthreads();
    if (tid == 0) {
        float ts = 0.f, ts2 = 0.f;
        for (int i = 0; i < 8; i++) { ts += red[i]; ts2 += red[8 + i]; }
        float m = ts * (1.f / DIMC);
        float var = ts2 * (1.f / DIMC) - m * m;
        red[16] = m; red[17] = rsqrtf(var + 1e-5f);
    }
    __syncthreads();
    float m = red[16], rs = red[17];
    int din = DIMC >> (3 - em[t]);
    int c = tid * 4;
    float4 gg = ((const float4*)g)[tid];
    float4 bb = ((const float4*)b)[tid];
    float o0 = (c + 0 < din) ? ((v.x - m) * rs * gg.x + bb.x) : 0.f;
    float o1 = (c + 1 < din) ? ((v.y - m) * rs * gg.y + bb.y) : 0.f;
    float o2 = (c + 2 < din) ? ((v.z - m) * rs * gg.z + bb.z) : 0.f;
    float o3 = (c + 3 < din) ? ((v.w - m) * rs * gg.w + bb.w) : 0.f;
    size_t o = (size_t)t * DIMC + c;
    *(uint32_t*)(g_xn + o)     = pack_h2(__float2half_rn(o0), __float2half_rn(o1));
    *(uint32_t*)(g_xn + o + 2) = pack_h2(__float2half_rn(o2), __float2half_rn(o3));
}

// LN2: which==0 -> k, which==1 -> v. Per-head single fp16.
__global__ void ln2kv_kernel(const float* __restrict__ g, const float* __restrict__ b) {
    int t = blockIdx.x;
    int which = blockIdx.y;
    const float4* row = (const float4*)(g_y + (size_t)t * 2048 + (size_t)DIMC * which);
    int tid = threadIdx.x;
    float4 v = row[tid];
    float s  = v.x + v.y + v.z + v.w;
    float s2 = v.x * v.x + v.y * v.y + v.z * v.z + v.w * v.w;
#pragma unroll
    for (int o = 16; o; o >>= 1) { s += __shfl_xor_sync(0xffffffffu, s, o); s2 += __shfl_xor_sync(0xffffffffu, s2, o); }
    __shared__ float red[18];
    int w = tid >> 5, l = tid & 31;
    if (l == 0) { red[w] = s; red[8 + w] = s2; }
    __syncthreads();
    if (tid == 0) {
        float ts = 0.f, ts2 = 0.f;
        for (int i = 0; i < 8; i++) { ts += red[i]; ts2 += red[8 + i]; }
        float m = ts * (1.f / DIMC);
        float var = ts2 * (1.f / DIMC) - m * m;
        red[16] = m; red[17] = rsqrtf(var + 1e-5f);
    }
    __syncthreads();
    float m = red[16], rs = red[17];
    int bb2 = t >> 10, ss = t & 1023;
    int c = tid * 4;
    float4 gg = ((const float4*)g)[tid];
    float4 bv = ((const float4*)b)[tid];
    float o0 = (v.x - m) * rs * gg.x + bv.x;
    float o1 = (v.y - m) * rs * gg.y + bv.y;
    float o2 = (v.z - m) * rs * gg.z + bv.z;
    float o3 = (v.w - m) * rs * gg.w + bv.w;
    int hh = c >> 6, hd = c & 63;
    size_t o = ((size_t)(bb2 * NHC + hh) * SEQC + ss) * HDC + hd;
    __half* d = which ? g_v : g_k;
    *(uint32_t*)(d + o)     = pack_h2(__float2half_rn(o0), __float2half_rn(o1));
    *(uint32_t*)(d + o + 2) = pack_h2(__float2half_rn(o2), __float2half_rn(o3));
}

// Final epilogue + pass-through tails (merged)
__global__ void final_kernel(const float* __restrict__ x, const int* __restrict__ em,
                             const float* __restrict__ rp, const float* __restrict__ cb,
                             const float* __restrict__ alpha, float* __restrict__ out) {
    size_t idx = (size_t)blockIdx.x * 256 + threadIdx.x;
    int t = (int)(idx >> 10);
    int d = (int)(idx & 1023);
    int m = em[t];
    int dout = (2 * DIMC) >> (3 - m);
    const float* zr = g_z + (size_t)t * 2 * DIMC;
    float za = (d < dout) ? (zr[d] + cb[d]) : 0.f;
    float zm = (DIMC + d < dout) ? (zr[DIMC + d] + cb[DIMC + d]) : 0.f;
    float pr = rp[t * 4 + m];
    out[idx] = x[idx] + za + (alpha[0] * pr + 1.f) * zm;
    if (idx < TOK)     out[(size_t)TOK * DIMC + idx] = (float)em[idx];
    if (idx < TOK * 4) out[(size_t)TOK * DIMC + TOK + idx] = rp[idx];
}

// ---------------------------------------------------------------------------
extern "C" void kernel_launch(void* const* d_in, const int* in_sizes, int n_in,
                              void* d_out, int out_size) {
    const float* x     = (const float*)d_in[0];
    const int*   em    = (const int*)d_in[1];
    const float* rp    = (const float*)d_in[2];
    const float* wexp  = (const float*)d_in[3];
    const float* mlpb  = (const float*)d_in[4];
    const float* wc    = (const float*)d_in[5];
    const float* cb    = (const float*)d_in[6];
    const float* n1g   = (const float*)d_in[7];
    const float* n1b   = (const float*)d_in[8];
    const float* n2g   = (const float*)d_in[9];
    const float* n2b   = (const float*)d_in[10];
    const float* alpha = (const float*)d_in[11];
    float* out = (float*)d_out;

    float *p_z;
    __half *p_xn, *p_we, *p_wc, *p_h;
    cudaGetSymbolAddress((void**)&p_z,  g_z);
    cudaGetSymbolAddress((void**)&p_xn, g_xn);
    cudaGetSymbolAddress((void**)&p_we, g_we);
    cudaGetSymbolAddress((void**)&p_wc, g_wc);
    cudaGetSymbolAddress((void**)&p_h,  g_h);

    cudaFuncSetAttribute(gemm_grouped_kernel<0>, cudaFuncAttributeMaxDynamicSharedMemorySize, GSM);
    cudaFuncSetAttribute(gemm_grouped_kernel<1>, cudaFuncAttributeMaxDynamicSharedMemorySize, GSM);
    cudaFuncSetAttribute(flash_kernel,           cudaFuncAttributeMaxDynamicSharedMemorySize, FSM);

    // 0) expert permutation (single CTA)
    perm_kernel<<<1, 1024>>>(em);

    // 0b) weight converts (fp32 -> fp16)
    convw_kernel<<<(EXPC * DIMC) / 4 / 256, 256>>>(wexp, p_we);
    convw_kernel<<<(2 * DIMC * CINC) / 4 / 256, 256>>>(wc, p_wc);

    // 1) LN1 + input mask -> xn fp16
    ln1_kernel<<<TOK, 256>>>(x, em, n1g, n1b);

    // 2) expand (grouped, plain fp16, fused epilogue)
    gemm_grouped_kernel<1><<<dim3(EXPC / 128, TOK / 128, 4), 512, GSM>>>(
        p_xn, DIMC, p_we, DIMC, nullptr, 0, mlpb,
        128, 1, EXPC, 0);

    // 3) LN2 -> k and v per-head single fp16
    ln2kv_kernel<<<dim3(TOK, 2), 256>>>(n2g, n2b);

    // 4) flash attention (plain fp16) -> g_h fp16 [:, 0:1024]
    flash_kernel<<<dim3(SEQC / 128, BH), 256, FSM>>>();

    // 5) contract (grouped, plain fp16): z = h @ Wc^T, N_e = 256<<e
    gemm_grouped_kernel<0><<<dim3(16, TOK / 128, 4), 512, GSM>>>(
        p_h, CINC, p_wc, CINC, p_z, 2 * DIMC, nullptr,
        CINC, 0, 256, 1);

    // 6) epilogue + tails (merged)
    final_kernel<<<(TOK * DIMC) / 256, 256>>>(x, em, rp, cb, alpha, out);
}

// round 13
// speedup vs baseline: 11.5378x; 1.0534x over previous
#include <cuda_runtime.h>
#include <cuda_fp16.h>
#include <math.h>
#include <stdint.h>

// Problem constants
#define TOK   8192        // B*N
#define DIMC  1024
#define EXPC  7168
#define CINC  5120
#define NHC   16
#define HDC   64
#define SEQC  1024
#define NB    8
#define BH    (NB * NHC)  // 128 batch-heads

#define LOG2E 1.44269504088896340736f

// ---------------------------------------------------------------------------
// Scratch (device globals; allocation-free)
// ---------------------------------------------------------------------------
__device__ float g_y [(size_t)TOK * 2 * DIMC];                //  67 MB (k,v fp32 pre-LN)
__device__ float g_z [(size_t)TOK * 2 * DIMC];                //  67 MB

__device__ __half g_xn[(size_t)TOK * DIMC];
__device__ __half g_we[(size_t)EXPC * DIMC];
__device__ __half g_wc[(size_t)2 * DIMC * CINC];
__device__ __half g_h [(size_t)TOK * CINC];

// attention operands (per-head [bh][seq][hd]; all single fp16)
__device__ __half g_q[(size_t)BH * SEQC * HDC];
__device__ __half g_k[(size_t)BH * SEQC * HDC];
__device__ __half g_v[(size_t)BH * SEQC * HDC];

// expert grouping
__device__ int g_cnt[4];
__device__ int g_goff[4];
__device__ int g_perm[TOK];

// ---------------------------------------------------------------------------
// PTX helpers
// ---------------------------------------------------------------------------
__device__ __forceinline__ uint32_t smem_u32(const void* p) {
    uint32_t a;
    asm("{ .reg .u64 t; cvta.to.shared.u64 t, %1; cvt.u32.u64 %0, t; }" : "=r"(a) : "l"(p));
    return a;
}
__device__ __forceinline__ void ldsm4(uint32_t* r, uint32_t a) {
    asm volatile("ldmatrix.sync.aligned.m8n8.x4.shared.b16 {%0,%1,%2,%3}, [%4];"
                 : "=r"(r[0]), "=r"(r[1]), "=r"(r[2]), "=r"(r[3]) : "r"(a));
}
__device__ __forceinline__ void ldsm4t(uint32_t* r, uint32_t a) {
    asm volatile("ldmatrix.sync.aligned.m8n8.x4.trans.shared.b16 {%0,%1,%2,%3}, [%4];"
                 : "=r"(r[0]), "=r"(r[1]), "=r"(r[2]), "=r"(r[3]) : "r"(a));
}
__device__ __forceinline__ void mma16816h(float* c, const uint32_t* a, const uint32_t* b) {
    asm volatile("mma.sync.aligned.m16n8k16.row.col.f32.f16.f16.f32 "
                 "{%0,%1,%2,%3}, {%4,%5,%6,%7}, {%8,%9}, {%0,%1,%2,%3};"
                 : "+f"(c[0]), "+f"(c[1]), "+f"(c[2]), "+f"(c[3])
                 : "r"(a[0]), "r"(a[1]), "r"(a[2]), "r"(a[3]), "r"(b[0]), "r"(b[1]));
}
__device__ __forceinline__ void cpa16(uint32_t s, const void* g) {
    asm volatile("cp.async.cg.shared.global [%0], [%1], 16;" :: "r"(s), "l"(g));
}
#define CP_COMMIT() asm volatile("cp.async.commit_group;")
#define CP_WAIT2()  asm volatile("cp.async.wait_group 2;")
#define CP_WAIT1()  asm volatile("cp.async.wait_group 1;")
#define CP_WAIT0()  asm volatile("cp.async.wait_group 0;")

#define SWZ(o) ((o) ^ (((o) >> 3) & 0x70))

__device__ __forceinline__ uint32_t pack_h2(__half a, __half b) {
    __half2 v(a, b);
    return *(uint32_t*)&v;
}
__device__ __forceinline__ float gelu1(float x) {
    return 0.5f * x * (1.f + erff(x * 0.70710678118654752f));
}

// ---------------------------------------------------------------------------
// Expert-grouped plain-fp16 HMMA GEMM with row gather. (512 thr, 4x4 warps,
// warp tile 32x32, CTA 128x128, K-chunk 64, 3-stage cp.async, 2 CTAs/SM)
// MODE 0: plain fp32 scatter (contract).
// MODE 1: expand fused epilogue (q fp16 / y fp32 / gelu h fp16).
// ---------------------------------------------------------------------------
#define GOA  0
#define GOB  16384
#define GBUF 32768
#define GSM  (1024 + 3 * GBUF)    // 99328

template<int MODE>
__global__ void __launch_bounds__(512, 2)
gemm_grouped_kernel(const __half* __restrict__ A, int lda,
                    const __half* __restrict__ B, int ldb,
                    float* __restrict__ C, int ldc,
                    const float* __restrict__ mlpb,
                    int Kbase, int Kscale, int Nbase, int Nscale) {
    const int e = blockIdx.z;
    const int cnt  = g_cnt[e];
    const int goff = g_goff[e];
    const int m0 = blockIdx.y * 128;
    if (m0 >= cnt) return;
    const int K    = Kscale ? (Kbase << e) : Kbase;
    const int Nlim = Nscale ? (Nbase << e) : Nbase;
    const int n0 = blockIdx.x * 128;
    if (n0 >= Nlim) return;

    extern __shared__ char smem_raw[];
    uint32_t sb0 = smem_u32(smem_raw);
    sb0 = (sb0 + 1023u) & ~1023u;
    int* tok = (int*)(smem_raw + (sb0 - smem_u32(smem_raw)));
    uint32_t sb = sb0 + 1024u;

    const int tid  = threadIdx.x;
    const int wid  = tid >> 5;
    const int lane = tid & 31;
    const int wm = wid & 3;
    const int wn = wid >> 2;

    if (tid < 128) {
        int gr = m0 + tid;
        tok[tid] = g_perm[goff + ((gr < cnt) ? gr : 0)];
    }
    __syncthreads();

    const __half* BB = B + (size_t)n0 * ldb;

    const int NC = K / 64;

    auto load_chunk = [&](int c) {
        uint32_t bufb = sb + (uint32_t)(c % 3) * GBUF;
        int k0 = c * 64;
#pragma unroll
        for (int it = 0; it < 2; it++) {
            int i = tid + it * 512;
            int r = i >> 3, kg = i & 7;
            const __half* src = A + (size_t)tok[r] * lda + k0 + kg * 8;
            cpa16(bufb + GOA + SWZ(r * 128 + kg * 16), src);
        }
#pragma unroll
        for (int it = 0; it < 2; it++) {
            int i = tid + it * 512;
            int r = i >> 3, kg = i & 7;
            const __half* src = BB + (size_t)r * ldb + k0 + kg * 8;
            cpa16(bufb + GOB + SWZ(r * 128 + kg * 16), src);
        }
        CP_COMMIT();
    };

    load_chunk(0);
    if (NC > 1) load_chunk(1);

    float acc[2][4][4];
#pragma unroll
    for (int i = 0; i < 2; i++)
#pragma unroll
        for (int j = 0; j < 4; j++)
#pragma unroll
            for (int k = 0; k < 4; k++) acc[i][j][k] = 0.f;

    const int a_r16 = lane & 15;
    const int a_kb  = (lane >> 4) * 16;
    const int b_r8  = ((lane >> 4) << 3) + (lane & 7);
    const int b_kb  = ((lane >> 3) & 1) * 16;

    for (int c = 0; c < NC; c++) {
        if (c + 2 < NC) load_chunk(c + 2);
        int pend = NC - 1 - c; if (pend > 2) pend = 2;
        if (pend == 2) CP_WAIT2(); else if (pend == 1) CP_WAIT1(); else CP_WAIT0();
        __syncthreads();

        uint32_t bufb = sb + (uint32_t)(c % 3) * GBUF;
#pragma unroll
        for (int kk = 0; kk < 4; kk++) {
            int kb = kk * 32;
            uint32_t ah[2][4];
#pragma unroll
            for (int mt = 0; mt < 2; mt++) {
                int r = wm * 32 + mt * 16 + a_r16;
                uint32_t off = (uint32_t)(r * 128) + (uint32_t)((kb + a_kb) ^ ((r & 7) << 4));
                ldsm4(ah[mt], bufb + GOA + off);
            }
#pragma unroll
            for (int ntp = 0; ntp < 2; ntp++) {
                int r = wn * 32 + ntp * 16 + b_r8;
                uint32_t off = (uint32_t)(r * 128) + (uint32_t)((kb + b_kb) ^ ((r & 7) << 4));
                uint32_t bf[4];
                ldsm4(bf, bufb + GOB + off);
#pragma unroll
                for (int mt = 0; mt < 2; mt++) {
                    mma16816h(acc[mt][2 * ntp],     ah[mt], bf);
                    mma16816h(acc[mt][2 * ntp + 1], ah[mt], bf + 2);
                }
            }
        }
        __syncthreads();
    }

    const int g = lane >> 2, t4 = lane & 3;

    if (MODE == 0) {
#pragma unroll
        for (int mt = 0; mt < 2; mt++) {
            int r0 = wm * 32 + mt * 16 + g;
            int r1 = r0 + 8;
            int tk0 = tok[r0], tk1 = tok[r1];
            bool ok0 = (m0 + r0) < cnt, ok1 = (m0 + r1) < cnt;
#pragma unroll
            for (int nt = 0; nt < 4; nt++) {
                int ncol = n0 + wn * 32 + nt * 8 + t4 * 2;
                if (ok0) *(float2*)(C + (size_t)tk0 * ldc + ncol) = make_float2(acc[mt][nt][0], acc[mt][nt][1]);
                if (ok1) *(float2*)(C + (size_t)tk1 * ldc + ncol) = make_float2(acc[mt][nt][2], acc[mt][nt][3]);
            }
        }
    } else {
#pragma unroll
        for (int mt = 0; mt < 2; mt++) {
            int r0 = wm * 32 + mt * 16 + g;
            int r1 = r0 + 8;
            int tk0 = tok[r0], tk1 = tok[r1];
            bool ok0 = (m0 + r0) < cnt, ok1 = (m0 + r1) < cnt;
            if (n0 < 1024) {
                // Q region: scale (1/8)*log2e -> g_q fp16 per-head layout
#pragma unroll
                for (int nt = 0; nt < 4; nt++) {
                    int d = n0 + wn * 32 + nt * 8 + t4 * 2;
                    int h = d >> 6, hd = d & 63;
                    const float QS = 0.125f * LOG2E;
                    if (ok0) {
                        size_t o = ((size_t)((tk0 >> 10) * NHC + h) * SEQC + (tk0 & 1023)) * HDC + hd;
                        *(uint32_t*)(g_q + o) = pack_h2(__float2half_rn(acc[mt][nt][0] * QS),
                                                       __float2half_rn(acc[mt][nt][1] * QS));
                    }
                    if (ok1) {
                        size_t o = ((size_t)((tk1 >> 10) * NHC + h) * SEQC + (tk1 & 1023)) * HDC + hd;
                        *(uint32_t*)(g_q + o) = pack_h2(__float2half_rn(acc[mt][nt][2] * QS),
                                                       __float2half_rn(acc[mt][nt][3] * QS));
                    }
                }
            } else if (n0 < 3072) {
                // K/V region: fp32 to g_y [TOK][2048]
#pragma unroll
                for (int nt = 0; nt < 4; nt++) {
                    int col = n0 - 1024 + wn * 32 + nt * 8 + t4 * 2;
                    if (ok0) *(float2*)(g_y + (size_t)tk0 * 2048 + col) = make_float2(acc[mt][nt][0], acc[mt][nt][1]);
                    if (ok1) *(float2*)(g_y + (size_t)tk1 * 2048 + col) = make_float2(acc[mt][nt][2], acc[mt][nt][3]);
                }
            } else {
                // MLP region: +bias, GELU -> g_h fp16 [:, 1024+j]
#pragma unroll
                for (int nt = 0; nt < 4; nt++) {
                    int j = n0 - 3072 + wn * 32 + nt * 8 + t4 * 2;
                    float b0 = mlpb[j], b1 = mlpb[j + 1];
                    if (ok0) {
                        __half u0 = __float2half_rn(gelu1(acc[mt][nt][0] + b0));
                        __half u1 = __float2half_rn(gelu1(acc[mt][nt][1] + b1));
                        *(uint32_t*)(g_h + (size_t)tk0 * CINC + 1024 + j) = pack_h2(u0, u1);
                    }
                    if (ok1) {
                        __half u0 = __float2half_rn(gelu1(acc[mt][nt][2] + b0));
                        __half u1 = __float2half_rn(gelu1(acc[mt][nt][3] + b1));
                        *(uint32_t*)(g_h + (size_t)tk1 * CINC + 1024 + j) = pack_h2(u0, u1);
                    }
                }
            }
        }
    }
}

// ---------------------------------------------------------------------------
// Flash attention (all single fp16): S = Q K, O = P V. 49 KB smem, 2 CTAs/SM.
// ---------------------------------------------------------------------------
#define FQ  0
#define FST 16384
#define FSS 16384
#define FSM (16384 + 2 * 16384 + 1024)   // 50176

__global__ void __launch_bounds__(256, 2)
flash_kernel() {
    extern __shared__ char smem_raw[];
    uint32_t sb = smem_u32(smem_raw);
    sb = (sb + 1023u) & ~1023u;

    const int tid  = threadIdx.x;
    const int wid  = tid >> 5;
    const int lane = tid & 31;
    const int bh = blockIdx.y;
    const int q0 = blockIdx.x * 128;
    const int b = bh >> 4, h = bh & 15;

    const size_t base = (size_t)bh * SEQC * HDC;

    auto load_q = [&]() {
#pragma unroll
        for (int it = 0; it < 4; it++) {
            int i = tid + it * 256;
            int r = i >> 3, kg = i & 7;
            const __half* src = g_q + base + (size_t)(q0 + r) * HDC + kg * 8;
            cpa16(sb + FQ + SWZ(r * 128 + kg * 16), src);
        }
    };
    auto load_kv = [&](int t) {
        uint32_t bufb = sb + FST + (uint32_t)(t & 1) * FSS;
#pragma unroll
        for (int it = 0; it < 2; it++) {
            int i = tid + it * 256;
            int r = i >> 3, kg = i & 7;
            const __half* src = g_k + base + (size_t)(t * 64 + r) * HDC + kg * 8;
            cpa16(bufb + SWZ(r * 128 + kg * 16), src);
        }
#pragma unroll
        for (int it = 0; it < 2; it++) {
            int i = tid + it * 256;
            int r = i >> 3, kg = i & 7;
            const __half* src = g_v + base + (size_t)(t * 64 + r) * HDC + kg * 8;
            cpa16(bufb + 8192 + SWZ(r * 128 + kg * 16), src);
        }
        CP_COMMIT();
    };

    load_q(); load_kv(0); CP_COMMIT();
    load_kv(1);

    const int a_r16 = lane & 15;
    const int a_kb  = (lane >> 4) * 16;
    const int b_r8  = ((lane >> 4) << 3) + (lane & 7);
    const int b_kb  = ((lane >> 3) & 1) * 16;
    const int v_r  = ((lane >> 3) & 1) * 8 + (lane & 7);
    const int v_cb = (lane >> 4) * 16;

    uint32_t qf[4][4];
    float o[8][4];
#pragma unroll
    for (int j = 0; j < 8; j++)
#pragma unroll
        for (int k = 0; k < 4; k++) o[j][k] = 0.f;
    float ml0 = -1e30f, ml1 = -1e30f, ls0 = 0.f, ls1 = 0.f;

    for (int t = 0; t < 16; t++) {
        if (t < 15) CP_WAIT1(); else CP_WAIT0();
        __syncthreads();
        if (t == 0) {
#pragma unroll
            for (int kk = 0; kk < 4; kk++) {
                int r = wid * 16 + a_r16;
                uint32_t off = (uint32_t)(r * 128) + (uint32_t)((kk * 32 + a_kb) ^ ((r & 7) << 4));
                ldsm4(qf[kk], sb + FQ + off);
            }
        }
        uint32_t bufb = sb + FST + (uint32_t)(t & 1) * FSS;

        float s[8][4];
#pragma unroll
        for (int j = 0; j < 8; j++)
#pragma unroll
            for (int k = 0; k < 4; k++) s[j][k] = 0.f;
#pragma unroll
        for (int kk = 0; kk < 4; kk++) {
#pragma unroll
            for (int ntp = 0; ntp < 4; ntp++) {
                int r = ntp * 16 + b_r8;
                uint32_t off = (uint32_t)(r * 128) + (uint32_t)((kk * 32 + b_kb) ^ ((r & 7) << 4));
                uint32_t kf[4];
                ldsm4(kf, bufb + off);
                mma16816h(s[2 * ntp],     qf[kk], kf);
                mma16816h(s[2 * ntp + 1], qf[kk], kf + 2);
            }
        }

        float m0t = -1e30f, m1t = -1e30f;
#pragma unroll
        for (int j = 0; j < 8; j++) {
            m0t = fmaxf(m0t, fmaxf(s[j][0], s[j][1]));
            m1t = fmaxf(m1t, fmaxf(s[j][2], s[j][3]));
        }
        m0t = fmaxf(m0t, __shfl_xor_sync(0xffffffffu, m0t, 1));
        m0t = fmaxf(m0t, __shfl_xor_sync(0xffffffffu, m0t, 2));
        m1t = fmaxf(m1t, __shfl_xor_sync(0xffffffffu, m1t, 1));
        m1t = fmaxf(m1t, __shfl_xor_sync(0xffffffffu, m1t, 2));
        float mn0 = fmaxf(ml0, m0t), mn1 = fmaxf(ml1, m1t);
        float sc0 = exp2f(ml0 - mn0), sc1 = exp2f(ml1 - mn1);
        ml0 = mn0; ml1 = mn1;
        float r0 = 0.f, r1 = 0.f;
#pragma unroll
        for (int j = 0; j < 8; j++) {
            s[j][0] = exp2f(s[j][0] - mn0);
            s[j][1] = exp2f(s[j][1] - mn0);
            s[j][2] = exp2f(s[j][2] - mn1);
            s[j][3] = exp2f(s[j][3] - mn1);
            r0 += s[j][0] + s[j][1];
            r1 += s[j][2] + s[j][3];
        }
        r0 += __shfl_xor_sync(0xffffffffu, r0, 1);
        r0 += __shfl_xor_sync(0xffffffffu, r0, 2);
        r1 += __shfl_xor_sync(0xffffffffu, r1, 1);
        r1 += __shfl_xor_sync(0xffffffffu, r1, 2);
        ls0 = ls0 * sc0 + r0;
        ls1 = ls1 * sc1 + r1;
#pragma unroll
        for (int j = 0; j < 8; j++) {
            o[j][0] *= sc0; o[j][1] *= sc0;
            o[j][2] *= sc1; o[j][3] *= sc1;
        }

        // pack P (single fp16) into A fragments
        uint32_t pa[4][4];
#pragma unroll
        for (int kt = 0; kt < 4; kt++) {
            pa[kt][0] = pack_h2(__float2half_rn(s[2 * kt][0]),     __float2half_rn(s[2 * kt][1]));
            pa[kt][1] = pack_h2(__float2half_rn(s[2 * kt][2]),     __float2half_rn(s[2 * kt][3]));
            pa[kt][2] = pack_h2(__float2half_rn(s[2 * kt + 1][0]), __float2half_rn(s[2 * kt + 1][1]));
            pa[kt][3] = pack_h2(__float2half_rn(s[2 * kt + 1][2]), __float2half_rn(s[2 * kt + 1][3]));
        }

        // O += P V (V via ldmatrix.trans from [keys][hd] tile)
#pragma unroll
        for (int kt = 0; kt < 4; kt++) {
#pragma unroll
            for (int nv = 0; nv < 4; nv++) {
                int r = kt * 16 + v_r;
                uint32_t off = (uint32_t)(r * 128) + (uint32_t)((nv * 32 + v_cb) ^ ((r & 7) << 4));
                uint32_t vf[4];
                ldsm4t(vf, bufb + 8192 + off);
                mma16816h(o[2 * nv],     pa[kt], vf);
                mma16816h(o[2 * nv + 1], pa[kt], vf + 2);
            }
        }
        __syncthreads();
        if (t + 2 < 16) load_kv(t + 2);
    }

    const int g = lane >> 2, t4 = lane & 3;
    float i0 = 1.f / ls0, i1 = 1.f / ls1;
    int tok0 = b * 1024 + q0 + wid * 16 + g;
    int tok1 = tok0 + 8;
#pragma unroll
    for (int j = 0; j < 8; j++) {
        int col = h * 64 + j * 8 + t4 * 2;
        *(uint32_t*)(g_h + (size_t)tok0 * CINC + col) =
            pack_h2(__float2half_rn(o[j][0] * i0), __float2half_rn(o[j][1] * i0));
        *(uint32_t*)(g_h + (size_t)tok1 * CINC + col) =
            pack_h2(__float2half_rn(o[j][2] * i1), __float2half_rn(o[j][3] * i1));
    }
}

// ---------------------------------------------------------------------------
// Expert permutation: single CTA
// ---------------------------------------------------------------------------
__global__ void __launch_bounds__(1024) perm_kernel(const int* __restrict__ em) {
    __shared__ int cnt[4], off[4], cur[4];
    int tid = threadIdx.x;
    if (tid < 4) { cnt[tid] = 0; cur[tid] = 0; }
    __syncthreads();
    int ev[8];
#pragma unroll
    for (int i = 0; i < 8; i++) {
        ev[i] = em[tid + i * 1024];
        atomicAdd(&cnt[ev[i]], 1);
    }
    __syncthreads();
    if (tid == 0) {
        int o = 0;
        for (int j = 0; j < 4; j++) { off[j] = o; g_goff[j] = o; g_cnt[j] = cnt[j]; o += cnt[j]; }
    }
    __syncthreads();
#pragma unroll
    for (int i = 0; i < 8; i++) {
        int p = atomicAdd(&cur[ev[i]], 1);
        g_perm[off[ev[i]] + p] = tid + i * 1024;
    }
}

// weight convert (fp32 -> fp16)
__global__ void convw_kernel(const float* __restrict__ s, __half* __restrict__ d) {
    size_t i = (size_t)blockIdx.x * 256 + threadIdx.x;
    float4 v = ((const float4*)s)[i];
    ((uint32_t*)d)[2 * i]     = pack_h2(__float2half_rn(v.x), __float2half_rn(v.y));
    ((uint32_t*)d)[2 * i + 1] = pack_h2(__float2half_rn(v.z), __float2half_rn(v.w));
}

// LN1 -> masked xn fp16
__global__ void ln1_kernel(const float* __restrict__ x, const int* __restrict__ em,
                           const float* __restrict__ g, const float* __restrict__ b) {
    int t = blockIdx.x;
    const float4* xr = (const float4*)(x + (size_t)t * DIMC);
    int tid = threadIdx.x;
    float4 v = xr[tid];
    float s  = v.x + v.y + v.z + v.w;
    float s2 = v.x * v.x + v.y * v.y + v.z * v.z + v.w * v.w;
#pragma unroll
    for (int o = 16; o; o >>= 1) { s += __shfl_xor_sync(0xffffffffu, s, o); s2 += __shfl_xor_sync(0xffffffffu, s2, o); }
    __shared__ float red[18];
    int w = tid >> 5, l = tid & 31;
    if (l == 0) { red[w] = s; red[8 + w] = s2; }
    __syncthreads();
    if (tid == 0) {
        float ts = 0.f, ts2 = 0.f;
        for (int i = 0; i < 8; i++) { ts += red[i]; ts2 += red[8 + i]; }
        float m = ts * (1.f / DIMC);
        float var = ts2 * (1.f / DIMC) - m * m;
        red[16] = m; red[17] = rsqrtf(var + 1e-5f);
    }
    __syncthreads();
    float m = red[16], rs = red[17];
    int din = DIMC >> (3 - em[t]);
    int c = tid * 4;
    float4 gg = ((const float4*)g)[tid];
    float4 bb = ((const float4*)b)[tid];
    float o0 = (c + 0 < din) ? ((v.x - m) * rs * gg.x + bb.x) : 0.f;
    float o1 = (c + 1 < din) ? ((v.y - m) * rs * gg.y + bb.y) : 0.f;
    float o2 = (c + 2 < din) ? ((v.z - m) * rs * gg.z + bb.z) : 0.f;
    float o3 = (c + 3 < din) ? ((v.w - m) * rs * gg.w + bb.w) : 0.f;
    size_t o = (size_t)t * DIMC + c;
    *(uint32_t*)(g_xn + o)     = pack_h2(__float2half_rn(o0), __float2half_rn(o1));
    *(uint32_t*)(g_xn + o + 2) = pack_h2(__float2half_rn(o2), __float2half_rn(o3));
}

// LN2: which==0 -> k, which==1 -> v. Per-head single fp16.
__global__ void ln2kv_kernel(const float* __restrict__ g, const float* __restrict__ b) {
    int t = blockIdx.x;
    int which = blockIdx.y;
    const float4* row = (const float4*)(g_y + (size_t)t * 2048 + (size_t)DIMC * which);
    int tid = threadIdx.x;
    float4 v = row[tid];
    float s  = v.x + v.y + v.z + v.w;
    float s2 = v.x * v.x + v.y * v.y + v.z * v.z + v.w * v.w;
#pragma unroll
    for (int o = 16; o; o >>= 1) { s += __shfl_xor_sync(0xffffffffu, s, o); s2 += __shfl_xor_sync(0xffffffffu, s2, o); }
    __shared__ float red[18];
    int w = tid >> 5, l = tid & 31;
    if (l == 0) { red[w] = s; red[8 + w] = s2; }
    __syncthreads();
    if (tid == 0) {
        float ts = 0.f, ts2 = 0.f;
        for (int i = 0; i < 8; i++) { ts += red[i]; ts2 += red[8 + i]; }
        float m = ts * (1.f / DIMC);
        float var = ts2 * (1.f / DIMC) - m * m;
        red[16] = m; red[17] = rsqrtf(var + 1e-5f);
    }
    __syncthreads();
    float m = red[16], rs = red[17];
    int bb2 = t >> 10, ss = t & 1023;
    int c = tid * 4;
    float4 gg = ((const float4*)g)[tid];
    float4 bv = ((const float4*)b)[tid];
    float o0 = (v.x - m) * rs * gg.x + bv.x;
    float o1 = (v.y - m) * rs * gg.y + bv.y;
    float o2 = (v.z - m) * rs * gg.z + bv.z;
    float o3 = (v.w - m) * rs * gg.w + bv.w;
    int hh = c >> 6, hd = c & 63;
    size_t o = ((size_t)(bb2 * NHC + hh) * SEQC + ss) * HDC + hd;
    __half* d = which ? g_v : g_k;
    *(uint32_t*)(d + o)     = pack_h2(__float2half_rn(o0), __float2half_rn(o1));
    *(uint32_t*)(d + o + 2) = pack_h2(__float2half_rn(o2), __float2half_rn(o3));
}

// Final epilogue + pass-through tails (merged)
__global__ void final_kernel(const float* __restrict__ x, const int* __restrict__ em,
                             const float* __restrict__ rp, const float* __restrict__ cb,
                             const float* __restrict__ alpha, float* __restrict__ out) {
    size_t idx = (size_t)blockIdx.x * 256 + threadIdx.x;
    int t = (int)(idx >> 10);
    int d = (int)(idx & 1023);
    int m = em[t];
    int dout = (2 * DIMC) >> (3 - m);
    const float* zr = g_z + (size_t)t * 2 * DIMC;
    float za = (d < dout) ? (zr[d] + cb[d]) : 0.f;
    float zm = (DIMC + d < dout) ? (zr[DIMC + d] + cb[DIMC + d]) : 0.f;
    float pr = rp[t * 4 + m];
    out[idx] = x[idx] + za + (alpha[0] * pr + 1.f) * zm;
    if (idx < TOK)     out[(size_t)TOK * DIMC + idx] = (float)em[idx];
    if (idx < TOK * 4) out[(size_t)TOK * DIMC + TOK + idx] = rp[idx];
}

// ---------------------------------------------------------------------------
extern "C" void kernel_launch(void* const* d_in, const int* in_sizes, int n_in,
                              void* d_out, int out_size) {
    const float* x     = (const float*)d_in[0];
    const int*   em    = (const int*)d_in[1];
    const float* rp    = (const float*)d_in[2];
    const float* wexp  = (const float*)d_in[3];
    const float* mlpb  = (const float*)d_in[4];
    const float* wc    = (const float*)d_in[5];
    const float* cb    = (const float*)d_in[6];
    const float* n1g   = (const float*)d_in[7];
    const float* n1b   = (const float*)d_in[8];
    const float* n2g   = (const float*)d_in[9];
    const float* n2b   = (const float*)d_in[10];
    const float* alpha = (const float*)d_in[11];
    float* out = (float*)d_out;

    float *p_z;
    __half *p_xn, *p_we, *p_wc, *p_h;
    cudaGetSymbolAddress((void**)&p_z,  g_z);
    cudaGetSymbolAddress((void**)&p_xn, g_xn);
    cudaGetSymbolAddress((void**)&p_we, g_we);
    cudaGetSymbolAddress((void**)&p_wc, g_wc);
    cudaGetSymbolAddress((void**)&p_h,  g_h);

    cudaFuncSetAttribute(gemm_grouped_kernel<0>, cudaFuncAttributeMaxDynamicSharedMemorySize, GSM);
    cudaFuncSetAttribute(gemm_grouped_kernel<1>, cudaFuncAttributeMaxDynamicSharedMemorySize, GSM);
    cudaFuncSetAttribute(flash_kernel,           cudaFuncAttributeMaxDynamicSharedMemorySize, FSM);

    // 0) expert permutation (single CTA)
    perm_kernel<<<1, 1024>>>(em);

    // 0b) weight converts (fp32 -> fp16)
    convw_kernel<<<(EXPC * DIMC) / 4 / 256, 256>>>(wexp, p_we);
    convw_kernel<<<(2 * DIMC * CINC) / 4 / 256, 256>>>(wc, p_wc);

    // 1) LN1 + input mask -> xn fp16
    ln1_kernel<<<TOK, 256>>>(x, em, n1g, n1b);

    // 2) expand (grouped, plain fp16, fused epilogue)
    gemm_grouped_kernel<1><<<dim3(EXPC / 128, TOK / 128, 4), 512, GSM>>>(
        p_xn, DIMC, p_we, DIMC, nullptr, 0, mlpb,
        128, 1, EXPC, 0);

    // 3) LN2 -> k and v per-head single fp16
    ln2kv_kernel<<<dim3(TOK, 2), 256>>>(n2g, n2b);

    // 4) flash attention (plain fp16) -> g_h fp16 [:, 0:1024]
    flash_kernel<<<dim3(SEQC / 128, BH), 256, FSM>>>();

    // 5) contract (grouped, plain fp16): z = h @ Wc^T, N_e = 256<<e
    gemm_grouped_kernel<0><<<dim3(16, TOK / 128, 4), 512, GSM>>>(
        p_h, CINC, p_wc, CINC, p_z, 2 * DIMC, nullptr,
        CINC, 0, 256, 1);

    // 6) epilogue + tails (merged)
    final_kernel<<<(TOK * DIMC) / 256, 256>>>(x, em, rp, cb, alpha, out);
}

// round 14
// speedup vs baseline: 11.5721x; 1.0030x over previous
#include <cuda_runtime.h>
#include <cuda_fp16.h>
#include <math.h>
#include <stdint.h>

// Problem constants
#define TOK   8192        // B*N
#define DIMC  1024
#define EXPC  7168
#define CINC  5120
#define NHC   16
#define HDC   64
#define SEQC  1024
#define NB    8
#define BH    (NB * NHC)  // 128 batch-heads

#define LOG2E 1.44269504088896340736f

// ---------------------------------------------------------------------------
// Scratch (device globals; allocation-free)
// ---------------------------------------------------------------------------
__device__ __half g_yh[(size_t)TOK * 2 * DIMC];               // 34 MB (k,v pre-LN fp16)
__device__ __half g_zh[(size_t)TOK * 2 * DIMC];               // 34 MB (contract out fp16)

__device__ __half g_xn[(size_t)TOK * DIMC];
__device__ __half g_we[(size_t)EXPC * DIMC];
__device__ __half g_wc[(size_t)2 * DIMC * CINC];
__device__ __half g_h [(size_t)TOK * CINC];

// attention operands (per-head [bh][seq][hd]; all single fp16)
__device__ __half g_q[(size_t)BH * SEQC * HDC];
__device__ __half g_k[(size_t)BH * SEQC * HDC];
__device__ __half g_v[(size_t)BH * SEQC * HDC];

// expert grouping
__device__ int g_cnt[4];
__device__ int g_goff[4];
__device__ int g_perm[TOK];

// ---------------------------------------------------------------------------
// PTX helpers
// ---------------------------------------------------------------------------
__device__ __forceinline__ uint32_t smem_u32(const void* p) {
    uint32_t a;
    asm("{ .reg .u64 t; cvta.to.shared.u64 t, %1; cvt.u32.u64 %0, t; }" : "=r"(a) : "l"(p));
    return a;
}
__device__ __forceinline__ void ldsm4(uint32_t* r, uint32_t a) {
    asm volatile("ldmatrix.sync.aligned.m8n8.x4.shared.b16 {%0,%1,%2,%3}, [%4];"
                 : "=r"(r[0]), "=r"(r[1]), "=r"(r[2]), "=r"(r[3]) : "r"(a));
}
__device__ __forceinline__ void ldsm4t(uint32_t* r, uint32_t a) {
    asm volatile("ldmatrix.sync.aligned.m8n8.x4.trans.shared.b16 {%0,%1,%2,%3}, [%4];"
                 : "=r"(r[0]), "=r"(r[1]), "=r"(r[2]), "=r"(r[3]) : "r"(a));
}
__device__ __forceinline__ void mma16816h(float* c, const uint32_t* a, const uint32_t* b) {
    asm volatile("mma.sync.aligned.m16n8k16.row.col.f32.f16.f16.f32 "
                 "{%0,%1,%2,%3}, {%4,%5,%6,%7}, {%8,%9}, {%0,%1,%2,%3};"
                 : "+f"(c[0]), "+f"(c[1]), "+f"(c[2]), "+f"(c[3])
                 : "r"(a[0]), "r"(a[1]), "r"(a[2]), "r"(a[3]), "r"(b[0]), "r"(b[1]));
}
__device__ __forceinline__ void cpa16(uint32_t s, const void* g) {
    asm volatile("cp.async.cg.shared.global [%0], [%1], 16;" :: "r"(s), "l"(g));
}
#define CP_COMMIT() asm volatile("cp.async.commit_group;")
#define CP_WAIT2()  asm volatile("cp.async.wait_group 2;")
#define CP_WAIT1()  asm volatile("cp.async.wait_group 1;")
#define CP_WAIT0()  asm volatile("cp.async.wait_group 0;")

#define SWZ(o) ((o) ^ (((o) >> 3) & 0x70))

__device__ __forceinline__ uint32_t pack_h2(__half a, __half b) {
    __half2 v(a, b);
    return *(uint32_t*)&v;
}
__device__ __forceinline__ float gelu1(float x) {
    return 0.5f * x * (1.f + erff(x * 0.70710678118654752f));
}

// ---------------------------------------------------------------------------
// Expert-grouped plain-fp16 HMMA GEMM with row gather. (512 thr, 4x4 warps,
// warp tile 32x32, CTA 128x128, K-chunk 64, 3-stage cp.async, 2 CTAs/SM)
// MODE 0: contract -> g_zh fp16.
// MODE 1: expand fused epilogue (q fp16 / y fp16 / gelu h fp16).
// ---------------------------------------------------------------------------
#define GOA  0
#define GOB  16384
#define GBUF 32768
#define GSM  (1024 + 3 * GBUF)    // 99328

template<int MODE>
__global__ void __launch_bounds__(512, 2)
gemm_grouped_kernel(const __half* __restrict__ A, int lda,
                    const __half* __restrict__ B, int ldb,
                    const float* __restrict__ mlpb,
                    int Kbase, int Kscale, int Nbase, int Nscale) {
    const int e = blockIdx.z;
    const int cnt  = g_cnt[e];
    const int goff = g_goff[e];
    const int m0 = blockIdx.y * 128;
    if (m0 >= cnt) return;
    const int K    = Kscale ? (Kbase << e) : Kbase;
    const int Nlim = Nscale ? (Nbase << e) : Nbase;
    const int n0 = blockIdx.x * 128;
    if (n0 >= Nlim) return;

    extern __shared__ char smem_raw[];
    uint32_t sb0 = smem_u32(smem_raw);
    sb0 = (sb0 + 1023u) & ~1023u;
    int* tok = (int*)(smem_raw + (sb0 - smem_u32(smem_raw)));
    uint32_t sb = sb0 + 1024u;

    const int tid  = threadIdx.x;
    const int wid  = tid >> 5;
    const int lane = tid & 31;
    const int wm = wid & 3;
    const int wn = wid >> 2;

    if (tid < 128) {
        int gr = m0 + tid;
        tok[tid] = g_perm[goff + ((gr < cnt) ? gr : 0)];
    }
    __syncthreads();

    const __half* BB = B + (size_t)n0 * ldb;

    const int NC = K / 64;

    auto load_chunk = [&](int c) {
        uint32_t bufb = sb + (uint32_t)(c % 3) * GBUF;
        int k0 = c * 64;
#pragma unroll
        for (int it = 0; it < 2; it++) {
            int i = tid + it * 512;
            int r = i >> 3, kg = i & 7;
            const __half* src = A + (size_t)tok[r] * lda + k0 + kg * 8;
            cpa16(bufb + GOA + SWZ(r * 128 + kg * 16), src);
        }
#pragma unroll
        for (int it = 0; it < 2; it++) {
            int i = tid + it * 512;
            int r = i >> 3, kg = i & 7;
            const __half* src = BB + (size_t)r * ldb + k0 + kg * 8;
            cpa16(bufb + GOB + SWZ(r * 128 + kg * 16), src);
        }
        CP_COMMIT();
    };

    load_chunk(0);
    if (NC > 1) load_chunk(1);

    float acc[2][4][4];
#pragma unroll
    for (int i = 0; i < 2; i++)
#pragma unroll
        for (int j = 0; j < 4; j++)
#pragma unroll
            for (int k = 0; k < 4; k++) acc[i][j][k] = 0.f;

    const int a_r16 = lane & 15;
    const int a_kb  = (lane >> 4) * 16;
    const int b_r8  = ((lane >> 4) << 3) + (lane & 7);
    const int b_kb  = ((lane >> 3) & 1) * 16;

    for (int c = 0; c < NC; c++) {
        if (c + 2 < NC) load_chunk(c + 2);
        int pend = NC - 1 - c; if (pend > 2) pend = 2;
        if (pend == 2) CP_WAIT2(); else if (pend == 1) CP_WAIT1(); else CP_WAIT0();
        __syncthreads();

        uint32_t bufb = sb + (uint32_t)(c % 3) * GBUF;
#pragma unroll
        for (int kk = 0; kk < 4; kk++) {
            int kb = kk * 32;
            uint32_t ah[2][4];
#pragma unroll
            for (int mt = 0; mt < 2; mt++) {
                int r = wm * 32 + mt * 16 + a_r16;
                uint32_t off = (uint32_t)(r * 128) + (uint32_t)((kb + a_kb) ^ ((r & 7) << 4));
                ldsm4(ah[mt], bufb + GOA + off);
            }
#pragma unroll
            for (int ntp = 0; ntp < 2; ntp++) {
                int r = wn * 32 + ntp * 16 + b_r8;
                uint32_t off = (uint32_t)(r * 128) + (uint32_t)((kb + b_kb) ^ ((r & 7) << 4));
                uint32_t bf[4];
                ldsm4(bf, bufb + GOB + off);
#pragma unroll
                for (int mt = 0; mt < 2; mt++) {
                    mma16816h(acc[mt][2 * ntp],     ah[mt], bf);
                    mma16816h(acc[mt][2 * ntp + 1], ah[mt], bf + 2);
                }
            }
        }
        __syncthreads();
    }

    const int g = lane >> 2, t4 = lane & 3;

    if (MODE == 0) {
        // contract: write fp16 z
#pragma unroll
        for (int mt = 0; mt < 2; mt++) {
            int r0 = wm * 32 + mt * 16 + g;
            int r1 = r0 + 8;
            int tk0 = tok[r0], tk1 = tok[r1];
            bool ok0 = (m0 + r0) < cnt, ok1 = (m0 + r1) < cnt;
#pragma unroll
            for (int nt = 0; nt < 4; nt++) {
                int ncol = n0 + wn * 32 + nt * 8 + t4 * 2;
                if (ok0) *(uint32_t*)(g_zh + (size_t)tk0 * 2048 + ncol) =
                    pack_h2(__float2half_rn(acc[mt][nt][0]), __float2half_rn(acc[mt][nt][1]));
                if (ok1) *(uint32_t*)(g_zh + (size_t)tk1 * 2048 + ncol) =
                    pack_h2(__float2half_rn(acc[mt][nt][2]), __float2half_rn(acc[mt][nt][3]));
            }
        }
    } else {
#pragma unroll
        for (int mt = 0; mt < 2; mt++) {
            int r0 = wm * 32 + mt * 16 + g;
            int r1 = r0 + 8;
            int tk0 = tok[r0], tk1 = tok[r1];
            bool ok0 = (m0 + r0) < cnt, ok1 = (m0 + r1) < cnt;
            if (n0 < 1024) {
                // Q region: scale (1/8)*log2e -> g_q fp16 per-head layout
#pragma unroll
                for (int nt = 0; nt < 4; nt++) {
                    int d = n0 + wn * 32 + nt * 8 + t4 * 2;
                    int h = d >> 6, hd = d & 63;
                    const float QS = 0.125f * LOG2E;
                    if (ok0) {
                        size_t o = ((size_t)((tk0 >> 10) * NHC + h) * SEQC + (tk0 & 1023)) * HDC + hd;
                        *(uint32_t*)(g_q + o) = pack_h2(__float2half_rn(acc[mt][nt][0] * QS),
                                                       __float2half_rn(acc[mt][nt][1] * QS));
                    }
                    if (ok1) {
                        size_t o = ((size_t)((tk1 >> 10) * NHC + h) * SEQC + (tk1 & 1023)) * HDC + hd;
                        *(uint32_t*)(g_q + o) = pack_h2(__float2half_rn(acc[mt][nt][2] * QS),
                                                       __float2half_rn(acc[mt][nt][3] * QS));
                    }
                }
            } else if (n0 < 3072) {
                // K/V region: fp16 to g_yh [TOK][2048]
#pragma unroll
                for (int nt = 0; nt < 4; nt++) {
                    int col = n0 - 1024 + wn * 32 + nt * 8 + t4 * 2;
                    if (ok0) *(uint32_t*)(g_yh + (size_t)tk0 * 2048 + col) =
                        pack_h2(__float2half_rn(acc[mt][nt][0]), __float2half_rn(acc[mt][nt][1]));
                    if (ok1) *(uint32_t*)(g_yh + (size_t)tk1 * 2048 + col) =
                        pack_h2(__float2half_rn(acc[mt][nt][2]), __float2half_rn(acc[mt][nt][3]));
                }
            } else {
                // MLP region: +bias, GELU -> g_h fp16 [:, 1024+j]
#pragma unroll
                for (int nt = 0; nt < 4; nt++) {
                    int j = n0 - 3072 + wn * 32 + nt * 8 + t4 * 2;
                    float b0 = mlpb[j], b1 = mlpb[j + 1];
                    if (ok0) {
                        __half u0 = __float2half_rn(gelu1(acc[mt][nt][0] + b0));
                        __half u1 = __float2half_rn(gelu1(acc[mt][nt][1] + b1));
                        *(uint32_t*)(g_h + (size_t)tk0 * CINC + 1024 + j) = pack_h2(u0, u1);
                    }
                    if (ok1) {
                        __half u0 = __float2half_rn(gelu1(acc[mt][nt][2] + b0));
                        __half u1 = __float2half_rn(gelu1(acc[mt][nt][3] + b1));
                        *(uint32_t*)(g_h + (size_t)tk1 * CINC + 1024 + j) = pack_h2(u0, u1);
                    }
                }
            }
        }
    }
}

// ---------------------------------------------------------------------------
// Flash attention (all single fp16): S = Q K, O = P V. 49 KB smem, 2 CTAs/SM.
// ---------------------------------------------------------------------------
#define FQ  0
#define FST 16384
#define FSS 16384
#define FSM (16384 + 2 * 16384 + 1024)   // 50176

__global__ void __launch_bounds__(256, 2)
flash_kernel() {
    extern __shared__ char smem_raw[];
    uint32_t sb = smem_u32(smem_raw);
    sb = (sb + 1023u) & ~1023u;

    const int tid  = threadIdx.x;
    const int wid  = tid >> 5;
    const int lane = tid & 31;
    const int bh = blockIdx.y;
    const int q0 = blockIdx.x * 128;
    const int b = bh >> 4, h = bh & 15;

    const size_t base = (size_t)bh * SEQC * HDC;

    auto load_q = [&]() {
#pragma unroll
        for (int it = 0; it < 4; it++) {
            int i = tid + it * 256;
            int r = i >> 3, kg = i & 7;
            const __half* src = g_q + base + (size_t)(q0 + r) * HDC + kg * 8;
            cpa16(sb + FQ + SWZ(r * 128 + kg * 16), src);
        }
    };
    auto load_kv = [&](int t) {
        uint32_t bufb = sb + FST + (uint32_t)(t & 1) * FSS;
#pragma unroll
        for (int it = 0; it < 2; it++) {
            int i = tid + it * 256;
            int r = i >> 3, kg = i & 7;
            const __half* src = g_k + base + (size_t)(t * 64 + r) * HDC + kg * 8;
            cpa16(bufb + SWZ(r * 128 + kg * 16), src);
        }
#pragma unroll
        for (int it = 0; it < 2; it++) {
            int i = tid + it * 256;
            int r = i >> 3, kg = i & 7;
            const __half* src = g_v + base + (size_t)(t * 64 + r) * HDC + kg * 8;
            cpa16(bufb + 8192 + SWZ(r * 128 + kg * 16), src);
        }
        CP_COMMIT();
    };

    load_q(); load_kv(0); CP_COMMIT();
    load_kv(1);

    const int a_r16 = lane & 15;
    const int a_kb  = (lane >> 4) * 16;
    const int b_r8  = ((lane >> 4) << 3) + (lane & 7);
    const int b_kb  = ((lane >> 3) & 1) * 16;
    const int v_r  = ((lane >> 3) & 1) * 8 + (lane & 7);
    const int v_cb = (lane >> 4) * 16;

    uint32_t qf[4][4];
    float o[8][4];
#pragma unroll
    for (int j = 0; j < 8; j++)
#pragma unroll
        for (int k = 0; k < 4; k++) o[j][k] = 0.f;
    float ml0 = -1e30f, ml1 = -1e30f, ls0 = 0.f, ls1 = 0.f;

    for (int t = 0; t < 16; t++) {
        if (t < 15) CP_WAIT1(); else CP_WAIT0();
        __syncthreads();
        if (t == 0) {
#pragma unroll
            for (int kk = 0; kk < 4; kk++) {
                int r = wid * 16 + a_r16;
                uint32_t off = (uint32_t)(r * 128) + (uint32_t)((kk * 32 + a_kb) ^ ((r & 7) << 4));
                ldsm4(qf[kk], sb + FQ + off);
            }
        }
        uint32_t bufb = sb + FST + (uint32_t)(t & 1) * FSS;

        float s[8][4];
#pragma unroll
        for (int j = 0; j < 8; j++)
#pragma unroll
            for (int k = 0; k < 4; k++) s[j][k] = 0.f;
#pragma unroll
        for (int kk = 0; kk < 4; kk++) {
#pragma unroll
            for (int ntp = 0; ntp < 4; ntp++) {
                int r = ntp * 16 + b_r8;
                uint32_t off = (uint32_t)(r * 128) + (uint32_t)((kk * 32 + b_kb) ^ ((r & 7) << 4));
                uint32_t kf[4];
                ldsm4(kf, bufb + off);
                mma16816h(s[2 * ntp],     qf[kk], kf);
                mma16816h(s[2 * ntp + 1], qf[kk], kf + 2);
            }
        }

        float m0t = -1e30f, m1t = -1e30f;
#pragma unroll
        for (int j = 0; j < 8; j++) {
            m0t = fmaxf(m0t, fmaxf(s[j][0], s[j][1]));
            m1t = fmaxf(m1t, fmaxf(s[j][2], s[j][3]));
        }
        m0t = fmaxf(m0t, __shfl_xor_sync(0xffffffffu, m0t, 1));
        m0t = fmaxf(m0t, __shfl_xor_sync(0xffffffffu, m0t, 2));
        m1t = fmaxf(m1t, __shfl_xor_sync(0xffffffffu, m1t, 1));
        m1t = fmaxf(m1t, __shfl_xor_sync(0xffffffffu, m1t, 2));
        float mn0 = fmaxf(ml0, m0t), mn1 = fmaxf(ml1, m1t);
        float sc0 = exp2f(ml0 - mn0), sc1 = exp2f(ml1 - mn1);
        ml0 = mn0; ml1 = mn1;
        float r0 = 0.f, r1 = 0.f;
#pragma unroll
        for (int j = 0; j < 8; j++) {
            s[j][0] = exp2f(s[j][0] - mn0);
            s[j][1] = exp2f(s[j][1] - mn0);
            s[j][2] = exp2f(s[j][2] - mn1);
            s[j][3] = exp2f(s[j][3] - mn1);
            r0 += s[j][0] + s[j][1];
            r1 += s[j][2] + s[j][3];
        }
        r0 += __shfl_xor_sync(0xffffffffu, r0, 1);
        r0 += __shfl_xor_sync(0xffffffffu, r0, 2);
        r1 += __shfl_xor_sync(0xffffffffu, r1, 1);
        r1 += __shfl_xor_sync(0xffffffffu, r1, 2);
        ls0 = ls0 * sc0 + r0;
        ls1 = ls1 * sc1 + r1;
#pragma unroll
        for (int j = 0; j < 8; j++) {
            o[j][0] *= sc0; o[j][1] *= sc0;
            o[j][2] *= sc1; o[j][3] *= sc1;
        }

        uint32_t pa[4][4];
#pragma unroll
        for (int kt = 0; kt < 4; kt++) {
            pa[kt][0] = pack_h2(__float2half_rn(s[2 * kt][0]),     __float2half_rn(s[2 * kt][1]));
            pa[kt][1] = pack_h2(__float2half_rn(s[2 * kt][2]),     __float2half_rn(s[2 * kt][3]));
            pa[kt][2] = pack_h2(__float2half_rn(s[2 * kt + 1][0]), __float2half_rn(s[2 * kt + 1][1]));
            pa[kt][3] = pack_h2(__float2half_rn(s[2 * kt + 1][2]), __float2half_rn(s[2 * kt + 1][3]));
        }

#pragma unroll
        for (int kt = 0; kt < 4; kt++) {
#pragma unroll
            for (int nv = 0; nv < 4; nv++) {
                int r = kt * 16 + v_r;
                uint32_t off = (uint32_t)(r * 128) + (uint32_t)((nv * 32 + v_cb) ^ ((r & 7) << 4));
                uint32_t vf[4];
                ldsm4t(vf, bufb + 8192 + off);
                mma16816h(o[2 * nv],     pa[kt], vf);
                mma16816h(o[2 * nv + 1], pa[kt], vf + 2);
            }
        }
        __syncthreads();
        if (t + 2 < 16) load_kv(t + 2);
    }

    const int g = lane >> 2, t4 = lane & 3;
    float i0 = 1.f / ls0, i1 = 1.f / ls1;
    int tok0 = b * 1024 + q0 + wid * 16 + g;
    int tok1 = tok0 + 8;
#pragma unroll
    for (int j = 0; j < 8; j++) {
        int col = h * 64 + j * 8 + t4 * 2;
        *(uint32_t*)(g_h + (size_t)tok0 * CINC + col) =
            pack_h2(__float2half_rn(o[j][0] * i0), __float2half_rn(o[j][1] * i0));
        *(uint32_t*)(g_h + (size_t)tok1 * CINC + col) =
            pack_h2(__float2half_rn(o[j][2] * i1), __float2half_rn(o[j][3] * i1));
    }
}

// ---------------------------------------------------------------------------
// Expert permutation: single CTA
// ---------------------------------------------------------------------------
__global__ void __launch_bounds__(1024) perm_kernel(const int* __restrict__ em) {
    __shared__ int cnt[4], off[4], cur[4];
    int tid = threadIdx.x;
    if (tid < 4) { cnt[tid] = 0; cur[tid] = 0; }
    __syncthreads();
    int ev[8];
#pragma unroll
    for (int i = 0; i < 8; i++) {
        ev[i] = em[tid + i * 1024];
        atomicAdd(&cnt[ev[i]], 1);
    }
    __syncthreads();
    if (tid == 0) {
        int o = 0;
        for (int j = 0; j < 4; j++) { off[j] = o; g_goff[j] = o; g_cnt[j] = cnt[j]; o += cnt[j]; }
    }
    __syncthreads();
#pragma unroll
    for (int i = 0; i < 8; i++) {
        int p = atomicAdd(&cur[ev[i]], 1);
        g_perm[off[ev[i]] + p] = tid + i * 1024;
    }
}

// weight convert (fp32 -> fp16)
__global__ void convw_kernel(const float* __restrict__ s, __half* __restrict__ d) {
    size_t i = (size_t)blockIdx.x * 256 + threadIdx.x;
    float4 v = ((const float4*)s)[i];
    ((uint32_t*)d)[2 * i]     = pack_h2(__float2half_rn(v.x), __float2half_rn(v.y));
    ((uint32_t*)d)[2 * i + 1] = pack_h2(__float2half_rn(v.z), __float2half_rn(v.w));
}

// LN1 -> masked xn fp16
__global__ void ln1_kernel(const float* __restrict__ x, const int* __restrict__ em,
                           const float* __restrict__ g, const float* __restrict__ b) {
    int t = blockIdx.x;
    const float4* xr = (const float4*)(x + (size_t)t * DIMC);
    int tid = threadIdx.x;
    float4 v = xr[tid];
    float s  = v.x + v.y + v.z + v.w;
    float s2 = v.x * v.x + v.y * v.y + v.z * v.z + v.w * v.w;
#pragma unroll
    for (int o = 16; o; o >>= 1) { s += __shfl_xor_sync(0xffffffffu, s, o); s2 += __shfl_xor_sync(0xffffffffu, s2, o); }
    __shared__ float red[18];
    int w = tid >> 5, l = tid & 31;
    if (l == 0) { red[w] = s; red[8 + w] = s2; }
    __syncthreads();
    if (tid == 0) {
        float ts = 0.f, ts2 = 0.f;
        for (int i = 0; i < 8; i++) { ts += red[i]; ts2 += red[8 + i]; }
        float m = ts * (1.f / DIMC);
        float var = ts2 * (1.f / DIMC) - m * m;
        red[16] = m; red[17] = rsqrtf(var + 1e-5f);
    }
    __syncthreads();
    float m = red[16], rs = red[17];
    int din = DIMC >> (3 - em[t]);
    int c = tid * 4;
    float4 gg = ((const float4*)g)[tid];
    float4 bb = ((const float4*)b)[tid];
    float o0 = (c + 0 < din) ? ((v.x - m) * rs * gg.x + bb.x) : 0.f;
    float o1 = (c + 1 < din) ? ((v.y - m) * rs * gg.y + bb.y) : 0.f;
    float o2 = (c + 2 < din) ? ((v.z - m) * rs * gg.z + bb.z) : 0.f;
    float o3 = (c + 3 < din) ? ((v.w - m) * rs * gg.w + bb.w) : 0.f;
    size_t o = (size_t)t * DIMC + c;
    *(uint32_t*)(g_xn + o)     = pack_h2(__float2half_rn(o0), __float2half_rn(o1));
    *(uint32_t*)(g_xn + o + 2) = pack_h2(__float2half_rn(o2), __float2half_rn(o3));
}

// LN2: which==0 -> k, which==1 -> v. Reads fp16 pre-LN values, fp32 stats.
__global__ void ln2kv_kernel(const float* __restrict__ g, const float* __restrict__ b) {
    int t = blockIdx.x;
    int which = blockIdx.y;
    const __half* row = g_yh + (size_t)t * 2048 + (size_t)DIMC * which;
    int tid = threadIdx.x;
    uint2 raw = *(const uint2*)(row + tid * 4);
    __half2 p0 = *(__half2*)&raw.x;
    __half2 p1 = *(__half2*)&raw.y;
    float4 v = make_float4(__half2float(p0.x), __half2float(p0.y),
                           __half2float(p1.x), __half2float(p1.y));
    float s  = v.x + v.y + v.z + v.w;
    float s2 = v.x * v.x + v.y * v.y + v.z * v.z + v.w * v.w;
#pragma unroll
    for (int o = 16; o; o >>= 1) { s += __shfl_xor_sync(0xffffffffu, s, o); s2 += __shfl_xor_sync(0xffffffffu, s2, o); }
    __shared__ float red[18];
    int w = tid >> 5, l = tid & 31;
    if (l == 0) { red[w] = s; red[8 + w] = s2; }
    __syncthreads();
    if (tid == 0) {
        float ts = 0.f, ts2 = 0.f;
        for (int i = 0; i < 8; i++) { ts += red[i]; ts2 += red[8 + i]; }
        float m = ts * (1.f / DIMC);
        float var = ts2 * (1.f / DIMC) - m * m;
        red[16] = m; red[17] = rsqrtf(var + 1e-5f);
    }
    __syncthreads();
    float m = red[16], rs = red[17];
    int bb2 = t >> 10, ss = t & 1023;
    int c = tid * 4;
    float4 gg = ((const float4*)g)[tid];
    float4 bv = ((const float4*)b)[tid];
    float o0 = (v.x - m) * rs * gg.x + bv.x;
    float o1 = (v.y - m) * rs * gg.y + bv.y;
    float o2 = (v.z - m) * rs * gg.z + bv.z;
    float o3 = (v.w - m) * rs * gg.w + bv.w;
    int hh = c >> 6, hd = c & 63;
    size_t o = ((size_t)(bb2 * NHC + hh) * SEQC + ss) * HDC + hd;
    __half* d = which ? g_v : g_k;
    *(uint32_t*)(d + o)     = pack_h2(__float2half_rn(o0), __float2half_rn(o1));
    *(uint32_t*)(d + o + 2) = pack_h2(__float2half_rn(o2), __float2half_rn(o3));
}

// Final epilogue + pass-through tails (merged); z read as fp16
__global__ void final_kernel(const float* __restrict__ x, const int* __restrict__ em,
                             const float* __restrict__ rp, const float* __restrict__ cb,
                             const float* __restrict__ alpha, float* __restrict__ out) {
    size_t idx = (size_t)blockIdx.x * 256 + threadIdx.x;
    int t = (int)(idx >> 10);
    int d = (int)(idx & 1023);
    int m = em[t];
    int dout = (2 * DIMC) >> (3 - m);
    const __half* zr = g_zh + (size_t)t * 2048;
    float za = (d < dout) ? (__half2float(zr[d]) + cb[d]) : 0.f;
    float zm = (DIMC + d < dout) ? (__half2float(zr[DIMC + d]) + cb[DIMC + d]) : 0.f;
    float pr = rp[t * 4 + m];
    out[idx] = x[idx] + za + (alpha[0] * pr + 1.f) * zm;
    if (idx < TOK)     out[(size_t)TOK * DIMC + idx] = (float)em[idx];
    if (idx < TOK * 4) out[(size_t)TOK * DIMC + TOK + idx] = rp[idx];
}

// ---------------------------------------------------------------------------
extern "C" void kernel_launch(void* const* d_in, const int* in_sizes, int n_in,
                              void* d_out, int out_size) {
    const float* x     = (const float*)d_in[0];
    const int*   em    = (const int*)d_in[1];
    const float* rp    = (const float*)d_in[2];
    const float* wexp  = (const float*)d_in[3];
    const float* mlpb  = (const float*)d_in[4];
    const float* wc    = (const float*)d_in[5];
    const float* cb    = (const float*)d_in[6];
    const float* n1g   = (const float*)d_in[7];
    const float* n1b   = (const float*)d_in[8];
    const float* n2g   = (const float*)d_in[9];
    const float* n2b   = (const float*)d_in[10];
    const float* alpha = (const float*)d_in[11];
    float* out = (float*)d_out;

    __half *p_xn, *p_we, *p_wc, *p_h;
    cudaGetSymbolAddress((void**)&p_xn, g_xn);
    cudaGetSymbolAddress((void**)&p_we, g_we);
    cudaGetSymbolAddress((void**)&p_wc, g_wc);
    cudaGetSymbolAddress((void**)&p_h,  g_h);

    cudaFuncSetAttribute(gemm_grouped_kernel<0>, cudaFuncAttributeMaxDynamicSharedMemorySize, GSM);
    cudaFuncSetAttribute(gemm_grouped_kernel<1>, cudaFuncAttributeMaxDynamicSharedMemorySize, GSM);
    cudaFuncSetAttribute(flash_kernel,           cudaFuncAttributeMaxDynamicSharedMemorySize, FSM);

    // 0) expert permutation (single CTA)
    perm_kernel<<<1, 1024>>>(em);

    // 0b) weight converts (fp32 -> fp16)
    convw_kernel<<<(EXPC * DIMC) / 4 / 256, 256>>>(wexp, p_we);
    convw_kernel<<<(2 * DIMC * CINC) / 4 / 256, 256>>>(wc, p_wc);

    // 1) LN1 + input mask -> xn fp16
    ln1_kernel<<<TOK, 256>>>(x, em, n1g, n1b);

    // 2) expand (grouped, plain fp16, fused epilogue)
    gemm_grouped_kernel<1><<<dim3(EXPC / 128, TOK / 128, 4), 512, GSM>>>(
        p_xn, DIMC, p_we, DIMC, mlpb,
        128, 1, EXPC, 0);

    // 3) LN2 -> k and v per-head single fp16
    ln2kv_kernel<<<dim3(TOK, 2), 256>>>(n2g, n2b);

    // 4) flash attention (plain fp16) -> g_h fp16 [:, 0:1024]
    flash_kernel<<<dim3(SEQC / 128, BH), 256, FSM>>>();

    // 5) contract (grouped, plain fp16): z = h @ Wc^T -> g_zh fp16
    gemm_grouped_kernel<0><<<dim3(16, TOK / 128, 4), 512, GSM>>>(
        p_h, CINC, p_wc, CINC, nullptr,
        CINC, 0, 256, 1);

    // 6) epilogue + tails (merged)
    final_kernel<<<(TOK * DIMC) / 256, 256>>>(x, em, rp, cb, alpha, out);
}

// round 15
// speedup vs baseline: 13.0479x; 1.1275x over previous
#include <cuda_runtime.h>
#include <cuda_fp16.h>
#include <math.h>
#include <stdint.h>

// Problem constants
#define TOK   8192        // B*N
#define DIMC  1024
#define EXPC  7168
#define CINC  5120
#define NHC   16
#define HDC   64
#define SEQC  1024
#define NB    8
#define BH    (NB * NHC)  // 128 batch-heads

#define LOG2E 1.44269504088896340736f

// ---------------------------------------------------------------------------
// Scratch (device globals; allocation-free)
// ---------------------------------------------------------------------------
__device__ __half g_yh[(size_t)TOK * 2 * DIMC];               // k,v pre-LN fp16

__device__ __half g_xn[(size_t)TOK * DIMC];
__device__ __half g_we[(size_t)EXPC * DIMC];
__device__ __half g_wc[(size_t)2 * DIMC * CINC];
__device__ __half g_h [(size_t)TOK * CINC];

// attention operands (per-head [bh][seq][hd]; all single fp16)
__device__ __half g_q[(size_t)BH * SEQC * HDC];
__device__ __half g_k[(size_t)BH * SEQC * HDC];
__device__ __half g_v[(size_t)BH * SEQC * HDC];

// expert grouping
__device__ int g_cnt[4];
__device__ int g_goff[4];
__device__ int g_perm[TOK];

// ---------------------------------------------------------------------------
// PTX helpers
// ---------------------------------------------------------------------------
__device__ __forceinline__ uint32_t smem_u32(const void* p) {
    uint32_t a;
    asm("{ .reg .u64 t; cvta.to.shared.u64 t, %1; cvt.u32.u64 %0, t; }" : "=r"(a) : "l"(p));
    return a;
}
__device__ __forceinline__ void ldsm4(uint32_t* r, uint32_t a) {
    asm volatile("ldmatrix.sync.aligned.m8n8.x4.shared.b16 {%0,%1,%2,%3}, [%4];"
                 : "=r"(r[0]), "=r"(r[1]), "=r"(r[2]), "=r"(r[3]) : "r"(a));
}
__device__ __forceinline__ void ldsm4t(uint32_t* r, uint32_t a) {
    asm volatile("ldmatrix.sync.aligned.m8n8.x4.trans.shared.b16 {%0,%1,%2,%3}, [%4];"
                 : "=r"(r[0]), "=r"(r[1]), "=r"(r[2]), "=r"(r[3]) : "r"(a));
}
__device__ __forceinline__ void mma16816h(float* c, const uint32_t* a, const uint32_t* b) {
    asm volatile("mma.sync.aligned.m16n8k16.row.col.f32.f16.f16.f32 "
                 "{%0,%1,%2,%3}, {%4,%5,%6,%7}, {%8,%9}, {%0,%1,%2,%3};"
                 : "+f"(c[0]), "+f"(c[1]), "+f"(c[2]), "+f"(c[3])
                 : "r"(a[0]), "r"(a[1]), "r"(a[2]), "r"(a[3]), "r"(b[0]), "r"(b[1]));
}
__device__ __forceinline__ void cpa16(uint32_t s, const void* g) {
    asm volatile("cp.async.cg.shared.global [%0], [%1], 16;" :: "r"(s), "l"(g));
}
#define CP_COMMIT() asm volatile("cp.async.commit_group;")
#define CP_WAIT2()  asm volatile("cp.async.wait_group 2;")
#define CP_WAIT1()  asm volatile("cp.async.wait_group 1;")
#define CP_WAIT0()  asm volatile("cp.async.wait_group 0;")

#define SWZ(o) ((o) ^ (((o) >> 3) & 0x70))

__device__ __forceinline__ uint32_t pack_h2(__half a, __half b) {
    __half2 v(a, b);
    return *(uint32_t*)&v;
}
__device__ __forceinline__ float gelu1(float x) {
    return 0.5f * x * (1.f + erff(x * 0.70710678118654752f));
}

#define GOA  0
#define GOB  16384
#define GBUF 32768
#define GSM  (1024 + 3 * GBUF)    // 99328

// ---------------------------------------------------------------------------
// Expand GEMM (grouped, plain fp16) with fused epilogue.
// e = 3 - blockIdx.z (heavy experts scheduled first).
// ---------------------------------------------------------------------------
__global__ void __launch_bounds__(512, 2)
expand_kernel(const float* __restrict__ mlpb) {
    const int e = 3 - blockIdx.z;
    const int cnt  = g_cnt[e];
    const int goff = g_goff[e];
    const int m0 = blockIdx.y * 128;
    if (m0 >= cnt) return;
    const int K  = 128 << e;
    const int n0 = blockIdx.x * 128;

    extern __shared__ char smem_raw[];
    uint32_t sb0 = smem_u32(smem_raw);
    sb0 = (sb0 + 1023u) & ~1023u;
    int* tok = (int*)(smem_raw + (sb0 - smem_u32(smem_raw)));
    uint32_t sb = sb0 + 1024u;

    const int tid  = threadIdx.x;
    const int lane = tid & 31;
    const int wid  = tid >> 5;
    const int wm = wid & 3;
    const int wn = wid >> 2;

    if (tid < 128) {
        int gr = m0 + tid;
        tok[tid] = g_perm[goff + ((gr < cnt) ? gr : 0)];
    }
    __syncthreads();

    const __half* BB = g_we + (size_t)n0 * DIMC;
    const int NC = K / 64;

    auto load_chunk = [&](int c) {
        uint32_t bufb = sb + (uint32_t)(c % 3) * GBUF;
        int k0 = c * 64;
#pragma unroll
        for (int it = 0; it < 2; it++) {
            int i = tid + it * 512;
            int r = i >> 3, kg = i & 7;
            const __half* src = g_xn + (size_t)tok[r] * DIMC + k0 + kg * 8;
            cpa16(bufb + GOA + SWZ(r * 128 + kg * 16), src);
        }
#pragma unroll
        for (int it = 0; it < 2; it++) {
            int i = tid + it * 512;
            int r = i >> 3, kg = i & 7;
            const __half* src = BB + (size_t)r * DIMC + k0 + kg * 8;
            cpa16(bufb + GOB + SWZ(r * 128 + kg * 16), src);
        }
        CP_COMMIT();
    };

    load_chunk(0);
    if (NC > 1) load_chunk(1);

    float acc[2][4][4];
#pragma unroll
    for (int i = 0; i < 2; i++)
#pragma unroll
        for (int j = 0; j < 4; j++)
#pragma unroll
            for (int k = 0; k < 4; k++) acc[i][j][k] = 0.f;

    const int a_r16 = lane & 15;
    const int a_kb  = (lane >> 4) * 16;
    const int b_r8  = ((lane >> 4) << 3) + (lane & 7);
    const int b_kb  = ((lane >> 3) & 1) * 16;

    for (int c = 0; c < NC; c++) {
        if (c + 2 < NC) load_chunk(c + 2);
        int pend = NC - 1 - c; if (pend > 2) pend = 2;
        if (pend == 2) CP_WAIT2(); else if (pend == 1) CP_WAIT1(); else CP_WAIT0();
        __syncthreads();

        uint32_t bufb = sb + (uint32_t)(c % 3) * GBUF;
#pragma unroll
        for (int kk = 0; kk < 4; kk++) {
            int kb = kk * 32;
            uint32_t ah[2][4];
#pragma unroll
            for (int mt = 0; mt < 2; mt++) {
                int r = wm * 32 + mt * 16 + a_r16;
                uint32_t off = (uint32_t)(r * 128) + (uint32_t)((kb + a_kb) ^ ((r & 7) << 4));
                ldsm4(ah[mt], bufb + GOA + off);
            }
#pragma unroll
            for (int ntp = 0; ntp < 2; ntp++) {
                int r = wn * 32 + ntp * 16 + b_r8;
                uint32_t off = (uint32_t)(r * 128) + (uint32_t)((kb + b_kb) ^ ((r & 7) << 4));
                uint32_t bf[4];
                ldsm4(bf, bufb + GOB + off);
#pragma unroll
                for (int mt = 0; mt < 2; mt++) {
                    mma16816h(acc[mt][2 * ntp],     ah[mt], bf);
                    mma16816h(acc[mt][2 * ntp + 1], ah[mt], bf + 2);
                }
            }
        }
        __syncthreads();
    }

    const int g = lane >> 2, t4 = lane & 3;

#pragma unroll
    for (int mt = 0; mt < 2; mt++) {
        int r0 = wm * 32 + mt * 16 + g;
        int r1 = r0 + 8;
        int tk0 = tok[r0], tk1 = tok[r1];
        bool ok0 = (m0 + r0) < cnt, ok1 = (m0 + r1) < cnt;
        if (n0 < 1024) {
            // Q region: scale (1/8)*log2e -> g_q fp16 per-head layout
#pragma unroll
            for (int nt = 0; nt < 4; nt++) {
                int d = n0 + wn * 32 + nt * 8 + t4 * 2;
                int h = d >> 6, hd = d & 63;
                const float QS = 0.125f * LOG2E;
                if (ok0) {
                    size_t o = ((size_t)((tk0 >> 10) * NHC + h) * SEQC + (tk0 & 1023)) * HDC + hd;
                    *(uint32_t*)(g_q + o) = pack_h2(__float2half_rn(acc[mt][nt][0] * QS),
                                                   __float2half_rn(acc[mt][nt][1] * QS));
                }
                if (ok1) {
                    size_t o = ((size_t)((tk1 >> 10) * NHC + h) * SEQC + (tk1 & 1023)) * HDC + hd;
                    *(uint32_t*)(g_q + o) = pack_h2(__float2half_rn(acc[mt][nt][2] * QS),
                                                   __float2half_rn(acc[mt][nt][3] * QS));
                }
            }
        } else if (n0 < 3072) {
            // K/V region: fp16 to g_yh [TOK][2048]
#pragma unroll
            for (int nt = 0; nt < 4; nt++) {
                int col = n0 - 1024 + wn * 32 + nt * 8 + t4 * 2;
                if (ok0) *(uint32_t*)(g_yh + (size_t)tk0 * 2048 + col) =
                    pack_h2(__float2half_rn(acc[mt][nt][0]), __float2half_rn(acc[mt][nt][1]));
                if (ok1) *(uint32_t*)(g_yh + (size_t)tk1 * 2048 + col) =
                    pack_h2(__float2half_rn(acc[mt][nt][2]), __float2half_rn(acc[mt][nt][3]));
            }
        } else {
            // MLP region: +bias, GELU -> g_h fp16 [:, 1024+j]
#pragma unroll
            for (int nt = 0; nt < 4; nt++) {
                int j = n0 - 3072 + wn * 32 + nt * 8 + t4 * 2;
                float b0 = mlpb[j], b1 = mlpb[j + 1];
                if (ok0) {
                    __half u0 = __float2half_rn(gelu1(acc[mt][nt][0] + b0));
                    __half u1 = __float2half_rn(gelu1(acc[mt][nt][1] + b1));
                    *(uint32_t*)(g_h + (size_t)tk0 * CINC + 1024 + j) = pack_h2(u0, u1);
                }
                if (ok1) {
                    __half u0 = __float2half_rn(gelu1(acc[mt][nt][2] + b0));
                    __half u1 = __float2half_rn(gelu1(acc[mt][nt][3] + b1));
                    *(uint32_t*)(g_h + (size_t)tk1 * CINC + 1024 + j) = pack_h2(u0, u1);
                }
            }
        }
    }
}

// ---------------------------------------------------------------------------
// Contract GEMM fused with final epilogue.
// e < 3: 128-col attn tile (grid.x in [0,8)); d >= dout tiles copy x.
//        (dout = 256<<e is a multiple of 128, mlp half fully masked.)
// e == 3: 64 attn cols + 64 matching mlp cols; smem exchange; full formula.
// ---------------------------------------------------------------------------
__global__ void __launch_bounds__(512, 2)
contract_kernel(const float* __restrict__ x, const float* __restrict__ rp,
                const float* __restrict__ cb, const float* __restrict__ alpha,
                float* __restrict__ out) {
    const int e = blockIdx.z;
    const bool E3 = (e == 3);
    if (!E3 && blockIdx.x >= 8) return;
    const int cnt  = g_cnt[e];
    const int goff = g_goff[e];
    const int m0 = blockIdx.y * 128;
    if (m0 >= cnt) return;
    const int dout = 256 << e;
    const int d0 = E3 ? blockIdx.x * 64 : blockIdx.x * 128;

    extern __shared__ char smem_raw[];
    uint32_t sb0 = smem_u32(smem_raw);
    uint32_t pad = ((sb0 + 1023u) & ~1023u) - sb0;
    char* gb = smem_raw + pad;
    uint32_t sb = sb0 + pad + 1024u;
    int* tok = (int*)gb;

    const int tid  = threadIdx.x;
    const int lane = tid & 31;
    const int wid  = tid >> 5;
    const int wm = wid & 3;
    const int wn = wid >> 2;

    if (tid < 128) {
        int gr = m0 + tid;
        tok[tid] = g_perm[goff + ((gr < cnt) ? gr : 0)];
    }
    __syncthreads();

    // Copy-only tiles: out = x
    if (!E3 && d0 >= dout) {
#pragma unroll
        for (int it = 0; it < 8; it++) {
            int i = tid + it * 512;
            int r = i >> 5, c4 = i & 31;
            if (m0 + r < cnt) {
                int tk = tok[r];
                *(float4*)(out + (size_t)tk * DIMC + d0 + c4 * 4) =
                    *(const float4*)(x + (size_t)tk * DIMC + d0 + c4 * 4);
            }
        }
        return;
    }

    const int NC = CINC / 64;   // 80

    auto load_chunk = [&](int c) {
        uint32_t bufb = sb + (uint32_t)(c % 3) * GBUF;
        int k0 = c * 64;
#pragma unroll
        for (int it = 0; it < 2; it++) {
            int i = tid + it * 512;
            int r = i >> 3, kg = i & 7;
            const __half* src = g_h + (size_t)tok[r] * CINC + k0 + kg * 8;
            cpa16(bufb + GOA + SWZ(r * 128 + kg * 16), src);
        }
#pragma unroll
        for (int it = 0; it < 2; it++) {
            int i = tid + it * 512;
            int r = i >> 3, kg = i & 7;
            int rowg = (E3 && r >= 64) ? (960 + d0 + r) : (d0 + r);
            const __half* src = g_wc + (size_t)rowg * CINC + k0 + kg * 8;
            cpa16(bufb + GOB + SWZ(r * 128 + kg * 16), src);
        }
        CP_COMMIT();
    };

    load_chunk(0);
    load_chunk(1);

    float acc[2][4][4];
#pragma unroll
    for (int i = 0; i < 2; i++)
#pragma unroll
        for (int j = 0; j < 4; j++)
#pragma unroll
            for (int k = 0; k < 4; k++) acc[i][j][k] = 0.f;

    const int a_r16 = lane & 15;
    const int a_kb  = (lane >> 4) * 16;
    const int b_r8  = ((lane >> 4) << 3) + (lane & 7);
    const int b_kb  = ((lane >> 3) & 1) * 16;

    for (int c = 0; c < NC; c++) {
        if (c + 2 < NC) load_chunk(c + 2);
        int pend = NC - 1 - c; if (pend > 2) pend = 2;
        if (pend == 2) CP_WAIT2(); else if (pend == 1) CP_WAIT1(); else CP_WAIT0();
        __syncthreads();

        uint32_t bufb = sb + (uint32_t)(c % 3) * GBUF;
#pragma unroll
        for (int kk = 0; kk < 4; kk++) {
            int kb = kk * 32;
            uint32_t ah[2][4];
#pragma unroll
            for (int mt = 0; mt < 2; mt++) {
                int r = wm * 32 + mt * 16 + a_r16;
                uint32_t off = (uint32_t)(r * 128) + (uint32_t)((kb + a_kb) ^ ((r & 7) << 4));
                ldsm4(ah[mt], bufb + GOA + off);
            }
#pragma unroll
            for (int ntp = 0; ntp < 2; ntp++) {
                int r = wn * 32 + ntp * 16 + b_r8;
                uint32_t off = (uint32_t)(r * 128) + (uint32_t)((kb + b_kb) ^ ((r & 7) << 4));
                uint32_t bf[4];
                ldsm4(bf, bufb + GOB + off);
#pragma unroll
                for (int mt = 0; mt < 2; mt++) {
                    mma16816h(acc[mt][2 * ntp],     ah[mt], bf);
                    mma16816h(acc[mt][2 * ntp + 1], ah[mt], bf + 2);
                }
            }
        }
        __syncthreads();
    }

    const int g = lane >> 2, t4 = lane & 3;

    if (!E3) {
        // out = x + z + cb over full 128-col attn tile (all cols < dout)
#pragma unroll
        for (int mt = 0; mt < 2; mt++) {
            int r0 = wm * 32 + mt * 16 + g;
            int r1 = r0 + 8;
            int tk0 = tok[r0], tk1 = tok[r1];
            bool ok0 = (m0 + r0) < cnt, ok1 = (m0 + r1) < cnt;
#pragma unroll
            for (int nt = 0; nt < 4; nt++) {
                int d = d0 + wn * 32 + nt * 8 + t4 * 2;
                float c0 = cb[d], c1 = cb[d + 1];
                if (ok0) {
                    float2 xv = *(const float2*)(x + (size_t)tk0 * DIMC + d);
                    *(float2*)(out + (size_t)tk0 * DIMC + d) =
                        make_float2(xv.x + acc[mt][nt][0] + c0, xv.y + acc[mt][nt][1] + c1);
                }
                if (ok1) {
                    float2 xv = *(const float2*)(x + (size_t)tk1 * DIMC + d);
                    *(float2*)(out + (size_t)tk1 * DIMC + d) =
                        make_float2(xv.x + acc[mt][nt][2] + c0, xv.y + acc[mt][nt][3] + c1);
                }
            }
        }
    } else {
        // e==3: mlp warps (wn>=2) publish zm via smem; attn warps combine.
        float* zbuf = (float*)(gb + 1024);     // stage buffers dead; 128x65 floats
        float av = alpha[0];
        if (wn >= 2) {
#pragma unroll
            for (int mt = 0; mt < 2; mt++) {
                int r0 = wm * 32 + mt * 16 + g;
#pragma unroll
                for (int nt = 0; nt < 4; nt++) {
                    int c = (wn - 2) * 32 + nt * 8 + t4 * 2;
                    float c0 = cb[1024 + d0 + c], c1 = cb[1024 + d0 + c + 1];
                    zbuf[r0 * 65 + c]           = acc[mt][nt][0] + c0;
                    zbuf[r0 * 65 + c + 1]       = acc[mt][nt][1] + c1;
                    zbuf[(r0 + 8) * 65 + c]     = acc[mt][nt][2] + c0;
                    zbuf[(r0 + 8) * 65 + c + 1] = acc[mt][nt][3] + c1;
                }
            }
        }
        __syncthreads();
        if (wn < 2) {
#pragma unroll
            for (int mt = 0; mt < 2; mt++) {
                int r0 = wm * 32 + mt * 16 + g;
                int r1 = r0 + 8;
                int tk0 = tok[r0], tk1 = tok[r1];
                bool ok0 = (m0 + r0) < cnt, ok1 = (m0 + r1) < cnt;
                float s0 = ok0 ? (av * rp[tk0 * 4 + 3] + 1.f) : 0.f;
                float s1 = ok1 ? (av * rp[tk1 * 4 + 3] + 1.f) : 0.f;
#pragma unroll
                for (int nt = 0; nt < 4; nt++) {
                    int c = wn * 32 + nt * 8 + t4 * 2;
                    int d = d0 + c;
                    float c0 = cb[d], c1 = cb[d + 1];
                    if (ok0) {
                        float2 xv = *(const float2*)(x + (size_t)tk0 * DIMC + d);
                        float zm0 = zbuf[r0 * 65 + c], zm1 = zbuf[r0 * 65 + c + 1];
                        *(float2*)(out + (size_t)tk0 * DIMC + d) =
                            make_float2(xv.x + acc[mt][nt][0] + c0 + s0 * zm0,
                                        xv.y + acc[mt][nt][1] + c1 + s0 * zm1);
                    }
                    if (ok1) {
                        float2 xv = *(const float2*)(x + (size_t)tk1 * DIMC + d);
                        float zm0 = zbuf[r1 * 65 + c], zm1 = zbuf[r1 * 65 + c + 1];
                        *(float2*)(out + (size_t)tk1 * DIMC + d) =
                            make_float2(xv.x + acc[mt][nt][2] + c0 + s1 * zm0,
                                        xv.y + acc[mt][nt][3] + c1 + s1 * zm1);
                    }
                }
            }
        }
    }
}

// ---------------------------------------------------------------------------
// Flash attention (all single fp16): S = Q K, O = P V. 49 KB smem, 2 CTAs/SM.
// ---------------------------------------------------------------------------
#define FQ  0
#define FST 16384
#define FSS 16384
#define FSM (16384 + 2 * 16384 + 1024)

__global__ void __launch_bounds__(256, 2)
flash_kernel() {
    extern __shared__ char smem_raw[];
    uint32_t sb = smem_u32(smem_raw);
    sb = (sb + 1023u) & ~1023u;

    const int tid  = threadIdx.x;
    const int wid  = tid >> 5;
    const int lane = tid & 31;
    const int bh = blockIdx.y;
    const int q0 = blockIdx.x * 128;
    const int b = bh >> 4, h = bh & 15;

    const size_t base = (size_t)bh * SEQC * HDC;

    auto load_q = [&]() {
#pragma unroll
        for (int it = 0; it < 4; it++) {
            int i = tid + it * 256;
            int r = i >> 3, kg = i & 7;
            const __half* src = g_q + base + (size_t)(q0 + r) * HDC + kg * 8;
            cpa16(sb + FQ + SWZ(r * 128 + kg * 16), src);
        }
    };
    auto load_kv = [&](int t) {
        uint32_t bufb = sb + FST + (uint32_t)(t & 1) * FSS;
#pragma unroll
        for (int it = 0; it < 2; it++) {
            int i = tid + it * 256;
            int r = i >> 3, kg = i & 7;
            const __half* src = g_k + base + (size_t)(t * 64 + r) * HDC + kg * 8;
            cpa16(bufb + SWZ(r * 128 + kg * 16), src);
        }
#pragma unroll
        for (int it = 0; it < 2; it++) {
            int i = tid + it * 256;
            int r = i >> 3, kg = i & 7;
            const __half* src = g_v + base + (size_t)(t * 64 + r) * HDC + kg * 8;
            cpa16(bufb + 8192 + SWZ(r * 128 + kg * 16), src);
        }
        CP_COMMIT();
    };

    load_q(); load_kv(0); CP_COMMIT();
    load_kv(1);

    const int a_r16 = lane & 15;
    const int a_kb  = (lane >> 4) * 16;
    const int b_r8  = ((lane >> 4) << 3) + (lane & 7);
    const int b_kb  = ((lane >> 3) & 1) * 16;
    const int v_r  = ((lane >> 3) & 1) * 8 + (lane & 7);
    const int v_cb = (lane >> 4) * 16;

    uint32_t qf[4][4];
    float o[8][4];
#pragma unroll
    for (int j = 0; j < 8; j++)
#pragma unroll
        for (int k = 0; k < 4; k++) o[j][k] = 0.f;
    float ml0 = -1e30f, ml1 = -1e30f, ls0 = 0.f, ls1 = 0.f;

    for (int t = 0; t < 16; t++) {
        if (t < 15) CP_WAIT1(); else CP_WAIT0();
        __syncthreads();
        if (t == 0) {
#pragma unroll
            for (int kk = 0; kk < 4; kk++) {
                int r = wid * 16 + a_r16;
                uint32_t off = (uint32_t)(r * 128) + (uint32_t)((kk * 32 + a_kb) ^ ((r & 7) << 4));
                ldsm4(qf[kk], sb + FQ + off);
            }
        }
        uint32_t bufb = sb + FST + (uint32_t)(t & 1) * FSS;

        float s[8][4];
#pragma unroll
        for (int j = 0; j < 8; j++)
#pragma unroll
            for (int k = 0; k < 4; k++) s[j][k] = 0.f;
#pragma unroll
        for (int kk = 0; kk < 4; kk++) {
#pragma unroll
            for (int ntp = 0; ntp < 4; ntp++) {
                int r = ntp * 16 + b_r8;
                uint32_t off = (uint32_t)(r * 128) + (uint32_t)((kk * 32 + b_kb) ^ ((r & 7) << 4));
                uint32_t kf[4];
                ldsm4(kf, bufb + off);
                mma16816h(s[2 * ntp],     qf[kk], kf);
                mma16816h(s[2 * ntp + 1], qf[kk], kf + 2);
            }
        }

        float m0t = -1e30f, m1t = -1e30f;
#pragma unroll
        for (int j = 0; j < 8; j++) {
            m0t = fmaxf(m0t, fmaxf(s[j][0], s[j][1]));
            m1t = fmaxf(m1t, fmaxf(s[j][2], s[j][3]));
        }
        m0t = fmaxf(m0t, __shfl_xor_sync(0xffffffffu, m0t, 1));
        m0t = fmaxf(m0t, __shfl_xor_sync(0xffffffffu, m0t, 2));
        m1t = fmaxf(m1t, __shfl_xor_sync(0xffffffffu, m1t, 1));
        m1t = fmaxf(m1t, __shfl_xor_sync(0xffffffffu, m1t, 2));
        float mn0 = fmaxf(ml0, m0t), mn1 = fmaxf(ml1, m1t);
        float sc0 = exp2f(ml0 - mn0), sc1 = exp2f(ml1 - mn1);
        ml0 = mn0; ml1 = mn1;
        float r0 = 0.f, r1 = 0.f;
#pragma unroll
        for (int j = 0; j < 8; j++) {
            s[j][0] = exp2f(s[j][0] - mn0);
            s[j][1] = exp2f(s[j][1] - mn0);
            s[j][2] = exp2f(s[j][2] - mn1);
            s[j][3] = exp2f(s[j][3] - mn1);
            r0 += s[j][0] + s[j][1];
            r1 += s[j][2] + s[j][3];
        }
        r0 += __shfl_xor_sync(0xffffffffu, r0, 1);
        r0 += __shfl_xor_sync(0xffffffffu, r0, 2);
        r1 += __shfl_xor_sync(0xffffffffu, r1, 1);
        r1 += __shfl_xor_sync(0xffffffffu, r1, 2);
        ls0 = ls0 * sc0 + r0;
        ls1 = ls1 * sc1 + r1;
#pragma unroll
        for (int j = 0; j < 8; j++) {
            o[j][0] *= sc0; o[j][1] *= sc0;
            o[j][2] *= sc1; o[j][3] *= sc1;
        }

        uint32_t pa[4][4];
#pragma unroll
        for (int kt = 0; kt < 4; kt++) {
            pa[kt][0] = pack_h2(__float2half_rn(s[2 * kt][0]),     __float2half_rn(s[2 * kt][1]));
            pa[kt][1] = pack_h2(__float2half_rn(s[2 * kt][2]),     __float2half_rn(s[2 * kt][3]));
            pa[kt][2] = pack_h2(__float2half_rn(s[2 * kt + 1][0]), __float2half_rn(s[2 * kt + 1][1]));
            pa[kt][3] = pack_h2(__float2half_rn(s[2 * kt + 1][2]), __float2half_rn(s[2 * kt + 1][3]));
        }

#pragma unroll
        for (int kt = 0; kt < 4; kt++) {
#pragma unroll
            for (int nv = 0; nv < 4; nv++) {
                int r = kt * 16 + v_r;
                uint32_t off = (uint32_t)(r * 128) + (uint32_t)((nv * 32 + v_cb) ^ ((r & 7) << 4));
                uint32_t vf[4];
                ldsm4t(vf, bufb + 8192 + off);
                mma16816h(o[2 * nv],     pa[kt], vf);
                mma16816h(o[2 * nv + 1], pa[kt], vf + 2);
            }
        }
        __syncthreads();
        if (t + 2 < 16) load_kv(t + 2);
    }

    const int g = lane >> 2, t4 = lane & 3;
    float i0 = 1.f / ls0, i1 = 1.f / ls1;
    int tok0 = b * 1024 + q0 + wid * 16 + g;
    int tok1 = tok0 + 8;
#pragma unroll
    for (int j = 0; j < 8; j++) {
        int col = h * 64 + j * 8 + t4 * 2;
        *(uint32_t*)(g_h + (size_t)tok0 * CINC + col) =
            pack_h2(__float2half_rn(o[j][0] * i0), __float2half_rn(o[j][1] * i0));
        *(uint32_t*)(g_h + (size_t)tok1 * CINC + col) =
            pack_h2(__float2half_rn(o[j][2] * i1), __float2half_rn(o[j][3] * i1));
    }
}

// ---------------------------------------------------------------------------
// Expert permutation (single CTA) + pass-through output tails
// ---------------------------------------------------------------------------
__global__ void __launch_bounds__(1024) perm_kernel(const int* __restrict__ em,
                                                    const float* __restrict__ rp,
                                                    float* __restrict__ out) {
    __shared__ int cnt[4], off[4], cur[4];
    int tid = threadIdx.x;
    if (tid < 4) { cnt[tid] = 0; cur[tid] = 0; }
    __syncthreads();
    int ev[8];
#pragma unroll
    for (int i = 0; i < 8; i++) {
        ev[i] = em[tid + i * 1024];
        atomicAdd(&cnt[ev[i]], 1);
    }
    __syncthreads();
    if (tid == 0) {
        int o = 0;
        for (int j = 0; j < 4; j++) { off[j] = o; g_goff[j] = o; g_cnt[j] = cnt[j]; o += cnt[j]; }
    }
    __syncthreads();
#pragma unroll
    for (int i = 0; i < 8; i++) {
        int p = atomicAdd(&cur[ev[i]], 1);
        g_perm[off[ev[i]] + p] = tid + i * 1024;
        out[(size_t)TOK * DIMC + tid + i * 1024] = (float)ev[i];
    }
#pragma unroll
    for (int i = 0; i < 32; i++) {
        int j = tid + i * 1024;
        out[(size_t)TOK * DIMC + TOK + j] = rp[j];
    }
}

// merged weight convert (fp32 -> fp16), both matrices in one launch
#define NW1 ((EXPC * DIMC) / 4)
__global__ void convw_kernel(const float* __restrict__ we, const float* __restrict__ wc,
                             __half* __restrict__ dwe, __half* __restrict__ dwc) {
    size_t i = (size_t)blockIdx.x * 256 + threadIdx.x;
    const float* s; __half* d; size_t j;
    if (i < NW1) { s = we; d = dwe; j = i; }
    else         { s = wc; d = dwc; j = i - NW1; }
    float4 v = ((const float4*)s)[j];
    ((uint32_t*)d)[2 * j]     = pack_h2(__float2half_rn(v.x), __float2half_rn(v.y));
    ((uint32_t*)d)[2 * j + 1] = pack_h2(__float2half_rn(v.z), __float2half_rn(v.w));
}

// LN1, warp-per-token (no CTA barrier). grid TOK/8, block 256.
__global__ void __launch_bounds__(256)
ln1_kernel(const float* __restrict__ x, const int* __restrict__ em,
           const float* __restrict__ g, const float* __restrict__ b) {
    int wid = threadIdx.x >> 5, lane = threadIdx.x & 31;
    int t = blockIdx.x * 8 + wid;
    const float4* xr = (const float4*)(x + (size_t)t * DIMC);
    float4 v[8];
    float s = 0.f, s2 = 0.f;
#pragma unroll
    for (int i = 0; i < 8; i++) {
        v[i] = xr[i * 32 + lane];
        s  += v[i].x + v[i].y + v[i].z + v[i].w;
        s2 += v[i].x * v[i].x + v[i].y * v[i].y + v[i].z * v[i].z + v[i].w * v[i].w;
    }
#pragma unroll
    for (int o = 16; o; o >>= 1) { s += __shfl_xor_sync(0xffffffffu, s, o); s2 += __shfl_xor_sync(0xffffffffu, s2, o); }
    float m = s * (1.f / DIMC);
    float rs = rsqrtf(s2 * (1.f / DIMC) - m * m + 1e-5f);
    int din = DIMC >> (3 - em[t]);
#pragma unroll
    for (int i = 0; i < 8; i++) {
        int c = i * 128 + lane * 4;
        float4 gg = ((const float4*)g)[i * 32 + lane];
        float4 bb = ((const float4*)b)[i * 32 + lane];
        float o0 = (c + 0 < din) ? ((v[i].x - m) * rs * gg.x + bb.x) : 0.f;
        float o1 = (c + 1 < din) ? ((v[i].y - m) * rs * gg.y + bb.y) : 0.f;
        float o2 = (c + 2 < din) ? ((v[i].z - m) * rs * gg.z + bb.z) : 0.f;
        float o3 = (c + 3 < din) ? ((v[i].w - m) * rs * gg.w + bb.w) : 0.f;
        size_t o = (size_t)t * DIMC + c;
        *(uint32_t*)(g_xn + o)     = pack_h2(__float2half_rn(o0), __float2half_rn(o1));
        *(uint32_t*)(g_xn + o + 2) = pack_h2(__float2half_rn(o2), __float2half_rn(o3));
    }
}

// LN2 warp-per-row: which==0 -> k, which==1 -> v. grid (TOK/8, 2), block 256.
__global__ void __launch_bounds__(256)
ln2kv_kernel(const float* __restrict__ g, const float* __restrict__ b) {
    int wid = threadIdx.x >> 5, lane = threadIdx.x & 31;
    int t = blockIdx.x * 8 + wid;
    int which = blockIdx.y;
    const __half* row = g_yh + (size_t)t * 2048 + (size_t)DIMC * which;
    float4 v[8];
    float s = 0.f, s2 = 0.f;
#pragma unroll
    for (int i = 0; i < 8; i++) {
        uint2 raw = *(const uint2*)(row + i * 128 + lane * 4);
        __half2 p0 = *(__half2*)&raw.x;
        __half2 p1 = *(__half2*)&raw.y;
        v[i] = make_float4(__half2float(p0.x), __half2float(p0.y),
                           __half2float(p1.x), __half2float(p1.y));
        s  += v[i].x + v[i].y + v[i].z + v[i].w;
        s2 += v[i].x * v[i].x + v[i].y * v[i].y + v[i].z * v[i].z + v[i].w * v[i].w;
    }
#pragma unroll
    for (int o = 16; o; o >>= 1) { s += __shfl_xor_sync(0xffffffffu, s, o); s2 += __shfl_xor_sync(0xffffffffu, s2, o); }
    float m = s * (1.f / DIMC);
    float rs = rsqrtf(s2 * (1.f / DIMC) - m * m + 1e-5f);
    int bb2 = t >> 10, ss = t & 1023;
    __half* d = which ? g_v : g_k;
#pragma unroll
    for (int i = 0; i < 8; i++) {
        int c = i * 128 + lane * 4;
        float4 gg = ((const float4*)g)[i * 32 + lane];
        float4 bv = ((const float4*)b)[i * 32 + lane];
        float o0 = (v[i].x - m) * rs * gg.x + bv.x;
        float o1 = (v[i].y - m) * rs * gg.y + bv.y;
        float o2 = (v[i].z - m) * rs * gg.z + bv.z;
        float o3 = (v[i].w - m) * rs * gg.w + bv.w;
        int hh = c >> 6, hd = c & 63;
        size_t o = ((size_t)(bb2 * NHC + hh) * SEQC + ss) * HDC + hd;
        *(uint32_t*)(d + o)     = pack_h2(__float2half_rn(o0), __float2half_rn(o1));
        *(uint32_t*)(d + o + 2) = pack_h2(__float2half_rn(o2), __float2half_rn(o3));
    }
}

// ---------------------------------------------------------------------------
extern "C" void kernel_launch(void* const* d_in, const int* in_sizes, int n_in,
                              void* d_out, int out_size) {
    const float* x     = (const float*)d_in[0];
    const int*   em    = (const int*)d_in[1];
    const float* rp    = (const float*)d_in[2];
    const float* wexp  = (const float*)d_in[3];
    const float* mlpb  = (const float*)d_in[4];
    const float* wc    = (const float*)d_in[5];
    const float* cb    = (const float*)d_in[6];
    const float* n1g   = (const float*)d_in[7];
    const float* n1b   = (const float*)d_in[8];
    const float* n2g   = (const float*)d_in[9];
    const float* n2b   = (const float*)d_in[10];
    const float* alpha = (const float*)d_in[11];
    float* out = (float*)d_out;

    __half *p_we, *p_wc;
    cudaGetSymbolAddress((void**)&p_we, g_we);
    cudaGetSymbolAddress((void**)&p_wc, g_wc);

    cudaFuncSetAttribute(expand_kernel,   cudaFuncAttributeMaxDynamicSharedMemorySize, GSM);
    cudaFuncSetAttribute(contract_kernel, cudaFuncAttributeMaxDynamicSharedMemorySize, GSM);
    cudaFuncSetAttribute(flash_kernel,    cudaFuncAttributeMaxDynamicSharedMemorySize, FSM);

    // 0) expert permutation + pass-through tails
    perm_kernel<<<1, 1024>>>(em, rp, out);

    // 0b) weight converts (merged)
    convw_kernel<<<(NW1 + (2 * DIMC * CINC) / 4) / 256, 256>>>(wexp, wc, p_we, p_wc);

    // 1) LN1 + input mask -> xn fp16 (warp per token)
    ln1_kernel<<<TOK / 8, 256>>>(x, em, n1g, n1b);

    // 2) expand (grouped, heavy experts first)
    expand_kernel<<<dim3(EXPC / 128, TOK / 128, 4), 512, GSM>>>(mlpb);

    // 3) LN2 -> k and v per-head fp16 (warp per row)
    ln2kv_kernel<<<dim3(TOK / 8, 2), 256>>>(n2g, n2b);

    // 4) flash attention -> g_h fp16 [:, 0:1024]
    flash_kernel<<<dim3(SEQC / 128, BH), 256, FSM>>>();

    // 5) contract fused with final epilogue -> out
    contract_kernel<<<dim3(16, TOK / 128, 4), 512, GSM>>>(x, rp, cb, alpha, out);
}

// round 16
// speedup vs baseline: 14.1558x; 1.0849x over previous
#include <cuda_runtime.h>
#include <cuda_fp16.h>
#include <math.h>
#include <stdint.h>

// Problem constants
#define TOK   8192        // B*N
#define DIMC  1024
#define EXPC  7168
#define CINC  5120
#define NHC   16
#define HDC   64
#define SEQC  1024
#define NB    8
#define BH    (NB * NHC)  // 128 batch-heads

#define LOG2E 1.44269504088896340736f

// ---------------------------------------------------------------------------
// Scratch (device globals; allocation-free)
// ---------------------------------------------------------------------------
__device__ __half g_yh[(size_t)TOK * 2 * DIMC];               // k,v pre-LN fp16

__device__ __half g_xn[(size_t)TOK * DIMC];
__device__ __half g_we[(size_t)EXPC * DIMC];
__device__ __half g_wc[(size_t)2 * DIMC * CINC];
__device__ __half g_h [(size_t)TOK * CINC];

// attention operands (per-head [bh][seq][hd]; all single fp16)
__device__ __half g_q[(size_t)BH * SEQC * HDC];
__device__ __half g_k[(size_t)BH * SEQC * HDC];
__device__ __half g_v[(size_t)BH * SEQC * HDC];

// expert grouping
__device__ int g_cnt[4];
__device__ int g_goff[4];
__device__ int g_perm[TOK];

// ---------------------------------------------------------------------------
// PTX helpers
// ---------------------------------------------------------------------------
__device__ __forceinline__ uint32_t smem_u32(const void* p) {
    uint32_t a;
    asm("{ .reg .u64 t; cvta.to.shared.u64 t, %1; cvt.u32.u64 %0, t; }" : "=r"(a) : "l"(p));
    return a;
}
__device__ __forceinline__ void ldsm4(uint32_t* r, uint32_t a) {
    asm volatile("ldmatrix.sync.aligned.m8n8.x4.shared.b16 {%0,%1,%2,%3}, [%4];"
                 : "=r"(r[0]), "=r"(r[1]), "=r"(r[2]), "=r"(r[3]) : "r"(a));
}
__device__ __forceinline__ void ldsm4t(uint32_t* r, uint32_t a) {
    asm volatile("ldmatrix.sync.aligned.m8n8.x4.trans.shared.b16 {%0,%1,%2,%3}, [%4];"
                 : "=r"(r[0]), "=r"(r[1]), "=r"(r[2]), "=r"(r[3]) : "r"(a));
}
__device__ __forceinline__ void mma16816h(float* c, const uint32_t* a, const uint32_t* b) {
    asm volatile("mma.sync.aligned.m16n8k16.row.col.f32.f16.f16.f32 "
                 "{%0,%1,%2,%3}, {%4,%5,%6,%7}, {%8,%9}, {%0,%1,%2,%3};"
                 : "+f"(c[0]), "+f"(c[1]), "+f"(c[2]), "+f"(c[3])
                 : "r"(a[0]), "r"(a[1]), "r"(a[2]), "r"(a[3]), "r"(b[0]), "r"(b[1]));
}
__device__ __forceinline__ void cpa16(uint32_t s, const void* g) {
    asm volatile("cp.async.cg.shared.global [%0], [%1], 16;" :: "r"(s), "l"(g));
}
#define CP_COMMIT() asm volatile("cp.async.commit_group;")
#define CP_WAIT2()  asm volatile("cp.async.wait_group 2;")
#define CP_WAIT1()  asm volatile("cp.async.wait_group 1;")
#define CP_WAIT0()  asm volatile("cp.async.wait_group 0;")

#define SWZ(o) ((o) ^ (((o) >> 3) & 0x70))

__device__ __forceinline__ uint32_t pack_h2(__half a, __half b) {
    __half2 v(a, b);
    return *(uint32_t*)&v;
}
__device__ __forceinline__ float gelu1(float x) {
    return 0.5f * x * (1.f + erff(x * 0.70710678118654752f));
}

#define GOA  0
#define GOB  16384
#define GBUF 32768
#define GSM  (1024 + 3 * GBUF)    // 99328

// ---------------------------------------------------------------------------
// Expand GEMM (grouped, plain fp16), 256 thr, 8 warps (2m x 4n), warp 64x32.
// e = 3 - blockIdx.z (heavy experts first). Fused epilogue by n-region.
// ---------------------------------------------------------------------------
__global__ void __launch_bounds__(256, 2)
expand_kernel(const float* __restrict__ mlpb) {
    const int e = 3 - blockIdx.z;
    const int cnt  = g_cnt[e];
    const int goff = g_goff[e];
    const int m0 = blockIdx.y * 128;
    if (m0 >= cnt) return;
    const int K  = 128 << e;
    const int n0 = blockIdx.x * 128;

    extern __shared__ char smem_raw[];
    uint32_t sb0 = smem_u32(smem_raw);
    sb0 = (sb0 + 1023u) & ~1023u;
    int* tok = (int*)(smem_raw + (sb0 - smem_u32(smem_raw)));
    uint32_t sb = sb0 + 1024u;

    const int tid  = threadIdx.x;
    const int lane = tid & 31;
    const int wid  = tid >> 5;
    const int wm = wid & 1;      // 64-row band
    const int wn = wid >> 1;     // 32-col band

    if (tid < 128) {
        int gr = m0 + tid;
        tok[tid] = g_perm[goff + ((gr < cnt) ? gr : 0)];
    }
    __syncthreads();

    const __half* BB = g_we + (size_t)n0 * DIMC;
    const int NC = K / 64;

    auto load_chunk = [&](int c) {
        uint32_t bufb = sb + (uint32_t)(c % 3) * GBUF;
        int k0 = c * 64;
#pragma unroll
        for (int it = 0; it < 4; it++) {
            int i = tid + it * 256;
            int r = i >> 3, kg = i & 7;
            const __half* src = g_xn + (size_t)tok[r] * DIMC + k0 + kg * 8;
            cpa16(bufb + GOA + SWZ(r * 128 + kg * 16), src);
        }
#pragma unroll
        for (int it = 0; it < 4; it++) {
            int i = tid + it * 256;
            int r = i >> 3, kg = i & 7;
            const __half* src = BB + (size_t)r * DIMC + k0 + kg * 8;
            cpa16(bufb + GOB + SWZ(r * 128 + kg * 16), src);
        }
        CP_COMMIT();
    };

    load_chunk(0);
    if (NC > 1) load_chunk(1);

    float acc[4][4][4];
#pragma unroll
    for (int i = 0; i < 4; i++)
#pragma unroll
        for (int j = 0; j < 4; j++)
#pragma unroll
            for (int k = 0; k < 4; k++) acc[i][j][k] = 0.f;

    const int a_r16 = lane & 15;
    const int a_kb  = (lane >> 4) * 16;
    const int b_r8  = ((lane >> 4) << 3) + (lane & 7);
    const int b_kb  = ((lane >> 3) & 1) * 16;

    for (int c = 0; c < NC; c++) {
        if (c + 2 < NC) load_chunk(c + 2);
        int pend = NC - 1 - c; if (pend > 2) pend = 2;
        if (pend == 2) CP_WAIT2(); else if (pend == 1) CP_WAIT1(); else CP_WAIT0();
        __syncthreads();

        uint32_t bufb = sb + (uint32_t)(c % 3) * GBUF;
#pragma unroll
        for (int kk = 0; kk < 4; kk++) {
            int kb = kk * 32;
            uint32_t ah[4][4];
#pragma unroll
            for (int mt = 0; mt < 4; mt++) {
                int r = wm * 64 + mt * 16 + a_r16;
                uint32_t off = (uint32_t)(r * 128) + (uint32_t)((kb + a_kb) ^ ((r & 7) << 4));
                ldsm4(ah[mt], bufb + GOA + off);
            }
#pragma unroll
            for (int ntp = 0; ntp < 2; ntp++) {
                int r = wn * 32 + ntp * 16 + b_r8;
                uint32_t off = (uint32_t)(r * 128) + (uint32_t)((kb + b_kb) ^ ((r & 7) << 4));
                uint32_t bf[4];
                ldsm4(bf, bufb + GOB + off);
#pragma unroll
                for (int mt = 0; mt < 4; mt++) {
                    mma16816h(acc[mt][2 * ntp],     ah[mt], bf);
                    mma16816h(acc[mt][2 * ntp + 1], ah[mt], bf + 2);
                }
            }
        }
        __syncthreads();
    }

    const int g = lane >> 2, t4 = lane & 3;

#pragma unroll
    for (int mt = 0; mt < 4; mt++) {
        int r0 = wm * 64 + mt * 16 + g;
        int r1 = r0 + 8;
        int tk0 = tok[r0], tk1 = tok[r1];
        bool ok0 = (m0 + r0) < cnt, ok1 = (m0 + r1) < cnt;
        if (n0 < 1024) {
#pragma unroll
            for (int nt = 0; nt < 4; nt++) {
                int d = n0 + wn * 32 + nt * 8 + t4 * 2;
                int h = d >> 6, hd = d & 63;
                const float QS = 0.125f * LOG2E;
                if (ok0) {
                    size_t o = ((size_t)((tk0 >> 10) * NHC + h) * SEQC + (tk0 & 1023)) * HDC + hd;
                    *(uint32_t*)(g_q + o) = pack_h2(__float2half_rn(acc[mt][nt][0] * QS),
                                                   __float2half_rn(acc[mt][nt][1] * QS));
                }
                if (ok1) {
                    size_t o = ((size_t)((tk1 >> 10) * NHC + h) * SEQC + (tk1 & 1023)) * HDC + hd;
                    *(uint32_t*)(g_q + o) = pack_h2(__float2half_rn(acc[mt][nt][2] * QS),
                                                   __float2half_rn(acc[mt][nt][3] * QS));
                }
            }
        } else if (n0 < 3072) {
#pragma unroll
            for (int nt = 0; nt < 4; nt++) {
                int col = n0 - 1024 + wn * 32 + nt * 8 + t4 * 2;
                if (ok0) *(uint32_t*)(g_yh + (size_t)tk0 * 2048 + col) =
                    pack_h2(__float2half_rn(acc[mt][nt][0]), __float2half_rn(acc[mt][nt][1]));
                if (ok1) *(uint32_t*)(g_yh + (size_t)tk1 * 2048 + col) =
                    pack_h2(__float2half_rn(acc[mt][nt][2]), __float2half_rn(acc[mt][nt][3]));
            }
        } else {
#pragma unroll
            for (int nt = 0; nt < 4; nt++) {
                int j = n0 - 3072 + wn * 32 + nt * 8 + t4 * 2;
                float b0 = mlpb[j], b1 = mlpb[j + 1];
                if (ok0) {
                    __half u0 = __float2half_rn(gelu1(acc[mt][nt][0] + b0));
                    __half u1 = __float2half_rn(gelu1(acc[mt][nt][1] + b1));
                    *(uint32_t*)(g_h + (size_t)tk0 * CINC + 1024 + j) = pack_h2(u0, u1);
                }
                if (ok1) {
                    __half u0 = __float2half_rn(gelu1(acc[mt][nt][2] + b0));
                    __half u1 = __float2half_rn(gelu1(acc[mt][nt][3] + b1));
                    *(uint32_t*)(g_h + (size_t)tk1 * CINC + 1024 + j) = pack_h2(u0, u1);
                }
            }
        }
    }
}

// ---------------------------------------------------------------------------
// Contract GEMM fused with final epilogue. 256 thr, warp 64x32.
// e < 3: 128-col attn tile; d >= dout tiles copy x.
// e == 3: 64 attn + 64 mlp cols; smem exchange (wn>=2 = mlp half).
// ---------------------------------------------------------------------------
__global__ void __launch_bounds__(256, 2)
contract_kernel(const float* __restrict__ x, const float* __restrict__ rp,
                const float* __restrict__ cb, const float* __restrict__ alpha,
                float* __restrict__ out) {
    const int e = blockIdx.z;
    const bool E3 = (e == 3);
    if (!E3 && blockIdx.x >= 8) return;
    const int cnt  = g_cnt[e];
    const int goff = g_goff[e];
    const int m0 = blockIdx.y * 128;
    if (m0 >= cnt) return;
    const int dout = 256 << e;
    const int d0 = E3 ? blockIdx.x * 64 : blockIdx.x * 128;

    extern __shared__ char smem_raw[];
    uint32_t sb0 = smem_u32(smem_raw);
    uint32_t pad = ((sb0 + 1023u) & ~1023u) - sb0;
    char* gb = smem_raw + pad;
    uint32_t sb = sb0 + pad + 1024u;
    int* tok = (int*)gb;

    const int tid  = threadIdx.x;
    const int lane = tid & 31;
    const int wid  = tid >> 5;
    const int wm = wid & 1;
    const int wn = wid >> 1;

    if (tid < 128) {
        int gr = m0 + tid;
        tok[tid] = g_perm[goff + ((gr < cnt) ? gr : 0)];
    }
    __syncthreads();

    if (!E3 && d0 >= dout) {
#pragma unroll
        for (int it = 0; it < 16; it++) {
            int i = tid + it * 256;
            int r = i >> 5, c4 = i & 31;
            if (m0 + r < cnt) {
                int tk = tok[r];
                *(float4*)(out + (size_t)tk * DIMC + d0 + c4 * 4) =
                    *(const float4*)(x + (size_t)tk * DIMC + d0 + c4 * 4);
            }
        }
        return;
    }

    const int NC = CINC / 64;   // 80

    auto load_chunk = [&](int c) {
        uint32_t bufb = sb + (uint32_t)(c % 3) * GBUF;
        int k0 = c * 64;
#pragma unroll
        for (int it = 0; it < 4; it++) {
            int i = tid + it * 256;
            int r = i >> 3, kg = i & 7;
            const __half* src = g_h + (size_t)tok[r] * CINC + k0 + kg * 8;
            cpa16(bufb + GOA + SWZ(r * 128 + kg * 16), src);
        }
#pragma unroll
        for (int it = 0; it < 4; it++) {
            int i = tid + it * 256;
            int r = i >> 3, kg = i & 7;
            int rowg = (E3 && r >= 64) ? (960 + d0 + r) : (d0 + r);
            const __half* src = g_wc + (size_t)rowg * CINC + k0 + kg * 8;
            cpa16(bufb + GOB + SWZ(r * 128 + kg * 16), src);
        }
        CP_COMMIT();
    };

    load_chunk(0);
    load_chunk(1);

    float acc[4][4][4];
#pragma unroll
    for (int i = 0; i < 4; i++)
#pragma unroll
        for (int j = 0; j < 4; j++)
#pragma unroll
            for (int k = 0; k < 4; k++) acc[i][j][k] = 0.f;

    const int a_r16 = lane & 15;
    const int a_kb  = (lane >> 4) * 16;
    const int b_r8  = ((lane >> 4) << 3) + (lane & 7);
    const int b_kb  = ((lane >> 3) & 1) * 16;

    for (int c = 0; c < NC; c++) {
        if (c + 2 < NC) load_chunk(c + 2);
        int pend = NC - 1 - c; if (pend > 2) pend = 2;
        if (pend == 2) CP_WAIT2(); else if (pend == 1) CP_WAIT1(); else CP_WAIT0();
        __syncthreads();

        uint32_t bufb = sb + (uint32_t)(c % 3) * GBUF;
#pragma unroll
        for (int kk = 0; kk < 4; kk++) {
            int kb = kk * 32;
            uint32_t ah[4][4];
#pragma unroll
            for (int mt = 0; mt < 4; mt++) {
                int r = wm * 64 + mt * 16 + a_r16;
                uint32_t off = (uint32_t)(r * 128) + (uint32_t)((kb + a_kb) ^ ((r & 7) << 4));
                ldsm4(ah[mt], bufb + GOA + off);
            }
#pragma unroll
            for (int ntp = 0; ntp < 2; ntp++) {
                int r = wn * 32 + ntp * 16 + b_r8;
                uint32_t off = (uint32_t)(r * 128) + (uint32_t)((kb + b_kb) ^ ((r & 7) << 4));
                uint32_t bf[4];
                ldsm4(bf, bufb + GOB + off);
#pragma unroll
                for (int mt = 0; mt < 4; mt++) {
                    mma16816h(acc[mt][2 * ntp],     ah[mt], bf);
                    mma16816h(acc[mt][2 * ntp + 1], ah[mt], bf + 2);
                }
            }
        }
        __syncthreads();
    }

    const int g = lane >> 2, t4 = lane & 3;

    if (!E3) {
#pragma unroll
        for (int mt = 0; mt < 4; mt++) {
            int r0 = wm * 64 + mt * 16 + g;
            int r1 = r0 + 8;
            int tk0 = tok[r0], tk1 = tok[r1];
            bool ok0 = (m0 + r0) < cnt, ok1 = (m0 + r1) < cnt;
#pragma unroll
            for (int nt = 0; nt < 4; nt++) {
                int d = d0 + wn * 32 + nt * 8 + t4 * 2;
                float c0 = cb[d], c1 = cb[d + 1];
                if (ok0) {
                    float2 xv = *(const float2*)(x + (size_t)tk0 * DIMC + d);
                    *(float2*)(out + (size_t)tk0 * DIMC + d) =
                        make_float2(xv.x + acc[mt][nt][0] + c0, xv.y + acc[mt][nt][1] + c1);
                }
                if (ok1) {
                    float2 xv = *(const float2*)(x + (size_t)tk1 * DIMC + d);
                    *(float2*)(out + (size_t)tk1 * DIMC + d) =
                        make_float2(xv.x + acc[mt][nt][2] + c0, xv.y + acc[mt][nt][3] + c1);
                }
            }
        }
    } else {
        float* zbuf = (float*)(gb + 1024);
        float av = alpha[0];
        if (wn >= 2) {
#pragma unroll
            for (int mt = 0; mt < 4; mt++) {
                int r0 = wm * 64 + mt * 16 + g;
#pragma unroll
                for (int nt = 0; nt < 4; nt++) {
                    int c = (wn - 2) * 32 + nt * 8 + t4 * 2;
                    float c0 = cb[1024 + d0 + c], c1 = cb[1024 + d0 + c + 1];
                    zbuf[r0 * 65 + c]           = acc[mt][nt][0] + c0;
                    zbuf[r0 * 65 + c + 1]       = acc[mt][nt][1] + c1;
                    zbuf[(r0 + 8) * 65 + c]     = acc[mt][nt][2] + c0;
                    zbuf[(r0 + 8) * 65 + c + 1] = acc[mt][nt][3] + c1;
                }
            }
        }
        __syncthreads();
        if (wn < 2) {
#pragma unroll
            for (int mt = 0; mt < 4; mt++) {
                int r0 = wm * 64 + mt * 16 + g;
                int r1 = r0 + 8;
                int tk0 = tok[r0], tk1 = tok[r1];
                bool ok0 = (m0 + r0) < cnt, ok1 = (m0 + r1) < cnt;
                float s0 = ok0 ? (av * rp[tk0 * 4 + 3] + 1.f) : 0.f;
                float s1 = ok1 ? (av * rp[tk1 * 4 + 3] + 1.f) : 0.f;
#pragma unroll
                for (int nt = 0; nt < 4; nt++) {
                    int c = wn * 32 + nt * 8 + t4 * 2;
                    int d = d0 + c;
                    float c0 = cb[d], c1 = cb[d + 1];
                    if (ok0) {
                        float2 xv = *(const float2*)(x + (size_t)tk0 * DIMC + d);
                        float zm0 = zbuf[r0 * 65 + c], zm1 = zbuf[r0 * 65 + c + 1];
                        *(float2*)(out + (size_t)tk0 * DIMC + d) =
                            make_float2(xv.x + acc[mt][nt][0] + c0 + s0 * zm0,
                                        xv.y + acc[mt][nt][1] + c1 + s0 * zm1);
                    }
                    if (ok1) {
                        float2 xv = *(const float2*)(x + (size_t)tk1 * DIMC + d);
                        float zm0 = zbuf[r1 * 65 + c], zm1 = zbuf[r1 * 65 + c + 1];
                        *(float2*)(out + (size_t)tk1 * DIMC + d) =
                            make_float2(xv.x + acc[mt][nt][2] + c0 + s1 * zm0,
                                        xv.y + acc[mt][nt][3] + c1 + s1 * zm1);
                    }
                }
            }
        }
    }
}

// ---------------------------------------------------------------------------
// Flash attention (all single fp16): S = Q K, O = P V. 49 KB smem, 2 CTAs/SM.
// ---------------------------------------------------------------------------
#define FQ  0
#define FST 16384
#define FSS 16384
#define FSM (16384 + 2 * 16384 + 1024)

__global__ void __launch_bounds__(256, 2)
flash_kernel() {
    extern __shared__ char smem_raw[];
    uint32_t sb = smem_u32(smem_raw);
    sb = (sb + 1023u) & ~1023u;

    const int tid  = threadIdx.x;
    const int wid  = tid >> 5;
    const int lane = tid & 31;
    const int bh = blockIdx.y;
    const int q0 = blockIdx.x * 128;
    const int b = bh >> 4, h = bh & 15;

    const size_t base = (size_t)bh * SEQC * HDC;

    auto load_q = [&]() {
#pragma unroll
        for (int it = 0; it < 4; it++) {
            int i = tid + it * 256;
            int r = i >> 3, kg = i & 7;
            const __half* src = g_q + base + (size_t)(q0 + r) * HDC + kg * 8;
            cpa16(sb + FQ + SWZ(r * 128 + kg * 16), src);
        }
    };
    auto load_kv = [&](int t) {
        uint32_t bufb = sb + FST + (uint32_t)(t & 1) * FSS;
#pragma unroll
        for (int it = 0; it < 2; it++) {
            int i = tid + it * 256;
            int r = i >> 3, kg = i & 7;
            const __half* src = g_k + base + (size_t)(t * 64 + r) * HDC + kg * 8;
            cpa16(bufb + SWZ(r * 128 + kg * 16), src);
        }
#pragma unroll
        for (int it = 0; it < 2; it++) {
            int i = tid + it * 256;
            int r = i >> 3, kg = i & 7;
            const __half* src = g_v + base + (size_t)(t * 64 + r) * HDC + kg * 8;
            cpa16(bufb + 8192 + SWZ(r * 128 + kg * 16), src);
        }
        CP_COMMIT();
    };

    load_q(); load_kv(0); CP_COMMIT();
    load_kv(1);

    const int a_r16 = lane & 15;
    const int a_kb  = (lane >> 4) * 16;
    const int b_r8  = ((lane >> 4) << 3) + (lane & 7);
    const int b_kb  = ((lane >> 3) & 1) * 16;
    const int v_r  = ((lane >> 3) & 1) * 8 + (lane & 7);
    const int v_cb = (lane >> 4) * 16;

    uint32_t qf[4][4];
    float o[8][4];
#pragma unroll
    for (int j = 0; j < 8; j++)
#pragma unroll
        for (int k = 0; k < 4; k++) o[j][k] = 0.f;
    float ml0 = -1e30f, ml1 = -1e30f, ls0 = 0.f, ls1 = 0.f;

    for (int t = 0; t < 16; t++) {
        if (t < 15) CP_WAIT1(); else CP_WAIT0();
        __syncthreads();
        if (t == 0) {
#pragma unroll
            for (int kk = 0; kk < 4; kk++) {
                int r = wid * 16 + a_r16;
                uint32_t off = (uint32_t)(r * 128) + (uint32_t)((kk * 32 + a_kb) ^ ((r & 7) << 4));
                ldsm4(qf[kk], sb + FQ + off);
            }
        }
        uint32_t bufb = sb + FST + (uint32_t)(t & 1) * FSS;

        float s[8][4];
#pragma unroll
        for (int j = 0; j < 8; j++)
#pragma unroll
            for (int k = 0; k < 4; k++) s[j][k] = 0.f;
#pragma unroll
        for (int kk = 0; kk < 4; kk++) {
#pragma unroll
            for (int ntp = 0; ntp < 4; ntp++) {
                int r = ntp * 16 + b_r8;
                uint32_t off = (uint32_t)(r * 128) + (uint32_t)((kk * 32 + b_kb) ^ ((r & 7) << 4));
                uint32_t kf[4];
                ldsm4(kf, bufb + off);
                mma16816h(s[2 * ntp],     qf[kk], kf);
                mma16816h(s[2 * ntp + 1], qf[kk], kf + 2);
            }
        }

        float m0t = -1e30f, m1t = -1e30f;
#pragma unroll
        for (int j = 0; j < 8; j++) {
            m0t = fmaxf(m0t, fmaxf(s[j][0], s[j][1]));
            m1t = fmaxf(m1t, fmaxf(s[j][2], s[j][3]));
        }
        m0t = fmaxf(m0t, __shfl_xor_sync(0xffffffffu, m0t, 1));
        m0t = fmaxf(m0t, __shfl_xor_sync(0xffffffffu, m0t, 2));
        m1t = fmaxf(m1t, __shfl_xor_sync(0xffffffffu, m1t, 1));
        m1t = fmaxf(m1t, __shfl_xor_sync(0xffffffffu, m1t, 2));
        float mn0 = fmaxf(ml0, m0t), mn1 = fmaxf(ml1, m1t);
        float sc0 = exp2f(ml0 - mn0), sc1 = exp2f(ml1 - mn1);
        ml0 = mn0; ml1 = mn1;
        float r0 = 0.f, r1 = 0.f;
#pragma unroll
        for (int j = 0; j < 8; j++) {
            s[j][0] = exp2f(s[j][0] - mn0);
            s[j][1] = exp2f(s[j][1] - mn0);
            s[j][2] = exp2f(s[j][2] - mn1);
            s[j][3] = exp2f(s[j][3] - mn1);
            r0 += s[j][0] + s[j][1];
            r1 += s[j][2] + s[j][3];
        }
        r0 += __shfl_xor_sync(0xffffffffu, r0, 1);
        r0 += __shfl_xor_sync(0xffffffffu, r0, 2);
        r1 += __shfl_xor_sync(0xffffffffu, r1, 1);
        r1 += __shfl_xor_sync(0xffffffffu, r1, 2);
        ls0 = ls0 * sc0 + r0;
        ls1 = ls1 * sc1 + r1;
#pragma unroll
        for (int j = 0; j < 8; j++) {
            o[j][0] *= sc0; o[j][1] *= sc0;
            o[j][2] *= sc1; o[j][3] *= sc1;
        }

        uint32_t pa[4][4];
#pragma unroll
        for (int kt = 0; kt < 4; kt++) {
            pa[kt][0] = pack_h2(__float2half_rn(s[2 * kt][0]),     __float2half_rn(s[2 * kt][1]));
            pa[kt][1] = pack_h2(__float2half_rn(s[2 * kt][2]),     __float2half_rn(s[2 * kt][3]));
            pa[kt][2] = pack_h2(__float2half_rn(s[2 * kt + 1][0]), __float2half_rn(s[2 * kt + 1][1]));
            pa[kt][3] = pack_h2(__float2half_rn(s[2 * kt + 1][2]), __float2half_rn(s[2 * kt + 1][3]));
        }

#pragma unroll
        for (int kt = 0; kt < 4; kt++) {
#pragma unroll
            for (int nv = 0; nv < 4; nv++) {
                int r = kt * 16 + v_r;
                uint32_t off = (uint32_t)(r * 128) + (uint32_t)((nv * 32 + v_cb) ^ ((r & 7) << 4));
                uint32_t vf[4];
                ldsm4t(vf, bufb + 8192 + off);
                mma16816h(o[2 * nv],     pa[kt], vf);
                mma16816h(o[2 * nv + 1], pa[kt], vf + 2);
            }
        }
        __syncthreads();
        if (t + 2 < 16) load_kv(t + 2);
    }

    const int g = lane >> 2, t4 = lane & 3;
    float i0 = 1.f / ls0, i1 = 1.f / ls1;
    int tok0 = b * 1024 + q0 + wid * 16 + g;
    int tok1 = tok0 + 8;
#pragma unroll
    for (int j = 0; j < 8; j++) {
        int col = h * 64 + j * 8 + t4 * 2;
        *(uint32_t*)(g_h + (size_t)tok0 * CINC + col) =
            pack_h2(__float2half_rn(o[j][0] * i0), __float2half_rn(o[j][1] * i0));
        *(uint32_t*)(g_h + (size_t)tok1 * CINC + col) =
            pack_h2(__float2half_rn(o[j][2] * i1), __float2half_rn(o[j][3] * i1));
    }
}

// ---------------------------------------------------------------------------
// Expert permutation (single CTA) + pass-through output tails
// ---------------------------------------------------------------------------
__global__ void __launch_bounds__(1024) perm_kernel(const int* __restrict__ em,
                                                    const float* __restrict__ rp,
                                                    float* __restrict__ out) {
    __shared__ int cnt[4], off[4], cur[4];
    int tid = threadIdx.x;
    if (tid < 4) { cnt[tid] = 0; cur[tid] = 0; }
    __syncthreads();
    int ev[8];
#pragma unroll
    for (int i = 0; i < 8; i++) {
        ev[i] = em[tid + i * 1024];
        atomicAdd(&cnt[ev[i]], 1);
    }
    __syncthreads();
    if (tid == 0) {
        int o = 0;
        for (int j = 0; j < 4; j++) { off[j] = o; g_goff[j] = o; g_cnt[j] = cnt[j]; o += cnt[j]; }
    }
    __syncthreads();
#pragma unroll
    for (int i = 0; i < 8; i++) {
        int p = atomicAdd(&cur[ev[i]], 1);
        g_perm[off[ev[i]] + p] = tid + i * 1024;
        out[(size_t)TOK * DIMC + tid + i * 1024] = (float)ev[i];
    }
#pragma unroll
    for (int i = 0; i < 32; i++) {
        int j = tid + i * 1024;
        out[(size_t)TOK * DIMC + TOK + j] = rp[j];
    }
}

// merged weight convert (fp32 -> fp16)
#define NW1 ((EXPC * DIMC) / 4)
__global__ void convw_kernel(const float* __restrict__ we, const float* __restrict__ wc,
                             __half* __restrict__ dwe, __half* __restrict__ dwc) {
    size_t i = (size_t)blockIdx.x * 256 + threadIdx.x;
    const float* s; __half* d; size_t j;
    if (i < NW1) { s = we; d = dwe; j = i; }
    else         { s = wc; d = dwc; j = i - NW1; }
    float4 v = ((const float4*)s)[j];
    ((uint32_t*)d)[2 * j]     = pack_h2(__float2half_rn(v.x), __float2half_rn(v.y));
    ((uint32_t*)d)[2 * j + 1] = pack_h2(__float2half_rn(v.z), __float2half_rn(v.w));
}

// LN1, warp-per-token. grid TOK/8, block 256.
__global__ void __launch_bounds__(256)
ln1_kernel(const float* __restrict__ x, const int* __restrict__ em,
           const float* __restrict__ g, const float* __restrict__ b) {
    int wid = threadIdx.x >> 5, lane = threadIdx.x & 31;
    int t = blockIdx.x * 8 + wid;
    const float4* xr = (const float4*)(x + (size_t)t * DIMC);
    float4 v[8];
    float s = 0.f, s2 = 0.f;
#pragma unroll
    for (int i = 0; i < 8; i++) {
        v[i] = xr[i * 32 + lane];
        s  += v[i].x + v[i].y + v[i].z + v[i].w;
        s2 += v[i].x * v[i].x + v[i].y * v[i].y + v[i].z * v[i].z + v[i].w * v[i].w;
    }
#pragma unroll
    for (int o = 16; o; o >>= 1) { s += __shfl_xor_sync(0xffffffffu, s, o); s2 += __shfl_xor_sync(0xffffffffu, s2, o); }
    float m = s * (1.f / DIMC);
    float rs = rsqrtf(s2 * (1.f / DIMC) - m * m + 1e-5f);
    int din = DIMC >> (3 - em[t]);
#pragma unroll
    for (int i = 0; i < 8; i++) {
        int c = i * 128 + lane * 4;
        float4 gg = ((const float4*)g)[i * 32 + lane];
        float4 bb = ((const float4*)b)[i * 32 + lane];
        float o0 = (c + 0 < din) ? ((v[i].x - m) * rs * gg.x + bb.x) : 0.f;
        float o1 = (c + 1 < din) ? ((v[i].y - m) * rs * gg.y + bb.y) : 0.f;
        float o2 = (c + 2 < din) ? ((v[i].z - m) * rs * gg.z + bb.z) : 0.f;
        float o3 = (c + 3 < din) ? ((v[i].w - m) * rs * gg.w + bb.w) : 0.f;
        size_t o = (size_t)t * DIMC + c;
        *(uint32_t*)(g_xn + o)     = pack_h2(__float2half_rn(o0), __float2half_rn(o1));
        *(uint32_t*)(g_xn + o + 2) = pack_h2(__float2half_rn(o2), __float2half_rn(o3));
    }
}

// LN2 warp-per-row: which==0 -> k, which==1 -> v. grid (TOK/8, 2), block 256.
__global__ void __launch_bounds__(256)
ln2kv_kernel(const float* __restrict__ g, const float* __restrict__ b) {
    int wid = threadIdx.x >> 5, lane = threadIdx.x & 31;
    int t = blockIdx.x * 8 + wid;
    int which = blockIdx.y;
    const __half* row = g_yh + (size_t)t * 2048 + (size_t)DIMC * which;
    float4 v[8];
    float s = 0.f, s2 = 0.f;
#pragma unroll
    for (int i = 0; i < 8; i++) {
        uint2 raw = *(const uint2*)(row + i * 128 + lane * 4);
        __half2 p0 = *(__half2*)&raw.x;
        __half2 p1 = *(__half2*)&raw.y;
        v[i] = make_float4(__half2float(p0.x), __half2float(p0.y),
                           __half2float(p1.x), __half2float(p1.y));
        s  += v[i].x + v[i].y + v[i].z + v[i].w;
        s2 += v[i].x * v[i].x + v[i].y * v[i].y + v[i].z * v[i].z + v[i].w * v[i].w;
    }
#pragma unroll
    for (int o = 16; o; o >>= 1) { s += __shfl_xor_sync(0xffffffffu, s, o); s2 += __shfl_xor_sync(0xffffffffu, s2, o); }
    float m = s * (1.f / DIMC);
    float rs = rsqrtf(s2 * (1.f / DIMC) - m * m + 1e-5f);
    int bb2 = t >> 10, ss = t & 1023;
    __half* d = which ? g_v : g_k;
#pragma unroll
    for (int i = 0; i < 8; i++) {
        int c = i * 128 + lane * 4;
        float4 gg = ((const float4*)g)[i * 32 + lane];
        float4 bv = ((const float4*)b)[i * 32 + lane];
        float o0 = (v[i].x - m) * rs * gg.x + bv.x;
        float o1 = (v[i].y - m) * rs * gg.y + bv.y;
        float o2 = (v[i].z - m) * rs * gg.z + bv.z;
        float o3 = (v[i].w - m) * rs * gg.w + bv.w;
        int hh = c >> 6, hd = c & 63;
        size_t o = ((size_t)(bb2 * NHC + hh) * SEQC + ss) * HDC + hd;
        *(uint32_t*)(d + o)     = pack_h2(__float2half_rn(o0), __float2half_rn(o1));
        *(uint32_t*)(d + o + 2) = pack_h2(__float2half_rn(o2), __float2half_rn(o3));
    }
}

// ---------------------------------------------------------------------------
extern "C" void kernel_launch(void* const* d_in, const int* in_sizes, int n_in,
                              void* d_out, int out_size) {
    const float* x     = (const float*)d_in[0];
    const int*   em    = (const int*)d_in[1];
    const float* rp    = (const float*)d_in[2];
    const float* wexp  = (const float*)d_in[3];
    const float* mlpb  = (const float*)d_in[4];
    const float* wc    = (const float*)d_in[5];
    const float* cb    = (const float*)d_in[6];
    const float* n1g   = (const float*)d_in[7];
    const float* n1b   = (const float*)d_in[8];
    const float* n2g   = (const float*)d_in[9];
    const float* n2b   = (const float*)d_in[10];
    const float* alpha = (const float*)d_in[11];
    float* out = (float*)d_out;

    __half *p_we, *p_wc;
    cudaGetSymbolAddress((void**)&p_we, g_we);
    cudaGetSymbolAddress((void**)&p_wc, g_wc);

    cudaFuncSetAttribute(expand_kernel,   cudaFuncAttributeMaxDynamicSharedMemorySize, GSM);
    cudaFuncSetAttribute(contract_kernel, cudaFuncAttributeMaxDynamicSharedMemorySize, GSM);
    cudaFuncSetAttribute(flash_kernel,    cudaFuncAttributeMaxDynamicSharedMemorySize, FSM);

    // 0) expert permutation + pass-through tails
    perm_kernel<<<1, 1024>>>(em, rp, out);

    // 0b) weight converts (merged)
    convw_kernel<<<(NW1 + (2 * DIMC * CINC) / 4) / 256, 256>>>(wexp, wc, p_we, p_wc);

    // 1) LN1 + input mask -> xn fp16 (warp per token)
    ln1_kernel<<<TOK / 8, 256>>>(x, em, n1g, n1b);

    // 2) expand (grouped, heavy experts first)
    expand_kernel<<<dim3(EXPC / 128, TOK / 128, 4), 256, GSM>>>(mlpb);

    // 3) LN2 -> k and v per-head fp16 (warp per row)
    ln2kv_kernel<<<dim3(TOK / 8, 2), 256>>>(n2g, n2b);

    // 4) flash attention -> g_h fp16 [:, 0:1024]
    flash_kernel<<<dim3(SEQC / 128, BH), 256, FSM>>>();

    // 5) contract fused with final epilogue -> out
    contract_kernel<<<dim3(16, TOK / 128, 4), 256, GSM>>>(x, rp, cb, alpha, out);
}